// round 2
// baseline (speedup 1.0000x reference)
#include <cuda_runtime.h>
#include <math.h>

#define BATCH 4
#define CIN 256
#define COUT 128
#define HH 64
#define WW 64
#define HW 4096
#define BN 64
#define KT 16

typedef unsigned long long ull;

// ---------------- scratch (static device globals; no allocs) ----------------
__device__ float g_xc[BATCH * CIN * HW];          // 16 MB
__device__ float g_x1[BATCH * COUT * HW];         // 8 MB
__device__ float g_cat[BATCH * 5 * CIN * HW];     // 80 MB
__device__ float g_proj[BATCH * CIN * HW];        // 16 MB
__device__ float g_xa[BATCH * COUT * HW];         // 8 MB
__device__ float g_O[BATCH * COUT * HW];          // 8 MB
__device__ float g_S[(size_t)BATCH * HW * HW];    // 268 MB (attention scores/probs)
__device__ float g_w3[3 * 9 * CIN * CIN];         // 7 MB transposed conv3x3 weights
__device__ float g_avg[BATCH * CIN];
__device__ float g_mx[BATCH * CIN];
__device__ float g_s[BATCH * CIN];
__device__ float g_bp[BATCH * CIN];

__device__ __forceinline__ float gelu_f(float x) {
    return 0.5f * x * (1.0f + erff(x * 0.70710678118654752440f));
}

// ---------------- packed f32x2 helpers ----------------
__device__ __forceinline__ ull pack2f(float x) {
    ull r; asm("mov.b64 %0, {%1, %1};" : "=l"(r) : "f"(x)); return r;
}
__device__ __forceinline__ ull pack2(float x, float y) {
    ull r; asm("mov.b64 %0, {%1, %2};" : "=l"(r) : "f"(x), "f"(y)); return r;
}
__device__ __forceinline__ void fma2(ull& d, ull a, ull b) {
    asm("fma.rn.f32x2 %0, %1, %2, %0;" : "+l"(d) : "l"(a), "l"(b));
}
__device__ __forceinline__ float2 unpk2(ull v) {
    float2 f; asm("mov.b64 {%0, %1}, %2;" : "=f"(f.x), "=f"(f.y) : "l"(v)); return f;
}

// ---------------- per-(b,c) mean & max over HW ----------------
__global__ void k_stats(const float* __restrict__ x) {
    int bc = blockIdx.x;
    const float* p = x + (size_t)bc * HW;
    int t = threadIdx.x;
    float s = 0.f, m = -1e30f;
    for (int i = t; i < HW; i += 256) { float v = p[i]; s += v; m = fmaxf(m, v); }
    __shared__ float ss[256], sm[256];
    ss[t] = s; sm[t] = m; __syncthreads();
    for (int o = 128; o > 0; o >>= 1) {
        if (t < o) { ss[t] += ss[t + o]; sm[t] = fmaxf(sm[t], sm[t + o]); }
        __syncthreads();
    }
    if (t == 0) { g_avg[bc] = ss[0] * (1.f / HW); g_mx[bc] = sm[0]; }
}

// ---------------- channel weighting MLP + global-pool ASPP branch ----------------
__global__ void k_cw(const float* __restrict__ w1, const float* __restrict__ bb1,
                     const float* __restrict__ lg, const float* __restrict__ lb,
                     const float* __restrict__ w2, const float* __restrict__ bb2,
                     const float* __restrict__ apw, const float* __restrict__ apg,
                     const float* __restrict__ apb) {
    int b = blockIdx.x, t = threadIdx.x;
    __shared__ float o[CIN];
    __shared__ float h[COUT];
    __shared__ float red[256];
    __shared__ float gp[CIN];
    float avg = g_avg[b * CIN + t], mx = g_mx[b * CIN + t];
    o[t] = fabsf(avg - mx) * avg;
    __syncthreads();
    float hv = 0.f;
    if (t < COUT) {
        hv = bb1[t];
        const float* wr = w1 + t * CIN;
        for (int i = 0; i < CIN; i++) hv = fmaf(o[i], wr[i], hv);
    }
    red[t] = (t < COUT) ? hv : 0.f; __syncthreads();
    for (int s = 128; s > 0; s >>= 1) { if (t < s) red[t] += red[t + s]; __syncthreads(); }
    float mu = red[0] * (1.f / COUT); __syncthreads();
    float dv = (t < COUT) ? (hv - mu) : 0.f;
    red[t] = dv * dv; __syncthreads();
    for (int s = 128; s > 0; s >>= 1) { if (t < s) red[t] += red[t + s]; __syncthreads(); }
    float var = red[0] * (1.f / COUT); __syncthreads();
    if (t < COUT) h[t] = lg[t] * ((hv - mu) * rsqrtf(var + 1e-5f)) + lb[t];
    __syncthreads();
    float sv = bb2[t];
    const float* wr2 = w2 + t * COUT;
    for (int j = 0; j < COUT; j++) sv = fmaf(h[j], wr2[j], sv);
    float sig = 1.f / (1.f + expf(-sv));
    g_s[b * CIN + t] = sig;
    gp[t] = (1.f + sig) * avg;     // mean of xc = (1+s) * mean(x)
    __syncthreads();
    float v = 0.f;
    const float* ar = apw + t * CIN;
    for (int i = 0; i < CIN; i++) v = fmaf(ar[i], gp[i], v);
    red[t] = v; __syncthreads();
    for (int s = 128; s > 0; s >>= 1) { if (t < s) red[t] += red[t + s]; __syncthreads(); }
    float mu2 = red[0] * (1.f / CIN); __syncthreads();
    float d2 = v - mu2; red[t] = d2 * d2; __syncthreads();
    for (int s = 128; s > 0; s >>= 1) { if (t < s) red[t] += red[t + s]; __syncthreads(); }
    float var2 = red[0] * (1.f / CIN); __syncthreads();
    float z = apg[t] * ((v - mu2) * rsqrtf(var2 + 1e-6f)) + apb[t];
    g_bp[b * CIN + t] = gelu_f(z);
}

// ---------------- xc = x * (1 + s) ----------------
__global__ void k_xc(const float* __restrict__ x) {
    int idx = blockIdx.x * 256 + threadIdx.x;
    const int n4 = BATCH * CIN * HW / 4;
    if (idx < n4) {
        int bc = idx / (HW / 4);
        float sc = 1.f + g_s[bc];
        float4 v = reinterpret_cast<const float4*>(x)[idx];
        v.x *= sc; v.y *= sc; v.z *= sc; v.w *= sc;
        reinterpret_cast<float4*>(g_xc)[idx] = v;
    }
}

// ---------------- broadcast bp into cat channels [1024,1280) ----------------
__global__ void k_bp() {
    int bc = blockIdx.x;
    int b = bc >> 8, c = bc & 255;
    float v = g_bp[bc];
    float4* dst = reinterpret_cast<float4*>(g_cat + ((size_t)b * 5 * CIN + 4 * CIN + c) * HW);
    float4 v4 = make_float4(v, v, v, v);
    for (int i = threadIdx.x; i < HW / 4; i += 256) dst[i] = v4;
}

// ---------------- transpose conv3x3 weights to [tap][m][c] ----------------
__global__ void k_transw(const float* __restrict__ w1, const float* __restrict__ w2,
                         const float* __restrict__ w3) {
    int e = blockIdx.x * 256 + threadIdx.x;   // 3 * 256 * 256
    if (e >= 3 * 65536) return;
    const float* srcs[3] = { w1, w2, w3 };
    int conv = e >> 16, mc = e & 65535, m = mc >> 8, c = mc & 255;
    const float* src = srcs[conv] + (size_t)m * 2304 + (size_t)c * 9;
    float* dst = g_w3 + (size_t)conv * 9 * 65536 + (size_t)m * 256 + c;
#pragma unroll
    for (int tap = 0; tap < 9; tap++) dst[(size_t)tap * 65536] = src[tap];
}

// ---------------- generic GEMM: Out[b,m,n] = sum_k W[m,k] * In[b,k,n] ----------------
// MODE 0: + bias[m]
// MODE 1: channels-first LayerNorm over m (eps 1e-6) + exact GELU (needs BM == M == 256)
// MODE 2: + Add[b,m,n]
// CONV3: implicit dilated 3x3 over taps; W is g_w3 layout [tap][m][c] (Kc=256), In is xc.
template <int BM, int MODE, bool CONV3>
__global__ void __launch_bounds__(256) k_gemm(
    const float* __restrict__ Wg, size_t wb_stride,
    const float* __restrict__ In, size_t in_bstride,
    const float* __restrict__ P1, const float* __restrict__ P2,
    const float* __restrict__ Addp, size_t add_bstride,
    float* __restrict__ Out, size_t out_bstride,
    int Kc, int dil) {
    constexpr int TM = BM / 32;
    const int b = blockIdx.y;
    const int y = blockIdx.x;          // spatial row; n0 = y*64
    const int n0 = y * BN;
    const int t = threadIdx.x;
    const int ty = t >> 3, tx = t & 7;

    __shared__ __align__(16) float As[KT][BM];
    __shared__ __align__(16) float Bs[KT][BN];
    __shared__ float red[(MODE == 1) ? 32 : 1][BN];
    __shared__ float cmean[BN], crstd[BN];

    ull acc2[TM][4];
#pragma unroll
    for (int i = 0; i < TM; i++)
#pragma unroll
        for (int j = 0; j < 4; j++) acc2[i][j] = 0ULL;

    const float* Wb = Wg + (size_t)b * wb_stride;
    const float* Inb = In + (size_t)b * in_bstride;

    const int ntaps = CONV3 ? 9 : 1;
    for (int tap = 0; tap < ntaps; ++tap) {
        int yy = y, dx = 0;
        if (CONV3) {
            int dy = (tap / 3 - 1) * dil;
            dx = (tap % 3 - 1) * dil;
            yy = y + dy;
            if ((unsigned)yy >= (unsigned)HH) continue;   // uniform: whole tap row OOB
        }
        for (int k0 = 0; k0 < Kc; k0 += KT) {
            // ---- A tile -> As[k][m]
            if (BM == 256) {
                int rowidx = CONV3 ? (tap * BM + t) : t;
                const float* wrow = Wb + (size_t)rowidx * Kc + k0;
#pragma unroll
                for (int q = 0; q < 4; q++) {
                    float4 v = *reinterpret_cast<const float4*>(wrow + q * 4);
                    As[q * 4 + 0][t] = v.x; As[q * 4 + 1][t] = v.y;
                    As[q * 4 + 2][t] = v.z; As[q * 4 + 3][t] = v.w;
                }
            } else {  // BM == 128
                int m = t >> 1, ko = (t & 1) * 8;
                const float* wrow = Wb + (size_t)m * Kc + k0 + ko;
#pragma unroll
                for (int q = 0; q < 2; q++) {
                    float4 v = *reinterpret_cast<const float4*>(wrow + q * 4);
                    As[ko + q * 4 + 0][m] = v.x; As[ko + q * 4 + 1][m] = v.y;
                    As[ko + q * 4 + 2][m] = v.z; As[ko + q * 4 + 3][m] = v.w;
                }
            }
            // ---- B tile -> Bs[k][n]
            {
                int k = t >> 4, nb = (t & 15) * 4;
                if (!CONV3) {
                    float4 v = *reinterpret_cast<const float4*>(
                        Inb + (size_t)(k0 + k) * HW + n0 + nb);
                    *reinterpret_cast<float4*>(&Bs[k][nb]) = v;
                } else {
                    const float* src = Inb + (size_t)(k0 + k) * HW + yy * WW;
#pragma unroll
                    for (int q = 0; q < 4; q++) {
                        int xx = nb + q + dx;
                        float v = 0.f;
                        if (xx >= 0 && xx < WW) v = src[xx];
                        Bs[k][nb + q] = v;
                    }
                }
            }
            __syncthreads();
#pragma unroll
            for (int k = 0; k < KT; k++) {
                ull a2[TM], b2[4];
#pragma unroll
                for (int i = 0; i < TM; i += 4) {
                    float4 v = *reinterpret_cast<const float4*>(&As[k][ty * TM + i]);
                    a2[i] = pack2f(v.x); a2[i + 1] = pack2f(v.y);
                    a2[i + 2] = pack2f(v.z); a2[i + 3] = pack2f(v.w);
                }
                {
                    float4 v0 = *reinterpret_cast<const float4*>(&Bs[k][tx * 8]);
                    float4 v1 = *reinterpret_cast<const float4*>(&Bs[k][tx * 8 + 4]);
                    b2[0] = pack2(v0.x, v0.y); b2[1] = pack2(v0.z, v0.w);
                    b2[2] = pack2(v1.x, v1.y); b2[3] = pack2(v1.z, v1.w);
                }
#pragma unroll
                for (int i = 0; i < TM; i++)
#pragma unroll
                    for (int j = 0; j < 4; j++) fma2(acc2[i][j], a2[i], b2[j]);
            }
            __syncthreads();
        }
    }

    // unpack accumulators
    float acc[TM][8];
#pragma unroll
    for (int i = 0; i < TM; i++)
#pragma unroll
        for (int j = 0; j < 4; j++) {
            float2 f = unpk2(acc2[i][j]);
            acc[i][2 * j] = f.x; acc[i][2 * j + 1] = f.y;
        }

    float* Ob = Out + (size_t)b * out_bstride;
    if (MODE == 1) {
#pragma unroll
        for (int j = 0; j < 8; j++) {
            float s = 0.f;
#pragma unroll
            for (int i = 0; i < TM; i++) s += acc[i][j];
            red[ty][tx * 8 + j] = s;
        }
        __syncthreads();
        if (t < BN) {
            float s = 0.f;
#pragma unroll
            for (int r = 0; r < 32; r++) s += red[r][t];
            cmean[t] = s * (1.f / BM);
        }
        __syncthreads();
#pragma unroll
        for (int j = 0; j < 8; j++) {
            float s = 0.f;
#pragma unroll
            for (int i = 0; i < TM; i++) { float d = acc[i][j]; s += d * d; }
            red[ty][tx * 8 + j] = s;
        }
        __syncthreads();
        if (t < BN) {
            float s = 0.f;
#pragma unroll
            for (int r = 0; r < 32; r++) s += red[r][t];
            float m = cmean[t];
            float var = s * (1.f / BM) - m * m;
            crstd[t] = rsqrtf(var + 1e-6f);
        }
        __syncthreads();
#pragma unroll
        for (int i = 0; i < TM; i++) {
            int m = ty * TM + i;
            float gmm = P1[m], bet = P2[m];
            float o8[8];
#pragma unroll
            for (int j = 0; j < 8; j++) {
                int n = tx * 8 + j;
                float v = (acc[i][j] - cmean[n]) * crstd[n] * gmm + bet;
                o8[j] = gelu_f(v);
            }
            float* dst = Ob + (size_t)m * HW + n0 + tx * 8;
            *reinterpret_cast<float4*>(dst) = make_float4(o8[0], o8[1], o8[2], o8[3]);
            *reinterpret_cast<float4*>(dst + 4) = make_float4(o8[4], o8[5], o8[6], o8[7]);
        }
    } else {
#pragma unroll
        for (int i = 0; i < TM; i++) {
            int m = ty * TM + i;
            float bias = (MODE == 0) ? P1[m] : 0.f;
            const float* addrow = (MODE == 2)
                ? (Addp + (size_t)b * add_bstride + (size_t)m * HW + n0 + tx * 8)
                : nullptr;
            float o8[8];
#pragma unroll
            for (int j = 0; j < 8; j++) {
                float v = acc[i][j] + bias;
                if (MODE == 2) v += addrow[j];
                o8[j] = v;
            }
            float* dst = Ob + (size_t)m * HW + n0 + tx * 8;
            *reinterpret_cast<float4*>(dst) = make_float4(o8[0], o8[1], o8[2], o8[3]);
            *reinterpret_cast<float4*>(dst + 4) = make_float4(o8[4], o8[5], o8[6], o8[7]);
        }
    }
}

// ---------------- S[b,q,p] = (1/64) sum_c xa[b,c,q] * x1[b,c,p] ----------------
__global__ void __launch_bounds__(256) k_sgemm() {
    const int b = blockIdx.z;
    const int m0 = blockIdx.y * 128;
    const int n0 = blockIdx.x * 64;
    const int t = threadIdx.x, ty = t >> 3, tx = t & 7;
    const float* Q = g_xa + (size_t)b * COUT * HW;
    const float* P = g_x1 + (size_t)b * COUT * HW;
    float* S = g_S + (size_t)b * HW * HW;
    __shared__ __align__(16) float As[KT][128];
    __shared__ __align__(16) float Bs[KT][64];
    ull acc2[4][4];
#pragma unroll
    for (int i = 0; i < 4; i++)
#pragma unroll
        for (int j = 0; j < 4; j++) acc2[i][j] = 0ULL;

    for (int k0 = 0; k0 < COUT; k0 += KT) {
        int k = t >> 4;
        {
            int mm = (t & 15) * 8;
            const float* src = Q + (size_t)(k0 + k) * HW + m0 + mm;
            *reinterpret_cast<float4*>(&As[k][mm]) = *reinterpret_cast<const float4*>(src);
            *reinterpret_cast<float4*>(&As[k][mm + 4]) = *reinterpret_cast<const float4*>(src + 4);
        }
        {
            int nb = (t & 15) * 4;
            *reinterpret_cast<float4*>(&Bs[k][nb]) =
                *reinterpret_cast<const float4*>(P + (size_t)(k0 + k) * HW + n0 + nb);
        }
        __syncthreads();
#pragma unroll
        for (int kk = 0; kk < KT; kk++) {
            ull a2[4], b2[4];
            float4 va = *reinterpret_cast<const float4*>(&As[kk][ty * 4]);
            a2[0] = pack2f(va.x); a2[1] = pack2f(va.y);
            a2[2] = pack2f(va.z); a2[3] = pack2f(va.w);
            float4 v0 = *reinterpret_cast<const float4*>(&Bs[kk][tx * 8]);
            float4 v1 = *reinterpret_cast<const float4*>(&Bs[kk][tx * 8 + 4]);
            b2[0] = pack2(v0.x, v0.y); b2[1] = pack2(v0.z, v0.w);
            b2[2] = pack2(v1.x, v1.y); b2[3] = pack2(v1.z, v1.w);
#pragma unroll
            for (int i = 0; i < 4; i++)
#pragma unroll
                for (int j = 0; j < 4; j++) fma2(acc2[i][j], a2[i], b2[j]);
        }
        __syncthreads();
    }
    const float sc = 1.f / 64.f;
#pragma unroll
    for (int i = 0; i < 4; i++) {
        int m = ty * 4 + i;
        float* dst = S + (size_t)(m0 + m) * HW + n0 + tx * 8;
        float o8[8];
#pragma unroll
        for (int j = 0; j < 4; j++) {
            float2 f = unpk2(acc2[i][j]);
            o8[2 * j] = f.x * sc; o8[2 * j + 1] = f.y * sc;
        }
        *reinterpret_cast<float4*>(dst) = make_float4(o8[0], o8[1], o8[2], o8[3]);
        *reinterpret_cast<float4*>(dst + 4) = make_float4(o8[4], o8[5], o8[6], o8[7]);
    }
}

// ---------------- row softmax over p (in place on g_S) ----------------
__global__ void __launch_bounds__(256) k_softmax() {
    const size_t row = blockIdx.x;
    float* r = g_S + row * (size_t)HW;
    __shared__ float buf[HW];
    __shared__ float red[256];
    int t = threadIdx.x;
    float m = -1e30f;
    for (int i = t; i < HW; i += 256) { float v = r[i]; buf[i] = v; m = fmaxf(m, v); }
    red[t] = m; __syncthreads();
    for (int s = 128; s > 0; s >>= 1) { if (t < s) red[t] = fmaxf(red[t], red[t + s]); __syncthreads(); }
    float mx = red[0]; __syncthreads();
    float s = 0.f;
    for (int i = t; i < HW; i += 256) { float e = expf(buf[i] - mx); buf[i] = e; s += e; }
    red[t] = s; __syncthreads();
    for (int o = 128; o > 0; o >>= 1) { if (t < o) red[t] += red[t + o]; __syncthreads(); }
    float inv = 1.f / red[0];
    for (int i = t; i < HW; i += 256) r[i] = buf[i] * inv;
}

// ---------------- host launch ----------------
extern "C" void kernel_launch(void* const* d_in, const int* in_sizes, int n_in,
                              void* d_out, int out_size) {
    (void)in_sizes; (void)n_in; (void)out_size;
    const float* x       = (const float*)d_in[0];
    const float* conv1_w = (const float*)d_in[1];
    const float* conv1_b = (const float*)d_in[2];
    const float* conv2_w = (const float*)d_in[3];
    const float* conv2_b = (const float*)d_in[4];
    const float* cw_w1   = (const float*)d_in[5];
    const float* cw_b1   = (const float*)d_in[6];
    const float* cw_ln_g = (const float*)d_in[7];
    const float* cw_ln_b = (const float*)d_in[8];
    const float* cw_w2   = (const float*)d_in[9];
    const float* cw_b2   = (const float*)d_in[10];
    const float* aspp0_w = (const float*)d_in[11];
    const float* aspp0_g = (const float*)d_in[12];
    const float* aspp0_b = (const float*)d_in[13];
    const float* aspp1_w = (const float*)d_in[14];
    const float* aspp1_g = (const float*)d_in[15];
    const float* aspp1_b = (const float*)d_in[16];
    const float* aspp2_w = (const float*)d_in[17];
    const float* aspp2_g = (const float*)d_in[18];
    const float* aspp2_b = (const float*)d_in[19];
    const float* aspp3_w = (const float*)d_in[20];
    const float* aspp3_g = (const float*)d_in[21];
    const float* aspp3_b = (const float*)d_in[22];
    const float* asppp_w = (const float*)d_in[23];
    const float* asppp_g = (const float*)d_in[24];
    const float* asppp_b = (const float*)d_in[25];
    const float* proj_w  = (const float*)d_in[26];
    const float* proj_g  = (const float*)d_in[27];
    const float* proj_b  = (const float*)d_in[28];

    void* pv;
    float *p_xc, *p_x1, *p_cat, *p_proj, *p_xa, *p_O, *p_S, *p_w3;
    cudaGetSymbolAddress(&pv, g_xc);   p_xc   = (float*)pv;
    cudaGetSymbolAddress(&pv, g_x1);   p_x1   = (float*)pv;
    cudaGetSymbolAddress(&pv, g_cat);  p_cat  = (float*)pv;
    cudaGetSymbolAddress(&pv, g_proj); p_proj = (float*)pv;
    cudaGetSymbolAddress(&pv, g_xa);   p_xa   = (float*)pv;
    cudaGetSymbolAddress(&pv, g_O);    p_O    = (float*)pv;
    cudaGetSymbolAddress(&pv, g_S);    p_S    = (float*)pv;
    cudaGetSymbolAddress(&pv, g_w3);   p_w3   = (float*)pv;

    dim3 g64(HW / BN, BATCH);

    k_stats<<<BATCH * CIN, 256>>>(x);
    k_cw<<<BATCH, 256>>>(cw_w1, cw_b1, cw_ln_g, cw_ln_b, cw_w2, cw_b2,
                         asppp_w, asppp_g, asppp_b);
    k_xc<<<(BATCH * CIN * HW / 4 + 255) / 256, 256>>>(x);
    k_transw<<<768, 256>>>(aspp1_w, aspp2_w, aspp3_w);
    k_bp<<<BATCH * CIN, 256>>>();

    // x1 = conv1(x) + b
    k_gemm<128, 0, false><<<g64, 256>>>(conv1_w, 0, x, (size_t)CIN * HW,
                                        conv1_b, nullptr, nullptr, 0,
                                        p_x1, (size_t)COUT * HW, CIN, 0);
    // ASPP branches into cat
    k_gemm<256, 1, false><<<g64, 256>>>(aspp0_w, 0, p_xc, (size_t)CIN * HW,
                                        aspp0_g, aspp0_b, nullptr, 0,
                                        p_cat, (size_t)5 * CIN * HW, CIN, 0);
    k_gemm<256, 1, true><<<g64, 256>>>(p_w3 + 0 * 9 * CIN * CIN, 0, p_xc, (size_t)CIN * HW,
                                       aspp1_g, aspp1_b, nullptr, 0,
                                       p_cat + 1 * CIN * HW, (size_t)5 * CIN * HW, CIN, 3);
    k_gemm<256, 1, true><<<g64, 256>>>(p_w3 + 1 * 9 * CIN * CIN, 0, p_xc, (size_t)CIN * HW,
                                       aspp2_g, aspp2_b, nullptr, 0,
                                       p_cat + 2 * CIN * HW, (size_t)5 * CIN * HW, CIN, 6);
    k_gemm<256, 1, true><<<g64, 256>>>(p_w3 + 2 * 9 * CIN * CIN, 0, p_xc, (size_t)CIN * HW,
                                       aspp3_g, aspp3_b, nullptr, 0,
                                       p_cat + 3 * CIN * HW, (size_t)5 * CIN * HW, CIN, 9);
    // proj = gelu(LN(conv1x1(cat)))
    k_gemm<256, 1, false><<<g64, 256>>>(proj_w, 0, p_cat, (size_t)5 * CIN * HW,
                                        proj_g, proj_b, nullptr, 0,
                                        p_proj, (size_t)CIN * HW, 5 * CIN, 0);
    // xa = conv1(proj) + b
    k_gemm<128, 0, false><<<g64, 256>>>(conv1_w, 0, p_proj, (size_t)CIN * HW,
                                        conv1_b, nullptr, nullptr, 0,
                                        p_xa, (size_t)COUT * HW, CIN, 0);
    // attention
    k_sgemm<<<dim3(HW / 64, HW / 128, BATCH), 256>>>();
    k_softmax<<<BATCH * HW, 256>>>();
    // L = x1 @ A  (+ xa)
    k_gemm<128, 2, false><<<g64, 256>>>(p_x1, (size_t)COUT * HW, p_S, (size_t)HW * HW,
                                        nullptr, nullptr, p_xa, (size_t)COUT * HW,
                                        p_O, (size_t)COUT * HW, HW, 0);
    // out = conv2(O) + b
    k_gemm<256, 0, false><<<g64, 256>>>(conv2_w, 0, p_O, (size_t)COUT * HW,
                                        conv2_b, nullptr, nullptr, 0,
                                        (float*)d_out, (size_t)CIN * HW, COUT, 0);
}

// round 3
// speedup vs baseline: 1.0436x; 1.0436x over previous
#include <cuda_runtime.h>
#include <math.h>

#define BATCH 4
#define CIN 256
#define COUT 128
#define HH 64
#define WW 64
#define HW 4096
#define BN 64
#define KT 16

typedef unsigned long long ull;

// ---------------- scratch (static device globals; no allocs) ----------------
__device__ float g_xc[BATCH * CIN * HW];
__device__ float g_x1[BATCH * COUT * HW];
__device__ float g_cat[BATCH * 5 * CIN * HW];
__device__ float g_proj[BATCH * CIN * HW];
__device__ float g_xa[BATCH * COUT * HW];
__device__ float g_O[BATCH * COUT * HW];
__device__ float g_S[(size_t)BATCH * HW * HW];
__device__ float g_w3[3 * 9 * CIN * CIN];
__device__ float g_avg[BATCH * CIN];
__device__ float g_mx[BATCH * CIN];
__device__ float g_s[BATCH * CIN];
__device__ float g_bp[BATCH * CIN];

__device__ __forceinline__ float gelu_f(float x) {
    return 0.5f * x * (1.0f + erff(x * 0.70710678118654752440f));
}

// ---------------- packed f32x2 helpers ----------------
__device__ __forceinline__ ull pack2f(float x) {
    ull r; asm("mov.b64 %0, {%1, %1};" : "=l"(r) : "f"(x)); return r;
}
__device__ __forceinline__ ull pack2(float x, float y) {
    ull r; asm("mov.b64 %0, {%1, %2};" : "=l"(r) : "f"(x), "f"(y)); return r;
}
__device__ __forceinline__ void fma2(ull& d, ull a, ull b) {
    asm("fma.rn.f32x2 %0, %1, %2, %0;" : "+l"(d) : "l"(a), "l"(b));
}
__device__ __forceinline__ float2 unpk2(ull v) {
    float2 f; asm("mov.b64 {%0, %1}, %2;" : "=f"(f.x), "=f"(f.y) : "l"(v)); return f;
}

// ---------------- per-(b,c) mean & max over HW ----------------
__global__ void k_stats(const float* __restrict__ x) {
    int bc = blockIdx.x;
    const float* p = x + (size_t)bc * HW;
    int t = threadIdx.x;
    float s = 0.f, m = -1e30f;
    for (int i = t; i < HW; i += 256) { float v = p[i]; s += v; m = fmaxf(m, v); }
    __shared__ float ss[256], sm[256];
    ss[t] = s; sm[t] = m; __syncthreads();
    for (int o = 128; o > 0; o >>= 1) {
        if (t < o) { ss[t] += ss[t + o]; sm[t] = fmaxf(sm[t], sm[t + o]); }
        __syncthreads();
    }
    if (t == 0) { g_avg[bc] = ss[0] * (1.f / HW); g_mx[bc] = sm[0]; }
}

// ---------------- channel weighting MLP + global-pool ASPP branch ----------------
__global__ void k_cw(const float* __restrict__ w1, const float* __restrict__ bb1,
                     const float* __restrict__ lg, const float* __restrict__ lb,
                     const float* __restrict__ w2, const float* __restrict__ bb2,
                     const float* __restrict__ apw, const float* __restrict__ apg,
                     const float* __restrict__ apb) {
    int b = blockIdx.x, t = threadIdx.x;
    __shared__ float o[CIN];
    __shared__ float h[COUT];
    __shared__ float red[256];
    __shared__ float gp[CIN];
    float avg = g_avg[b * CIN + t], mx = g_mx[b * CIN + t];
    o[t] = fabsf(avg - mx) * avg;
    __syncthreads();
    float hv = 0.f;
    if (t < COUT) {
        hv = bb1[t];
        const float* wr = w1 + t * CIN;
        for (int i = 0; i < CIN; i++) hv = fmaf(o[i], wr[i], hv);
    }
    red[t] = (t < COUT) ? hv : 0.f; __syncthreads();
    for (int s = 128; s > 0; s >>= 1) { if (t < s) red[t] += red[t + s]; __syncthreads(); }
    float mu = red[0] * (1.f / COUT); __syncthreads();
    float dv = (t < COUT) ? (hv - mu) : 0.f;
    red[t] = dv * dv; __syncthreads();
    for (int s = 128; s > 0; s >>= 1) { if (t < s) red[t] += red[t + s]; __syncthreads(); }
    float var = red[0] * (1.f / COUT); __syncthreads();
    if (t < COUT) h[t] = lg[t] * ((hv - mu) * rsqrtf(var + 1e-5f)) + lb[t];
    __syncthreads();
    float sv = bb2[t];
    const float* wr2 = w2 + t * COUT;
    for (int j = 0; j < COUT; j++) sv = fmaf(h[j], wr2[j], sv);
    float sig = 1.f / (1.f + expf(-sv));
    g_s[b * CIN + t] = sig;
    gp[t] = (1.f + sig) * avg;
    __syncthreads();
    float v = 0.f;
    const float* ar = apw + t * CIN;
    for (int i = 0; i < CIN; i++) v = fmaf(ar[i], gp[i], v);
    red[t] = v; __syncthreads();
    for (int s = 128; s > 0; s >>= 1) { if (t < s) red[t] += red[t + s]; __syncthreads(); }
    float mu2 = red[0] * (1.f / CIN); __syncthreads();
    float d2 = v - mu2; red[t] = d2 * d2; __syncthreads();
    for (int s = 128; s > 0; s >>= 1) { if (t < s) red[t] += red[t + s]; __syncthreads(); }
    float var2 = red[0] * (1.f / CIN); __syncthreads();
    float z = apg[t] * ((v - mu2) * rsqrtf(var2 + 1e-6f)) + apb[t];
    g_bp[b * CIN + t] = gelu_f(z);
}

// ---------------- xc = x * (1 + s) ----------------
__global__ void k_xc(const float* __restrict__ x) {
    int idx = blockIdx.x * 256 + threadIdx.x;
    const int n4 = BATCH * CIN * HW / 4;
    if (idx < n4) {
        int bc = idx / (HW / 4);
        float sc = 1.f + g_s[bc];
        float4 v = reinterpret_cast<const float4*>(x)[idx];
        v.x *= sc; v.y *= sc; v.z *= sc; v.w *= sc;
        reinterpret_cast<float4*>(g_xc)[idx] = v;
    }
}

// ---------------- broadcast bp into cat channels [1024,1280) ----------------
__global__ void k_bp() {
    int bc = blockIdx.x;
    int b = bc >> 8, c = bc & 255;
    float v = g_bp[bc];
    float4* dst = reinterpret_cast<float4*>(g_cat + ((size_t)b * 5 * CIN + 4 * CIN + c) * HW);
    float4 v4 = make_float4(v, v, v, v);
    for (int i = threadIdx.x; i < HW / 4; i += 256) dst[i] = v4;
}

// ---------------- transpose conv3x3 weights to [tap][m][c] ----------------
__global__ void k_transw(const float* __restrict__ w1, const float* __restrict__ w2,
                         const float* __restrict__ w3) {
    int e = blockIdx.x * 256 + threadIdx.x;
    if (e >= 3 * 65536) return;
    const float* srcs[3] = { w1, w2, w3 };
    int conv = e >> 16, mc = e & 65535, m = mc >> 8, c = mc & 255;
    const float* src = srcs[conv] + (size_t)m * 2304 + (size_t)c * 9;
    float* dst = g_w3 + (size_t)conv * 9 * 65536 + (size_t)m * 256 + c;
#pragma unroll
    for (int tap = 0; tap < 9; tap++) dst[(size_t)tap * 65536] = src[tap];
}

// ---------------- generic pipelined GEMM: Out[b,m,n] = sum_k W[m,k] * In[b,k,n] ----------
// MODE 0: + bias[m]
// MODE 1: channels-first LayerNorm over m (eps 1e-6) + exact GELU (needs BM == M == 256)
// MODE 2: + Add[b,m,n]
// CONV3: implicit dilated 3x3; W is g_w3 layout [tap][m][c] (Kc=256), In is xc.
template <int BM, int MODE, bool CONV3>
__global__ void __launch_bounds__(256, 2) k_gemm(
    const float* __restrict__ Wg, size_t wb_stride,
    const float* __restrict__ In, size_t in_bstride,
    const float* __restrict__ P1, const float* __restrict__ P2,
    const float* __restrict__ Addp, size_t add_bstride,
    float* __restrict__ Out, size_t out_bstride,
    int Kc, int dil) {
    constexpr int TM = BM / 32;
    constexpr int NAREG = (BM == 256) ? 4 : 2;   // float4 A prefetch regs per thread
    const int b = blockIdx.y;
    const int y = blockIdx.x;
    const int n0 = y * BN;
    const int t = threadIdx.x;
    const int ty = t >> 3, tx = t & 7;

    __shared__ __align__(16) float As[2][KT][BM];
    __shared__ __align__(16) float Bs[2][KT][BN];
    __shared__ int s_tap[9], s_yy[9], s_dx[9];
    __shared__ int s_ntap;

    if (CONV3) {
        if (t == 0) {
            int n = 0;
            for (int tap = 0; tap < 9; tap++) {
                int yy = y + (tap / 3 - 1) * dil;
                if ((unsigned)yy < (unsigned)HH) {
                    s_tap[n] = tap; s_yy[n] = yy; s_dx[n] = (tap % 3 - 1) * dil; n++;
                }
            }
            s_ntap = n;
        }
        __syncthreads();
    }

    const int nk = Kc / KT;
    const int total = CONV3 ? (s_ntap * nk) : nk;

    const float* Wb = Wg + (size_t)b * wb_stride;
    const float* Inb = In + (size_t)b * in_bstride;

    ull acc2[TM][4];
#pragma unroll
    for (int i = 0; i < TM; i++)
#pragma unroll
        for (int j = 0; j < 4; j++) acc2[i][j] = 0ULL;

    float4 ra[NAREG];
    float rb[4];

    // ---- prefetch lambdas (global -> regs) ----
    auto loadG = [&](int it) {
        int tap_i = CONV3 ? (it / nk) : 0;
        int k0 = (CONV3 ? (it - tap_i * nk) : it) * KT;
        // A
        if (BM == 256) {
            int rowidx = CONV3 ? (s_tap[tap_i] * 256 + t) : t;
            const float* wrow = Wb + (size_t)rowidx * Kc + k0;
#pragma unroll
            for (int q = 0; q < 4; q++)
                ra[q] = *reinterpret_cast<const float4*>(wrow + q * 4);
        } else {
            int m = t >> 1, ko = (t & 1) * 8;
            const float* wrow = Wb + (size_t)m * Kc + k0 + ko;
#pragma unroll
            for (int q = 0; q < 2; q++)
                ra[q] = *reinterpret_cast<const float4*>(wrow + q * 4);
        }
        // B
        int k = t >> 4, nb = (t & 15) * 4;
        if (!CONV3) {
            float4 v = *reinterpret_cast<const float4*>(Inb + (size_t)(k0 + k) * HW + n0 + nb);
            rb[0] = v.x; rb[1] = v.y; rb[2] = v.z; rb[3] = v.w;
        } else {
            int yy = s_yy[tap_i], dx = s_dx[tap_i];
            const float* src = Inb + (size_t)(k0 + k) * HW + yy * WW;
#pragma unroll
            for (int q = 0; q < 4; q++) {
                int xx = nb + q + dx;
                rb[q] = (xx >= 0 && xx < WW) ? src[xx] : 0.f;
            }
        }
    };
    auto storeS = [&](int buf) {
        if (BM == 256) {
#pragma unroll
            for (int q = 0; q < 4; q++) {
                As[buf][q * 4 + 0][t] = ra[q].x; As[buf][q * 4 + 1][t] = ra[q].y;
                As[buf][q * 4 + 2][t] = ra[q].z; As[buf][q * 4 + 3][t] = ra[q].w;
            }
        } else {
            int m = t >> 1, ko = (t & 1) * 8;
#pragma unroll
            for (int q = 0; q < 2; q++) {
                As[buf][ko + q * 4 + 0][m] = ra[q].x; As[buf][ko + q * 4 + 1][m] = ra[q].y;
                As[buf][ko + q * 4 + 2][m] = ra[q].z; As[buf][ko + q * 4 + 3][m] = ra[q].w;
            }
        }
        int k = t >> 4, nb = (t & 15) * 4;
        Bs[buf][k][nb] = rb[0]; Bs[buf][k][nb + 1] = rb[1];
        Bs[buf][k][nb + 2] = rb[2]; Bs[buf][k][nb + 3] = rb[3];
    };

    loadG(0);
    storeS(0);
    __syncthreads();

    for (int it = 0; it < total; ++it) {
        int cur = it & 1;
        bool more = (it + 1 < total);
        if (more) loadG(it + 1);
#pragma unroll
        for (int k = 0; k < KT; k++) {
            ull a2[TM], b2[4];
#pragma unroll
            for (int i = 0; i < TM; i += 4) {
                float4 v = *reinterpret_cast<const float4*>(&As[cur][k][ty * TM + i]);
                a2[i] = pack2f(v.x); a2[i + 1] = pack2f(v.y);
                a2[i + 2] = pack2f(v.z); a2[i + 3] = pack2f(v.w);
            }
            {
                float4 v0 = *reinterpret_cast<const float4*>(&Bs[cur][k][tx * 8]);
                float4 v1 = *reinterpret_cast<const float4*>(&Bs[cur][k][tx * 8 + 4]);
                b2[0] = pack2(v0.x, v0.y); b2[1] = pack2(v0.z, v0.w);
                b2[2] = pack2(v1.x, v1.y); b2[3] = pack2(v1.z, v1.w);
            }
#pragma unroll
            for (int i = 0; i < TM; i++)
#pragma unroll
                for (int j = 0; j < 4; j++) fma2(acc2[i][j], a2[i], b2[j]);
        }
        if (more) storeS(cur ^ 1);
        __syncthreads();
    }

    // unpack accumulators
    float acc[TM][8];
#pragma unroll
    for (int i = 0; i < TM; i++)
#pragma unroll
        for (int j = 0; j < 4; j++) {
            float2 f = unpk2(acc2[i][j]);
            acc[i][2 * j] = f.x; acc[i][2 * j + 1] = f.y;
        }

    float* Ob = Out + (size_t)b * out_bstride;
    if (MODE == 1) {
        // alias reduction buffers onto the (now dead) tile buffers
        float (*red)[BN] = reinterpret_cast<float (*)[BN]>(&As[0][0][0]); // 8 KB
        float* cmean = &Bs[0][0][0];
        float* crstd = &Bs[0][0][0] + BN;
#pragma unroll
        for (int j = 0; j < 8; j++) {
            float s = 0.f;
#pragma unroll
            for (int i = 0; i < TM; i++) s += acc[i][j];
            red[ty][tx * 8 + j] = s;
        }
        __syncthreads();
        if (t < BN) {
            float s = 0.f;
#pragma unroll
            for (int r = 0; r < 32; r++) s += red[r][t];
            cmean[t] = s * (1.f / BM);
        }
        __syncthreads();
#pragma unroll
        for (int j = 0; j < 8; j++) {
            float s = 0.f;
#pragma unroll
            for (int i = 0; i < TM; i++) { float d = acc[i][j]; s += d * d; }
            red[ty][tx * 8 + j] = s;
        }
        __syncthreads();
        if (t < BN) {
            float s = 0.f;
#pragma unroll
            for (int r = 0; r < 32; r++) s += red[r][t];
            float m = cmean[t];
            float var = s * (1.f / BM) - m * m;
            crstd[t] = rsqrtf(var + 1e-6f);
        }
        __syncthreads();
#pragma unroll
        for (int i = 0; i < TM; i++) {
            int m = ty * TM + i;
            float gmm = P1[m], bet = P2[m];
            float o8[8];
#pragma unroll
            for (int j = 0; j < 8; j++) {
                int n = tx * 8 + j;
                float v = (acc[i][j] - cmean[n]) * crstd[n] * gmm + bet;
                o8[j] = gelu_f(v);
            }
            float* dst = Ob + (size_t)m * HW + n0 + tx * 8;
            *reinterpret_cast<float4*>(dst) = make_float4(o8[0], o8[1], o8[2], o8[3]);
            *reinterpret_cast<float4*>(dst + 4) = make_float4(o8[4], o8[5], o8[6], o8[7]);
        }
    } else {
#pragma unroll
        for (int i = 0; i < TM; i++) {
            int m = ty * TM + i;
            float bias = (MODE == 0) ? P1[m] : 0.f;
            const float* addrow = (MODE == 2)
                ? (Addp + (size_t)b * add_bstride + (size_t)m * HW + n0 + tx * 8)
                : nullptr;
            float o8[8];
#pragma unroll
            for (int j = 0; j < 8; j++) {
                float v = acc[i][j] + bias;
                if (MODE == 2) v += addrow[j];
                o8[j] = v;
            }
            float* dst = Ob + (size_t)m * HW + n0 + tx * 8;
            *reinterpret_cast<float4*>(dst) = make_float4(o8[0], o8[1], o8[2], o8[3]);
            *reinterpret_cast<float4*>(dst + 4) = make_float4(o8[4], o8[5], o8[6], o8[7]);
        }
    }
}

// ---------------- S[b,q,p] = (1/64) sum_c xa[b,c,q] * x1[b,c,p] (pipelined) ----------------
__global__ void __launch_bounds__(256, 2) k_sgemm() {
    const int b = blockIdx.z;
    const int m0 = blockIdx.y * 128;
    const int n0 = blockIdx.x * 64;
    const int t = threadIdx.x, ty = t >> 3, tx = t & 7;
    const float* Q = g_xa + (size_t)b * COUT * HW;
    const float* P = g_x1 + (size_t)b * COUT * HW;
    float* S = g_S + (size_t)b * HW * HW;
    __shared__ __align__(16) float As[2][KT][128];
    __shared__ __align__(16) float Bs[2][KT][64];
    ull acc2[4][4];
#pragma unroll
    for (int i = 0; i < 4; i++)
#pragma unroll
        for (int j = 0; j < 4; j++) acc2[i][j] = 0ULL;

    float4 ra0, ra1, rbv;
    auto loadG = [&](int it) {
        int k0 = it * KT;
        int k = t >> 4;
        int mm = (t & 15) * 8;
        const float* src = Q + (size_t)(k0 + k) * HW + m0 + mm;
        ra0 = *reinterpret_cast<const float4*>(src);
        ra1 = *reinterpret_cast<const float4*>(src + 4);
        int nb = (t & 15) * 4;
        rbv = *reinterpret_cast<const float4*>(P + (size_t)(k0 + k) * HW + n0 + nb);
    };
    auto storeS = [&](int buf) {
        int k = t >> 4;
        int mm = (t & 15) * 8;
        *reinterpret_cast<float4*>(&As[buf][k][mm]) = ra0;
        *reinterpret_cast<float4*>(&As[buf][k][mm + 4]) = ra1;
        int nb = (t & 15) * 4;
        *reinterpret_cast<float4*>(&Bs[buf][k][nb]) = rbv;
    };

    const int total = COUT / KT;
    loadG(0);
    storeS(0);
    __syncthreads();

    for (int it = 0; it < total; ++it) {
        int cur = it & 1;
        bool more = (it + 1 < total);
        if (more) loadG(it + 1);
#pragma unroll
        for (int kk = 0; kk < KT; kk++) {
            ull a2[4], b2[4];
            float4 va = *reinterpret_cast<const float4*>(&As[cur][kk][ty * 4]);
            a2[0] = pack2f(va.x); a2[1] = pack2f(va.y);
            a2[2] = pack2f(va.z); a2[3] = pack2f(va.w);
            float4 v0 = *reinterpret_cast<const float4*>(&Bs[cur][kk][tx * 8]);
            float4 v1 = *reinterpret_cast<const float4*>(&Bs[cur][kk][tx * 8 + 4]);
            b2[0] = pack2(v0.x, v0.y); b2[1] = pack2(v0.z, v0.w);
            b2[2] = pack2(v1.x, v1.y); b2[3] = pack2(v1.z, v1.w);
#pragma unroll
            for (int i = 0; i < 4; i++)
#pragma unroll
                for (int j = 0; j < 4; j++) fma2(acc2[i][j], a2[i], b2[j]);
        }
        if (more) storeS(cur ^ 1);
        __syncthreads();
    }
    const float sc = 1.f / 64.f;
#pragma unroll
    for (int i = 0; i < 4; i++) {
        int m = ty * 4 + i;
        float* dst = S + (size_t)(m0 + m) * HW + n0 + tx * 8;
        float o8[8];
#pragma unroll
        for (int j = 0; j < 4; j++) {
            float2 f = unpk2(acc2[i][j]);
            o8[2 * j] = f.x * sc; o8[2 * j + 1] = f.y * sc;
        }
        *reinterpret_cast<float4*>(dst) = make_float4(o8[0], o8[1], o8[2], o8[3]);
        *reinterpret_cast<float4*>(dst + 4) = make_float4(o8[4], o8[5], o8[6], o8[7]);
    }
}

// ---------------- row softmax over p (in place on g_S) ----------------
__global__ void __launch_bounds__(256) k_softmax() {
    const size_t row = blockIdx.x;
    float* r = g_S + row * (size_t)HW;
    __shared__ float buf[HW];
    __shared__ float red[256];
    int t = threadIdx.x;
    float m = -1e30f;
    for (int i = t; i < HW; i += 256) { float v = r[i]; buf[i] = v; m = fmaxf(m, v); }
    red[t] = m; __syncthreads();
    for (int s = 128; s > 0; s >>= 1) { if (t < s) red[t] = fmaxf(red[t], red[t + s]); __syncthreads(); }
    float mx = red[0]; __syncthreads();
    float s = 0.f;
    for (int i = t; i < HW; i += 256) { float e = expf(buf[i] - mx); buf[i] = e; s += e; }
    red[t] = s; __syncthreads();
    for (int o = 128; o > 0; o >>= 1) { if (t < o) red[t] += red[t + o]; __syncthreads(); }
    float inv = 1.f / red[0];
    for (int i = t; i < HW; i += 256) r[i] = buf[i] * inv;
}

// ---------------- host launch ----------------
extern "C" void kernel_launch(void* const* d_in, const int* in_sizes, int n_in,
                              void* d_out, int out_size) {
    (void)in_sizes; (void)n_in; (void)out_size;
    const float* x       = (const float*)d_in[0];
    const float* conv1_w = (const float*)d_in[1];
    const float* conv1_b = (const float*)d_in[2];
    const float* conv2_w = (const float*)d_in[3];
    const float* conv2_b = (const float*)d_in[4];
    const float* cw_w1   = (const float*)d_in[5];
    const float* cw_b1   = (const float*)d_in[6];
    const float* cw_ln_g = (const float*)d_in[7];
    const float* cw_ln_b = (const float*)d_in[8];
    const float* cw_w2   = (const float*)d_in[9];
    const float* cw_b2   = (const float*)d_in[10];
    const float* aspp0_w = (const float*)d_in[11];
    const float* aspp0_g = (const float*)d_in[12];
    const float* aspp0_b = (const float*)d_in[13];
    const float* aspp1_w = (const float*)d_in[14];
    const float* aspp1_g = (const float*)d_in[15];
    const float* aspp1_b = (const float*)d_in[16];
    const float* aspp2_w = (const float*)d_in[17];
    const float* aspp2_g = (const float*)d_in[18];
    const float* aspp2_b = (const float*)d_in[19];
    const float* aspp3_w = (const float*)d_in[20];
    const float* aspp3_g = (const float*)d_in[21];
    const float* aspp3_b = (const float*)d_in[22];
    const float* asppp_w = (const float*)d_in[23];
    const float* asppp_g = (const float*)d_in[24];
    const float* asppp_b = (const float*)d_in[25];
    const float* proj_w  = (const float*)d_in[26];
    const float* proj_g  = (const float*)d_in[27];
    const float* proj_b  = (const float*)d_in[28];

    void* pv;
    float *p_xc, *p_x1, *p_cat, *p_proj, *p_xa, *p_O, *p_S, *p_w3;
    cudaGetSymbolAddress(&pv, g_xc);   p_xc   = (float*)pv;
    cudaGetSymbolAddress(&pv, g_x1);   p_x1   = (float*)pv;
    cudaGetSymbolAddress(&pv, g_cat);  p_cat  = (float*)pv;
    cudaGetSymbolAddress(&pv, g_proj); p_proj = (float*)pv;
    cudaGetSymbolAddress(&pv, g_xa);   p_xa   = (float*)pv;
    cudaGetSymbolAddress(&pv, g_O);    p_O    = (float*)pv;
    cudaGetSymbolAddress(&pv, g_S);    p_S    = (float*)pv;
    cudaGetSymbolAddress(&pv, g_w3);   p_w3   = (float*)pv;

    dim3 g64(HW / BN, BATCH);

    k_stats<<<BATCH * CIN, 256>>>(x);
    k_cw<<<BATCH, 256>>>(cw_w1, cw_b1, cw_ln_g, cw_ln_b, cw_w2, cw_b2,
                         asppp_w, asppp_g, asppp_b);
    k_xc<<<(BATCH * CIN * HW / 4 + 255) / 256, 256>>>(x);
    k_transw<<<768, 256>>>(aspp1_w, aspp2_w, aspp3_w);
    k_bp<<<BATCH * CIN, 256>>>();

    // x1 = conv1(x) + b
    k_gemm<128, 0, false><<<g64, 256>>>(conv1_w, 0, x, (size_t)CIN * HW,
                                        conv1_b, nullptr, nullptr, 0,
                                        p_x1, (size_t)COUT * HW, CIN, 0);
    // ASPP branches into cat
    k_gemm<256, 1, false><<<g64, 256>>>(aspp0_w, 0, p_xc, (size_t)CIN * HW,
                                        aspp0_g, aspp0_b, nullptr, 0,
                                        p_cat, (size_t)5 * CIN * HW, CIN, 0);
    k_gemm<256, 1, true><<<g64, 256>>>(p_w3 + 0 * 9 * CIN * CIN, 0, p_xc, (size_t)CIN * HW,
                                       aspp1_g, aspp1_b, nullptr, 0,
                                       p_cat + 1 * CIN * HW, (size_t)5 * CIN * HW, CIN, 3);
    k_gemm<256, 1, true><<<g64, 256>>>(p_w3 + 1 * 9 * CIN * CIN, 0, p_xc, (size_t)CIN * HW,
                                       aspp2_g, aspp2_b, nullptr, 0,
                                       p_cat + 2 * CIN * HW, (size_t)5 * CIN * HW, CIN, 6);
    k_gemm<256, 1, true><<<g64, 256>>>(p_w3 + 2 * 9 * CIN * CIN, 0, p_xc, (size_t)CIN * HW,
                                       aspp3_g, aspp3_b, nullptr, 0,
                                       p_cat + 3 * CIN * HW, (size_t)5 * CIN * HW, CIN, 9);
    // proj = gelu(LN(conv1x1(cat)))
    k_gemm<256, 1, false><<<g64, 256>>>(proj_w, 0, p_cat, (size_t)5 * CIN * HW,
                                        proj_g, proj_b, nullptr, 0,
                                        p_proj, (size_t)CIN * HW, 5 * CIN, 0);
    // xa = conv1(proj) + b
    k_gemm<128, 0, false><<<g64, 256>>>(conv1_w, 0, p_proj, (size_t)CIN * HW,
                                        conv1_b, nullptr, nullptr, 0,
                                        p_xa, (size_t)COUT * HW, CIN, 0);
    // attention
    k_sgemm<<<dim3(HW / 64, HW / 128, BATCH), 256>>>();
    k_softmax<<<BATCH * HW, 256>>>();
    // L = x1 @ A  (+ xa)
    k_gemm<128, 2, false><<<g64, 256>>>(p_x1, (size_t)COUT * HW, p_S, (size_t)HW * HW,
                                        nullptr, nullptr, p_xa, (size_t)COUT * HW,
                                        p_O, (size_t)COUT * HW, HW, 0);
    // out = conv2(O) + b
    k_gemm<256, 0, false><<<g64, 256>>>(conv2_w, 0, p_O, (size_t)COUT * HW,
                                        conv2_b, nullptr, nullptr, 0,
                                        (float*)d_out, (size_t)CIN * HW, COUT, 0);
}

// round 5
// speedup vs baseline: 1.2385x; 1.1867x over previous
#include <cuda_runtime.h>
#include <cuda_bf16.h>
#include <math.h>
#include <stdint.h>

#define BATCH 4
#define CIN 256
#define COUT 128
#define HH 64
#define WW 64
#define HW 4096
#define BN 64
#define KT 16

typedef unsigned long long ull;

// ---------------- scratch (static device globals; no allocs) ----------------
__device__ float g_x1[BATCH * COUT * HW];
__device__ float g_proj[BATCH * CIN * HW];
__device__ float g_xa[BATCH * COUT * HW];
__device__ float g_O[BATCH * COUT * HW];
__device__ float g_S[(size_t)BATCH * HW * HW];
__device__ float g_avg[BATCH * CIN];
__device__ float g_mx[BATCH * CIN];
__device__ float g_s[BATCH * CIN];
__device__ float g_bp[BATCH * CIN];
// bf16 split operands
__device__ __nv_bfloat16 g_xth[BATCH * HW * CIN];              // xcT hi  [b][hw][c]
__device__ __nv_bfloat16 g_xtl[BATCH * HW * CIN];              // xcT lo
__device__ __nv_bfloat16 g_cth[(size_t)BATCH * HW * 5 * CIN];  // catT hi [b][hw][1280]
__device__ __nv_bfloat16 g_ctl[(size_t)BATCH * HW * 5 * CIN];  // catT lo
__device__ __nv_bfloat16 g_w3h[3 * 9 * CIN * CIN];             // [conv][tap][m][c]
__device__ __nv_bfloat16 g_w3l[3 * 9 * CIN * CIN];
__device__ __nv_bfloat16 g_a0h[CIN * CIN];
__device__ __nv_bfloat16 g_a0l[CIN * CIN];
__device__ __nv_bfloat16 g_pjh[CIN * 5 * CIN];
__device__ __nv_bfloat16 g_pjl[CIN * 5 * CIN];

__device__ __forceinline__ float gelu_f(float x) {
    return 0.5f * x * (1.0f + erff(x * 0.70710678118654752440f));
}
__device__ __forceinline__ void splitf(float v, __nv_bfloat16& h, __nv_bfloat16& l) {
    h = __float2bfloat16(v);
    l = __float2bfloat16(v - __bfloat162float(h));
}

// ---------------- HMMA m16n8k16 bf16 (sm_80+ baseline ISA, legal on sm_103) ----------
__device__ __forceinline__ void mma16816(float* d, const uint32_t* a, const uint32_t* b) {
    asm volatile(
        "mma.sync.aligned.m16n8k16.row.col.f32.bf16.bf16.f32 "
        "{%0,%1,%2,%3}, {%4,%5,%6,%7}, {%8,%9}, {%0,%1,%2,%3};"
        : "+f"(d[0]), "+f"(d[1]), "+f"(d[2]), "+f"(d[3])
        : "r"(a[0]), "r"(a[1]), "r"(a[2]), "r"(a[3]), "r"(b[0]), "r"(b[1]));
}

// ---------------- packed helpers for FFMA path ----------------
__device__ __forceinline__ ull pack2f(float x) {
    ull r; asm("mov.b64 %0, {%1, %1};" : "=l"(r) : "f"(x)); return r;
}
__device__ __forceinline__ ull pack2(float x, float y) {
    ull r; asm("mov.b64 %0, {%1, %2};" : "=l"(r) : "f"(x), "f"(y)); return r;
}
__device__ __forceinline__ void fma2(ull& d, ull a, ull b) {
    asm("fma.rn.f32x2 %0, %1, %2, %0;" : "+l"(d) : "l"(a), "l"(b));
}
__device__ __forceinline__ float2 unpk2(ull v) {
    float2 f; asm("mov.b64 {%0, %1}, %2;" : "=f"(f.x), "=f"(f.y) : "l"(v)); return f;
}

// ---------------- weight split/transpose ----------------
__global__ void k_wsplit(const float* __restrict__ w1, const float* __restrict__ w2,
                         const float* __restrict__ w3, const float* __restrict__ a0,
                         const float* __restrict__ pj) {
    int e = blockIdx.x * 256 + threadIdx.x;
    if (e < 196608) {
        const float* srcs[3] = { w1, w2, w3 };
        int conv = e >> 16, mc = e & 65535, m = mc >> 8, c = mc & 255;
        const float* src = srcs[conv] + (size_t)m * 2304 + (size_t)c * 9;
        size_t dbase = (size_t)conv * 9 * 65536 + (size_t)m * 256 + c;
#pragma unroll
        for (int tap = 0; tap < 9; tap++) {
            __nv_bfloat16 h, l; splitf(src[tap], h, l);
            g_w3h[dbase + (size_t)tap * 65536] = h;
            g_w3l[dbase + (size_t)tap * 65536] = l;
        }
    } else if (e < 262144) {
        int i = e - 196608;
        __nv_bfloat16 h, l; splitf(a0[i], h, l);
        g_a0h[i] = h; g_a0l[i] = l;
    } else if (e < 589824) {
        int i = e - 262144;
        __nv_bfloat16 h, l; splitf(pj[i], h, l);
        g_pjh[i] = h; g_pjl[i] = l;
    }
}

// ---------------- per-(b,c) mean & max over HW ----------------
__global__ void k_stats(const float* __restrict__ x) {
    int bc = blockIdx.x;
    const float* p = x + (size_t)bc * HW;
    int t = threadIdx.x;
    float s = 0.f, m = -1e30f;
    for (int i = t; i < HW; i += 256) { float v = p[i]; s += v; m = fmaxf(m, v); }
    __shared__ float ss[256], sm[256];
    ss[t] = s; sm[t] = m; __syncthreads();
    for (int o = 128; o > 0; o >>= 1) {
        if (t < o) { ss[t] += ss[t + o]; sm[t] = fmaxf(sm[t], sm[t + o]); }
        __syncthreads();
    }
    if (t == 0) { g_avg[bc] = ss[0] * (1.f / HW); g_mx[bc] = sm[0]; }
}

// ---------------- channel weighting MLP + global-pool ASPP branch ----------------
__global__ void k_cw(const float* __restrict__ w1, const float* __restrict__ bb1,
                     const float* __restrict__ lg, const float* __restrict__ lb,
                     const float* __restrict__ w2, const float* __restrict__ bb2,
                     const float* __restrict__ apw, const float* __restrict__ apg,
                     const float* __restrict__ apb) {
    int b = blockIdx.x, t = threadIdx.x;
    __shared__ float o[CIN];
    __shared__ float h[COUT];
    __shared__ float red[256];
    __shared__ float gp[CIN];
    float avg = g_avg[b * CIN + t], mx = g_mx[b * CIN + t];
    o[t] = fabsf(avg - mx) * avg;
    __syncthreads();
    float hv = 0.f;
    if (t < COUT) {
        hv = bb1[t];
        const float* wr = w1 + t * CIN;
        for (int i = 0; i < CIN; i++) hv = fmaf(o[i], wr[i], hv);
    }
    red[t] = (t < COUT) ? hv : 0.f; __syncthreads();
    for (int s = 128; s > 0; s >>= 1) { if (t < s) red[t] += red[t + s]; __syncthreads(); }
    float mu = red[0] * (1.f / COUT); __syncthreads();
    float dv = (t < COUT) ? (hv - mu) : 0.f;
    red[t] = dv * dv; __syncthreads();
    for (int s = 128; s > 0; s >>= 1) { if (t < s) red[t] += red[t + s]; __syncthreads(); }
    float var = red[0] * (1.f / COUT); __syncthreads();
    if (t < COUT) h[t] = lg[t] * ((hv - mu) * rsqrtf(var + 1e-5f)) + lb[t];
    __syncthreads();
    float sv = bb2[t];
    const float* wr2 = w2 + t * COUT;
    for (int j = 0; j < COUT; j++) sv = fmaf(h[j], wr2[j], sv);
    float sig = 1.f / (1.f + expf(-sv));
    g_s[b * CIN + t] = sig;
    gp[t] = (1.f + sig) * avg;
    __syncthreads();
    float v = 0.f;
    const float* ar = apw + t * CIN;
    for (int i = 0; i < CIN; i++) v = fmaf(ar[i], gp[i], v);
    red[t] = v; __syncthreads();
    for (int s = 128; s > 0; s >>= 1) { if (t < s) red[t] += red[t + s]; __syncthreads(); }
    float mu2 = red[0] * (1.f / CIN); __syncthreads();
    float d2 = v - mu2; red[t] = d2 * d2; __syncthreads();
    for (int s = 128; s > 0; s >>= 1) { if (t < s) red[t] += red[t + s]; __syncthreads(); }
    float var2 = red[0] * (1.f / CIN); __syncthreads();
    float z = apg[t] * ((v - mu2) * rsqrtf(var2 + 1e-6f)) + apb[t];
    g_bp[b * CIN + t] = gelu_f(z);
}

// ---------------- xcT split: x[b][c][hw]*(1+s) -> bf16 hi/lo [b][hw][c] ----------------
__global__ void k_xcsplit(const float* __restrict__ x) {
    __shared__ float tile[32][33];
    int b = blockIdx.z, c0 = blockIdx.y * 32, h0 = blockIdx.x * 32;
    int t = threadIdx.x;
    const float* xb = x + ((size_t)b * CIN + c0) * HW + h0;
#pragma unroll
    for (int i = 0; i < 4; i++) {
        int r = (t >> 5) + 8 * i;
        tile[r][t & 31] = xb[(size_t)r * HW + (t & 31)];
    }
    __syncthreads();
#pragma unroll
    for (int i = 0; i < 4; i++) {
        int hr = (t >> 5) + 8 * i, cc = t & 31;
        float v = tile[cc][hr] * (1.f + g_s[b * CIN + c0 + cc]);
        __nv_bfloat16 h, l; splitf(v, h, l);
        size_t idx = ((size_t)b * HW + h0 + hr) * CIN + c0 + cc;
        g_xth[idx] = h; g_xtl[idx] = l;
    }
}

// ---------------- bp broadcast into catT channels [1024,1280) ----------------
__global__ void k_bp_cat() {
    int b = blockIdx.y, h0 = blockIdx.x * 32;
    int c = threadIdx.x;
    __nv_bfloat16 h, l; splitf(g_bp[b * CIN + c], h, l);
    for (int r = 0; r < 32; r++) {
        size_t idx = ((size_t)b * HW + h0 + r) * 1280 + 1024 + c;
        g_cth[idx] = h; g_ctl[idx] = l;
    }
}

// ---------------- HMMA bf16x2-split GEMM, 256x64 tile, LN+GELU epilogue ----------
// Out[b,m,n] = GELU(LN_m( sum_k W[m,k]*In[b,k,n] )),  In given transposed [n][k].
// 8 warps: 4 along M (64 rows each) x 2 along N (32 cols each). BK=32.
// smem buffer layout (bytes, per buf, pitch 80B/row):
//   Ah: 0..20480  Al: 20480..40960  Bh: 40960..46080  Bl: 46080..51200
template <bool CONV3, bool CATOUT>
__global__ void __launch_bounds__(256, 1) k_hgemm(
    const __nv_bfloat16* __restrict__ Whi, const __nv_bfloat16* __restrict__ Wlo,
    const __nv_bfloat16* __restrict__ Ihi, const __nv_bfloat16* __restrict__ Ilo,
    const float* __restrict__ gam, const float* __restrict__ bet,
    float* __restrict__ outF, __nv_bfloat16* __restrict__ cth, __nv_bfloat16* __restrict__ ctl,
    int coff, int Kc, int dil) {
    extern __shared__ __align__(16) char dsm[];
    __shared__ int s_tapn, s_tp[9], s_yy[9], s_dx[9];
    __shared__ float sgam[256], sbet[256], smean[64], srstd[64];
    __shared__ float red4[4][64];

    const int b = blockIdx.y, y = blockIdx.x;
    const int t = threadIdx.x, wid = t >> 5, lane = t & 31;
    const int mw = wid >> 1, nw = wid & 1;

    if (CONV3 && t == 0) {
        int n = 0;
        for (int tap = 0; tap < 9; tap++) {
            int yy = y + (tap / 3 - 1) * dil;
            if ((unsigned)yy < 64u) {
                s_tp[n] = tap; s_yy[n] = yy; s_dx[n] = (tap % 3 - 1) * dil; n++;
            }
        }
        s_tapn = n;
    }
    sgam[t] = gam[t]; sbet[t] = bet[t];
    __syncthreads();

    const int nkc = Kc / 32;
    const int T = CONV3 ? s_tapn * nkc : nkc;
    const __nv_bfloat16* Ib_hi = Ihi + (size_t)b * HW * Kc;
    const __nv_bfloat16* Ib_lo = Ilo + (size_t)b * HW * Kc;

    float acc[4][4][4];
#pragma unroll
    for (int i = 0; i < 4; i++)
#pragma unroll
        for (int j = 0; j < 4; j++)
#pragma unroll
            for (int r = 0; r < 4; r++) acc[i][j][r] = 0.f;

    uint4 rah[4], ral[4], rbh, rbl;

    auto loadG = [&](int it) {
        int tap_i = CONV3 ? (it / nkc) : 0;
        int kc = (CONV3 ? (it - tap_i * nkc) : it) * 32;
        int grow = CONV3 ? (s_tp[tap_i] * 256 + t) : t;
        const __nv_bfloat16* ah = Whi + (size_t)grow * Kc + kc;
        const __nv_bfloat16* al = Wlo + (size_t)grow * Kc + kc;
#pragma unroll
        for (int q = 0; q < 4; q++) {
            rah[q] = *reinterpret_cast<const uint4*>(ah + q * 8);
            ral[q] = *reinterpret_cast<const uint4*>(al + q * 8);
        }
        int n = t >> 2, q = t & 3;
        int hw; bool ok = true;
        if (CONV3) {
            int xx = n + s_dx[tap_i];
            ok = ((unsigned)xx < 64u);
            hw = s_yy[tap_i] * 64 + xx;
        } else hw = y * 64 + n;
        uint4 z = make_uint4(0, 0, 0, 0);
        rbh = ok ? *reinterpret_cast<const uint4*>(Ib_hi + (size_t)hw * Kc + kc + q * 8) : z;
        rbl = ok ? *reinterpret_cast<const uint4*>(Ib_lo + (size_t)hw * Kc + kc + q * 8) : z;
    };
    auto storeS = [&](int buf) {
        char* base = dsm + buf * 51200;
#pragma unroll
        for (int q = 0; q < 4; q++) {
            *reinterpret_cast<uint4*>(base + t * 80 + q * 16) = rah[q];
            *reinterpret_cast<uint4*>(base + 20480 + t * 80 + q * 16) = ral[q];
        }
        int n = t >> 2, q = t & 3;
        *reinterpret_cast<uint4*>(base + 40960 + n * 80 + q * 16) = rbh;
        *reinterpret_cast<uint4*>(base + 46080 + n * 80 + q * 16) = rbl;
    };

    loadG(0);
    storeS(0);
    __syncthreads();

    const int lr = lane >> 2, lc = 2 * (lane & 3);
    for (int it = 0; it < T; ++it) {
        int cur = it & 1;
        bool more = (it + 1 < T);
        if (more) loadG(it + 1);
        const char* base = dsm + cur * 51200;
        const char* Asm = base;
        const char* Alm = base + 20480;
        const char* Bhm = base + 40960;
        const char* Blm = base + 46080;
#pragma unroll
        for (int ks = 0; ks < 2; ks++) {
            int kb = ks * 16;
            uint32_t bh[4][2], bl[4][2];
#pragma unroll
            for (int j = 0; j < 4; j++) {
                int n = nw * 32 + j * 8 + lr;
                int off = n * 80 + (kb + lc) * 2;
                bh[j][0] = *reinterpret_cast<const uint32_t*>(Bhm + off);
                bh[j][1] = *reinterpret_cast<const uint32_t*>(Bhm + off + 16);
                bl[j][0] = *reinterpret_cast<const uint32_t*>(Blm + off);
                bl[j][1] = *reinterpret_cast<const uint32_t*>(Blm + off + 16);
            }
#pragma unroll
            for (int i = 0; i < 4; i++) {
                int r = mw * 64 + i * 16 + lr;
                int off = r * 80 + (kb + lc) * 2;
                uint32_t ah[4], al[4];
                ah[0] = *reinterpret_cast<const uint32_t*>(Asm + off);
                ah[1] = *reinterpret_cast<const uint32_t*>(Asm + off + 640);
                ah[2] = *reinterpret_cast<const uint32_t*>(Asm + off + 16);
                ah[3] = *reinterpret_cast<const uint32_t*>(Asm + off + 656);
                al[0] = *reinterpret_cast<const uint32_t*>(Alm + off);
                al[1] = *reinterpret_cast<const uint32_t*>(Alm + off + 640);
                al[2] = *reinterpret_cast<const uint32_t*>(Alm + off + 16);
                al[3] = *reinterpret_cast<const uint32_t*>(Alm + off + 656);
#pragma unroll
                for (int j = 0; j < 4; j++) {
                    mma16816(acc[i][j], ah, bh[j]);
                    mma16816(acc[i][j], ah, bl[j]);
                    mma16816(acc[i][j], al, bh[j]);
                }
            }
        }
        if (more) storeS(cur ^ 1);
        __syncthreads();
    }

    // ---- stage D (256x64 fp32) into smem [m][65]
    float* Ds = reinterpret_cast<float*>(dsm);
#pragma unroll
    for (int i = 0; i < 4; i++) {
        int r0 = mw * 64 + i * 16 + lr;
#pragma unroll
        for (int j = 0; j < 4; j++) {
            int c = nw * 32 + j * 8 + lc;
            Ds[r0 * 65 + c] = acc[i][j][0];
            Ds[r0 * 65 + c + 1] = acc[i][j][1];
            Ds[(r0 + 8) * 65 + c] = acc[i][j][2];
            Ds[(r0 + 8) * 65 + c + 1] = acc[i][j][3];
        }
    }
    __syncthreads();
    int n = t & 63, p = t >> 6;
    {
        float s = 0.f;
        for (int mm = p * 64; mm < p * 64 + 64; mm++) s += Ds[mm * 65 + n];
        red4[p][n] = s;
    }
    __syncthreads();
    if (t < 64) smean[t] = (red4[0][t] + red4[1][t] + red4[2][t] + red4[3][t]) * (1.f / 256.f);
    __syncthreads();
    {
        float mu = smean[n], s = 0.f;
        for (int mm = p * 64; mm < p * 64 + 64; mm++) {
            float d = Ds[mm * 65 + n] - mu; s += d * d;
        }
        red4[p][n] = s;
    }
    __syncthreads();
    if (t < 64)
        srstd[t] = rsqrtf((red4[0][t] + red4[1][t] + red4[2][t] + red4[3][t]) * (1.f / 256.f) + 1e-6f);
    __syncthreads();
    {
        float mu = smean[n], rs = srstd[n];
        if (CATOUT) {
            size_t rowb = ((size_t)b * HW + y * 64 + n) * 1280 + coff;
            for (int mm = p * 64; mm < p * 64 + 64; mm++) {
                float vv = gelu_f((Ds[mm * 65 + n] - mu) * rs * sgam[mm] + sbet[mm]);
                __nv_bfloat16 h, l; splitf(vv, h, l);
                cth[rowb + mm] = h; ctl[rowb + mm] = l;
            }
        } else {
            size_t ob = (size_t)b * CIN * HW + y * 64 + n;
            for (int mm = p * 64; mm < p * 64 + 64; mm++) {
                float vv = gelu_f((Ds[mm * 65 + n] - mu) * rs * sgam[mm] + sbet[mm]);
                outF[ob + (size_t)mm * HW] = vv;
            }
        }
    }
}

// ---------------- FFMA pipelined GEMM (conv1 / xa / L / conv2) ----------------
template <int BM, int MODE>
__global__ void __launch_bounds__(256, 2) k_gemm(
    const float* __restrict__ Wg, size_t wb_stride,
    const float* __restrict__ In, size_t in_bstride,
    const float* __restrict__ P1,
    const float* __restrict__ Addp, size_t add_bstride,
    float* __restrict__ Out, size_t out_bstride,
    int Kc) {
    constexpr int TM = BM / 32;
    constexpr int NAREG = (BM == 256) ? 4 : 2;
    const int b = blockIdx.y;
    const int y = blockIdx.x;
    const int n0 = y * BN;
    const int t = threadIdx.x;
    const int ty = t >> 3, tx = t & 7;

    __shared__ __align__(16) float As[2][KT][BM];
    __shared__ __align__(16) float Bs[2][KT][BN];

    const int total = Kc / KT;
    const float* Wb = Wg + (size_t)b * wb_stride;
    const float* Inb = In + (size_t)b * in_bstride;

    ull acc2[TM][4];
#pragma unroll
    for (int i = 0; i < TM; i++)
#pragma unroll
        for (int j = 0; j < 4; j++) acc2[i][j] = 0ULL;

    float4 ra[NAREG];
    float rb[4];

    auto loadG = [&](int it) {
        int k0 = it * KT;
        if (BM == 256) {
            const float* wrow = Wb + (size_t)t * Kc + k0;
#pragma unroll
            for (int q = 0; q < 4; q++)
                ra[q] = *reinterpret_cast<const float4*>(wrow + q * 4);
        } else {
            int m = t >> 1, ko = (t & 1) * 8;
            const float* wrow = Wb + (size_t)m * Kc + k0 + ko;
#pragma unroll
            for (int q = 0; q < 2; q++)
                ra[q] = *reinterpret_cast<const float4*>(wrow + q * 4);
        }
        int k = t >> 4, nb = (t & 15) * 4;
        float4 v = *reinterpret_cast<const float4*>(Inb + (size_t)(k0 + k) * HW + n0 + nb);
        rb[0] = v.x; rb[1] = v.y; rb[2] = v.z; rb[3] = v.w;
    };
    auto storeS = [&](int buf) {
        if (BM == 256) {
#pragma unroll
            for (int q = 0; q < 4; q++) {
                As[buf][q * 4 + 0][t] = ra[q].x; As[buf][q * 4 + 1][t] = ra[q].y;
                As[buf][q * 4 + 2][t] = ra[q].z; As[buf][q * 4 + 3][t] = ra[q].w;
            }
        } else {
            int m = t >> 1, ko = (t & 1) * 8;
#pragma unroll
            for (int q = 0; q < 2; q++) {
                As[buf][ko + q * 4 + 0][m] = ra[q].x; As[buf][ko + q * 4 + 1][m] = ra[q].y;
                As[buf][ko + q * 4 + 2][m] = ra[q].z; As[buf][ko + q * 4 + 3][m] = ra[q].w;
            }
        }
        int k = t >> 4, nb = (t & 15) * 4;
        Bs[buf][k][nb] = rb[0]; Bs[buf][k][nb + 1] = rb[1];
        Bs[buf][k][nb + 2] = rb[2]; Bs[buf][k][nb + 3] = rb[3];
    };

    loadG(0);
    storeS(0);
    __syncthreads();

    for (int it = 0; it < total; ++it) {
        int cur = it & 1;
        bool more = (it + 1 < total);
        if (more) loadG(it + 1);
#pragma unroll
        for (int k = 0; k < KT; k++) {
            ull a2[TM], b2[4];
#pragma unroll
            for (int i = 0; i < TM; i += 4) {
                float4 v = *reinterpret_cast<const float4*>(&As[cur][k][ty * TM + i]);
                a2[i] = pack2f(v.x); a2[i + 1] = pack2f(v.y);
                a2[i + 2] = pack2f(v.z); a2[i + 3] = pack2f(v.w);
            }
            {
                float4 v0 = *reinterpret_cast<const float4*>(&Bs[cur][k][tx * 8]);
                float4 v1 = *reinterpret_cast<const float4*>(&Bs[cur][k][tx * 8 + 4]);
                b2[0] = pack2(v0.x, v0.y); b2[1] = pack2(v0.z, v0.w);
                b2[2] = pack2(v1.x, v1.y); b2[3] = pack2(v1.z, v1.w);
            }
#pragma unroll
            for (int i = 0; i < TM; i++)
#pragma unroll
                for (int j = 0; j < 4; j++) fma2(acc2[i][j], a2[i], b2[j]);
        }
        if (more) storeS(cur ^ 1);
        __syncthreads();
    }

    float* Ob = Out + (size_t)b * out_bstride;
#pragma unroll
    for (int i = 0; i < TM; i++) {
        int m = ty * TM + i;
        float bias = (MODE == 0) ? P1[m] : 0.f;
        const float* addrow = (MODE == 2)
            ? (Addp + (size_t)b * add_bstride + (size_t)m * HW + n0 + tx * 8)
            : nullptr;
        float o8[8];
#pragma unroll
        for (int j = 0; j < 4; j++) {
            float2 f = unpk2(acc2[i][j]);
            o8[2 * j] = f.x + bias; o8[2 * j + 1] = f.y + bias;
            if (MODE == 2) { o8[2 * j] += addrow[2 * j]; o8[2 * j + 1] += addrow[2 * j + 1]; }
        }
        float* dst = Ob + (size_t)m * HW + n0 + tx * 8;
        *reinterpret_cast<float4*>(dst) = make_float4(o8[0], o8[1], o8[2], o8[3]);
        *reinterpret_cast<float4*>(dst + 4) = make_float4(o8[4], o8[5], o8[6], o8[7]);
    }
}

// ---------------- S[b,q,p] = (1/64) sum_c xa[b,c,q] * x1[b,c,p] ----------------
__global__ void __launch_bounds__(256, 2) k_sgemm() {
    const int b = blockIdx.z;
    const int m0 = blockIdx.y * 128;
    const int n0 = blockIdx.x * 64;
    const int t = threadIdx.x, ty = t >> 3, tx = t & 7;
    const float* Q = g_xa + (size_t)b * COUT * HW;
    const float* P = g_x1 + (size_t)b * COUT * HW;
    float* S = g_S + (size_t)b * HW * HW;
    __shared__ __align__(16) float As[2][KT][128];
    __shared__ __align__(16) float Bs[2][KT][64];
    ull acc2[4][4];
#pragma unroll
    for (int i = 0; i < 4; i++)
#pragma unroll
        for (int j = 0; j < 4; j++) acc2[i][j] = 0ULL;

    float4 ra0, ra1, rbv;
    auto loadG = [&](int it) {
        int k0 = it * KT;
        int k = t >> 4;
        int mm = (t & 15) * 8;
        const float* src = Q + (size_t)(k0 + k) * HW + m0 + mm;
        ra0 = *reinterpret_cast<const float4*>(src);
        ra1 = *reinterpret_cast<const float4*>(src + 4);
        int nb = (t & 15) * 4;
        rbv = *reinterpret_cast<const float4*>(P + (size_t)(k0 + k) * HW + n0 + nb);
    };
    auto storeS = [&](int buf) {
        int k = t >> 4;
        int mm = (t & 15) * 8;
        *reinterpret_cast<float4*>(&As[buf][k][mm]) = ra0;
        *reinterpret_cast<float4*>(&As[buf][k][mm + 4]) = ra1;
        int nb = (t & 15) * 4;
        *reinterpret_cast<float4*>(&Bs[buf][k][nb]) = rbv;
    };

    const int total = COUT / KT;
    loadG(0);
    storeS(0);
    __syncthreads();

    for (int it = 0; it < total; ++it) {
        int cur = it & 1;
        bool more = (it + 1 < total);
        if (more) loadG(it + 1);
#pragma unroll
        for (int kk = 0; kk < KT; kk++) {
            ull a2[4], b2[4];
            float4 va = *reinterpret_cast<const float4*>(&As[cur][kk][ty * 4]);
            a2[0] = pack2f(va.x); a2[1] = pack2f(va.y);
            a2[2] = pack2f(va.z); a2[3] = pack2f(va.w);
            float4 v0 = *reinterpret_cast<const float4*>(&Bs[cur][kk][tx * 8]);
            float4 v1 = *reinterpret_cast<const float4*>(&Bs[cur][kk][tx * 8 + 4]);
            b2[0] = pack2(v0.x, v0.y); b2[1] = pack2(v0.z, v0.w);
            b2[2] = pack2(v1.x, v1.y); b2[3] = pack2(v1.z, v1.w);
#pragma unroll
            for (int i = 0; i < 4; i++)
#pragma unroll
                for (int j = 0; j < 4; j++) fma2(acc2[i][j], a2[i], b2[j]);
        }
        if (more) storeS(cur ^ 1);
        __syncthreads();
    }
    const float sc = 1.f / 64.f;
#pragma unroll
    for (int i = 0; i < 4; i++) {
        int m = ty * 4 + i;
        float* dst = S + (size_t)(m0 + m) * HW + n0 + tx * 8;
        float o8[8];
#pragma unroll
        for (int j = 0; j < 4; j++) {
            float2 f = unpk2(acc2[i][j]);
            o8[2 * j] = f.x * sc; o8[2 * j + 1] = f.y * sc;
        }
        *reinterpret_cast<float4*>(dst) = make_float4(o8[0], o8[1], o8[2], o8[3]);
        *reinterpret_cast<float4*>(dst + 4) = make_float4(o8[4], o8[5], o8[6], o8[7]);
    }
}

// ---------------- row softmax over p (in place on g_S) ----------------
__global__ void __launch_bounds__(256) k_softmax() {
    const size_t row = blockIdx.x;
    float* r = g_S + row * (size_t)HW;
    __shared__ float buf[HW];
    __shared__ float red[256];
    int t = threadIdx.x;
    float m = -1e30f;
    for (int i = t; i < HW; i += 256) { float v = r[i]; buf[i] = v; m = fmaxf(m, v); }
    red[t] = m; __syncthreads();
    for (int s = 128; s > 0; s >>= 1) { if (t < s) red[t] = fmaxf(red[t], red[t + s]); __syncthreads(); }
    float mx = red[0]; __syncthreads();
    float s = 0.f;
    for (int i = t; i < HW; i += 256) { float e = expf(buf[i] - mx); buf[i] = e; s += e; }
    red[t] = s; __syncthreads();
    for (int o = 128; o > 0; o >>= 1) { if (t < o) red[t] += red[t + o]; __syncthreads(); }
    float inv = 1.f / red[0];
    for (int i = t; i < HW; i += 256) r[i] = buf[i] * inv;
}

// ---------------- host launch ----------------
extern "C" void kernel_launch(void* const* d_in, const int* in_sizes, int n_in,
                              void* d_out, int out_size) {
    (void)in_sizes; (void)n_in; (void)out_size;
    const float* x       = (const float*)d_in[0];
    const float* conv1_w = (const float*)d_in[1];
    const float* conv1_b = (const float*)d_in[2];
    const float* conv2_w = (const float*)d_in[3];
    const float* conv2_b = (const float*)d_in[4];
    const float* cw_w1   = (const float*)d_in[5];
    const float* cw_b1   = (const float*)d_in[6];
    const float* cw_ln_g = (const float*)d_in[7];
    const float* cw_ln_b = (const float*)d_in[8];
    const float* cw_w2   = (const float*)d_in[9];
    const float* cw_b2   = (const float*)d_in[10];
    const float* aspp0_w = (const float*)d_in[11];
    const float* aspp0_g = (const float*)d_in[12];
    const float* aspp0_b = (const float*)d_in[13];
    const float* aspp1_w = (const float*)d_in[14];
    const float* aspp1_g = (const float*)d_in[15];
    const float* aspp1_b = (const float*)d_in[16];
    const float* aspp2_w = (const float*)d_in[17];
    const float* aspp2_g = (const float*)d_in[18];
    const float* aspp2_b = (const float*)d_in[19];
    const float* aspp3_w = (const float*)d_in[20];
    const float* aspp3_g = (const float*)d_in[21];
    const float* aspp3_b = (const float*)d_in[22];
    const float* asppp_w = (const float*)d_in[23];
    const float* asppp_g = (const float*)d_in[24];
    const float* asppp_b = (const float*)d_in[25];
    const float* proj_w  = (const float*)d_in[26];
    const float* proj_g  = (const float*)d_in[27];
    const float* proj_b  = (const float*)d_in[28];

    void* pv;
    float *p_x1, *p_proj, *p_xa, *p_O, *p_S;
    __nv_bfloat16 *p_xth, *p_xtl, *p_cth, *p_ctl, *p_w3h, *p_w3l, *p_a0h, *p_a0l, *p_pjh, *p_pjl;
    cudaGetSymbolAddress(&pv, g_x1);   p_x1   = (float*)pv;
    cudaGetSymbolAddress(&pv, g_proj); p_proj = (float*)pv;
    cudaGetSymbolAddress(&pv, g_xa);   p_xa   = (float*)pv;
    cudaGetSymbolAddress(&pv, g_O);    p_O    = (float*)pv;
    cudaGetSymbolAddress(&pv, g_S);    p_S    = (float*)pv;
    cudaGetSymbolAddress(&pv, g_xth);  p_xth  = (__nv_bfloat16*)pv;
    cudaGetSymbolAddress(&pv, g_xtl);  p_xtl  = (__nv_bfloat16*)pv;
    cudaGetSymbolAddress(&pv, g_cth);  p_cth  = (__nv_bfloat16*)pv;
    cudaGetSymbolAddress(&pv, g_ctl);  p_ctl  = (__nv_bfloat16*)pv;
    cudaGetSymbolAddress(&pv, g_w3h);  p_w3h  = (__nv_bfloat16*)pv;
    cudaGetSymbolAddress(&pv, g_w3l);  p_w3l  = (__nv_bfloat16*)pv;
    cudaGetSymbolAddress(&pv, g_a0h);  p_a0h  = (__nv_bfloat16*)pv;
    cudaGetSymbolAddress(&pv, g_a0l);  p_a0l  = (__nv_bfloat16*)pv;
    cudaGetSymbolAddress(&pv, g_pjh);  p_pjh  = (__nv_bfloat16*)pv;
    cudaGetSymbolAddress(&pv, g_pjl);  p_pjl  = (__nv_bfloat16*)pv;

    const int TG_SMEM = 102400;  // 2 x 51200 double buffer; epilogue stage (66,560B) aliases it
    cudaFuncSetAttribute(k_hgemm<false, true>, cudaFuncAttributeMaxDynamicSharedMemorySize, TG_SMEM);
    cudaFuncSetAttribute(k_hgemm<true, true>, cudaFuncAttributeMaxDynamicSharedMemorySize, TG_SMEM);
    cudaFuncSetAttribute(k_hgemm<false, false>, cudaFuncAttributeMaxDynamicSharedMemorySize, TG_SMEM);

    dim3 g64(HW / BN, BATCH);

    k_wsplit<<<2304, 256>>>(aspp1_w, aspp2_w, aspp3_w, aspp0_w, proj_w);
    k_stats<<<BATCH * CIN, 256>>>(x);
    k_cw<<<BATCH, 256>>>(cw_w1, cw_b1, cw_ln_g, cw_ln_b, cw_w2, cw_b2,
                         asppp_w, asppp_g, asppp_b);
    // x1 = conv1(x) + b
    k_gemm<128, 0><<<g64, 256>>>(conv1_w, 0, x, (size_t)CIN * HW, conv1_b,
                                 nullptr, 0, p_x1, (size_t)COUT * HW, CIN);
    // activation split/transpose + bp broadcast
    k_xcsplit<<<dim3(128, 8, BATCH), 256>>>(x);
    k_bp_cat<<<dim3(128, BATCH), 256>>>();
    // ASPP branches (HMMA bf16x2-split)
    k_hgemm<false, true><<<g64, 256, TG_SMEM>>>(p_a0h, p_a0l, p_xth, p_xtl,
        aspp0_g, aspp0_b, nullptr, p_cth, p_ctl, 0, CIN, 0);
    k_hgemm<true, true><<<g64, 256, TG_SMEM>>>(p_w3h + 0 * 9 * 65536, p_w3l + 0 * 9 * 65536,
        p_xth, p_xtl, aspp1_g, aspp1_b, nullptr, p_cth, p_ctl, 256, CIN, 3);
    k_hgemm<true, true><<<g64, 256, TG_SMEM>>>(p_w3h + 1 * 9 * 65536, p_w3l + 1 * 9 * 65536,
        p_xth, p_xtl, aspp2_g, aspp2_b, nullptr, p_cth, p_ctl, 512, CIN, 6);
    k_hgemm<true, true><<<g64, 256, TG_SMEM>>>(p_w3h + 2 * 9 * 65536, p_w3l + 2 * 9 * 65536,
        p_xth, p_xtl, aspp3_g, aspp3_b, nullptr, p_cth, p_ctl, 768, CIN, 9);
    // proj (HMMA, K=1280) -> f32
    k_hgemm<false, false><<<g64, 256, TG_SMEM>>>(p_pjh, p_pjl, p_cth, p_ctl,
        proj_g, proj_b, p_proj, nullptr, nullptr, 0, 5 * CIN, 0);
    // xa = conv1(proj) + b
    k_gemm<128, 0><<<g64, 256>>>(conv1_w, 0, p_proj, (size_t)CIN * HW, conv1_b,
                                 nullptr, 0, p_xa, (size_t)COUT * HW, CIN);
    // attention
    k_sgemm<<<dim3(HW / 64, HW / 128, BATCH), 256>>>();
    k_softmax<<<BATCH * HW, 256>>>();
    k_gemm<128, 2><<<g64, 256>>>(p_x1, (size_t)COUT * HW, p_S, (size_t)HW * HW,
                                 nullptr, p_xa, (size_t)COUT * HW,
                                 p_O, (size_t)COUT * HW, HW);
    // out = conv2(O) + b
    k_gemm<256, 0><<<g64, 256>>>(conv2_w, 0, p_O, (size_t)COUT * HW, conv2_b,
                                 nullptr, 0, (float*)d_out, (size_t)CIN * HW, COUT);
}

// round 6
// speedup vs baseline: 1.6130x; 1.3023x over previous
#include <cuda_runtime.h>
#include <cuda_bf16.h>
#include <math.h>
#include <stdint.h>

#define BATCH 4
#define CIN 256
#define COUT 128
#define HH 64
#define WW 64
#define HW 4096
#define BN 64
#define KT 16

typedef unsigned long long ull;

// ---------------- scratch (static device globals; no allocs) ----------------
__device__ float g_x1[BATCH * COUT * HW];
__device__ float g_proj[BATCH * CIN * HW];
__device__ float g_xa[BATCH * COUT * HW];
__device__ float g_O[BATCH * COUT * HW];
__device__ float g_S[(size_t)BATCH * HW * HW];
__device__ float g_avg[BATCH * CIN];
__device__ float g_mx[BATCH * CIN];
__device__ float g_s[BATCH * CIN];
__device__ float g_bp[BATCH * CIN];
// bf16 split operands
__device__ __nv_bfloat16 g_xth[BATCH * HW * CIN];              // xcT hi  [b][hw][c]
__device__ __nv_bfloat16 g_xtl[BATCH * HW * CIN];              // xcT lo
__device__ __nv_bfloat16 g_cth[(size_t)BATCH * HW * 5 * CIN];  // catT hi [b][hw][1280]
__device__ __nv_bfloat16 g_ctl[(size_t)BATCH * HW * 5 * CIN];  // catT lo
__device__ __nv_bfloat16 g_w3h[3 * 9 * CIN * CIN];             // [conv][tap][m][c]
__device__ __nv_bfloat16 g_w3l[3 * 9 * CIN * CIN];
__device__ __nv_bfloat16 g_a0h[CIN * CIN];
__device__ __nv_bfloat16 g_a0l[CIN * CIN];
__device__ __nv_bfloat16 g_pjh[CIN * 5 * CIN];
__device__ __nv_bfloat16 g_pjl[CIN * 5 * CIN];
// attention operands
__device__ __nv_bfloat16 g_x1th[BATCH * HW * COUT];  // x1T hi [b][hw][c]
__device__ __nv_bfloat16 g_x1tl[BATCH * HW * COUT];
__device__ __nv_bfloat16 g_xath[BATCH * HW * COUT];  // xaT hi [b][hw][c]
__device__ __nv_bfloat16 g_xatl[BATCH * HW * COUT];
__device__ __nv_bfloat16 g_x1h[BATCH * COUT * HW];   // x1 straight split [b][c][hw]
__device__ __nv_bfloat16 g_x1l[BATCH * COUT * HW];
__device__ __nv_bfloat16 g_Ah[(size_t)BATCH * HW * HW];  // softmax probs hi [b][q][p]
__device__ __nv_bfloat16 g_Al[(size_t)BATCH * HW * HW];

__device__ __forceinline__ float gelu_f(float x) {
    return 0.5f * x * (1.0f + erff(x * 0.70710678118654752440f));
}
__device__ __forceinline__ void splitf(float v, __nv_bfloat16& h, __nv_bfloat16& l) {
    h = __float2bfloat16(v);
    l = __float2bfloat16(v - __bfloat162float(h));
}

// ---------------- HMMA m16n8k16 bf16 ----------------
__device__ __forceinline__ void mma16816(float* d, const uint32_t* a, const uint32_t* b) {
    asm volatile(
        "mma.sync.aligned.m16n8k16.row.col.f32.bf16.bf16.f32 "
        "{%0,%1,%2,%3}, {%4,%5,%6,%7}, {%8,%9}, {%0,%1,%2,%3};"
        : "+f"(d[0]), "+f"(d[1]), "+f"(d[2]), "+f"(d[3])
        : "r"(a[0]), "r"(a[1]), "r"(a[2]), "r"(a[3]), "r"(b[0]), "r"(b[1]));
}

// ---------------- packed helpers for FFMA path ----------------
__device__ __forceinline__ ull pack2f(float x) {
    ull r; asm("mov.b64 %0, {%1, %1};" : "=l"(r) : "f"(x)); return r;
}
__device__ __forceinline__ ull pack2(float x, float y) {
    ull r; asm("mov.b64 %0, {%1, %2};" : "=l"(r) : "f"(x), "f"(y)); return r;
}
__device__ __forceinline__ void fma2(ull& d, ull a, ull b) {
    asm("fma.rn.f32x2 %0, %1, %2, %0;" : "+l"(d) : "l"(a), "l"(b));
}
__device__ __forceinline__ float2 unpk2(ull v) {
    float2 f; asm("mov.b64 {%0, %1}, %2;" : "=f"(f.x), "=f"(f.y) : "l"(v)); return f;
}

// ---------------- prep: weight split/transpose + per-(b,c) stats ----------------
__global__ void k_prep(const float* __restrict__ w1, const float* __restrict__ w2,
                       const float* __restrict__ w3, const float* __restrict__ a0,
                       const float* __restrict__ pj, const float* __restrict__ x) {
    if (blockIdx.x < 2304) {
        int e = blockIdx.x * 256 + threadIdx.x;
        if (e < 196608) {
            const float* srcs[3] = { w1, w2, w3 };
            int conv = e >> 16, mc = e & 65535, m = mc >> 8, c = mc & 255;
            const float* src = srcs[conv] + (size_t)m * 2304 + (size_t)c * 9;
            size_t dbase = (size_t)conv * 9 * 65536 + (size_t)m * 256 + c;
#pragma unroll
            for (int tap = 0; tap < 9; tap++) {
                __nv_bfloat16 h, l; splitf(src[tap], h, l);
                g_w3h[dbase + (size_t)tap * 65536] = h;
                g_w3l[dbase + (size_t)tap * 65536] = l;
            }
        } else if (e < 262144) {
            int i = e - 196608;
            __nv_bfloat16 h, l; splitf(a0[i], h, l);
            g_a0h[i] = h; g_a0l[i] = l;
        } else if (e < 589824) {
            int i = e - 262144;
            __nv_bfloat16 h, l; splitf(pj[i], h, l);
            g_pjh[i] = h; g_pjl[i] = l;
        }
    } else {
        int bc = blockIdx.x - 2304;
        const float* p = x + (size_t)bc * HW;
        int t = threadIdx.x;
        float s = 0.f, m = -1e30f;
        for (int i = t; i < HW; i += 256) { float v = p[i]; s += v; m = fmaxf(m, v); }
        __shared__ float ss[256], sm[256];
        ss[t] = s; sm[t] = m; __syncthreads();
        for (int o = 128; o > 0; o >>= 1) {
            if (t < o) { ss[t] += ss[t + o]; sm[t] = fmaxf(sm[t], sm[t + o]); }
            __syncthreads();
        }
        if (t == 0) { g_avg[bc] = ss[0] * (1.f / HW); g_mx[bc] = sm[0]; }
    }
}

// ---------------- channel weighting MLP + global-pool ASPP branch ----------------
__global__ void k_cw(const float* __restrict__ w1, const float* __restrict__ bb1,
                     const float* __restrict__ lg, const float* __restrict__ lb,
                     const float* __restrict__ w2, const float* __restrict__ bb2,
                     const float* __restrict__ apw, const float* __restrict__ apg,
                     const float* __restrict__ apb) {
    int b = blockIdx.x, t = threadIdx.x;
    __shared__ float o[CIN];
    __shared__ float h[COUT];
    __shared__ float red[256];
    __shared__ float gp[CIN];
    float avg = g_avg[b * CIN + t], mx = g_mx[b * CIN + t];
    o[t] = fabsf(avg - mx) * avg;
    __syncthreads();
    float hv = 0.f;
    if (t < COUT) {
        hv = bb1[t];
        const float* wr = w1 + t * CIN;
        for (int i = 0; i < CIN; i++) hv = fmaf(o[i], wr[i], hv);
    }
    red[t] = (t < COUT) ? hv : 0.f; __syncthreads();
    for (int s = 128; s > 0; s >>= 1) { if (t < s) red[t] += red[t + s]; __syncthreads(); }
    float mu = red[0] * (1.f / COUT); __syncthreads();
    float dv = (t < COUT) ? (hv - mu) : 0.f;
    red[t] = dv * dv; __syncthreads();
    for (int s = 128; s > 0; s >>= 1) { if (t < s) red[t] += red[t + s]; __syncthreads(); }
    float var = red[0] * (1.f / COUT); __syncthreads();
    if (t < COUT) h[t] = lg[t] * ((hv - mu) * rsqrtf(var + 1e-5f)) + lb[t];
    __syncthreads();
    float sv = bb2[t];
    const float* wr2 = w2 + t * COUT;
    for (int j = 0; j < COUT; j++) sv = fmaf(h[j], wr2[j], sv);
    float sig = 1.f / (1.f + expf(-sv));
    g_s[b * CIN + t] = sig;
    gp[t] = (1.f + sig) * avg;
    __syncthreads();
    float v = 0.f;
    const float* ar = apw + t * CIN;
    for (int i = 0; i < CIN; i++) v = fmaf(ar[i], gp[i], v);
    red[t] = v; __syncthreads();
    for (int s = 128; s > 0; s >>= 1) { if (t < s) red[t] += red[t + s]; __syncthreads(); }
    float mu2 = red[0] * (1.f / CIN); __syncthreads();
    float d2 = v - mu2; red[t] = d2 * d2; __syncthreads();
    for (int s = 128; s > 0; s >>= 1) { if (t < s) red[t] += red[t + s]; __syncthreads(); }
    float var2 = red[0] * (1.f / CIN); __syncthreads();
    float z = apg[t] * ((v - mu2) * rsqrtf(var2 + 1e-6f)) + apb[t];
    g_bp[b * CIN + t] = gelu_f(z);
}

// ---------------- xcT split: x[b][c][hw]*(1+s) -> bf16 hi/lo [b][hw][c] ----------------
__global__ void k_xcsplit(const float* __restrict__ x) {
    __shared__ float tile[32][33];
    int b = blockIdx.z, c0 = blockIdx.y * 32, h0 = blockIdx.x * 32;
    int t = threadIdx.x;
    const float* xb = x + ((size_t)b * CIN + c0) * HW + h0;
#pragma unroll
    for (int i = 0; i < 4; i++) {
        int r = (t >> 5) + 8 * i;
        tile[r][t & 31] = xb[(size_t)r * HW + (t & 31)];
    }
    __syncthreads();
#pragma unroll
    for (int i = 0; i < 4; i++) {
        int hr = (t >> 5) + 8 * i, cc = t & 31;
        float v = tile[cc][hr] * (1.f + g_s[b * CIN + c0 + cc]);
        __nv_bfloat16 h, l; splitf(v, h, l);
        size_t idx = ((size_t)b * HW + h0 + hr) * CIN + c0 + cc;
        g_xth[idx] = h; g_xtl[idx] = l;
    }
}

// ---------------- split/transpose for 128-channel fp32 maps ----------------
template <bool STRAIGHT>
__global__ void k_splitT(const float* __restrict__ in,
                         __nv_bfloat16* __restrict__ th, __nv_bfloat16* __restrict__ tl,
                         __nv_bfloat16* __restrict__ sh, __nv_bfloat16* __restrict__ sl) {
    __shared__ float tile[32][33];
    int b = blockIdx.z, c0 = blockIdx.y * 32, h0 = blockIdx.x * 32;
    int t = threadIdx.x;
    const float* ib = in + ((size_t)b * COUT + c0) * HW + h0;
#pragma unroll
    for (int i = 0; i < 4; i++) {
        int r = (t >> 5) + 8 * i, col = t & 31;
        float v = ib[(size_t)r * HW + col];
        tile[r][col] = v;
        if (STRAIGHT) {
            __nv_bfloat16 h, l; splitf(v, h, l);
            size_t idx = ((size_t)b * COUT + c0 + r) * HW + h0 + col;
            sh[idx] = h; sl[idx] = l;
        }
    }
    __syncthreads();
#pragma unroll
    for (int i = 0; i < 4; i++) {
        int hr = (t >> 5) + 8 * i, cc = t & 31;
        float v = tile[cc][hr];
        __nv_bfloat16 h, l; splitf(v, h, l);
        size_t idx = ((size_t)b * HW + h0 + hr) * COUT + c0 + cc;
        th[idx] = h; tl[idx] = l;
    }
}

// ---------------- bp broadcast into catT channels [1024,1280) ----------------
__global__ void k_bp_cat() {
    int b = blockIdx.y, h0 = blockIdx.x * 32;
    int c = threadIdx.x;
    __nv_bfloat16 h, l; splitf(g_bp[b * CIN + c], h, l);
    for (int r = 0; r < 32; r++) {
        size_t idx = ((size_t)b * HW + h0 + r) * 1280 + 1024 + c;
        g_cth[idx] = h; g_ctl[idx] = l;
    }
}

// ---------------- HMMA bf16x2-split GEMM, 256x64 tile, LN+GELU epilogue ----------
template <bool CONV3, bool CATOUT>
__global__ void __launch_bounds__(256, 1) k_hgemm(
    const __nv_bfloat16* __restrict__ Whi, const __nv_bfloat16* __restrict__ Wlo,
    const __nv_bfloat16* __restrict__ Ihi, const __nv_bfloat16* __restrict__ Ilo,
    const float* __restrict__ gam, const float* __restrict__ bet,
    float* __restrict__ outF, __nv_bfloat16* __restrict__ cth, __nv_bfloat16* __restrict__ ctl,
    int coff, int Kc, int dil) {
    extern __shared__ __align__(16) char dsm[];
    __shared__ int s_tapn, s_tp[9], s_yy[9], s_dx[9];
    __shared__ float sgam[256], sbet[256], smean[64], srstd[64];
    __shared__ float red4[4][64];

    const int b = blockIdx.y, y = blockIdx.x;
    const int t = threadIdx.x, wid = t >> 5, lane = t & 31;
    const int mw = wid >> 1, nw = wid & 1;

    if (CONV3 && t == 0) {
        int n = 0;
        for (int tap = 0; tap < 9; tap++) {
            int yy = y + (tap / 3 - 1) * dil;
            if ((unsigned)yy < 64u) {
                s_tp[n] = tap; s_yy[n] = yy; s_dx[n] = (tap % 3 - 1) * dil; n++;
            }
        }
        s_tapn = n;
    }
    sgam[t] = gam[t]; sbet[t] = bet[t];
    __syncthreads();

    const int nkc = Kc / 32;
    const int T = CONV3 ? s_tapn * nkc : nkc;
    const __nv_bfloat16* Ib_hi = Ihi + (size_t)b * HW * Kc;
    const __nv_bfloat16* Ib_lo = Ilo + (size_t)b * HW * Kc;

    float acc[4][4][4];
#pragma unroll
    for (int i = 0; i < 4; i++)
#pragma unroll
        for (int j = 0; j < 4; j++)
#pragma unroll
            for (int r = 0; r < 4; r++) acc[i][j][r] = 0.f;

    uint4 rah[4], ral[4], rbh, rbl;

    auto loadG = [&](int it) {
        int tap_i = CONV3 ? (it / nkc) : 0;
        int kc = (CONV3 ? (it - tap_i * nkc) : it) * 32;
        int grow = CONV3 ? (s_tp[tap_i] * 256 + t) : t;
        const __nv_bfloat16* ah = Whi + (size_t)grow * Kc + kc;
        const __nv_bfloat16* al = Wlo + (size_t)grow * Kc + kc;
#pragma unroll
        for (int q = 0; q < 4; q++) {
            rah[q] = *reinterpret_cast<const uint4*>(ah + q * 8);
            ral[q] = *reinterpret_cast<const uint4*>(al + q * 8);
        }
        int n = t >> 2, q = t & 3;
        int hw; bool ok = true;
        if (CONV3) {
            int xx = n + s_dx[tap_i];
            ok = ((unsigned)xx < 64u);
            hw = s_yy[tap_i] * 64 + xx;
        } else hw = y * 64 + n;
        uint4 z = make_uint4(0, 0, 0, 0);
        rbh = ok ? *reinterpret_cast<const uint4*>(Ib_hi + (size_t)hw * Kc + kc + q * 8) : z;
        rbl = ok ? *reinterpret_cast<const uint4*>(Ib_lo + (size_t)hw * Kc + kc + q * 8) : z;
    };
    auto storeS = [&](int buf) {
        char* base = dsm + buf * 51200;
#pragma unroll
        for (int q = 0; q < 4; q++) {
            *reinterpret_cast<uint4*>(base + t * 80 + q * 16) = rah[q];
            *reinterpret_cast<uint4*>(base + 20480 + t * 80 + q * 16) = ral[q];
        }
        int n = t >> 2, q = t & 3;
        *reinterpret_cast<uint4*>(base + 40960 + n * 80 + q * 16) = rbh;
        *reinterpret_cast<uint4*>(base + 46080 + n * 80 + q * 16) = rbl;
    };

    loadG(0);
    storeS(0);
    __syncthreads();

    const int lr = lane >> 2, lc = 2 * (lane & 3);
    for (int it = 0; it < T; ++it) {
        int cur = it & 1;
        bool more = (it + 1 < T);
        if (more) loadG(it + 1);
        const char* base = dsm + cur * 51200;
        const char* Asm = base;
        const char* Alm = base + 20480;
        const char* Bhm = base + 40960;
        const char* Blm = base + 46080;
#pragma unroll
        for (int ks = 0; ks < 2; ks++) {
            int kb = ks * 16;
            uint32_t bh[4][2], bl[4][2];
#pragma unroll
            for (int j = 0; j < 4; j++) {
                int n = nw * 32 + j * 8 + lr;
                int off = n * 80 + (kb + lc) * 2;
                bh[j][0] = *reinterpret_cast<const uint32_t*>(Bhm + off);
                bh[j][1] = *reinterpret_cast<const uint32_t*>(Bhm + off + 16);
                bl[j][0] = *reinterpret_cast<const uint32_t*>(Blm + off);
                bl[j][1] = *reinterpret_cast<const uint32_t*>(Blm + off + 16);
            }
#pragma unroll
            for (int i = 0; i < 4; i++) {
                int r = mw * 64 + i * 16 + lr;
                int off = r * 80 + (kb + lc) * 2;
                uint32_t ah[4], al[4];
                ah[0] = *reinterpret_cast<const uint32_t*>(Asm + off);
                ah[1] = *reinterpret_cast<const uint32_t*>(Asm + off + 640);
                ah[2] = *reinterpret_cast<const uint32_t*>(Asm + off + 16);
                ah[3] = *reinterpret_cast<const uint32_t*>(Asm + off + 656);
                al[0] = *reinterpret_cast<const uint32_t*>(Alm + off);
                al[1] = *reinterpret_cast<const uint32_t*>(Alm + off + 640);
                al[2] = *reinterpret_cast<const uint32_t*>(Alm + off + 16);
                al[3] = *reinterpret_cast<const uint32_t*>(Alm + off + 656);
#pragma unroll
                for (int j = 0; j < 4; j++) {
                    mma16816(acc[i][j], ah, bh[j]);
                    mma16816(acc[i][j], ah, bl[j]);
                    mma16816(acc[i][j], al, bh[j]);
                }
            }
        }
        if (more) storeS(cur ^ 1);
        __syncthreads();
    }

    float* Ds = reinterpret_cast<float*>(dsm);
#pragma unroll
    for (int i = 0; i < 4; i++) {
        int r0 = mw * 64 + i * 16 + lr;
#pragma unroll
        for (int j = 0; j < 4; j++) {
            int c = nw * 32 + j * 8 + lc;
            Ds[r0 * 65 + c] = acc[i][j][0];
            Ds[r0 * 65 + c + 1] = acc[i][j][1];
            Ds[(r0 + 8) * 65 + c] = acc[i][j][2];
            Ds[(r0 + 8) * 65 + c + 1] = acc[i][j][3];
        }
    }
    __syncthreads();
    int n = t & 63, p = t >> 6;
    {
        float s = 0.f;
        for (int mm = p * 64; mm < p * 64 + 64; mm++) s += Ds[mm * 65 + n];
        red4[p][n] = s;
    }
    __syncthreads();
    if (t < 64) smean[t] = (red4[0][t] + red4[1][t] + red4[2][t] + red4[3][t]) * (1.f / 256.f);
    __syncthreads();
    {
        float mu = smean[n], s = 0.f;
        for (int mm = p * 64; mm < p * 64 + 64; mm++) {
            float d = Ds[mm * 65 + n] - mu; s += d * d;
        }
        red4[p][n] = s;
    }
    __syncthreads();
    if (t < 64)
        srstd[t] = rsqrtf((red4[0][t] + red4[1][t] + red4[2][t] + red4[3][t]) * (1.f / 256.f) + 1e-6f);
    __syncthreads();
    {
        float mu = smean[n], rs = srstd[n];
        if (CATOUT) {
            size_t rowb = ((size_t)b * HW + y * 64 + n) * 1280 + coff;
            for (int mm = p * 64; mm < p * 64 + 64; mm++) {
                float vv = gelu_f((Ds[mm * 65 + n] - mu) * rs * sgam[mm] + sbet[mm]);
                __nv_bfloat16 h, l; splitf(vv, h, l);
                cth[rowb + mm] = h; ctl[rowb + mm] = l;
            }
        } else {
            size_t ob = (size_t)b * CIN * HW + y * 64 + n;
            for (int mm = p * 64; mm < p * 64 + 64; mm++) {
                float vv = gelu_f((Ds[mm * 65 + n] - mu) * rs * sgam[mm] + sbet[mm]);
                outF[ob + (size_t)mm * HW] = vv;
            }
        }
    }
}

// ---------------- HMMA S-GEMM: S[b,q,p] = (1/64) sum_c xaT[q,c] * x1T[p,c] ----------
// 128(q) x 64(p) tile, K=128. Per buf: Ah 0, Al 10240, Bh 20480, Bl 25600 (30720 tot)
__global__ void __launch_bounds__(256, 1) k_sgemm_h() {
    extern __shared__ __align__(16) char dsm[];
    const int b = blockIdx.z, q0 = blockIdx.y * 128, p0 = blockIdx.x * 64;
    const int t = threadIdx.x, wid = t >> 5, lane = t & 31;
    const int mw = wid >> 1, nw = wid & 1;
    const int lr = lane >> 2, lc = 2 * (lane & 3);
    const __nv_bfloat16* Qh = g_xath + (size_t)b * HW * COUT;
    const __nv_bfloat16* Ql = g_xatl + (size_t)b * HW * COUT;
    const __nv_bfloat16* Ph = g_x1th + (size_t)b * HW * COUT;
    const __nv_bfloat16* Pl = g_x1tl + (size_t)b * HW * COUT;

    float acc[2][4][4];
#pragma unroll
    for (int i = 0; i < 2; i++)
#pragma unroll
        for (int j = 0; j < 4; j++)
#pragma unroll
            for (int r = 0; r < 4; r++) acc[i][j][r] = 0.f;

    uint4 rah[2], ral[2], rbh, rbl;
    auto loadG = [&](int it) {
        int kc = it * 32;
        int ar = t >> 1, ak = (t & 1) * 16;
        const __nv_bfloat16* sh = Qh + (size_t)(q0 + ar) * COUT + kc + ak;
        const __nv_bfloat16* sl = Ql + (size_t)(q0 + ar) * COUT + kc + ak;
        rah[0] = *reinterpret_cast<const uint4*>(sh);
        rah[1] = *reinterpret_cast<const uint4*>(sh + 8);
        ral[0] = *reinterpret_cast<const uint4*>(sl);
        ral[1] = *reinterpret_cast<const uint4*>(sl + 8);
        int br = t >> 2, bk = (t & 3) * 8;
        rbh = *reinterpret_cast<const uint4*>(Ph + (size_t)(p0 + br) * COUT + kc + bk);
        rbl = *reinterpret_cast<const uint4*>(Pl + (size_t)(p0 + br) * COUT + kc + bk);
    };
    auto storeS = [&](int buf) {
        char* base = dsm + buf * 30720;
        int ar = t >> 1, ak = (t & 1) * 16;
        *reinterpret_cast<uint4*>(base + ar * 80 + ak * 2) = rah[0];
        *reinterpret_cast<uint4*>(base + ar * 80 + ak * 2 + 16) = rah[1];
        *reinterpret_cast<uint4*>(base + 10240 + ar * 80 + ak * 2) = ral[0];
        *reinterpret_cast<uint4*>(base + 10240 + ar * 80 + ak * 2 + 16) = ral[1];
        int br = t >> 2, bk = (t & 3) * 8;
        *reinterpret_cast<uint4*>(base + 20480 + br * 80 + bk * 2) = rbh;
        *reinterpret_cast<uint4*>(base + 25600 + br * 80 + bk * 2) = rbl;
    };

    loadG(0); storeS(0); __syncthreads();

    for (int it = 0; it < 4; ++it) {
        int cur = it & 1;
        bool more = (it + 1 < 4);
        if (more) loadG(it + 1);
        const char* base = dsm + cur * 30720;
        const char* Asm = base;
        const char* Alm = base + 10240;
        const char* Bhm = base + 20480;
        const char* Blm = base + 25600;
#pragma unroll
        for (int ks = 0; ks < 2; ks++) {
            int kb = ks * 16;
            uint32_t bh[4][2], bl[4][2];
#pragma unroll
            for (int j = 0; j < 4; j++) {
                int n = nw * 32 + j * 8 + lr;
                int off = n * 80 + (kb + lc) * 2;
                bh[j][0] = *reinterpret_cast<const uint32_t*>(Bhm + off);
                bh[j][1] = *reinterpret_cast<const uint32_t*>(Bhm + off + 16);
                bl[j][0] = *reinterpret_cast<const uint32_t*>(Blm + off);
                bl[j][1] = *reinterpret_cast<const uint32_t*>(Blm + off + 16);
            }
#pragma unroll
            for (int i = 0; i < 2; i++) {
                int r = mw * 32 + i * 16 + lr;
                int off = r * 80 + (kb + lc) * 2;
                uint32_t ah[4], al[4];
                ah[0] = *reinterpret_cast<const uint32_t*>(Asm + off);
                ah[1] = *reinterpret_cast<const uint32_t*>(Asm + off + 640);
                ah[2] = *reinterpret_cast<const uint32_t*>(Asm + off + 16);
                ah[3] = *reinterpret_cast<const uint32_t*>(Asm + off + 656);
                al[0] = *reinterpret_cast<const uint32_t*>(Alm + off);
                al[1] = *reinterpret_cast<const uint32_t*>(Alm + off + 640);
                al[2] = *reinterpret_cast<const uint32_t*>(Alm + off + 16);
                al[3] = *reinterpret_cast<const uint32_t*>(Alm + off + 656);
#pragma unroll
                for (int j = 0; j < 4; j++) {
                    mma16816(acc[i][j], ah, bh[j]);
                    mma16816(acc[i][j], ah, bl[j]);
                    mma16816(acc[i][j], al, bh[j]);
                }
            }
        }
        if (more) storeS(cur ^ 1);
        __syncthreads();
    }

    float* S = g_S + (size_t)b * HW * HW;
    const float sc = 1.f / 64.f;
#pragma unroll
    for (int i = 0; i < 2; i++) {
#pragma unroll
        for (int j = 0; j < 4; j++) {
            int q = q0 + mw * 32 + i * 16 + lr;
            int p = p0 + nw * 32 + j * 8 + lc;
            float2 v0 = make_float2(acc[i][j][0] * sc, acc[i][j][1] * sc);
            float2 v1 = make_float2(acc[i][j][2] * sc, acc[i][j][3] * sc);
            *reinterpret_cast<float2*>(S + (size_t)q * HW + p) = v0;
            *reinterpret_cast<float2*>(S + (size_t)(q + 8) * HW + p) = v1;
        }
    }
}

// ---------------- row softmax; emits bf16 hi/lo probs ----------------
__global__ void __launch_bounds__(256) k_softmax() {
    const size_t row = blockIdx.x;
    const float* r = g_S + row * (size_t)HW;
    __nv_bfloat16* oh = g_Ah + row * (size_t)HW;
    __nv_bfloat16* ol = g_Al + row * (size_t)HW;
    __shared__ float buf[HW];
    __shared__ float red[256];
    int t = threadIdx.x;
    float m = -1e30f;
    for (int i = t; i < HW; i += 256) { float v = r[i]; buf[i] = v; m = fmaxf(m, v); }
    red[t] = m; __syncthreads();
    for (int s = 128; s > 0; s >>= 1) { if (t < s) red[t] = fmaxf(red[t], red[t + s]); __syncthreads(); }
    float mx = red[0]; __syncthreads();
    float s = 0.f;
    for (int i = t; i < HW; i += 256) { float e = expf(buf[i] - mx); buf[i] = e; s += e; }
    red[t] = s; __syncthreads();
    for (int o = 128; o > 0; o >>= 1) { if (t < o) red[t] += red[t + o]; __syncthreads(); }
    float inv = 1.f / red[0];
    for (int i = t; i < HW; i += 256) {
        float p = buf[i] * inv;
        __nv_bfloat16 h, l; splitf(p, h, l);
        oh[i] = h; ol[i] = l;
    }
}

// ---------------- HMMA L-GEMM: O[b,c,j] = sum_q x1[c,q]*A[q,j] + xa[c,j] ----------
// 128(c) x 64(j) tile, K=4096. Per buf: Ah 0 (10240), Al 10240, Bh 20480 (64x68),
// Bl 24832; bufsz 29184.  B tile transposed from A-probs [q][j] -> smem [j][q].
__global__ void __launch_bounds__(256, 1) k_lgemm_h() {
    extern __shared__ __align__(16) char dsm[];
    const int b = blockIdx.y, j0g = blockIdx.x * 64;
    const int t = threadIdx.x, wid = t >> 5, lane = t & 31;
    const int mw = wid >> 1, nw = wid & 1;
    const int lr = lane >> 2, lc = 2 * (lane & 3);
    const __nv_bfloat16* Xh = g_x1h + (size_t)b * COUT * HW;
    const __nv_bfloat16* Xl = g_x1l + (size_t)b * COUT * HW;
    const __nv_bfloat16* Aph = g_Ah + (size_t)b * HW * HW;
    const __nv_bfloat16* Apl = g_Al + (size_t)b * HW * HW;

    float acc[2][4][4];
#pragma unroll
    for (int i = 0; i < 2; i++)
#pragma unroll
        for (int j = 0; j < 4; j++)
#pragma unroll
            for (int r = 0; r < 4; r++) acc[i][j][r] = 0.f;

    uint4 rah[2], ral[2];
    ushort4 rb[4];
    auto loadG = [&](int it) {
        int kc = it * 32;
        int ar = t >> 1, ak = (t & 1) * 16;
        const __nv_bfloat16* sh = Xh + (size_t)ar * HW + kc + ak;
        const __nv_bfloat16* sl = Xl + (size_t)ar * HW + kc + ak;
        rah[0] = *reinterpret_cast<const uint4*>(sh);
        rah[1] = *reinterpret_cast<const uint4*>(sh + 8);
        ral[0] = *reinterpret_cast<const uint4*>(sl);
        ral[1] = *reinterpret_cast<const uint4*>(sl + 8);
        int qp = t >> 4, jt = t & 15;
        size_t a0 = (size_t)(kc + 2 * qp) * HW + j0g + jt * 4;
        rb[0] = *reinterpret_cast<const ushort4*>(Aph + a0);
        rb[1] = *reinterpret_cast<const ushort4*>(Aph + a0 + HW);
        rb[2] = *reinterpret_cast<const ushort4*>(Apl + a0);
        rb[3] = *reinterpret_cast<const ushort4*>(Apl + a0 + HW);
    };
    auto storeS = [&](int buf) {
        char* base = dsm + buf * 29184;
        int ar = t >> 1, ak = (t & 1) * 16;
        *reinterpret_cast<uint4*>(base + ar * 80 + ak * 2) = rah[0];
        *reinterpret_cast<uint4*>(base + ar * 80 + ak * 2 + 16) = rah[1];
        *reinterpret_cast<uint4*>(base + 10240 + ar * 80 + ak * 2) = ral[0];
        *reinterpret_cast<uint4*>(base + 10240 + ar * 80 + ak * 2 + 16) = ral[1];
        int qp = t >> 4, jt = t & 15;
        char* bh = base + 20480;
        char* bl = base + 24832;
        int j4 = jt * 4;
        *reinterpret_cast<uint32_t*>(bh + (j4 + 0) * 68 + qp * 4) =
            (uint32_t)rb[0].x | ((uint32_t)rb[1].x << 16);
        *reinterpret_cast<uint32_t*>(bh + (j4 + 1) * 68 + qp * 4) =
            (uint32_t)rb[0].y | ((uint32_t)rb[1].y << 16);
        *reinterpret_cast<uint32_t*>(bh + (j4 + 2) * 68 + qp * 4) =
            (uint32_t)rb[0].z | ((uint32_t)rb[1].z << 16);
        *reinterpret_cast<uint32_t*>(bh + (j4 + 3) * 68 + qp * 4) =
            (uint32_t)rb[0].w | ((uint32_t)rb[1].w << 16);
        *reinterpret_cast<uint32_t*>(bl + (j4 + 0) * 68 + qp * 4) =
            (uint32_t)rb[2].x | ((uint32_t)rb[3].x << 16);
        *reinterpret_cast<uint32_t*>(bl + (j4 + 1) * 68 + qp * 4) =
            (uint32_t)rb[2].y | ((uint32_t)rb[3].y << 16);
        *reinterpret_cast<uint32_t*>(bl + (j4 + 2) * 68 + qp * 4) =
            (uint32_t)rb[2].z | ((uint32_t)rb[3].z << 16);
        *reinterpret_cast<uint32_t*>(bl + (j4 + 3) * 68 + qp * 4) =
            (uint32_t)rb[2].w | ((uint32_t)rb[3].w << 16);
    };

    loadG(0); storeS(0); __syncthreads();

    const int T = HW / 32;
    for (int it = 0; it < T; ++it) {
        int cur = it & 1;
        bool more = (it + 1 < T);
        if (more) loadG(it + 1);
        const char* base = dsm + cur * 29184;
        const char* Asm = base;
        const char* Alm = base + 10240;
        const char* Bhm = base + 20480;
        const char* Blm = base + 24832;
#pragma unroll
        for (int ks = 0; ks < 2; ks++) {
            int kb = ks * 16;
            uint32_t bh[4][2], bl[4][2];
#pragma unroll
            for (int j = 0; j < 4; j++) {
                int n = nw * 32 + j * 8 + lr;
                int off = n * 68 + (kb + lc) * 2;
                bh[j][0] = *reinterpret_cast<const uint32_t*>(Bhm + off);
                bh[j][1] = *reinterpret_cast<const uint32_t*>(Bhm + off + 16);
                bl[j][0] = *reinterpret_cast<const uint32_t*>(Blm + off);
                bl[j][1] = *reinterpret_cast<const uint32_t*>(Blm + off + 16);
            }
#pragma unroll
            for (int i = 0; i < 2; i++) {
                int r = mw * 32 + i * 16 + lr;
                int off = r * 80 + (kb + lc) * 2;
                uint32_t ah[4], al[4];
                ah[0] = *reinterpret_cast<const uint32_t*>(Asm + off);
                ah[1] = *reinterpret_cast<const uint32_t*>(Asm + off + 640);
                ah[2] = *reinterpret_cast<const uint32_t*>(Asm + off + 16);
                ah[3] = *reinterpret_cast<const uint32_t*>(Asm + off + 656);
                al[0] = *reinterpret_cast<const uint32_t*>(Alm + off);
                al[1] = *reinterpret_cast<const uint32_t*>(Alm + off + 640);
                al[2] = *reinterpret_cast<const uint32_t*>(Alm + off + 16);
                al[3] = *reinterpret_cast<const uint32_t*>(Alm + off + 656);
#pragma unroll
                for (int j = 0; j < 4; j++) {
                    mma16816(acc[i][j], ah, bh[j]);
                    mma16816(acc[i][j], ah, bl[j]);
                    mma16816(acc[i][j], al, bh[j]);
                }
            }
        }
        if (more) storeS(cur ^ 1);
        __syncthreads();
    }

    const float* xab = g_xa + (size_t)b * COUT * HW;
    float* Ob = g_O + (size_t)b * COUT * HW;
#pragma unroll
    for (int i = 0; i < 2; i++) {
#pragma unroll
        for (int j = 0; j < 4; j++) {
            int c = mw * 32 + i * 16 + lr;
            int col = j0g + nw * 32 + j * 8 + lc;
            size_t i0 = (size_t)c * HW + col;
            size_t i8 = (size_t)(c + 8) * HW + col;
            float2 x0 = *reinterpret_cast<const float2*>(xab + i0);
            float2 x8 = *reinterpret_cast<const float2*>(xab + i8);
            *reinterpret_cast<float2*>(Ob + i0) =
                make_float2(acc[i][j][0] + x0.x, acc[i][j][1] + x0.y);
            *reinterpret_cast<float2*>(Ob + i8) =
                make_float2(acc[i][j][2] + x8.x, acc[i][j][3] + x8.y);
        }
    }
}

// ---------------- FFMA pipelined GEMM (conv1 / xa / conv2) ----------------
template <int BM, int MODE>
__global__ void __launch_bounds__(256, 2) k_gemm(
    const float* __restrict__ Wg, size_t wb_stride,
    const float* __restrict__ In, size_t in_bstride,
    const float* __restrict__ P1,
    const float* __restrict__ Addp, size_t add_bstride,
    float* __restrict__ Out, size_t out_bstride,
    int Kc) {
    constexpr int TM = BM / 32;
    constexpr int NAREG = (BM == 256) ? 4 : 2;
    const int b = blockIdx.y;
    const int y = blockIdx.x;
    const int n0 = y * BN;
    const int t = threadIdx.x;
    const int ty = t >> 3, tx = t & 7;

    __shared__ __align__(16) float As[2][KT][BM];
    __shared__ __align__(16) float Bs[2][KT][BN];

    const int total = Kc / KT;
    const float* Wb = Wg + (size_t)b * wb_stride;
    const float* Inb = In + (size_t)b * in_bstride;

    ull acc2[TM][4];
#pragma unroll
    for (int i = 0; i < TM; i++)
#pragma unroll
        for (int j = 0; j < 4; j++) acc2[i][j] = 0ULL;

    float4 ra[NAREG];
    float rb[4];

    auto loadG = [&](int it) {
        int k0 = it * KT;
        if (BM == 256) {
            const float* wrow = Wb + (size_t)t * Kc + k0;
#pragma unroll
            for (int q = 0; q < 4; q++)
                ra[q] = *reinterpret_cast<const float4*>(wrow + q * 4);
        } else {
            int m = t >> 1, ko = (t & 1) * 8;
            const float* wrow = Wb + (size_t)m * Kc + k0 + ko;
#pragma unroll
            for (int q = 0; q < 2; q++)
                ra[q] = *reinterpret_cast<const float4*>(wrow + q * 4);
        }
        int k = t >> 4, nb = (t & 15) * 4;
        float4 v = *reinterpret_cast<const float4*>(Inb + (size_t)(k0 + k) * HW + n0 + nb);
        rb[0] = v.x; rb[1] = v.y; rb[2] = v.z; rb[3] = v.w;
    };
    auto storeS = [&](int buf) {
        if (BM == 256) {
#pragma unroll
            for (int q = 0; q < 4; q++) {
                As[buf][q * 4 + 0][t] = ra[q].x; As[buf][q * 4 + 1][t] = ra[q].y;
                As[buf][q * 4 + 2][t] = ra[q].z; As[buf][q * 4 + 3][t] = ra[q].w;
            }
        } else {
            int m = t >> 1, ko = (t & 1) * 8;
#pragma unroll
            for (int q = 0; q < 2; q++) {
                As[buf][ko + q * 4 + 0][m] = ra[q].x; As[buf][ko + q * 4 + 1][m] = ra[q].y;
                As[buf][ko + q * 4 + 2][m] = ra[q].z; As[buf][ko + q * 4 + 3][m] = ra[q].w;
            }
        }
        int k = t >> 4, nb = (t & 15) * 4;
        Bs[buf][k][nb] = rb[0]; Bs[buf][k][nb + 1] = rb[1];
        Bs[buf][k][nb + 2] = rb[2]; Bs[buf][k][nb + 3] = rb[3];
    };

    loadG(0);
    storeS(0);
    __syncthreads();

    for (int it = 0; it < total; ++it) {
        int cur = it & 1;
        bool more = (it + 1 < total);
        if (more) loadG(it + 1);
#pragma unroll
        for (int k = 0; k < KT; k++) {
            ull a2[TM], b2[4];
#pragma unroll
            for (int i = 0; i < TM; i += 4) {
                float4 v = *reinterpret_cast<const float4*>(&As[cur][k][ty * TM + i]);
                a2[i] = pack2f(v.x); a2[i + 1] = pack2f(v.y);
                a2[i + 2] = pack2f(v.z); a2[i + 3] = pack2f(v.w);
            }
            {
                float4 v0 = *reinterpret_cast<const float4*>(&Bs[cur][k][tx * 8]);
                float4 v1 = *reinterpret_cast<const float4*>(&Bs[cur][k][tx * 8 + 4]);
                b2[0] = pack2(v0.x, v0.y); b2[1] = pack2(v0.z, v0.w);
                b2[2] = pack2(v1.x, v1.y); b2[3] = pack2(v1.z, v1.w);
            }
#pragma unroll
            for (int i = 0; i < TM; i++)
#pragma unroll
                for (int j = 0; j < 4; j++) fma2(acc2[i][j], a2[i], b2[j]);
        }
        if (more) storeS(cur ^ 1);
        __syncthreads();
    }

    float* Ob = Out + (size_t)b * out_bstride;
#pragma unroll
    for (int i = 0; i < TM; i++) {
        int m = ty * TM + i;
        float bias = (MODE == 0) ? P1[m] : 0.f;
        const float* addrow = (MODE == 2)
            ? (Addp + (size_t)b * add_bstride + (size_t)m * HW + n0 + tx * 8)
            : nullptr;
        float o8[8];
#pragma unroll
        for (int j = 0; j < 4; j++) {
            float2 f = unpk2(acc2[i][j]);
            o8[2 * j] = f.x + bias; o8[2 * j + 1] = f.y + bias;
            if (MODE == 2) { o8[2 * j] += addrow[2 * j]; o8[2 * j + 1] += addrow[2 * j + 1]; }
        }
        float* dst = Ob + (size_t)m * HW + n0 + tx * 8;
        *reinterpret_cast<float4*>(dst) = make_float4(o8[0], o8[1], o8[2], o8[3]);
        *reinterpret_cast<float4*>(dst + 4) = make_float4(o8[4], o8[5], o8[6], o8[7]);
    }
}

// ---------------- host launch ----------------
extern "C" void kernel_launch(void* const* d_in, const int* in_sizes, int n_in,
                              void* d_out, int out_size) {
    (void)in_sizes; (void)n_in; (void)out_size;
    const float* x       = (const float*)d_in[0];
    const float* conv1_w = (const float*)d_in[1];
    const float* conv1_b = (const float*)d_in[2];
    const float* conv2_w = (const float*)d_in[3];
    const float* conv2_b = (const float*)d_in[4];
    const float* cw_w1   = (const float*)d_in[5];
    const float* cw_b1   = (const float*)d_in[6];
    const float* cw_ln_g = (const float*)d_in[7];
    const float* cw_ln_b = (const float*)d_in[8];
    const float* cw_w2   = (const float*)d_in[9];
    const float* cw_b2   = (const float*)d_in[10];
    const float* aspp0_w = (const float*)d_in[11];
    const float* aspp0_g = (const float*)d_in[12];
    const float* aspp0_b = (const float*)d_in[13];
    const float* aspp1_w = (const float*)d_in[14];
    const float* aspp1_g = (const float*)d_in[15];
    const float* aspp1_b = (const float*)d_in[16];
    const float* aspp2_w = (const float*)d_in[17];
    const float* aspp2_g = (const float*)d_in[18];
    const float* aspp2_b = (const float*)d_in[19];
    const float* aspp3_w = (const float*)d_in[20];
    const float* aspp3_g = (const float*)d_in[21];
    const float* aspp3_b = (const float*)d_in[22];
    const float* asppp_w = (const float*)d_in[23];
    const float* asppp_g = (const float*)d_in[24];
    const float* asppp_b = (const float*)d_in[25];
    const float* proj_w  = (const float*)d_in[26];
    const float* proj_g  = (const float*)d_in[27];
    const float* proj_b  = (const float*)d_in[28];

    void* pv;
    float *p_x1, *p_proj, *p_xa;
    __nv_bfloat16 *p_xth, *p_xtl, *p_cth, *p_ctl, *p_w3h, *p_w3l, *p_a0h, *p_a0l, *p_pjh, *p_pjl;
    __nv_bfloat16 *p_x1th, *p_x1tl, *p_xath, *p_xatl, *p_x1h, *p_x1l;
    float *p_O;
    cudaGetSymbolAddress(&pv, g_x1);   p_x1   = (float*)pv;
    cudaGetSymbolAddress(&pv, g_proj); p_proj = (float*)pv;
    cudaGetSymbolAddress(&pv, g_xa);   p_xa   = (float*)pv;
    cudaGetSymbolAddress(&pv, g_O);    p_O    = (float*)pv;
    cudaGetSymbolAddress(&pv, g_xth);  p_xth  = (__nv_bfloat16*)pv;
    cudaGetSymbolAddress(&pv, g_xtl);  p_xtl  = (__nv_bfloat16*)pv;
    cudaGetSymbolAddress(&pv, g_cth);  p_cth  = (__nv_bfloat16*)pv;
    cudaGetSymbolAddress(&pv, g_ctl);  p_ctl  = (__nv_bfloat16*)pv;
    cudaGetSymbolAddress(&pv, g_w3h);  p_w3h  = (__nv_bfloat16*)pv;
    cudaGetSymbolAddress(&pv, g_w3l);  p_w3l  = (__nv_bfloat16*)pv;
    cudaGetSymbolAddress(&pv, g_a0h);  p_a0h  = (__nv_bfloat16*)pv;
    cudaGetSymbolAddress(&pv, g_a0l);  p_a0l  = (__nv_bfloat16*)pv;
    cudaGetSymbolAddress(&pv, g_pjh);  p_pjh  = (__nv_bfloat16*)pv;
    cudaGetSymbolAddress(&pv, g_pjl);  p_pjl  = (__nv_bfloat16*)pv;
    cudaGetSymbolAddress(&pv, g_x1th); p_x1th = (__nv_bfloat16*)pv;
    cudaGetSymbolAddress(&pv, g_x1tl); p_x1tl = (__nv_bfloat16*)pv;
    cudaGetSymbolAddress(&pv, g_xath); p_xath = (__nv_bfloat16*)pv;
    cudaGetSymbolAddress(&pv, g_xatl); p_xatl = (__nv_bfloat16*)pv;
    cudaGetSymbolAddress(&pv, g_x1h);  p_x1h  = (__nv_bfloat16*)pv;
    cudaGetSymbolAddress(&pv, g_x1l);  p_x1l  = (__nv_bfloat16*)pv;

    const int TG_SMEM = 102400;
    cudaFuncSetAttribute(k_hgemm<false, true>, cudaFuncAttributeMaxDynamicSharedMemorySize, TG_SMEM);
    cudaFuncSetAttribute(k_hgemm<true, true>, cudaFuncAttributeMaxDynamicSharedMemorySize, TG_SMEM);
    cudaFuncSetAttribute(k_hgemm<false, false>, cudaFuncAttributeMaxDynamicSharedMemorySize, TG_SMEM);
    cudaFuncSetAttribute(k_sgemm_h, cudaFuncAttributeMaxDynamicSharedMemorySize, 61440);
    cudaFuncSetAttribute(k_lgemm_h, cudaFuncAttributeMaxDynamicSharedMemorySize, 58368);

    dim3 g64(HW / BN, BATCH);

    // 1-3: prep (so launch #4 = first HMMA ASPP kernel gets profiled)
    k_prep<<<3328, 256>>>(aspp1_w, aspp2_w, aspp3_w, aspp0_w, proj_w, x);
    k_cw<<<BATCH, 256>>>(cw_w1, cw_b1, cw_ln_g, cw_ln_b, cw_w2, cw_b2,
                         asppp_w, asppp_g, asppp_b);
    k_xcsplit<<<dim3(128, 8, BATCH), 256>>>(x);
    // 4-7: ASPP branches (HMMA)
    k_hgemm<false, true><<<g64, 256, TG_SMEM>>>(p_a0h, p_a0l, p_xth, p_xtl,
        aspp0_g, aspp0_b, nullptr, p_cth, p_ctl, 0, CIN, 0);
    k_hgemm<true, true><<<g64, 256, TG_SMEM>>>(p_w3h + 0 * 9 * 65536, p_w3l + 0 * 9 * 65536,
        p_xth, p_xtl, aspp1_g, aspp1_b, nullptr, p_cth, p_ctl, 256, CIN, 3);
    k_hgemm<true, true><<<g64, 256, TG_SMEM>>>(p_w3h + 1 * 9 * 65536, p_w3l + 1 * 9 * 65536,
        p_xth, p_xtl, aspp2_g, aspp2_b, nullptr, p_cth, p_ctl, 512, CIN, 6);
    k_hgemm<true, true><<<g64, 256, TG_SMEM>>>(p_w3h + 2 * 9 * 65536, p_w3l + 2 * 9 * 65536,
        p_xth, p_xtl, aspp3_g, aspp3_b, nullptr, p_cth, p_ctl, 768, CIN, 9);
    // 8: global-pool branch into catT
    k_bp_cat<<<dim3(128, BATCH), 256>>>();
    // 9: proj (HMMA, K=1280) -> f32
    k_hgemm<false, false><<<g64, 256, TG_SMEM>>>(p_pjh, p_pjl, p_cth, p_ctl,
        proj_g, proj_b, p_proj, nullptr, nullptr, 0, 5 * CIN, 0);
    // 10-11: conv1 twice (FFMA)
    k_gemm<128, 0><<<g64, 256>>>(conv1_w, 0, x, (size_t)CIN * HW, conv1_b,
                                 nullptr, 0, p_x1, (size_t)COUT * HW, CIN);
    k_gemm<128, 0><<<g64, 256>>>(conv1_w, 0, p_proj, (size_t)CIN * HW, conv1_b,
                                 nullptr, 0, p_xa, (size_t)COUT * HW, CIN);
    // 12-13: split x1 (straight + T), xa (T)
    k_splitT<true><<<dim3(128, 4, BATCH), 256>>>(p_x1, p_x1th, p_x1tl, p_x1h, p_x1l);
    k_splitT<false><<<dim3(128, 4, BATCH), 256>>>(p_xa, p_xath, p_xatl, nullptr, nullptr);
    // 14-16: attention (HMMA S, softmax->bf16, HMMA L with +xa)
    k_sgemm_h<<<dim3(64, 32, BATCH), 256, 61440>>>();
    k_softmax<<<BATCH * HW, 256>>>();
    k_lgemm_h<<<dim3(64, BATCH), 256, 58368>>>();
    // 17: out = conv2(O) + b (FFMA)
    k_gemm<256, 0><<<g64, 256>>>(conv2_w, 0, p_O, (size_t)COUT * HW, conv2_b,
                                 nullptr, 0, (float*)d_out, (size_t)CIN * HW, COUT);
}

// round 7
// speedup vs baseline: 1.8842x; 1.1682x over previous
#include <cuda_runtime.h>
#include <cuda_bf16.h>
#include <math.h>
#include <stdint.h>

#define BATCH 4
#define CIN 256
#define COUT 128
#define HH 64
#define WW 64
#define HW 4096
#define BN 64
#define KT 16

typedef unsigned long long ull;

// ---------------- scratch (static device globals; no allocs) ----------------
__device__ float g_x1[BATCH * COUT * HW];
__device__ float g_proj[BATCH * CIN * HW];
__device__ float g_xa[BATCH * COUT * HW];
__device__ float g_O[BATCH * COUT * HW];
__device__ float g_S[(size_t)BATCH * HW * HW];
__device__ float g_avg[BATCH * CIN];
__device__ float g_mx[BATCH * CIN];
__device__ float g_s[BATCH * CIN];
__device__ float g_bp[BATCH * CIN];
// bf16 split operands
__device__ __nv_bfloat16 g_xth[BATCH * HW * CIN];              // xcT hi  [b][hw][c]
__device__ __nv_bfloat16 g_xtl[BATCH * HW * CIN];              // xcT lo
__device__ __nv_bfloat16 g_cth[(size_t)BATCH * HW * 5 * CIN];  // catT hi [b][hw][1280]
__device__ __nv_bfloat16 g_ctl[(size_t)BATCH * HW * 5 * CIN];  // catT lo
__device__ __nv_bfloat16 g_w3h[3 * 9 * CIN * CIN];             // [conv][tap][m][c]
__device__ __nv_bfloat16 g_w3l[3 * 9 * CIN * CIN];
__device__ __nv_bfloat16 g_a0h[CIN * CIN];
__device__ __nv_bfloat16 g_a0l[CIN * CIN];
__device__ __nv_bfloat16 g_pjh[CIN * 5 * CIN];
__device__ __nv_bfloat16 g_pjl[CIN * 5 * CIN];
// attention operands
__device__ __nv_bfloat16 g_x1th[BATCH * HW * COUT];  // x1T hi [b][hw][c]
__device__ __nv_bfloat16 g_x1tl[BATCH * HW * COUT];
__device__ __nv_bfloat16 g_xath[BATCH * HW * COUT];  // xaT hi [b][hw][c]
__device__ __nv_bfloat16 g_xatl[BATCH * HW * COUT];
__device__ __nv_bfloat16 g_x1h[BATCH * COUT * HW];   // x1 straight split [b][c][hw]
__device__ __nv_bfloat16 g_x1l[BATCH * COUT * HW];
__device__ __nv_bfloat16 g_Ah[(size_t)BATCH * HW * HW];  // softmax probs hi [b][q][p]
__device__ __nv_bfloat16 g_Al[(size_t)BATCH * HW * HW];

__device__ __forceinline__ float gelu_f(float x) {
    return 0.5f * x * (1.0f + erff(x * 0.70710678118654752440f));
}
__device__ __forceinline__ void splitf(float v, __nv_bfloat16& h, __nv_bfloat16& l) {
    h = __float2bfloat16(v);
    l = __float2bfloat16(v - __bfloat162float(h));
}

// ---------------- HMMA m16n8k16 bf16 ----------------
__device__ __forceinline__ void mma16816(float* d, const uint32_t* a, const uint32_t* b) {
    asm volatile(
        "mma.sync.aligned.m16n8k16.row.col.f32.bf16.bf16.f32 "
        "{%0,%1,%2,%3}, {%4,%5,%6,%7}, {%8,%9}, {%0,%1,%2,%3};"
        : "+f"(d[0]), "+f"(d[1]), "+f"(d[2]), "+f"(d[3])
        : "r"(a[0]), "r"(a[1]), "r"(a[2]), "r"(a[3]), "r"(b[0]), "r"(b[1]));
}

// ---------------- packed helpers for FFMA path ----------------
__device__ __forceinline__ ull pack2f(float x) {
    ull r; asm("mov.b64 %0, {%1, %1};" : "=l"(r) : "f"(x)); return r;
}
__device__ __forceinline__ ull pack2(float x, float y) {
    ull r; asm("mov.b64 %0, {%1, %2};" : "=l"(r) : "f"(x), "f"(y)); return r;
}
__device__ __forceinline__ void fma2(ull& d, ull a, ull b) {
    asm("fma.rn.f32x2 %0, %1, %2, %0;" : "+l"(d) : "l"(a), "l"(b));
}
__device__ __forceinline__ float2 unpk2(ull v) {
    float2 f; asm("mov.b64 {%0, %1}, %2;" : "=f"(f.x), "=f"(f.y) : "l"(v)); return f;
}

// ---------------- prep: weight split/transpose + per-(b,c) stats ----------------
__global__ void k_prep(const float* __restrict__ w1, const float* __restrict__ w2,
                       const float* __restrict__ w3, const float* __restrict__ a0,
                       const float* __restrict__ pj, const float* __restrict__ x) {
    if (blockIdx.x < 2304) {
        int e = blockIdx.x * 256 + threadIdx.x;
        if (e < 196608) {
            const float* srcs[3] = { w1, w2, w3 };
            int conv = e >> 16, mc = e & 65535, m = mc >> 8, c = mc & 255;
            const float* src = srcs[conv] + (size_t)m * 2304 + (size_t)c * 9;
            size_t dbase = (size_t)conv * 9 * 65536 + (size_t)m * 256 + c;
#pragma unroll
            for (int tap = 0; tap < 9; tap++) {
                __nv_bfloat16 h, l; splitf(src[tap], h, l);
                g_w3h[dbase + (size_t)tap * 65536] = h;
                g_w3l[dbase + (size_t)tap * 65536] = l;
            }
        } else if (e < 262144) {
            int i = e - 196608;
            __nv_bfloat16 h, l; splitf(a0[i], h, l);
            g_a0h[i] = h; g_a0l[i] = l;
        } else if (e < 589824) {
            int i = e - 262144;
            __nv_bfloat16 h, l; splitf(pj[i], h, l);
            g_pjh[i] = h; g_pjl[i] = l;
        }
    } else {
        int bc = blockIdx.x - 2304;
        const float* p = x + (size_t)bc * HW;
        int t = threadIdx.x;
        float s = 0.f, m = -1e30f;
        for (int i = t; i < HW; i += 256) { float v = p[i]; s += v; m = fmaxf(m, v); }
        __shared__ float ss[256], sm[256];
        ss[t] = s; sm[t] = m; __syncthreads();
        for (int o = 128; o > 0; o >>= 1) {
            if (t < o) { ss[t] += ss[t + o]; sm[t] = fmaxf(sm[t], sm[t + o]); }
            __syncthreads();
        }
        if (t == 0) { g_avg[bc] = ss[0] * (1.f / HW); g_mx[bc] = sm[0]; }
    }
}

// ---------------- channel weighting MLP + global-pool ASPP branch ----------------
__global__ void k_cw(const float* __restrict__ w1, const float* __restrict__ bb1,
                     const float* __restrict__ lg, const float* __restrict__ lb,
                     const float* __restrict__ w2, const float* __restrict__ bb2,
                     const float* __restrict__ apw, const float* __restrict__ apg,
                     const float* __restrict__ apb) {
    int b = blockIdx.x, t = threadIdx.x;
    __shared__ float o[CIN];
    __shared__ float h[COUT];
    __shared__ float red[256];
    __shared__ float gp[CIN];
    float avg = g_avg[b * CIN + t], mx = g_mx[b * CIN + t];
    o[t] = fabsf(avg - mx) * avg;
    __syncthreads();
    float hv = 0.f;
    if (t < COUT) {
        hv = bb1[t];
        const float* wr = w1 + t * CIN;
        for (int i = 0; i < CIN; i++) hv = fmaf(o[i], wr[i], hv);
    }
    red[t] = (t < COUT) ? hv : 0.f; __syncthreads();
    for (int s = 128; s > 0; s >>= 1) { if (t < s) red[t] += red[t + s]; __syncthreads(); }
    float mu = red[0] * (1.f / COUT); __syncthreads();
    float dv = (t < COUT) ? (hv - mu) : 0.f;
    red[t] = dv * dv; __syncthreads();
    for (int s = 128; s > 0; s >>= 1) { if (t < s) red[t] += red[t + s]; __syncthreads(); }
    float var = red[0] * (1.f / COUT); __syncthreads();
    if (t < COUT) h[t] = lg[t] * ((hv - mu) * rsqrtf(var + 1e-5f)) + lb[t];
    __syncthreads();
    float sv = bb2[t];
    const float* wr2 = w2 + t * COUT;
    for (int j = 0; j < COUT; j++) sv = fmaf(h[j], wr2[j], sv);
    float sig = 1.f / (1.f + expf(-sv));
    g_s[b * CIN + t] = sig;
    gp[t] = (1.f + sig) * avg;
    __syncthreads();
    float v = 0.f;
    const float* ar = apw + t * CIN;
    for (int i = 0; i < CIN; i++) v = fmaf(ar[i], gp[i], v);
    red[t] = v; __syncthreads();
    for (int s = 128; s > 0; s >>= 1) { if (t < s) red[t] += red[t + s]; __syncthreads(); }
    float mu2 = red[0] * (1.f / CIN); __syncthreads();
    float d2 = v - mu2; red[t] = d2 * d2; __syncthreads();
    for (int s = 128; s > 0; s >>= 1) { if (t < s) red[t] += red[t + s]; __syncthreads(); }
    float var2 = red[0] * (1.f / CIN); __syncthreads();
    float z = apg[t] * ((v - mu2) * rsqrtf(var2 + 1e-6f)) + apb[t];
    g_bp[b * CIN + t] = gelu_f(z);
}

// ---------------- xcT split: x[b][c][hw]*(1+s) -> bf16 hi/lo [b][hw][c] ----------------
__global__ void k_xcsplit(const float* __restrict__ x) {
    __shared__ float tile[32][33];
    int b = blockIdx.z, c0 = blockIdx.y * 32, h0 = blockIdx.x * 32;
    int t = threadIdx.x;
    const float* xb = x + ((size_t)b * CIN + c0) * HW + h0;
#pragma unroll
    for (int i = 0; i < 4; i++) {
        int r = (t >> 5) + 8 * i;
        tile[r][t & 31] = xb[(size_t)r * HW + (t & 31)];
    }
    __syncthreads();
#pragma unroll
    for (int i = 0; i < 4; i++) {
        int hr = (t >> 5) + 8 * i, cc = t & 31;
        float v = tile[cc][hr] * (1.f + g_s[b * CIN + c0 + cc]);
        __nv_bfloat16 h, l; splitf(v, h, l);
        size_t idx = ((size_t)b * HW + h0 + hr) * CIN + c0 + cc;
        g_xth[idx] = h; g_xtl[idx] = l;
    }
}

// ---------------- split/transpose for 128-channel fp32 maps ----------------
template <bool STRAIGHT>
__global__ void k_splitT(const float* __restrict__ in,
                         __nv_bfloat16* __restrict__ th, __nv_bfloat16* __restrict__ tl,
                         __nv_bfloat16* __restrict__ sh, __nv_bfloat16* __restrict__ sl) {
    __shared__ float tile[32][33];
    int b = blockIdx.z, c0 = blockIdx.y * 32, h0 = blockIdx.x * 32;
    int t = threadIdx.x;
    const float* ib = in + ((size_t)b * COUT + c0) * HW + h0;
#pragma unroll
    for (int i = 0; i < 4; i++) {
        int r = (t >> 5) + 8 * i, col = t & 31;
        float v = ib[(size_t)r * HW + col];
        tile[r][col] = v;
        if (STRAIGHT) {
            __nv_bfloat16 h, l; splitf(v, h, l);
            size_t idx = ((size_t)b * COUT + c0 + r) * HW + h0 + col;
            sh[idx] = h; sl[idx] = l;
        }
    }
    __syncthreads();
#pragma unroll
    for (int i = 0; i < 4; i++) {
        int hr = (t >> 5) + 8 * i, cc = t & 31;
        float v = tile[cc][hr];
        __nv_bfloat16 h, l; splitf(v, h, l);
        size_t idx = ((size_t)b * HW + h0 + hr) * COUT + c0 + cc;
        th[idx] = h; tl[idx] = l;
    }
}

// ---------------- bp broadcast into catT channels [1024,1280) ----------------
__global__ void k_bp_cat() {
    int b = blockIdx.y, h0 = blockIdx.x * 32;
    int c = threadIdx.x;
    __nv_bfloat16 h, l; splitf(g_bp[b * CIN + c], h, l);
    for (int r = 0; r < 32; r++) {
        size_t idx = ((size_t)b * HW + h0 + r) * 1280 + 1024 + c;
        g_cth[idx] = h; g_ctl[idx] = l;
    }
}

// ---------------- HMMA bf16x2-split GEMM, 256x128 tile, 512 thr, LN+GELU epilogue ----
// Out[b,m,n] = GELU(LN_m( sum_k W[m,k]*In[b,k,n] )),  In transposed [hw][k].
// 16 warps: 4(M) x 4(N); warp tile 64x32. BK=32.
// Per buf (61440B): Ah 0, Al 20480, Bh 40960, Bl 51200. Epilogue Ds 256x132 f32.
template <bool CONV3, bool CATOUT>
__global__ void __launch_bounds__(512, 1) k_hgemm(
    const __nv_bfloat16* __restrict__ Whi, const __nv_bfloat16* __restrict__ Wlo,
    const __nv_bfloat16* __restrict__ Ihi, const __nv_bfloat16* __restrict__ Ilo,
    const float* __restrict__ gam, const float* __restrict__ bet,
    float* __restrict__ outF, __nv_bfloat16* __restrict__ cth, __nv_bfloat16* __restrict__ ctl,
    int coff, int Kc, int dil) {
    extern __shared__ __align__(16) char dsm[];
    __shared__ int s_tapn, s_tp[9], s_dy[9], s_dx[9];
    __shared__ float sgam[256], sbet[256], smean[128], srstd[128];
    __shared__ float red4[4][128];

    const int b = blockIdx.y, y = blockIdx.x;       // y: 128-wide spatial tile (2 rows)
    const int t = threadIdx.x, wid = t >> 5, lane = t & 31;
    const int mw = wid >> 2, nw = wid & 3;

    if (CONV3 && t == 0) {
        int n = 0;
        for (int tap = 0; tap < 9; tap++) {
            int dy = (tap / 3 - 1) * dil;
            int y0 = y * 2 + dy, y1 = y * 2 + 1 + dy;
            if ((unsigned)y0 < 64u || (unsigned)y1 < 64u) {
                s_tp[n] = tap; s_dy[n] = dy; s_dx[n] = (tap % 3 - 1) * dil; n++;
            }
        }
        s_tapn = n;
    }
    if (t < 256) { sgam[t] = gam[t]; sbet[t] = bet[t]; }
    __syncthreads();

    const int nkc = Kc / 32;
    const int T = CONV3 ? s_tapn * nkc : nkc;
    const __nv_bfloat16* Ib_hi = Ihi + (size_t)b * HW * Kc;
    const __nv_bfloat16* Ib_lo = Ilo + (size_t)b * HW * Kc;

    float acc[4][4][4];
#pragma unroll
    for (int i = 0; i < 4; i++)
#pragma unroll
        for (int j = 0; j < 4; j++)
#pragma unroll
            for (int r = 0; r < 4; r++) acc[i][j][r] = 0.f;

    uint4 rah[2], ral[2], rbh, rbl;

    auto loadG = [&](int it) {
        int tap_i = CONV3 ? (it / nkc) : 0;
        int kc = (CONV3 ? (it - tap_i * nkc) : it) * 32;
        int arow = t >> 1, ak = (t & 1) * 16;
        int grow = CONV3 ? (s_tp[tap_i] * 256 + arow) : arow;
        const __nv_bfloat16* ah = Whi + (size_t)grow * Kc + kc + ak;
        const __nv_bfloat16* al = Wlo + (size_t)grow * Kc + kc + ak;
        rah[0] = *reinterpret_cast<const uint4*>(ah);
        rah[1] = *reinterpret_cast<const uint4*>(ah + 8);
        ral[0] = *reinterpret_cast<const uint4*>(al);
        ral[1] = *reinterpret_cast<const uint4*>(al + 8);
        int n = t >> 2, q = t & 3;
        int hw; bool ok = true;
        if (CONV3) {
            int yy = y * 2 + (n >> 6) + s_dy[tap_i];
            int xx = (n & 63) + s_dx[tap_i];
            ok = ((unsigned)yy < 64u) && ((unsigned)xx < 64u);
            hw = yy * 64 + xx;
        } else hw = y * 128 + n;
        uint4 z = make_uint4(0, 0, 0, 0);
        rbh = ok ? *reinterpret_cast<const uint4*>(Ib_hi + (size_t)hw * Kc + kc + q * 8) : z;
        rbl = ok ? *reinterpret_cast<const uint4*>(Ib_lo + (size_t)hw * Kc + kc + q * 8) : z;
    };
    auto storeS = [&](int buf) {
        char* base = dsm + buf * 61440;
        int arow = t >> 1, ak = (t & 1) * 16;
        *reinterpret_cast<uint4*>(base + arow * 80 + ak * 2) = rah[0];
        *reinterpret_cast<uint4*>(base + arow * 80 + ak * 2 + 16) = rah[1];
        *reinterpret_cast<uint4*>(base + 20480 + arow * 80 + ak * 2) = ral[0];
        *reinterpret_cast<uint4*>(base + 20480 + arow * 80 + ak * 2 + 16) = ral[1];
        int n = t >> 2, q = t & 3;
        *reinterpret_cast<uint4*>(base + 40960 + n * 80 + q * 16) = rbh;
        *reinterpret_cast<uint4*>(base + 51200 + n * 80 + q * 16) = rbl;
    };

    loadG(0);
    storeS(0);
    __syncthreads();

    const int lr = lane >> 2, lc = 2 * (lane & 3);
    for (int it = 0; it < T; ++it) {
        int cur = it & 1;
        bool more = (it + 1 < T);
        if (more) loadG(it + 1);
        const char* base = dsm + cur * 61440;
        const char* Asm = base;
        const char* Alm = base + 20480;
        const char* Bhm = base + 40960;
        const char* Blm = base + 51200;
#pragma unroll
        for (int ks = 0; ks < 2; ks++) {
            int kb = ks * 16;
            uint32_t bh[4][2], bl[4][2];
#pragma unroll
            for (int j = 0; j < 4; j++) {
                int n = nw * 32 + j * 8 + lr;
                int off = n * 80 + (kb + lc) * 2;
                bh[j][0] = *reinterpret_cast<const uint32_t*>(Bhm + off);
                bh[j][1] = *reinterpret_cast<const uint32_t*>(Bhm + off + 16);
                bl[j][0] = *reinterpret_cast<const uint32_t*>(Blm + off);
                bl[j][1] = *reinterpret_cast<const uint32_t*>(Blm + off + 16);
            }
#pragma unroll
            for (int i = 0; i < 4; i++) {
                int r = mw * 64 + i * 16 + lr;
                int off = r * 80 + (kb + lc) * 2;
                uint32_t ah[4], al[4];
                ah[0] = *reinterpret_cast<const uint32_t*>(Asm + off);
                ah[1] = *reinterpret_cast<const uint32_t*>(Asm + off + 640);
                ah[2] = *reinterpret_cast<const uint32_t*>(Asm + off + 16);
                ah[3] = *reinterpret_cast<const uint32_t*>(Asm + off + 656);
                al[0] = *reinterpret_cast<const uint32_t*>(Alm + off);
                al[1] = *reinterpret_cast<const uint32_t*>(Alm + off + 640);
                al[2] = *reinterpret_cast<const uint32_t*>(Alm + off + 16);
                al[3] = *reinterpret_cast<const uint32_t*>(Alm + off + 656);
#pragma unroll
                for (int j = 0; j < 4; j++) {
                    mma16816(acc[i][j], ah, bh[j]);
                    mma16816(acc[i][j], ah, bl[j]);
                    mma16816(acc[i][j], al, bh[j]);
                }
            }
        }
        if (more) storeS(cur ^ 1);
        __syncthreads();
    }

    // ---- stage D (256x128 fp32) into smem, pitch 132
    float* Ds = reinterpret_cast<float*>(dsm);
#pragma unroll
    for (int i = 0; i < 4; i++) {
        int r0 = mw * 64 + i * 16 + lr;
#pragma unroll
        for (int j = 0; j < 4; j++) {
            int c = nw * 32 + j * 8 + lc;
            Ds[r0 * 132 + c] = acc[i][j][0];
            Ds[r0 * 132 + c + 1] = acc[i][j][1];
            Ds[(r0 + 8) * 132 + c] = acc[i][j][2];
            Ds[(r0 + 8) * 132 + c + 1] = acc[i][j][3];
        }
    }
    __syncthreads();
    int n = t & 127, p = t >> 7;
    {
        float s = 0.f;
        for (int mm = p * 64; mm < p * 64 + 64; mm++) s += Ds[mm * 132 + n];
        red4[p][n] = s;
    }
    __syncthreads();
    if (t < 128) smean[t] = (red4[0][t] + red4[1][t] + red4[2][t] + red4[3][t]) * (1.f / 256.f);
    __syncthreads();
    {
        float mu = smean[n], s = 0.f;
        for (int mm = p * 64; mm < p * 64 + 64; mm++) {
            float d = Ds[mm * 132 + n] - mu; s += d * d;
        }
        red4[p][n] = s;
    }
    __syncthreads();
    if (t < 128)
        srstd[t] = rsqrtf((red4[0][t] + red4[1][t] + red4[2][t] + red4[3][t]) * (1.f / 256.f) + 1e-6f);
    __syncthreads();
    {
        float mu = smean[n], rs = srstd[n];
        if (CATOUT) {
            size_t rowb = ((size_t)b * HW + y * 128 + n) * 1280 + coff;
            for (int mm = p * 64; mm < p * 64 + 64; mm++) {
                float vv = gelu_f((Ds[mm * 132 + n] - mu) * rs * sgam[mm] + sbet[mm]);
                __nv_bfloat16 h, l; splitf(vv, h, l);
                cth[rowb + mm] = h; ctl[rowb + mm] = l;
            }
        } else {
            size_t ob = (size_t)b * CIN * HW + y * 128 + n;
            for (int mm = p * 64; mm < p * 64 + 64; mm++) {
                float vv = gelu_f((Ds[mm * 132 + n] - mu) * rs * sgam[mm] + sbet[mm]);
                outF[ob + (size_t)mm * HW] = vv;
            }
        }
    }
}

// ---------------- HMMA S-GEMM: S[b,q,p] = (1/64) sum_c xaT[q,c] * x1T[p,c] ----------
__global__ void __launch_bounds__(256, 1) k_sgemm_h() {
    extern __shared__ __align__(16) char dsm[];
    const int b = blockIdx.z, q0 = blockIdx.y * 128, p0 = blockIdx.x * 64;
    const int t = threadIdx.x, wid = t >> 5, lane = t & 31;
    const int mw = wid >> 1, nw = wid & 1;
    const int lr = lane >> 2, lc = 2 * (lane & 3);
    const __nv_bfloat16* Qh = g_xath + (size_t)b * HW * COUT;
    const __nv_bfloat16* Ql = g_xatl + (size_t)b * HW * COUT;
    const __nv_bfloat16* Ph = g_x1th + (size_t)b * HW * COUT;
    const __nv_bfloat16* Pl = g_x1tl + (size_t)b * HW * COUT;

    float acc[2][4][4];
#pragma unroll
    for (int i = 0; i < 2; i++)
#pragma unroll
        for (int j = 0; j < 4; j++)
#pragma unroll
            for (int r = 0; r < 4; r++) acc[i][j][r] = 0.f;

    uint4 rah[2], ral[2], rbh, rbl;
    auto loadG = [&](int it) {
        int kc = it * 32;
        int ar = t >> 1, ak = (t & 1) * 16;
        const __nv_bfloat16* sh = Qh + (size_t)(q0 + ar) * COUT + kc + ak;
        const __nv_bfloat16* sl = Ql + (size_t)(q0 + ar) * COUT + kc + ak;
        rah[0] = *reinterpret_cast<const uint4*>(sh);
        rah[1] = *reinterpret_cast<const uint4*>(sh + 8);
        ral[0] = *reinterpret_cast<const uint4*>(sl);
        ral[1] = *reinterpret_cast<const uint4*>(sl + 8);
        int br = t >> 2, bk = (t & 3) * 8;
        rbh = *reinterpret_cast<const uint4*>(Ph + (size_t)(p0 + br) * COUT + kc + bk);
        rbl = *reinterpret_cast<const uint4*>(Pl + (size_t)(p0 + br) * COUT + kc + bk);
    };
    auto storeS = [&](int buf) {
        char* base = dsm + buf * 30720;
        int ar = t >> 1, ak = (t & 1) * 16;
        *reinterpret_cast<uint4*>(base + ar * 80 + ak * 2) = rah[0];
        *reinterpret_cast<uint4*>(base + ar * 80 + ak * 2 + 16) = rah[1];
        *reinterpret_cast<uint4*>(base + 10240 + ar * 80 + ak * 2) = ral[0];
        *reinterpret_cast<uint4*>(base + 10240 + ar * 80 + ak * 2 + 16) = ral[1];
        int br = t >> 2, bk = (t & 3) * 8;
        *reinterpret_cast<uint4*>(base + 20480 + br * 80 + bk * 2) = rbh;
        *reinterpret_cast<uint4*>(base + 25600 + br * 80 + bk * 2) = rbl;
    };

    loadG(0); storeS(0); __syncthreads();

    for (int it = 0; it < 4; ++it) {
        int cur = it & 1;
        bool more = (it + 1 < 4);
        if (more) loadG(it + 1);
        const char* base = dsm + cur * 30720;
        const char* Asm = base;
        const char* Alm = base + 10240;
        const char* Bhm = base + 20480;
        const char* Blm = base + 25600;
#pragma unroll
        for (int ks = 0; ks < 2; ks++) {
            int kb = ks * 16;
            uint32_t bh[4][2], bl[4][2];
#pragma unroll
            for (int j = 0; j < 4; j++) {
                int n = nw * 32 + j * 8 + lr;
                int off = n * 80 + (kb + lc) * 2;
                bh[j][0] = *reinterpret_cast<const uint32_t*>(Bhm + off);
                bh[j][1] = *reinterpret_cast<const uint32_t*>(Bhm + off + 16);
                bl[j][0] = *reinterpret_cast<const uint32_t*>(Blm + off);
                bl[j][1] = *reinterpret_cast<const uint32_t*>(Blm + off + 16);
            }
#pragma unroll
            for (int i = 0; i < 2; i++) {
                int r = mw * 32 + i * 16 + lr;
                int off = r * 80 + (kb + lc) * 2;
                uint32_t ah[4], al[4];
                ah[0] = *reinterpret_cast<const uint32_t*>(Asm + off);
                ah[1] = *reinterpret_cast<const uint32_t*>(Asm + off + 640);
                ah[2] = *reinterpret_cast<const uint32_t*>(Asm + off + 16);
                ah[3] = *reinterpret_cast<const uint32_t*>(Asm + off + 656);
                al[0] = *reinterpret_cast<const uint32_t*>(Alm + off);
                al[1] = *reinterpret_cast<const uint32_t*>(Alm + off + 640);
                al[2] = *reinterpret_cast<const uint32_t*>(Alm + off + 16);
                al[3] = *reinterpret_cast<const uint32_t*>(Alm + off + 656);
#pragma unroll
                for (int j = 0; j < 4; j++) {
                    mma16816(acc[i][j], ah, bh[j]);
                    mma16816(acc[i][j], ah, bl[j]);
                    mma16816(acc[i][j], al, bh[j]);
                }
            }
        }
        if (more) storeS(cur ^ 1);
        __syncthreads();
    }

    float* S = g_S + (size_t)b * HW * HW;
    const float sc = 1.f / 64.f;
#pragma unroll
    for (int i = 0; i < 2; i++) {
#pragma unroll
        for (int j = 0; j < 4; j++) {
            int q = q0 + mw * 32 + i * 16 + lr;
            int p = p0 + nw * 32 + j * 8 + lc;
            float2 v0 = make_float2(acc[i][j][0] * sc, acc[i][j][1] * sc);
            float2 v1 = make_float2(acc[i][j][2] * sc, acc[i][j][3] * sc);
            *reinterpret_cast<float2*>(S + (size_t)q * HW + p) = v0;
            *reinterpret_cast<float2*>(S + (size_t)(q + 8) * HW + p) = v1;
        }
    }
}

// ---------------- row softmax; emits bf16 hi/lo probs ----------------
__global__ void __launch_bounds__(256) k_softmax() {
    const size_t row = blockIdx.x;
    const float* r = g_S + row * (size_t)HW;
    __nv_bfloat16* oh = g_Ah + row * (size_t)HW;
    __nv_bfloat16* ol = g_Al + row * (size_t)HW;
    __shared__ float buf[HW];
    __shared__ float red[256];
    int t = threadIdx.x;
    float m = -1e30f;
    for (int i = t; i < HW; i += 256) { float v = r[i]; buf[i] = v; m = fmaxf(m, v); }
    red[t] = m; __syncthreads();
    for (int s = 128; s > 0; s >>= 1) { if (t < s) red[t] = fmaxf(red[t], red[t + s]); __syncthreads(); }
    float mx = red[0]; __syncthreads();
    float s = 0.f;
    for (int i = t; i < HW; i += 256) { float e = expf(buf[i] - mx); buf[i] = e; s += e; }
    red[t] = s; __syncthreads();
    for (int o = 128; o > 0; o >>= 1) { if (t < o) red[t] += red[t + o]; __syncthreads(); }
    float inv = 1.f / red[0];
    for (int i = t; i < HW; i += 256) {
        float p = buf[i] * inv;
        __nv_bfloat16 h, l; splitf(p, h, l);
        oh[i] = h; ol[i] = l;
    }
}

// ---------------- HMMA L-GEMM: O[b,c,j] = sum_q x1[c,q]*A[q,j] + xa[c,j] ----------
__global__ void __launch_bounds__(256, 1) k_lgemm_h() {
    extern __shared__ __align__(16) char dsm[];
    const int b = blockIdx.y, j0g = blockIdx.x * 64;
    const int t = threadIdx.x, wid = t >> 5, lane = t & 31;
    const int mw = wid >> 1, nw = wid & 1;
    const int lr = lane >> 2, lc = 2 * (lane & 3);
    const __nv_bfloat16* Xh = g_x1h + (size_t)b * COUT * HW;
    const __nv_bfloat16* Xl = g_x1l + (size_t)b * COUT * HW;
    const __nv_bfloat16* Aph = g_Ah + (size_t)b * HW * HW;
    const __nv_bfloat16* Apl = g_Al + (size_t)b * HW * HW;

    float acc[2][4][4];
#pragma unroll
    for (int i = 0; i < 2; i++)
#pragma unroll
        for (int j = 0; j < 4; j++)
#pragma unroll
            for (int r = 0; r < 4; r++) acc[i][j][r] = 0.f;

    uint4 rah[2], ral[2];
    ushort4 rb[4];
    auto loadG = [&](int it) {
        int kc = it * 32;
        int ar = t >> 1, ak = (t & 1) * 16;
        const __nv_bfloat16* sh = Xh + (size_t)ar * HW + kc + ak;
        const __nv_bfloat16* sl = Xl + (size_t)ar * HW + kc + ak;
        rah[0] = *reinterpret_cast<const uint4*>(sh);
        rah[1] = *reinterpret_cast<const uint4*>(sh + 8);
        ral[0] = *reinterpret_cast<const uint4*>(sl);
        ral[1] = *reinterpret_cast<const uint4*>(sl + 8);
        int qp = t >> 4, jt = t & 15;
        size_t a0 = (size_t)(kc + 2 * qp) * HW + j0g + jt * 4;
        rb[0] = *reinterpret_cast<const ushort4*>(Aph + a0);
        rb[1] = *reinterpret_cast<const ushort4*>(Aph + a0 + HW);
        rb[2] = *reinterpret_cast<const ushort4*>(Apl + a0);
        rb[3] = *reinterpret_cast<const ushort4*>(Apl + a0 + HW);
    };
    auto storeS = [&](int buf) {
        char* base = dsm + buf * 29184;
        int ar = t >> 1, ak = (t & 1) * 16;
        *reinterpret_cast<uint4*>(base + ar * 80 + ak * 2) = rah[0];
        *reinterpret_cast<uint4*>(base + ar * 80 + ak * 2 + 16) = rah[1];
        *reinterpret_cast<uint4*>(base + 10240 + ar * 80 + ak * 2) = ral[0];
        *reinterpret_cast<uint4*>(base + 10240 + ar * 80 + ak * 2 + 16) = ral[1];
        int qp = t >> 4, jt = t & 15;
        char* bh = base + 20480;
        char* bl = base + 24832;
        int j4 = jt * 4;
        *reinterpret_cast<uint32_t*>(bh + (j4 + 0) * 68 + qp * 4) =
            (uint32_t)rb[0].x | ((uint32_t)rb[1].x << 16);
        *reinterpret_cast<uint32_t*>(bh + (j4 + 1) * 68 + qp * 4) =
            (uint32_t)rb[0].y | ((uint32_t)rb[1].y << 16);
        *reinterpret_cast<uint32_t*>(bh + (j4 + 2) * 68 + qp * 4) =
            (uint32_t)rb[0].z | ((uint32_t)rb[1].z << 16);
        *reinterpret_cast<uint32_t*>(bh + (j4 + 3) * 68 + qp * 4) =
            (uint32_t)rb[0].w | ((uint32_t)rb[1].w << 16);
        *reinterpret_cast<uint32_t*>(bl + (j4 + 0) * 68 + qp * 4) =
            (uint32_t)rb[2].x | ((uint32_t)rb[3].x << 16);
        *reinterpret_cast<uint32_t*>(bl + (j4 + 1) * 68 + qp * 4) =
            (uint32_t)rb[2].y | ((uint32_t)rb[3].y << 16);
        *reinterpret_cast<uint32_t*>(bl + (j4 + 2) * 68 + qp * 4) =
            (uint32_t)rb[2].z | ((uint32_t)rb[3].z << 16);
        *reinterpret_cast<uint32_t*>(bl + (j4 + 3) * 68 + qp * 4) =
            (uint32_t)rb[2].w | ((uint32_t)rb[3].w << 16);
    };

    loadG(0); storeS(0); __syncthreads();

    const int T = HW / 32;
    for (int it = 0; it < T; ++it) {
        int cur = it & 1;
        bool more = (it + 1 < T);
        if (more) loadG(it + 1);
        const char* base = dsm + cur * 29184;
        const char* Asm = base;
        const char* Alm = base + 10240;
        const char* Bhm = base + 20480;
        const char* Blm = base + 24832;
#pragma unroll
        for (int ks = 0; ks < 2; ks++) {
            int kb = ks * 16;
            uint32_t bh[4][2], bl[4][2];
#pragma unroll
            for (int j = 0; j < 4; j++) {
                int n = nw * 32 + j * 8 + lr;
                int off = n * 68 + (kb + lc) * 2;
                bh[j][0] = *reinterpret_cast<const uint32_t*>(Bhm + off);
                bh[j][1] = *reinterpret_cast<const uint32_t*>(Bhm + off + 16);
                bl[j][0] = *reinterpret_cast<const uint32_t*>(Blm + off);
                bl[j][1] = *reinterpret_cast<const uint32_t*>(Blm + off + 16);
            }
#pragma unroll
            for (int i = 0; i < 2; i++) {
                int r = mw * 32 + i * 16 + lr;
                int off = r * 80 + (kb + lc) * 2;
                uint32_t ah[4], al[4];
                ah[0] = *reinterpret_cast<const uint32_t*>(Asm + off);
                ah[1] = *reinterpret_cast<const uint32_t*>(Asm + off + 640);
                ah[2] = *reinterpret_cast<const uint32_t*>(Asm + off + 16);
                ah[3] = *reinterpret_cast<const uint32_t*>(Asm + off + 656);
                al[0] = *reinterpret_cast<const uint32_t*>(Alm + off);
                al[1] = *reinterpret_cast<const uint32_t*>(Alm + off + 640);
                al[2] = *reinterpret_cast<const uint32_t*>(Alm + off + 16);
                al[3] = *reinterpret_cast<const uint32_t*>(Alm + off + 656);
#pragma unroll
                for (int j = 0; j < 4; j++) {
                    mma16816(acc[i][j], ah, bh[j]);
                    mma16816(acc[i][j], ah, bl[j]);
                    mma16816(acc[i][j], al, bh[j]);
                }
            }
        }
        if (more) storeS(cur ^ 1);
        __syncthreads();
    }

    const float* xab = g_xa + (size_t)b * COUT * HW;
    float* Ob = g_O + (size_t)b * COUT * HW;
#pragma unroll
    for (int i = 0; i < 2; i++) {
#pragma unroll
        for (int j = 0; j < 4; j++) {
            int c = mw * 32 + i * 16 + lr;
            int col = j0g + nw * 32 + j * 8 + lc;
            size_t i0 = (size_t)c * HW + col;
            size_t i8 = (size_t)(c + 8) * HW + col;
            float2 x0 = *reinterpret_cast<const float2*>(xab + i0);
            float2 x8 = *reinterpret_cast<const float2*>(xab + i8);
            *reinterpret_cast<float2*>(Ob + i0) =
                make_float2(acc[i][j][0] + x0.x, acc[i][j][1] + x0.y);
            *reinterpret_cast<float2*>(Ob + i8) =
                make_float2(acc[i][j][2] + x8.x, acc[i][j][3] + x8.y);
        }
    }
}

// ---------------- FFMA pipelined GEMM (conv1 / xa / conv2) ----------------
template <int BM, int MODE>
__global__ void __launch_bounds__(256, 2) k_gemm(
    const float* __restrict__ Wg, size_t wb_stride,
    const float* __restrict__ In, size_t in_bstride,
    const float* __restrict__ P1,
    const float* __restrict__ Addp, size_t add_bstride,
    float* __restrict__ Out, size_t out_bstride,
    int Kc) {
    constexpr int TM = BM / 32;
    constexpr int NAREG = (BM == 256) ? 4 : 2;
    const int b = blockIdx.y;
    const int y = blockIdx.x;
    const int n0 = y * BN;
    const int t = threadIdx.x;
    const int ty = t >> 3, tx = t & 7;

    __shared__ __align__(16) float As[2][KT][BM];
    __shared__ __align__(16) float Bs[2][KT][BN];

    const int total = Kc / KT;
    const float* Wb = Wg + (size_t)b * wb_stride;
    const float* Inb = In + (size_t)b * in_bstride;

    ull acc2[TM][4];
#pragma unroll
    for (int i = 0; i < TM; i++)
#pragma unroll
        for (int j = 0; j < 4; j++) acc2[i][j] = 0ULL;

    float4 ra[NAREG];
    float rb[4];

    auto loadG = [&](int it) {
        int k0 = it * KT;
        if (BM == 256) {
            const float* wrow = Wb + (size_t)t * Kc + k0;
#pragma unroll
            for (int q = 0; q < 4; q++)
                ra[q] = *reinterpret_cast<const float4*>(wrow + q * 4);
        } else {
            int m = t >> 1, ko = (t & 1) * 8;
            const float* wrow = Wb + (size_t)m * Kc + k0 + ko;
#pragma unroll
            for (int q = 0; q < 2; q++)
                ra[q] = *reinterpret_cast<const float4*>(wrow + q * 4);
        }
        int k = t >> 4, nb = (t & 15) * 4;
        float4 v = *reinterpret_cast<const float4*>(Inb + (size_t)(k0 + k) * HW + n0 + nb);
        rb[0] = v.x; rb[1] = v.y; rb[2] = v.z; rb[3] = v.w;
    };
    auto storeS = [&](int buf) {
        if (BM == 256) {
#pragma unroll
            for (int q = 0; q < 4; q++) {
                As[buf][q * 4 + 0][t] = ra[q].x; As[buf][q * 4 + 1][t] = ra[q].y;
                As[buf][q * 4 + 2][t] = ra[q].z; As[buf][q * 4 + 3][t] = ra[q].w;
            }
        } else {
            int m = t >> 1, ko = (t & 1) * 8;
#pragma unroll
            for (int q = 0; q < 2; q++) {
                As[buf][ko + q * 4 + 0][m] = ra[q].x; As[buf][ko + q * 4 + 1][m] = ra[q].y;
                As[buf][ko + q * 4 + 2][m] = ra[q].z; As[buf][ko + q * 4 + 3][m] = ra[q].w;
            }
        }
        int k = t >> 4, nb = (t & 15) * 4;
        Bs[buf][k][nb] = rb[0]; Bs[buf][k][nb + 1] = rb[1];
        Bs[buf][k][nb + 2] = rb[2]; Bs[buf][k][nb + 3] = rb[3];
    };

    loadG(0);
    storeS(0);
    __syncthreads();

    for (int it = 0; it < total; ++it) {
        int cur = it & 1;
        bool more = (it + 1 < total);
        if (more) loadG(it + 1);
#pragma unroll
        for (int k = 0; k < KT; k++) {
            ull a2[TM], b2[4];
#pragma unroll
            for (int i = 0; i < TM; i += 4) {
                float4 v = *reinterpret_cast<const float4*>(&As[cur][k][ty * TM + i]);
                a2[i] = pack2f(v.x); a2[i + 1] = pack2f(v.y);
                a2[i + 2] = pack2f(v.z); a2[i + 3] = pack2f(v.w);
            }
            {
                float4 v0 = *reinterpret_cast<const float4*>(&Bs[cur][k][tx * 8]);
                float4 v1 = *reinterpret_cast<const float4*>(&Bs[cur][k][tx * 8 + 4]);
                b2[0] = pack2(v0.x, v0.y); b2[1] = pack2(v0.z, v0.w);
                b2[2] = pack2(v1.x, v1.y); b2[3] = pack2(v1.z, v1.w);
            }
#pragma unroll
            for (int i = 0; i < TM; i++)
#pragma unroll
                for (int j = 0; j < 4; j++) fma2(acc2[i][j], a2[i], b2[j]);
        }
        if (more) storeS(cur ^ 1);
        __syncthreads();
    }

    float* Ob = Out + (size_t)b * out_bstride;
#pragma unroll
    for (int i = 0; i < TM; i++) {
        int m = ty * TM + i;
        float bias = (MODE == 0) ? P1[m] : 0.f;
        const float* addrow = (MODE == 2)
            ? (Addp + (size_t)b * add_bstride + (size_t)m * HW + n0 + tx * 8)
            : nullptr;
        float o8[8];
#pragma unroll
        for (int j = 0; j < 4; j++) {
            float2 f = unpk2(acc2[i][j]);
            o8[2 * j] = f.x + bias; o8[2 * j + 1] = f.y + bias;
            if (MODE == 2) { o8[2 * j] += addrow[2 * j]; o8[2 * j + 1] += addrow[2 * j + 1]; }
        }
        float* dst = Ob + (size_t)m * HW + n0 + tx * 8;
        *reinterpret_cast<float4*>(dst) = make_float4(o8[0], o8[1], o8[2], o8[3]);
        *reinterpret_cast<float4*>(dst + 4) = make_float4(o8[4], o8[5], o8[6], o8[7]);
    }
}

// ---------------- host launch ----------------
extern "C" void kernel_launch(void* const* d_in, const int* in_sizes, int n_in,
                              void* d_out, int out_size) {
    (void)in_sizes; (void)n_in; (void)out_size;
    const float* x       = (const float*)d_in[0];
    const float* conv1_w = (const float*)d_in[1];
    const float* conv1_b = (const float*)d_in[2];
    const float* conv2_w = (const float*)d_in[3];
    const float* conv2_b = (const float*)d_in[4];
    const float* cw_w1   = (const float*)d_in[5];
    const float* cw_b1   = (const float*)d_in[6];
    const float* cw_ln_g = (const float*)d_in[7];
    const float* cw_ln_b = (const float*)d_in[8];
    const float* cw_w2   = (const float*)d_in[9];
    const float* cw_b2   = (const float*)d_in[10];
    const float* aspp0_w = (const float*)d_in[11];
    const float* aspp0_g = (const float*)d_in[12];
    const float* aspp0_b = (const float*)d_in[13];
    const float* aspp1_w = (const float*)d_in[14];
    const float* aspp1_g = (const float*)d_in[15];
    const float* aspp1_b = (const float*)d_in[16];
    const float* aspp2_w = (const float*)d_in[17];
    const float* aspp2_g = (const float*)d_in[18];
    const float* aspp2_b = (const float*)d_in[19];
    const float* aspp3_w = (const float*)d_in[20];
    const float* aspp3_g = (const float*)d_in[21];
    const float* aspp3_b = (const float*)d_in[22];
    const float* asppp_w = (const float*)d_in[23];
    const float* asppp_g = (const float*)d_in[24];
    const float* asppp_b = (const float*)d_in[25];
    const float* proj_w  = (const float*)d_in[26];
    const float* proj_g  = (const float*)d_in[27];
    const float* proj_b  = (const float*)d_in[28];

    void* pv;
    float *p_x1, *p_proj, *p_xa, *p_O;
    __nv_bfloat16 *p_xth, *p_xtl, *p_cth, *p_ctl, *p_w3h, *p_w3l, *p_a0h, *p_a0l, *p_pjh, *p_pjl;
    __nv_bfloat16 *p_x1th, *p_x1tl, *p_xath, *p_xatl, *p_x1h, *p_x1l;
    cudaGetSymbolAddress(&pv, g_x1);   p_x1   = (float*)pv;
    cudaGetSymbolAddress(&pv, g_proj); p_proj = (float*)pv;
    cudaGetSymbolAddress(&pv, g_xa);   p_xa   = (float*)pv;
    cudaGetSymbolAddress(&pv, g_O);    p_O    = (float*)pv;
    cudaGetSymbolAddress(&pv, g_xth);  p_xth  = (__nv_bfloat16*)pv;
    cudaGetSymbolAddress(&pv, g_xtl);  p_xtl  = (__nv_bfloat16*)pv;
    cudaGetSymbolAddress(&pv, g_cth);  p_cth  = (__nv_bfloat16*)pv;
    cudaGetSymbolAddress(&pv, g_ctl);  p_ctl  = (__nv_bfloat16*)pv;
    cudaGetSymbolAddress(&pv, g_w3h);  p_w3h  = (__nv_bfloat16*)pv;
    cudaGetSymbolAddress(&pv, g_w3l);  p_w3l  = (__nv_bfloat16*)pv;
    cudaGetSymbolAddress(&pv, g_a0h);  p_a0h  = (__nv_bfloat16*)pv;
    cudaGetSymbolAddress(&pv, g_a0l);  p_a0l  = (__nv_bfloat16*)pv;
    cudaGetSymbolAddress(&pv, g_pjh);  p_pjh  = (__nv_bfloat16*)pv;
    cudaGetSymbolAddress(&pv, g_pjl);  p_pjl  = (__nv_bfloat16*)pv;
    cudaGetSymbolAddress(&pv, g_x1th); p_x1th = (__nv_bfloat16*)pv;
    cudaGetSymbolAddress(&pv, g_x1tl); p_x1tl = (__nv_bfloat16*)pv;
    cudaGetSymbolAddress(&pv, g_xath); p_xath = (__nv_bfloat16*)pv;
    cudaGetSymbolAddress(&pv, g_xatl); p_xatl = (__nv_bfloat16*)pv;
    cudaGetSymbolAddress(&pv, g_x1h);  p_x1h  = (__nv_bfloat16*)pv;
    cudaGetSymbolAddress(&pv, g_x1l);  p_x1l  = (__nv_bfloat16*)pv;

    const int TG_SMEM = 135168;   // max(2x61440 mainloop, 256x132x4 epilogue)
    cudaFuncSetAttribute(k_hgemm<false, true>, cudaFuncAttributeMaxDynamicSharedMemorySize, TG_SMEM);
    cudaFuncSetAttribute(k_hgemm<true, true>, cudaFuncAttributeMaxDynamicSharedMemorySize, TG_SMEM);
    cudaFuncSetAttribute(k_hgemm<false, false>, cudaFuncAttributeMaxDynamicSharedMemorySize, TG_SMEM);
    cudaFuncSetAttribute(k_sgemm_h, cudaFuncAttributeMaxDynamicSharedMemorySize, 61440);
    cudaFuncSetAttribute(k_lgemm_h, cudaFuncAttributeMaxDynamicSharedMemorySize, 58368);

    dim3 g64(HW / BN, BATCH);
    dim3 gh(HW / 128, BATCH);

    // 1-3: prep (launch #4 = aspp0 HMMA gets profiled)
    k_prep<<<3328, 256>>>(aspp1_w, aspp2_w, aspp3_w, aspp0_w, proj_w, x);
    k_cw<<<BATCH, 256>>>(cw_w1, cw_b1, cw_ln_g, cw_ln_b, cw_w2, cw_b2,
                         asppp_w, asppp_g, asppp_b);
    k_xcsplit<<<dim3(128, 8, BATCH), 256>>>(x);
    // 4-7: ASPP branches (HMMA, 512-thread 256x128 tiles)
    k_hgemm<false, true><<<gh, 512, TG_SMEM>>>(p_a0h, p_a0l, p_xth, p_xtl,
        aspp0_g, aspp0_b, nullptr, p_cth, p_ctl, 0, CIN, 0);
    k_hgemm<true, true><<<gh, 512, TG_SMEM>>>(p_w3h + 0 * 9 * 65536, p_w3l + 0 * 9 * 65536,
        p_xth, p_xtl, aspp1_g, aspp1_b, nullptr, p_cth, p_ctl, 256, CIN, 3);
    k_hgemm<true, true><<<gh, 512, TG_SMEM>>>(p_w3h + 1 * 9 * 65536, p_w3l + 1 * 9 * 65536,
        p_xth, p_xtl, aspp2_g, aspp2_b, nullptr, p_cth, p_ctl, 512, CIN, 6);
    k_hgemm<true, true><<<gh, 512, TG_SMEM>>>(p_w3h + 2 * 9 * 65536, p_w3l + 2 * 9 * 65536,
        p_xth, p_xtl, aspp3_g, aspp3_b, nullptr, p_cth, p_ctl, 768, CIN, 9);
    // 8: global-pool branch into catT
    k_bp_cat<<<dim3(128, BATCH), 256>>>();
    // 9: proj (HMMA, K=1280) -> f32
    k_hgemm<false, false><<<gh, 512, TG_SMEM>>>(p_pjh, p_pjl, p_cth, p_ctl,
        proj_g, proj_b, p_proj, nullptr, nullptr, 0, 5 * CIN, 0);
    // 10-11: conv1 twice (FFMA)
    k_gemm<128, 0><<<g64, 256>>>(conv1_w, 0, x, (size_t)CIN * HW, conv1_b,
                                 nullptr, 0, p_x1, (size_t)COUT * HW, CIN);
    k_gemm<128, 0><<<g64, 256>>>(conv1_w, 0, p_proj, (size_t)CIN * HW, conv1_b,
                                 nullptr, 0, p_xa, (size_t)COUT * HW, CIN);
    // 12-13: split x1 (straight + T), xa (T)
    k_splitT<true><<<dim3(128, 4, BATCH), 256>>>(p_x1, p_x1th, p_x1tl, p_x1h, p_x1l);
    k_splitT<false><<<dim3(128, 4, BATCH), 256>>>(p_xa, p_xath, p_xatl, nullptr, nullptr);
    // 14-16: attention (HMMA S, softmax->bf16, HMMA L with +xa)
    k_sgemm_h<<<dim3(64, 32, BATCH), 256, 61440>>>();
    k_softmax<<<BATCH * HW, 256>>>();
    k_lgemm_h<<<dim3(64, BATCH), 256, 58368>>>();
    // 17: out = conv2(O) + b (FFMA)
    k_gemm<256, 0><<<g64, 256>>>(conv2_w, 0, p_O, (size_t)COUT * HW, conv2_b,
                                 nullptr, 0, (float*)d_out, (size_t)CIN * HW, COUT);
}

// round 8
// speedup vs baseline: 2.2642x; 1.2017x over previous
#include <cuda_runtime.h>
#include <cuda_bf16.h>
#include <math.h>
#include <stdint.h>

#define BATCH 4
#define CIN 256
#define COUT 128
#define HH 64
#define WW 64
#define HW 4096
#define BN 64
#define KT 16

typedef unsigned long long ull;

// ---------------- scratch (static device globals; no allocs) ----------------
__device__ float g_x1[BATCH * COUT * HW];
__device__ float g_proj[BATCH * CIN * HW];
__device__ float g_xa[BATCH * COUT * HW];
__device__ float g_O[BATCH * COUT * HW];
__device__ float g_S[(size_t)BATCH * HW * HW];
__device__ float g_avg[BATCH * CIN];
__device__ float g_mx[BATCH * CIN];
__device__ float g_s[BATCH * CIN];
__device__ float g_bp[BATCH * CIN];
// bf16 split operands
__device__ __nv_bfloat16 g_xth[BATCH * HW * CIN];              // xcT hi  [b][hw][c]
__device__ __nv_bfloat16 g_xtl[BATCH * HW * CIN];              // xcT lo
__device__ __nv_bfloat16 g_cth[(size_t)BATCH * HW * 5 * CIN];  // catT hi [b][hw][1280]
__device__ __nv_bfloat16 g_ctl[(size_t)BATCH * HW * 5 * CIN];  // catT lo
__device__ __nv_bfloat16 g_w3h[3 * 9 * CIN * CIN];             // [conv][tap][m][c]
__device__ __nv_bfloat16 g_w3l[3 * 9 * CIN * CIN];
__device__ __nv_bfloat16 g_a0h[CIN * CIN];
__device__ __nv_bfloat16 g_a0l[CIN * CIN];
__device__ __nv_bfloat16 g_pjh[CIN * 5 * CIN];
__device__ __nv_bfloat16 g_pjl[CIN * 5 * CIN];
// attention operands
__device__ __nv_bfloat16 g_x1th[BATCH * HW * COUT];  // x1T hi [b][hw][c]
__device__ __nv_bfloat16 g_x1tl[BATCH * HW * COUT];
__device__ __nv_bfloat16 g_xath[BATCH * HW * COUT];  // xaT hi [b][hw][c]
__device__ __nv_bfloat16 g_xatl[BATCH * HW * COUT];
__device__ __nv_bfloat16 g_x1h[BATCH * COUT * HW];   // x1 straight split [b][c][hw]
__device__ __nv_bfloat16 g_x1l[BATCH * COUT * HW];
__device__ __nv_bfloat16 g_Ah[(size_t)BATCH * HW * HW];  // softmax probs hi [b][q][p]
__device__ __nv_bfloat16 g_Al[(size_t)BATCH * HW * HW];

__device__ __forceinline__ float gelu_f(float x) {
    return 0.5f * x * (1.0f + erff(x * 0.70710678118654752440f));
}
__device__ __forceinline__ void splitf(float v, __nv_bfloat16& h, __nv_bfloat16& l) {
    h = __float2bfloat16(v);
    l = __float2bfloat16(v - __bfloat162float(h));
}

// ---------------- HMMA m16n8k16 bf16 ----------------
__device__ __forceinline__ void mma16816(float* d, const uint32_t* a, const uint32_t* b) {
    asm volatile(
        "mma.sync.aligned.m16n8k16.row.col.f32.bf16.bf16.f32 "
        "{%0,%1,%2,%3}, {%4,%5,%6,%7}, {%8,%9}, {%0,%1,%2,%3};"
        : "+f"(d[0]), "+f"(d[1]), "+f"(d[2]), "+f"(d[3])
        : "r"(a[0]), "r"(a[1]), "r"(a[2]), "r"(a[3]), "r"(b[0]), "r"(b[1]));
}

// ---------------- cp.async helpers ----------------
__device__ __forceinline__ void cp16(uint32_t d, const void* s, int ssz) {
    asm volatile("cp.async.ca.shared.global [%0], [%1], 16, %2;"
                 :: "r"(d), "l"(s), "r"(ssz) : "memory");
}
#define CP_COMMIT() asm volatile("cp.async.commit_group;" ::: "memory")
#define CP_WAIT1()  asm volatile("cp.async.wait_group 1;" ::: "memory")
#define CP_WAIT0()  asm volatile("cp.async.wait_group 0;" ::: "memory")

// ---------------- packed helpers for FFMA path ----------------
__device__ __forceinline__ ull pack2f(float x) {
    ull r; asm("mov.b64 %0, {%1, %1};" : "=l"(r) : "f"(x)); return r;
}
__device__ __forceinline__ ull pack2(float x, float y) {
    ull r; asm("mov.b64 %0, {%1, %2};" : "=l"(r) : "f"(x), "f"(y)); return r;
}
__device__ __forceinline__ void fma2(ull& d, ull a, ull b) {
    asm("fma.rn.f32x2 %0, %1, %2, %0;" : "+l"(d) : "l"(a), "l"(b));
}
__device__ __forceinline__ float2 unpk2(ull v) {
    float2 f; asm("mov.b64 {%0, %1}, %2;" : "=f"(f.x), "=f"(f.y) : "l"(v)); return f;
}

// ---------------- prep: weight split/transpose + per-(b,c) stats ----------------
__global__ void k_prep(const float* __restrict__ w1, const float* __restrict__ w2,
                       const float* __restrict__ w3, const float* __restrict__ a0,
                       const float* __restrict__ pj, const float* __restrict__ x) {
    if (blockIdx.x < 2304) {
        int e = blockIdx.x * 256 + threadIdx.x;
        if (e < 196608) {
            const float* srcs[3] = { w1, w2, w3 };
            int conv = e >> 16, mc = e & 65535, m = mc >> 8, c = mc & 255;
            const float* src = srcs[conv] + (size_t)m * 2304 + (size_t)c * 9;
            size_t dbase = (size_t)conv * 9 * 65536 + (size_t)m * 256 + c;
#pragma unroll
            for (int tap = 0; tap < 9; tap++) {
                __nv_bfloat16 h, l; splitf(src[tap], h, l);
                g_w3h[dbase + (size_t)tap * 65536] = h;
                g_w3l[dbase + (size_t)tap * 65536] = l;
            }
        } else if (e < 262144) {
            int i = e - 196608;
            __nv_bfloat16 h, l; splitf(a0[i], h, l);
            g_a0h[i] = h; g_a0l[i] = l;
        } else if (e < 589824) {
            int i = e - 262144;
            __nv_bfloat16 h, l; splitf(pj[i], h, l);
            g_pjh[i] = h; g_pjl[i] = l;
        }
    } else {
        int bc = blockIdx.x - 2304;
        const float* p = x + (size_t)bc * HW;
        int t = threadIdx.x;
        float s = 0.f, m = -1e30f;
        for (int i = t; i < HW; i += 256) { float v = p[i]; s += v; m = fmaxf(m, v); }
        __shared__ float ss[256], sm[256];
        ss[t] = s; sm[t] = m; __syncthreads();
        for (int o = 128; o > 0; o >>= 1) {
            if (t < o) { ss[t] += ss[t + o]; sm[t] = fmaxf(sm[t], sm[t + o]); }
            __syncthreads();
        }
        if (t == 0) { g_avg[bc] = ss[0] * (1.f / HW); g_mx[bc] = sm[0]; }
    }
}

// ---------------- channel weighting MLP + global-pool ASPP branch ----------------
__global__ void k_cw(const float* __restrict__ w1, const float* __restrict__ bb1,
                     const float* __restrict__ lg, const float* __restrict__ lb,
                     const float* __restrict__ w2, const float* __restrict__ bb2,
                     const float* __restrict__ apw, const float* __restrict__ apg,
                     const float* __restrict__ apb) {
    int b = blockIdx.x, t = threadIdx.x;
    __shared__ float o[CIN];
    __shared__ float h[COUT];
    __shared__ float red[256];
    __shared__ float gp[CIN];
    float avg = g_avg[b * CIN + t], mx = g_mx[b * CIN + t];
    o[t] = fabsf(avg - mx) * avg;
    __syncthreads();
    float hv = 0.f;
    if (t < COUT) {
        hv = bb1[t];
        const float* wr = w1 + t * CIN;
        for (int i = 0; i < CIN; i++) hv = fmaf(o[i], wr[i], hv);
    }
    red[t] = (t < COUT) ? hv : 0.f; __syncthreads();
    for (int s = 128; s > 0; s >>= 1) { if (t < s) red[t] += red[t + s]; __syncthreads(); }
    float mu = red[0] * (1.f / COUT); __syncthreads();
    float dv = (t < COUT) ? (hv - mu) : 0.f;
    red[t] = dv * dv; __syncthreads();
    for (int s = 128; s > 0; s >>= 1) { if (t < s) red[t] += red[t + s]; __syncthreads(); }
    float var = red[0] * (1.f / COUT); __syncthreads();
    if (t < COUT) h[t] = lg[t] * ((hv - mu) * rsqrtf(var + 1e-5f)) + lb[t];
    __syncthreads();
    float sv = bb2[t];
    const float* wr2 = w2 + t * COUT;
    for (int j = 0; j < COUT; j++) sv = fmaf(h[j], wr2[j], sv);
    float sig = 1.f / (1.f + expf(-sv));
    g_s[b * CIN + t] = sig;
    gp[t] = (1.f + sig) * avg;
    __syncthreads();
    float v = 0.f;
    const float* ar = apw + t * CIN;
    for (int i = 0; i < CIN; i++) v = fmaf(ar[i], gp[i], v);
    red[t] = v; __syncthreads();
    for (int s = 128; s > 0; s >>= 1) { if (t < s) red[t] += red[t + s]; __syncthreads(); }
    float mu2 = red[0] * (1.f / CIN); __syncthreads();
    float d2 = v - mu2; red[t] = d2 * d2; __syncthreads();
    for (int s = 128; s > 0; s >>= 1) { if (t < s) red[t] += red[t + s]; __syncthreads(); }
    float var2 = red[0] * (1.f / CIN); __syncthreads();
    float z = apg[t] * ((v - mu2) * rsqrtf(var2 + 1e-6f)) + apb[t];
    g_bp[b * CIN + t] = gelu_f(z);
}

// ---------------- xcT split: x[b][c][hw]*(1+s) -> bf16 hi/lo [b][hw][c] ----------------
__global__ void k_xcsplit(const float* __restrict__ x) {
    __shared__ float tile[32][33];
    int b = blockIdx.z, c0 = blockIdx.y * 32, h0 = blockIdx.x * 32;
    int t = threadIdx.x;
    const float* xb = x + ((size_t)b * CIN + c0) * HW + h0;
#pragma unroll
    for (int i = 0; i < 4; i++) {
        int r = (t >> 5) + 8 * i;
        tile[r][t & 31] = xb[(size_t)r * HW + (t & 31)];
    }
    __syncthreads();
#pragma unroll
    for (int i = 0; i < 4; i++) {
        int hr = (t >> 5) + 8 * i, cc = t & 31;
        float v = tile[cc][hr] * (1.f + g_s[b * CIN + c0 + cc]);
        __nv_bfloat16 h, l; splitf(v, h, l);
        size_t idx = ((size_t)b * HW + h0 + hr) * CIN + c0 + cc;
        g_xth[idx] = h; g_xtl[idx] = l;
    }
}

// ---------------- split/transpose for 128-channel fp32 maps ----------------
template <bool STRAIGHT>
__global__ void k_splitT(const float* __restrict__ in,
                         __nv_bfloat16* __restrict__ th, __nv_bfloat16* __restrict__ tl,
                         __nv_bfloat16* __restrict__ sh, __nv_bfloat16* __restrict__ sl) {
    __shared__ float tile[32][33];
    int b = blockIdx.z, c0 = blockIdx.y * 32, h0 = blockIdx.x * 32;
    int t = threadIdx.x;
    const float* ib = in + ((size_t)b * COUT + c0) * HW + h0;
#pragma unroll
    for (int i = 0; i < 4; i++) {
        int r = (t >> 5) + 8 * i, col = t & 31;
        float v = ib[(size_t)r * HW + col];
        tile[r][col] = v;
        if (STRAIGHT) {
            __nv_bfloat16 h, l; splitf(v, h, l);
            size_t idx = ((size_t)b * COUT + c0 + r) * HW + h0 + col;
            sh[idx] = h; sl[idx] = l;
        }
    }
    __syncthreads();
#pragma unroll
    for (int i = 0; i < 4; i++) {
        int hr = (t >> 5) + 8 * i, cc = t & 31;
        float v = tile[cc][hr];
        __nv_bfloat16 h, l; splitf(v, h, l);
        size_t idx = ((size_t)b * HW + h0 + hr) * COUT + c0 + cc;
        th[idx] = h; tl[idx] = l;
    }
}

// ---------------- bp broadcast into catT channels [1024,1280) ----------------
__global__ void k_bp_cat() {
    int b = blockIdx.y, h0 = blockIdx.x * 32;
    int c = threadIdx.x;
    __nv_bfloat16 h, l; splitf(g_bp[b * CIN + c], h, l);
    for (int r = 0; r < 32; r++) {
        size_t idx = ((size_t)b * HW + h0 + r) * 1280 + 1024 + c;
        g_cth[idx] = h; g_ctl[idx] = l;
    }
}

// ---------------- HMMA bf16x2-split GEMM, 256x128 tile, 512 thr, cp.async mainloop ----
// Out[b,m,n] = GELU(LN_m( sum_k W[m,k]*In[b,k,n] )),  In transposed [hw][k].
// 16 warps: 4(M) x 4(N); warp tile 64x32. BK=32.
// Per buf (61440B): Ah 0, Al 20480, Bh 40960, Bl 51200. Epilogue Ds 256x129 f32.
template <bool CONV3, bool CATOUT>
__global__ void __launch_bounds__(512, 1) k_hgemm(
    const __nv_bfloat16* __restrict__ Whi, const __nv_bfloat16* __restrict__ Wlo,
    const __nv_bfloat16* __restrict__ Ihi, const __nv_bfloat16* __restrict__ Ilo,
    const float* __restrict__ gam, const float* __restrict__ bet,
    float* __restrict__ outF, __nv_bfloat16* __restrict__ cth, __nv_bfloat16* __restrict__ ctl,
    int coff, int Kc, int dil) {
    extern __shared__ __align__(16) char dsm[];
    __shared__ int s_tapn, s_tp[9], s_dy[9], s_dx[9];
    __shared__ float sgam[256], sbet[256], smean[128], srstd[128];
    __shared__ float red4[4][128];

    const int b = blockIdx.y, y = blockIdx.x;       // y: 128-wide spatial tile (2 rows)
    const int t = threadIdx.x, wid = t >> 5, lane = t & 31;
    const int mw = wid >> 2, nw = wid & 3;
    const uint32_t sbase = (uint32_t)__cvta_generic_to_shared(dsm);

    if (CONV3 && t == 0) {
        int n = 0;
        for (int tap = 0; tap < 9; tap++) {
            int dy = (tap / 3 - 1) * dil;
            int y0 = y * 2 + dy, y1 = y * 2 + 1 + dy;
            if ((unsigned)y0 < 64u || (unsigned)y1 < 64u) {
                s_tp[n] = tap; s_dy[n] = dy; s_dx[n] = (tap % 3 - 1) * dil; n++;
            }
        }
        s_tapn = n;
    }
    if (t < 256) { sgam[t] = gam[t]; sbet[t] = bet[t]; }
    __syncthreads();

    const int nkc = Kc / 32;
    const int T = CONV3 ? s_tapn * nkc : nkc;
    const __nv_bfloat16* Ib_hi = Ihi + (size_t)b * HW * Kc;
    const __nv_bfloat16* Ib_lo = Ilo + (size_t)b * HW * Kc;

    float acc[4][4][4];
#pragma unroll
    for (int i = 0; i < 4; i++)
#pragma unroll
        for (int j = 0; j < 4; j++)
#pragma unroll
            for (int r = 0; r < 4; r++) acc[i][j][r] = 0.f;

    // ---- async G->S tile load (6 x cp16 per thread), zero regs held ----
    auto loadG = [&](int it, int buf) {
        int tap_i = CONV3 ? (it / nkc) : 0;
        int kc = (CONV3 ? (it - tap_i * nkc) : it) * 32;
        uint32_t base = sbase + buf * 61440;
        int arow = t >> 1, ak = (t & 1) * 16;
        int grow = CONV3 ? (s_tp[tap_i] * 256 + arow) : arow;
        const __nv_bfloat16* ah = Whi + (size_t)grow * Kc + kc + ak;
        const __nv_bfloat16* al = Wlo + (size_t)grow * Kc + kc + ak;
        uint32_t da = base + arow * 80 + ak * 2;
        cp16(da, ah, 16);
        cp16(da + 16, ah + 8, 16);
        cp16(da + 20480, al, 16);
        cp16(da + 20480 + 16, al + 8, 16);
        int n = t >> 2, q = t & 3;
        int hw; int ok = 16;
        if (CONV3) {
            int yy = y * 2 + (n >> 6) + s_dy[tap_i];
            int xx = (n & 63) + s_dx[tap_i];
            if ((unsigned)yy < 64u && (unsigned)xx < 64u) hw = yy * 64 + xx;
            else { hw = 0; ok = 0; }
        } else hw = y * 128 + n;
        uint32_t db = base + 40960 + n * 80 + q * 16;
        cp16(db, Ib_hi + (size_t)hw * Kc + kc + q * 8, ok);
        cp16(db + 10240, Ib_lo + (size_t)hw * Kc + kc + q * 8, ok);
        CP_COMMIT();
    };

    loadG(0, 0);
    if (T > 1) loadG(1, 1);

    const int lr = lane >> 2, lc = 2 * (lane & 3);
    for (int it = 0; it < T; ++it) {
        int cur = it & 1;
        if (it + 1 < T) CP_WAIT1(); else CP_WAIT0();
        __syncthreads();
        const char* base = dsm + cur * 61440;
        const char* Asm = base;
        const char* Alm = base + 20480;
        const char* Bhm = base + 40960;
        const char* Blm = base + 51200;
#pragma unroll
        for (int ks = 0; ks < 2; ks++) {
            int kb = ks * 16;
            uint32_t bh[4][2], bl[4][2];
#pragma unroll
            for (int j = 0; j < 4; j++) {
                int n = nw * 32 + j * 8 + lr;
                int off = n * 80 + (kb + lc) * 2;
                bh[j][0] = *reinterpret_cast<const uint32_t*>(Bhm + off);
                bh[j][1] = *reinterpret_cast<const uint32_t*>(Bhm + off + 16);
                bl[j][0] = *reinterpret_cast<const uint32_t*>(Blm + off);
                bl[j][1] = *reinterpret_cast<const uint32_t*>(Blm + off + 16);
            }
#pragma unroll
            for (int i = 0; i < 4; i++) {
                int r = mw * 64 + i * 16 + lr;
                int off = r * 80 + (kb + lc) * 2;
                uint32_t ah[4], al[4];
                ah[0] = *reinterpret_cast<const uint32_t*>(Asm + off);
                ah[1] = *reinterpret_cast<const uint32_t*>(Asm + off + 640);
                ah[2] = *reinterpret_cast<const uint32_t*>(Asm + off + 16);
                ah[3] = *reinterpret_cast<const uint32_t*>(Asm + off + 656);
                al[0] = *reinterpret_cast<const uint32_t*>(Alm + off);
                al[1] = *reinterpret_cast<const uint32_t*>(Alm + off + 640);
                al[2] = *reinterpret_cast<const uint32_t*>(Alm + off + 16);
                al[3] = *reinterpret_cast<const uint32_t*>(Alm + off + 656);
#pragma unroll
                for (int j = 0; j < 4; j++) {
                    mma16816(acc[i][j], ah, bh[j]);
                    mma16816(acc[i][j], ah, bl[j]);
                    mma16816(acc[i][j], al, bh[j]);
                }
            }
        }
        __syncthreads();
        if (it + 2 < T) loadG(it + 2, cur);
    }

    // ---- stage D (256x128 fp32) into smem, pitch 129
    float* Ds = reinterpret_cast<float*>(dsm);
#pragma unroll
    for (int i = 0; i < 4; i++) {
        int r0 = mw * 64 + i * 16 + lr;
#pragma unroll
        for (int j = 0; j < 4; j++) {
            int c = nw * 32 + j * 8 + lc;
            Ds[r0 * 129 + c] = acc[i][j][0];
            Ds[r0 * 129 + c + 1] = acc[i][j][1];
            Ds[(r0 + 8) * 129 + c] = acc[i][j][2];
            Ds[(r0 + 8) * 129 + c + 1] = acc[i][j][3];
        }
    }
    __syncthreads();
    {
        int n = t & 127, p = t >> 7;
        float s = 0.f;
        for (int mm = p * 64; mm < p * 64 + 64; mm++) s += Ds[mm * 129 + n];
        red4[p][n] = s;
        __syncthreads();
        if (t < 128)
            smean[t] = (red4[0][t] + red4[1][t] + red4[2][t] + red4[3][t]) * (1.f / 256.f);
        __syncthreads();
        float mu = smean[n];
        s = 0.f;
        for (int mm = p * 64; mm < p * 64 + 64; mm++) {
            float d = Ds[mm * 129 + n] - mu; s += d * d;
        }
        red4[p][n] = s;
        __syncthreads();
        if (t < 128)
            srstd[t] = rsqrtf((red4[0][t] + red4[1][t] + red4[2][t] + red4[3][t]) * (1.f / 256.f) + 1e-6f);
        __syncthreads();
    }
    if (CATOUT) {
        // thread t owns output row n2 = t>>2 and 64 contiguous channels
        int n2 = t >> 2, m0q = (t & 3) * 64;
        float mu = smean[n2], rs = srstd[n2];
        size_t rowb = ((size_t)b * HW + y * 128 + n2) * 1280 + coff + m0q;
#pragma unroll
        for (int blk = 0; blk < 64; blk += 8) {
            __align__(16) unsigned short h8[8], l8[8];
#pragma unroll
            for (int j = 0; j < 8; j++) {
                int m = m0q + blk + j;
                float vv = gelu_f((Ds[m * 129 + n2] - mu) * rs * sgam[m] + sbet[m]);
                __nv_bfloat16 h, l; splitf(vv, h, l);
                h8[j] = *reinterpret_cast<unsigned short*>(&h);
                l8[j] = *reinterpret_cast<unsigned short*>(&l);
            }
            *reinterpret_cast<uint4*>(cth + rowb + blk) = *reinterpret_cast<uint4*>(h8);
            *reinterpret_cast<uint4*>(ctl + rowb + blk) = *reinterpret_cast<uint4*>(l8);
        }
    } else {
        // thread t owns channel m = t>>1 and 64 contiguous hw positions
        int m = t >> 1, nh = (t & 1) * 64;
        float gmm = sgam[m], bt2 = sbet[m];
        size_t ob = ((size_t)b * CIN + m) * HW + y * 128 + nh;
#pragma unroll
        for (int blk = 0; blk < 64; blk += 4) {
            float4 v4;
            float* vp = &v4.x;
#pragma unroll
            for (int j = 0; j < 4; j++) {
                int n3 = nh + blk + j;
                vp[j] = gelu_f((Ds[m * 129 + n3] - smean[n3]) * srstd[n3] * gmm + bt2);
            }
            *reinterpret_cast<float4*>(outF + ob + blk) = v4;
        }
    }
}

// ---------------- HMMA S-GEMM: S[b,q,p] = (1/64) sum_c xaT[q,c] * x1T[p,c] ----------
__global__ void __launch_bounds__(256, 1) k_sgemm_h() {
    extern __shared__ __align__(16) char dsm[];
    const int b = blockIdx.z, q0 = blockIdx.y * 128, p0 = blockIdx.x * 64;
    const int t = threadIdx.x, wid = t >> 5, lane = t & 31;
    const int mw = wid >> 1, nw = wid & 1;
    const int lr = lane >> 2, lc = 2 * (lane & 3);
    const __nv_bfloat16* Qh = g_xath + (size_t)b * HW * COUT;
    const __nv_bfloat16* Ql = g_xatl + (size_t)b * HW * COUT;
    const __nv_bfloat16* Ph = g_x1th + (size_t)b * HW * COUT;
    const __nv_bfloat16* Pl = g_x1tl + (size_t)b * HW * COUT;

    float acc[2][4][4];
#pragma unroll
    for (int i = 0; i < 2; i++)
#pragma unroll
        for (int j = 0; j < 4; j++)
#pragma unroll
            for (int r = 0; r < 4; r++) acc[i][j][r] = 0.f;

    uint4 rah[2], ral[2], rbh, rbl;
    auto loadG = [&](int it) {
        int kc = it * 32;
        int ar = t >> 1, ak = (t & 1) * 16;
        const __nv_bfloat16* sh = Qh + (size_t)(q0 + ar) * COUT + kc + ak;
        const __nv_bfloat16* sl = Ql + (size_t)(q0 + ar) * COUT + kc + ak;
        rah[0] = *reinterpret_cast<const uint4*>(sh);
        rah[1] = *reinterpret_cast<const uint4*>(sh + 8);
        ral[0] = *reinterpret_cast<const uint4*>(sl);
        ral[1] = *reinterpret_cast<const uint4*>(sl + 8);
        int br = t >> 2, bk = (t & 3) * 8;
        rbh = *reinterpret_cast<const uint4*>(Ph + (size_t)(p0 + br) * COUT + kc + bk);
        rbl = *reinterpret_cast<const uint4*>(Pl + (size_t)(p0 + br) * COUT + kc + bk);
    };
    auto storeS = [&](int buf) {
        char* base = dsm + buf * 30720;
        int ar = t >> 1, ak = (t & 1) * 16;
        *reinterpret_cast<uint4*>(base + ar * 80 + ak * 2) = rah[0];
        *reinterpret_cast<uint4*>(base + ar * 80 + ak * 2 + 16) = rah[1];
        *reinterpret_cast<uint4*>(base + 10240 + ar * 80 + ak * 2) = ral[0];
        *reinterpret_cast<uint4*>(base + 10240 + ar * 80 + ak * 2 + 16) = ral[1];
        int br = t >> 2, bk = (t & 3) * 8;
        *reinterpret_cast<uint4*>(base + 20480 + br * 80 + bk * 2) = rbh;
        *reinterpret_cast<uint4*>(base + 25600 + br * 80 + bk * 2) = rbl;
    };

    loadG(0); storeS(0); __syncthreads();

    for (int it = 0; it < 4; ++it) {
        int cur = it & 1;
        bool more = (it + 1 < 4);
        if (more) loadG(it + 1);
        const char* base = dsm + cur * 30720;
        const char* Asm = base;
        const char* Alm = base + 10240;
        const char* Bhm = base + 20480;
        const char* Blm = base + 25600;
#pragma unroll
        for (int ks = 0; ks < 2; ks++) {
            int kb = ks * 16;
            uint32_t bh[4][2], bl[4][2];
#pragma unroll
            for (int j = 0; j < 4; j++) {
                int n = nw * 32 + j * 8 + lr;
                int off = n * 80 + (kb + lc) * 2;
                bh[j][0] = *reinterpret_cast<const uint32_t*>(Bhm + off);
                bh[j][1] = *reinterpret_cast<const uint32_t*>(Bhm + off + 16);
                bl[j][0] = *reinterpret_cast<const uint32_t*>(Blm + off);
                bl[j][1] = *reinterpret_cast<const uint32_t*>(Blm + off + 16);
            }
#pragma unroll
            for (int i = 0; i < 2; i++) {
                int r = mw * 32 + i * 16 + lr;
                int off = r * 80 + (kb + lc) * 2;
                uint32_t ah[4], al[4];
                ah[0] = *reinterpret_cast<const uint32_t*>(Asm + off);
                ah[1] = *reinterpret_cast<const uint32_t*>(Asm + off + 640);
                ah[2] = *reinterpret_cast<const uint32_t*>(Asm + off + 16);
                ah[3] = *reinterpret_cast<const uint32_t*>(Asm + off + 656);
                al[0] = *reinterpret_cast<const uint32_t*>(Alm + off);
                al[1] = *reinterpret_cast<const uint32_t*>(Alm + off + 640);
                al[2] = *reinterpret_cast<const uint32_t*>(Alm + off + 16);
                al[3] = *reinterpret_cast<const uint32_t*>(Alm + off + 656);
#pragma unroll
                for (int j = 0; j < 4; j++) {
                    mma16816(acc[i][j], ah, bh[j]);
                    mma16816(acc[i][j], ah, bl[j]);
                    mma16816(acc[i][j], al, bh[j]);
                }
            }
        }
        if (more) storeS(cur ^ 1);
        __syncthreads();
    }

    float* S = g_S + (size_t)b * HW * HW;
    const float sc = 1.f / 64.f;
#pragma unroll
    for (int i = 0; i < 2; i++) {
#pragma unroll
        for (int j = 0; j < 4; j++) {
            int q = q0 + mw * 32 + i * 16 + lr;
            int p = p0 + nw * 32 + j * 8 + lc;
            float2 v0 = make_float2(acc[i][j][0] * sc, acc[i][j][1] * sc);
            float2 v1 = make_float2(acc[i][j][2] * sc, acc[i][j][3] * sc);
            *reinterpret_cast<float2*>(S + (size_t)q * HW + p) = v0;
            *reinterpret_cast<float2*>(S + (size_t)(q + 8) * HW + p) = v1;
        }
    }
}

// ---------------- row softmax; emits bf16 hi/lo probs ----------------
__global__ void __launch_bounds__(256) k_softmax() {
    const size_t row = blockIdx.x;
    const float* r = g_S + row * (size_t)HW;
    __nv_bfloat16* oh = g_Ah + row * (size_t)HW;
    __nv_bfloat16* ol = g_Al + row * (size_t)HW;
    __shared__ float buf[HW];
    __shared__ float red[256];
    int t = threadIdx.x;
    float m = -1e30f;
    for (int i = t; i < HW; i += 256) { float v = r[i]; buf[i] = v; m = fmaxf(m, v); }
    red[t] = m; __syncthreads();
    for (int s = 128; s > 0; s >>= 1) { if (t < s) red[t] = fmaxf(red[t], red[t + s]); __syncthreads(); }
    float mx = red[0]; __syncthreads();
    float s = 0.f;
    for (int i = t; i < HW; i += 256) { float e = expf(buf[i] - mx); buf[i] = e; s += e; }
    red[t] = s; __syncthreads();
    for (int o = 128; o > 0; o >>= 1) { if (t < o) red[t] += red[t + o]; __syncthreads(); }
    float inv = 1.f / red[0];
    for (int i = t; i < HW; i += 256) {
        float p = buf[i] * inv;
        __nv_bfloat16 h, l; splitf(p, h, l);
        oh[i] = h; ol[i] = l;
    }
}

// ---------------- HMMA L-GEMM: O[b,c,j] = sum_q x1[c,q]*A[q,j] + xa[c,j] ----------
__global__ void __launch_bounds__(256, 1) k_lgemm_h() {
    extern __shared__ __align__(16) char dsm[];
    const int b = blockIdx.y, j0g = blockIdx.x * 64;
    const int t = threadIdx.x, wid = t >> 5, lane = t & 31;
    const int mw = wid >> 1, nw = wid & 1;
    const int lr = lane >> 2, lc = 2 * (lane & 3);
    const __nv_bfloat16* Xh = g_x1h + (size_t)b * COUT * HW;
    const __nv_bfloat16* Xl = g_x1l + (size_t)b * COUT * HW;
    const __nv_bfloat16* Aph = g_Ah + (size_t)b * HW * HW;
    const __nv_bfloat16* Apl = g_Al + (size_t)b * HW * HW;

    float acc[2][4][4];
#pragma unroll
    for (int i = 0; i < 2; i++)
#pragma unroll
        for (int j = 0; j < 4; j++)
#pragma unroll
            for (int r = 0; r < 4; r++) acc[i][j][r] = 0.f;

    uint4 rah[2], ral[2];
    ushort4 rb[4];
    auto loadG = [&](int it) {
        int kc = it * 32;
        int ar = t >> 1, ak = (t & 1) * 16;
        const __nv_bfloat16* sh = Xh + (size_t)ar * HW + kc + ak;
        const __nv_bfloat16* sl = Xl + (size_t)ar * HW + kc + ak;
        rah[0] = *reinterpret_cast<const uint4*>(sh);
        rah[1] = *reinterpret_cast<const uint4*>(sh + 8);
        ral[0] = *reinterpret_cast<const uint4*>(sl);
        ral[1] = *reinterpret_cast<const uint4*>(sl + 8);
        int qp = t >> 4, jt = t & 15;
        size_t a0 = (size_t)(kc + 2 * qp) * HW + j0g + jt * 4;
        rb[0] = *reinterpret_cast<const ushort4*>(Aph + a0);
        rb[1] = *reinterpret_cast<const ushort4*>(Aph + a0 + HW);
        rb[2] = *reinterpret_cast<const ushort4*>(Apl + a0);
        rb[3] = *reinterpret_cast<const ushort4*>(Apl + a0 + HW);
    };
    auto storeS = [&](int buf) {
        char* base = dsm + buf * 29184;
        int ar = t >> 1, ak = (t & 1) * 16;
        *reinterpret_cast<uint4*>(base + ar * 80 + ak * 2) = rah[0];
        *reinterpret_cast<uint4*>(base + ar * 80 + ak * 2 + 16) = rah[1];
        *reinterpret_cast<uint4*>(base + 10240 + ar * 80 + ak * 2) = ral[0];
        *reinterpret_cast<uint4*>(base + 10240 + ar * 80 + ak * 2 + 16) = ral[1];
        int qp = t >> 4, jt = t & 15;
        char* bh = base + 20480;
        char* bl = base + 24832;
        int j4 = jt * 4;
        *reinterpret_cast<uint32_t*>(bh + (j4 + 0) * 68 + qp * 4) =
            (uint32_t)rb[0].x | ((uint32_t)rb[1].x << 16);
        *reinterpret_cast<uint32_t*>(bh + (j4 + 1) * 68 + qp * 4) =
            (uint32_t)rb[0].y | ((uint32_t)rb[1].y << 16);
        *reinterpret_cast<uint32_t*>(bh + (j4 + 2) * 68 + qp * 4) =
            (uint32_t)rb[0].z | ((uint32_t)rb[1].z << 16);
        *reinterpret_cast<uint32_t*>(bh + (j4 + 3) * 68 + qp * 4) =
            (uint32_t)rb[0].w | ((uint32_t)rb[1].w << 16);
        *reinterpret_cast<uint32_t*>(bl + (j4 + 0) * 68 + qp * 4) =
            (uint32_t)rb[2].x | ((uint32_t)rb[3].x << 16);
        *reinterpret_cast<uint32_t*>(bl + (j4 + 1) * 68 + qp * 4) =
            (uint32_t)rb[2].y | ((uint32_t)rb[3].y << 16);
        *reinterpret_cast<uint32_t*>(bl + (j4 + 2) * 68 + qp * 4) =
            (uint32_t)rb[2].z | ((uint32_t)rb[3].z << 16);
        *reinterpret_cast<uint32_t*>(bl + (j4 + 3) * 68 + qp * 4) =
            (uint32_t)rb[2].w | ((uint32_t)rb[3].w << 16);
    };

    loadG(0); storeS(0); __syncthreads();

    const int T = HW / 32;
    for (int it = 0; it < T; ++it) {
        int cur = it & 1;
        bool more = (it + 1 < T);
        if (more) loadG(it + 1);
        const char* base = dsm + cur * 29184;
        const char* Asm = base;
        const char* Alm = base + 10240;
        const char* Bhm = base + 20480;
        const char* Blm = base + 24832;
#pragma unroll
        for (int ks = 0; ks < 2; ks++) {
            int kb = ks * 16;
            uint32_t bh[4][2], bl[4][2];
#pragma unroll
            for (int j = 0; j < 4; j++) {
                int n = nw * 32 + j * 8 + lr;
                int off = n * 68 + (kb + lc) * 2;
                bh[j][0] = *reinterpret_cast<const uint32_t*>(Bhm + off);
                bh[j][1] = *reinterpret_cast<const uint32_t*>(Bhm + off + 16);
                bl[j][0] = *reinterpret_cast<const uint32_t*>(Blm + off);
                bl[j][1] = *reinterpret_cast<const uint32_t*>(Blm + off + 16);
            }
#pragma unroll
            for (int i = 0; i < 2; i++) {
                int r = mw * 32 + i * 16 + lr;
                int off = r * 80 + (kb + lc) * 2;
                uint32_t ah[4], al[4];
                ah[0] = *reinterpret_cast<const uint32_t*>(Asm + off);
                ah[1] = *reinterpret_cast<const uint32_t*>(Asm + off + 640);
                ah[2] = *reinterpret_cast<const uint32_t*>(Asm + off + 16);
                ah[3] = *reinterpret_cast<const uint32_t*>(Asm + off + 656);
                al[0] = *reinterpret_cast<const uint32_t*>(Alm + off);
                al[1] = *reinterpret_cast<const uint32_t*>(Alm + off + 640);
                al[2] = *reinterpret_cast<const uint32_t*>(Alm + off + 16);
                al[3] = *reinterpret_cast<const uint32_t*>(Alm + off + 656);
#pragma unroll
                for (int j = 0; j < 4; j++) {
                    mma16816(acc[i][j], ah, bh[j]);
                    mma16816(acc[i][j], ah, bl[j]);
                    mma16816(acc[i][j], al, bh[j]);
                }
            }
        }
        if (more) storeS(cur ^ 1);
        __syncthreads();
    }

    const float* xab = g_xa + (size_t)b * COUT * HW;
    float* Ob = g_O + (size_t)b * COUT * HW;
#pragma unroll
    for (int i = 0; i < 2; i++) {
#pragma unroll
        for (int j = 0; j < 4; j++) {
            int c = mw * 32 + i * 16 + lr;
            int col = j0g + nw * 32 + j * 8 + lc;
            size_t i0 = (size_t)c * HW + col;
            size_t i8 = (size_t)(c + 8) * HW + col;
            float2 x0 = *reinterpret_cast<const float2*>(xab + i0);
            float2 x8 = *reinterpret_cast<const float2*>(xab + i8);
            *reinterpret_cast<float2*>(Ob + i0) =
                make_float2(acc[i][j][0] + x0.x, acc[i][j][1] + x0.y);
            *reinterpret_cast<float2*>(Ob + i8) =
                make_float2(acc[i][j][2] + x8.x, acc[i][j][3] + x8.y);
        }
    }
}

// ---------------- FFMA pipelined GEMM (conv1 / xa / conv2) ----------------
template <int BM, int MODE>
__global__ void __launch_bounds__(256, 2) k_gemm(
    const float* __restrict__ Wg, size_t wb_stride,
    const float* __restrict__ In, size_t in_bstride,
    const float* __restrict__ P1,
    const float* __restrict__ Addp, size_t add_bstride,
    float* __restrict__ Out, size_t out_bstride,
    int Kc) {
    constexpr int TM = BM / 32;
    constexpr int NAREG = (BM == 256) ? 4 : 2;
    const int b = blockIdx.y;
    const int y = blockIdx.x;
    const int n0 = y * BN;
    const int t = threadIdx.x;
    const int ty = t >> 3, tx = t & 7;

    __shared__ __align__(16) float As[2][KT][BM];
    __shared__ __align__(16) float Bs[2][KT][BN];

    const int total = Kc / KT;
    const float* Wb = Wg + (size_t)b * wb_stride;
    const float* Inb = In + (size_t)b * in_bstride;

    ull acc2[TM][4];
#pragma unroll
    for (int i = 0; i < TM; i++)
#pragma unroll
        for (int j = 0; j < 4; j++) acc2[i][j] = 0ULL;

    float4 ra[NAREG];
    float rb[4];

    auto loadG = [&](int it) {
        int k0 = it * KT;
        if (BM == 256) {
            const float* wrow = Wb + (size_t)t * Kc + k0;
#pragma unroll
            for (int q = 0; q < 4; q++)
                ra[q] = *reinterpret_cast<const float4*>(wrow + q * 4);
        } else {
            int m = t >> 1, ko = (t & 1) * 8;
            const float* wrow = Wb + (size_t)m * Kc + k0 + ko;
#pragma unroll
            for (int q = 0; q < 2; q++)
                ra[q] = *reinterpret_cast<const float4*>(wrow + q * 4);
        }
        int k = t >> 4, nb = (t & 15) * 4;
        float4 v = *reinterpret_cast<const float4*>(Inb + (size_t)(k0 + k) * HW + n0 + nb);
        rb[0] = v.x; rb[1] = v.y; rb[2] = v.z; rb[3] = v.w;
    };
    auto storeS = [&](int buf) {
        if (BM == 256) {
#pragma unroll
            for (int q = 0; q < 4; q++) {
                As[buf][q * 4 + 0][t] = ra[q].x; As[buf][q * 4 + 1][t] = ra[q].y;
                As[buf][q * 4 + 2][t] = ra[q].z; As[buf][q * 4 + 3][t] = ra[q].w;
            }
        } else {
            int m = t >> 1, ko = (t & 1) * 8;
#pragma unroll
            for (int q = 0; q < 2; q++) {
                As[buf][ko + q * 4 + 0][m] = ra[q].x; As[buf][ko + q * 4 + 1][m] = ra[q].y;
                As[buf][ko + q * 4 + 2][m] = ra[q].z; As[buf][ko + q * 4 + 3][m] = ra[q].w;
            }
        }
        int k = t >> 4, nb = (t & 15) * 4;
        Bs[buf][k][nb] = rb[0]; Bs[buf][k][nb + 1] = rb[1];
        Bs[buf][k][nb + 2] = rb[2]; Bs[buf][k][nb + 3] = rb[3];
    };

    loadG(0);
    storeS(0);
    __syncthreads();

    for (int it = 0; it < total; ++it) {
        int cur = it & 1;
        bool more = (it + 1 < total);
        if (more) loadG(it + 1);
#pragma unroll
        for (int k = 0; k < KT; k++) {
            ull a2[TM], b2[4];
#pragma unroll
            for (int i = 0; i < TM; i += 4) {
                float4 v = *reinterpret_cast<const float4*>(&As[cur][k][ty * TM + i]);
                a2[i] = pack2f(v.x); a2[i + 1] = pack2f(v.y);
                a2[i + 2] = pack2f(v.z); a2[i + 3] = pack2f(v.w);
            }
            {
                float4 v0 = *reinterpret_cast<const float4*>(&Bs[cur][k][tx * 8]);
                float4 v1 = *reinterpret_cast<const float4*>(&Bs[cur][k][tx * 8 + 4]);
                b2[0] = pack2(v0.x, v0.y); b2[1] = pack2(v0.z, v0.w);
                b2[2] = pack2(v1.x, v1.y); b2[3] = pack2(v1.z, v1.w);
            }
#pragma unroll
            for (int i = 0; i < TM; i++)
#pragma unroll
                for (int j = 0; j < 4; j++) fma2(acc2[i][j], a2[i], b2[j]);
        }
        if (more) storeS(cur ^ 1);
        __syncthreads();
    }

    float* Ob = Out + (size_t)b * out_bstride;
#pragma unroll
    for (int i = 0; i < TM; i++) {
        int m = ty * TM + i;
        float bias = (MODE == 0) ? P1[m] : 0.f;
        const float* addrow = (MODE == 2)
            ? (Addp + (size_t)b * add_bstride + (size_t)m * HW + n0 + tx * 8)
            : nullptr;
        float o8[8];
#pragma unroll
        for (int j = 0; j < 4; j++) {
            float2 f = unpk2(acc2[i][j]);
            o8[2 * j] = f.x + bias; o8[2 * j + 1] = f.y + bias;
            if (MODE == 2) { o8[2 * j] += addrow[2 * j]; o8[2 * j + 1] += addrow[2 * j + 1]; }
        }
        float* dst = Ob + (size_t)m * HW + n0 + tx * 8;
        *reinterpret_cast<float4*>(dst) = make_float4(o8[0], o8[1], o8[2], o8[3]);
        *reinterpret_cast<float4*>(dst + 4) = make_float4(o8[4], o8[5], o8[6], o8[7]);
    }
}

// ---------------- host launch ----------------
extern "C" void kernel_launch(void* const* d_in, const int* in_sizes, int n_in,
                              void* d_out, int out_size) {
    (void)in_sizes; (void)n_in; (void)out_size;
    const float* x       = (const float*)d_in[0];
    const float* conv1_w = (const float*)d_in[1];
    const float* conv1_b = (const float*)d_in[2];
    const float* conv2_w = (const float*)d_in[3];
    const float* conv2_b = (const float*)d_in[4];
    const float* cw_w1   = (const float*)d_in[5];
    const float* cw_b1   = (const float*)d_in[6];
    const float* cw_ln_g = (const float*)d_in[7];
    const float* cw_ln_b = (const float*)d_in[8];
    const float* cw_w2   = (const float*)d_in[9];
    const float* cw_b2   = (const float*)d_in[10];
    const float* aspp0_w = (const float*)d_in[11];
    const float* aspp0_g = (const float*)d_in[12];
    const float* aspp0_b = (const float*)d_in[13];
    const float* aspp1_w = (const float*)d_in[14];
    const float* aspp1_g = (const float*)d_in[15];
    const float* aspp1_b = (const float*)d_in[16];
    const float* aspp2_w = (const float*)d_in[17];
    const float* aspp2_g = (const float*)d_in[18];
    const float* aspp2_b = (const float*)d_in[19];
    const float* aspp3_w = (const float*)d_in[20];
    const float* aspp3_g = (const float*)d_in[21];
    const float* aspp3_b = (const float*)d_in[22];
    const float* asppp_w = (const float*)d_in[23];
    const float* asppp_g = (const float*)d_in[24];
    const float* asppp_b = (const float*)d_in[25];
    const float* proj_w  = (const float*)d_in[26];
    const float* proj_g  = (const float*)d_in[27];
    const float* proj_b  = (const float*)d_in[28];

    void* pv;
    float *p_x1, *p_proj, *p_xa, *p_O;
    __nv_bfloat16 *p_xth, *p_xtl, *p_cth, *p_ctl, *p_w3h, *p_w3l, *p_a0h, *p_a0l, *p_pjh, *p_pjl;
    __nv_bfloat16 *p_x1th, *p_x1tl, *p_xath, *p_xatl, *p_x1h, *p_x1l;
    cudaGetSymbolAddress(&pv, g_x1);   p_x1   = (float*)pv;
    cudaGetSymbolAddress(&pv, g_proj); p_proj = (float*)pv;
    cudaGetSymbolAddress(&pv, g_xa);   p_xa   = (float*)pv;
    cudaGetSymbolAddress(&pv, g_O);    p_O    = (float*)pv;
    cudaGetSymbolAddress(&pv, g_xth);  p_xth  = (__nv_bfloat16*)pv;
    cudaGetSymbolAddress(&pv, g_xtl);  p_xtl  = (__nv_bfloat16*)pv;
    cudaGetSymbolAddress(&pv, g_cth);  p_cth  = (__nv_bfloat16*)pv;
    cudaGetSymbolAddress(&pv, g_ctl);  p_ctl  = (__nv_bfloat16*)pv;
    cudaGetSymbolAddress(&pv, g_w3h);  p_w3h  = (__nv_bfloat16*)pv;
    cudaGetSymbolAddress(&pv, g_w3l);  p_w3l  = (__nv_bfloat16*)pv;
    cudaGetSymbolAddress(&pv, g_a0h);  p_a0h  = (__nv_bfloat16*)pv;
    cudaGetSymbolAddress(&pv, g_a0l);  p_a0l  = (__nv_bfloat16*)pv;
    cudaGetSymbolAddress(&pv, g_pjh);  p_pjh  = (__nv_bfloat16*)pv;
    cudaGetSymbolAddress(&pv, g_pjl);  p_pjl  = (__nv_bfloat16*)pv;
    cudaGetSymbolAddress(&pv, g_x1th); p_x1th = (__nv_bfloat16*)pv;
    cudaGetSymbolAddress(&pv, g_x1tl); p_x1tl = (__nv_bfloat16*)pv;
    cudaGetSymbolAddress(&pv, g_xath); p_xath = (__nv_bfloat16*)pv;
    cudaGetSymbolAddress(&pv, g_xatl); p_xatl = (__nv_bfloat16*)pv;
    cudaGetSymbolAddress(&pv, g_x1h);  p_x1h  = (__nv_bfloat16*)pv;
    cudaGetSymbolAddress(&pv, g_x1l);  p_x1l  = (__nv_bfloat16*)pv;

    const int TG_SMEM = 135168;   // max(2x61440 mainloop, 256x129x4 = 132096 epilogue)
    cudaFuncSetAttribute(k_hgemm<false, true>, cudaFuncAttributeMaxDynamicSharedMemorySize, TG_SMEM);
    cudaFuncSetAttribute(k_hgemm<true, true>, cudaFuncAttributeMaxDynamicSharedMemorySize, TG_SMEM);
    cudaFuncSetAttribute(k_hgemm<false, false>, cudaFuncAttributeMaxDynamicSharedMemorySize, TG_SMEM);
    cudaFuncSetAttribute(k_sgemm_h, cudaFuncAttributeMaxDynamicSharedMemorySize, 61440);
    cudaFuncSetAttribute(k_lgemm_h, cudaFuncAttributeMaxDynamicSharedMemorySize, 58368);

    dim3 g64(HW / BN, BATCH);
    dim3 gh(HW / 128, BATCH);

    // 1-3: prep (launch #4 = aspp0 HMMA gets profiled)
    k_prep<<<3328, 256>>>(aspp1_w, aspp2_w, aspp3_w, aspp0_w, proj_w, x);
    k_cw<<<BATCH, 256>>>(cw_w1, cw_b1, cw_ln_g, cw_ln_b, cw_w2, cw_b2,
                         asppp_w, asppp_g, asppp_b);
    k_xcsplit<<<dim3(128, 8, BATCH), 256>>>(x);
    // 4-7: ASPP branches (HMMA, cp.async 256x128 tiles)
    k_hgemm<false, true><<<gh, 512, TG_SMEM>>>(p_a0h, p_a0l, p_xth, p_xtl,
        aspp0_g, aspp0_b, nullptr, p_cth, p_ctl, 0, CIN, 0);
    k_hgemm<true, true><<<gh, 512, TG_SMEM>>>(p_w3h + 0 * 9 * 65536, p_w3l + 0 * 9 * 65536,
        p_xth, p_xtl, aspp1_g, aspp1_b, nullptr, p_cth, p_ctl, 256, CIN, 3);
    k_hgemm<true, true><<<gh, 512, TG_SMEM>>>(p_w3h + 1 * 9 * 65536, p_w3l + 1 * 9 * 65536,
        p_xth, p_xtl, aspp2_g, aspp2_b, nullptr, p_cth, p_ctl, 512, CIN, 6);
    k_hgemm<true, true><<<gh, 512, TG_SMEM>>>(p_w3h + 2 * 9 * 65536, p_w3l + 2 * 9 * 65536,
        p_xth, p_xtl, aspp3_g, aspp3_b, nullptr, p_cth, p_ctl, 768, CIN, 9);
    // 8: global-pool branch into catT
    k_bp_cat<<<dim3(128, BATCH), 256>>>();
    // 9: proj (HMMA, K=1280) -> f32
    k_hgemm<false, false><<<gh, 512, TG_SMEM>>>(p_pjh, p_pjl, p_cth, p_ctl,
        proj_g, proj_b, p_proj, nullptr, nullptr, 0, 5 * CIN, 0);
    // 10-11: conv1 twice (FFMA)
    k_gemm<128, 0><<<g64, 256>>>(conv1_w, 0, x, (size_t)CIN * HW, conv1_b,
                                 nullptr, 0, p_x1, (size_t)COUT * HW, CIN);
    k_gemm<128, 0><<<g64, 256>>>(conv1_w, 0, p_proj, (size_t)CIN * HW, conv1_b,
                                 nullptr, 0, p_xa, (size_t)COUT * HW, CIN);
    // 12-13: split x1 (straight + T), xa (T)
    k_splitT<true><<<dim3(128, 4, BATCH), 256>>>(p_x1, p_x1th, p_x1tl, p_x1h, p_x1l);
    k_splitT<false><<<dim3(128, 4, BATCH), 256>>>(p_xa, p_xath, p_xatl, nullptr, nullptr);
    // 14-16: attention (HMMA S, softmax->bf16, HMMA L with +xa)
    k_sgemm_h<<<dim3(64, 32, BATCH), 256, 61440>>>();
    k_softmax<<<BATCH * HW, 256>>>();
    k_lgemm_h<<<dim3(64, BATCH), 256, 58368>>>();
    // 17: out = conv2(O) + b (FFMA)
    k_gemm<256, 0><<<g64, 256>>>(conv2_w, 0, p_O, (size_t)COUT * HW, conv2_b,
                                 nullptr, 0, (float*)d_out, (size_t)CIN * HW, COUT);
}

// round 9
// speedup vs baseline: 2.3913x; 1.0561x over previous
#include <cuda_runtime.h>
#include <cuda_bf16.h>
#include <math.h>
#include <stdint.h>

#define BATCH 4
#define CIN 256
#define COUT 128
#define HH 64
#define WW 64
#define HW 4096
#define BN 64
#define KT 16

typedef unsigned long long ull;

// ---------------- scratch (static device globals; no allocs) ----------------
__device__ float g_x1[BATCH * COUT * HW];
__device__ float g_proj[BATCH * CIN * HW];
__device__ float g_xa[BATCH * COUT * HW];
__device__ float g_S[(size_t)BATCH * HW * HW];
__device__ float g_avg[BATCH * CIN];
__device__ float g_mx[BATCH * CIN];
__device__ float g_s[BATCH * CIN];
__device__ float g_bp[BATCH * CIN];
// bf16 split operands
__device__ __nv_bfloat16 g_xth[BATCH * HW * CIN];              // xcT hi  [b][hw][c]
__device__ __nv_bfloat16 g_xtl[BATCH * HW * CIN];              // xcT lo
__device__ __nv_bfloat16 g_cth[(size_t)BATCH * HW * 5 * CIN];  // catT hi [b][hw][1280]
__device__ __nv_bfloat16 g_ctl[(size_t)BATCH * HW * 5 * CIN];  // catT lo
__device__ __nv_bfloat16 g_w3h[3 * 9 * CIN * CIN];             // [conv][tap][m][c]
__device__ __nv_bfloat16 g_w3l[3 * 9 * CIN * CIN];
__device__ __nv_bfloat16 g_a0h[CIN * CIN];
__device__ __nv_bfloat16 g_a0l[CIN * CIN];
__device__ __nv_bfloat16 g_pjh[CIN * 5 * CIN];
__device__ __nv_bfloat16 g_pjl[CIN * 5 * CIN];
__device__ __nv_bfloat16 g_c2h[CIN * COUT];                    // conv2 weights split
__device__ __nv_bfloat16 g_c2l[CIN * COUT];
// attention operands
__device__ __nv_bfloat16 g_x1th[BATCH * HW * COUT];  // x1T hi [b][hw][c]
__device__ __nv_bfloat16 g_x1tl[BATCH * HW * COUT];
__device__ __nv_bfloat16 g_xath[BATCH * HW * COUT];  // xaT hi [b][hw][c]
__device__ __nv_bfloat16 g_xatl[BATCH * HW * COUT];
__device__ __nv_bfloat16 g_x1h[BATCH * COUT * HW];   // x1 straight split [b][c][hw]
__device__ __nv_bfloat16 g_x1l[BATCH * COUT * HW];
__device__ __nv_bfloat16 g_Ah[(size_t)BATCH * HW * HW];  // softmax probs hi [b][q][p]
__device__ __nv_bfloat16 g_Al[(size_t)BATCH * HW * HW];
__device__ __nv_bfloat16 g_oth[BATCH * HW * COUT];   // OT hi [b][hw][c] (L-gemm out)
__device__ __nv_bfloat16 g_otl[BATCH * HW * COUT];

__device__ __forceinline__ float gelu_f(float x) {
    return 0.5f * x * (1.0f + erff(x * 0.70710678118654752440f));
}
__device__ __forceinline__ void splitf(float v, __nv_bfloat16& h, __nv_bfloat16& l) {
    h = __float2bfloat16(v);
    l = __float2bfloat16(v - __bfloat162float(h));
}

// ---------------- HMMA m16n8k16 bf16 ----------------
__device__ __forceinline__ void mma16816(float* d, const uint32_t* a, const uint32_t* b) {
    asm volatile(
        "mma.sync.aligned.m16n8k16.row.col.f32.bf16.bf16.f32 "
        "{%0,%1,%2,%3}, {%4,%5,%6,%7}, {%8,%9}, {%0,%1,%2,%3};"
        : "+f"(d[0]), "+f"(d[1]), "+f"(d[2]), "+f"(d[3])
        : "r"(a[0]), "r"(a[1]), "r"(a[2]), "r"(a[3]), "r"(b[0]), "r"(b[1]));
}
__device__ __forceinline__ void ldsm_x4(uint32_t* r, uint32_t addr) {
    asm volatile("ldmatrix.sync.aligned.m8n8.x4.shared.b16 {%0,%1,%2,%3}, [%4];"
                 : "=r"(r[0]), "=r"(r[1]), "=r"(r[2]), "=r"(r[3]) : "r"(addr));
}
__device__ __forceinline__ void ldsm_x2(uint32_t* r, uint32_t addr) {
    asm volatile("ldmatrix.sync.aligned.m8n8.x2.shared.b16 {%0,%1}, [%2];"
                 : "=r"(r[0]), "=r"(r[1]) : "r"(addr));
}

// ---------------- cp.async helpers ----------------
__device__ __forceinline__ void cp16(uint32_t d, const void* s, int ssz) {
    asm volatile("cp.async.ca.shared.global [%0], [%1], 16, %2;"
                 :: "r"(d), "l"(s), "r"(ssz) : "memory");
}
#define CP_COMMIT() asm volatile("cp.async.commit_group;" ::: "memory")
#define CP_WAIT1()  asm volatile("cp.async.wait_group 1;" ::: "memory")
#define CP_WAIT0()  asm volatile("cp.async.wait_group 0;" ::: "memory")

// ---------------- packed helpers for FFMA path ----------------
__device__ __forceinline__ ull pack2f(float x) {
    ull r; asm("mov.b64 %0, {%1, %1};" : "=l"(r) : "f"(x)); return r;
}
__device__ __forceinline__ ull pack2(float x, float y) {
    ull r; asm("mov.b64 %0, {%1, %2};" : "=l"(r) : "f"(x), "f"(y)); return r;
}
__device__ __forceinline__ void fma2(ull& d, ull a, ull b) {
    asm("fma.rn.f32x2 %0, %1, %2, %0;" : "+l"(d) : "l"(a), "l"(b));
}
__device__ __forceinline__ float2 unpk2(ull v) {
    float2 f; asm("mov.b64 {%0, %1}, %2;" : "=f"(f.x), "=f"(f.y) : "l"(v)); return f;
}

// ---------------- prep: weight split/transpose + per-(b,c) stats ----------------
__global__ void k_prep(const float* __restrict__ w1, const float* __restrict__ w2,
                       const float* __restrict__ w3, const float* __restrict__ a0,
                       const float* __restrict__ pj, const float* __restrict__ c2,
                       const float* __restrict__ x) {
    if (blockIdx.x < 2432) {
        int e = blockIdx.x * 256 + threadIdx.x;
        if (e < 196608) {
            const float* srcs[3] = { w1, w2, w3 };
            int conv = e >> 16, mc = e & 65535, m = mc >> 8, c = mc & 255;
            const float* src = srcs[conv] + (size_t)m * 2304 + (size_t)c * 9;
            size_t dbase = (size_t)conv * 9 * 65536 + (size_t)m * 256 + c;
#pragma unroll
            for (int tap = 0; tap < 9; tap++) {
                __nv_bfloat16 h, l; splitf(src[tap], h, l);
                g_w3h[dbase + (size_t)tap * 65536] = h;
                g_w3l[dbase + (size_t)tap * 65536] = l;
            }
        } else if (e < 262144) {
            int i = e - 196608;
            __nv_bfloat16 h, l; splitf(a0[i], h, l);
            g_a0h[i] = h; g_a0l[i] = l;
        } else if (e < 589824) {
            int i = e - 262144;
            __nv_bfloat16 h, l; splitf(pj[i], h, l);
            g_pjh[i] = h; g_pjl[i] = l;
        } else if (e < 622592) {
            int i = e - 589824;
            __nv_bfloat16 h, l; splitf(c2[i], h, l);
            g_c2h[i] = h; g_c2l[i] = l;
        }
    } else {
        int bc = blockIdx.x - 2432;
        const float* p = x + (size_t)bc * HW;
        int t = threadIdx.x;
        float s = 0.f, m = -1e30f;
        for (int i = t; i < HW; i += 256) { float v = p[i]; s += v; m = fmaxf(m, v); }
        __shared__ float ss[256], sm[256];
        ss[t] = s; sm[t] = m; __syncthreads();
        for (int o = 128; o > 0; o >>= 1) {
            if (t < o) { ss[t] += ss[t + o]; sm[t] = fmaxf(sm[t], sm[t + o]); }
            __syncthreads();
        }
        if (t == 0) { g_avg[bc] = ss[0] * (1.f / HW); g_mx[bc] = sm[0]; }
    }
}

// ---------------- channel weighting MLP + global-pool ASPP branch ----------------
__global__ void k_cw(const float* __restrict__ w1, const float* __restrict__ bb1,
                     const float* __restrict__ lg, const float* __restrict__ lb,
                     const float* __restrict__ w2, const float* __restrict__ bb2,
                     const float* __restrict__ apw, const float* __restrict__ apg,
                     const float* __restrict__ apb) {
    int b = blockIdx.x, t = threadIdx.x;
    __shared__ float o[CIN];
    __shared__ float h[COUT];
    __shared__ float red[256];
    __shared__ float gp[CIN];
    float avg = g_avg[b * CIN + t], mx = g_mx[b * CIN + t];
    o[t] = fabsf(avg - mx) * avg;
    __syncthreads();
    float hv = 0.f;
    if (t < COUT) {
        hv = bb1[t];
        const float* wr = w1 + t * CIN;
        for (int i = 0; i < CIN; i++) hv = fmaf(o[i], wr[i], hv);
    }
    red[t] = (t < COUT) ? hv : 0.f; __syncthreads();
    for (int s = 128; s > 0; s >>= 1) { if (t < s) red[t] += red[t + s]; __syncthreads(); }
    float mu = red[0] * (1.f / COUT); __syncthreads();
    float dv = (t < COUT) ? (hv - mu) : 0.f;
    red[t] = dv * dv; __syncthreads();
    for (int s = 128; s > 0; s >>= 1) { if (t < s) red[t] += red[t + s]; __syncthreads(); }
    float var = red[0] * (1.f / COUT); __syncthreads();
    if (t < COUT) h[t] = lg[t] * ((hv - mu) * rsqrtf(var + 1e-5f)) + lb[t];
    __syncthreads();
    float sv = bb2[t];
    const float* wr2 = w2 + t * COUT;
    for (int j = 0; j < COUT; j++) sv = fmaf(h[j], wr2[j], sv);
    float sig = 1.f / (1.f + expf(-sv));
    g_s[b * CIN + t] = sig;
    gp[t] = (1.f + sig) * avg;
    __syncthreads();
    float v = 0.f;
    const float* ar = apw + t * CIN;
    for (int i = 0; i < CIN; i++) v = fmaf(ar[i], gp[i], v);
    red[t] = v; __syncthreads();
    for (int s = 128; s > 0; s >>= 1) { if (t < s) red[t] += red[t + s]; __syncthreads(); }
    float mu2 = red[0] * (1.f / CIN); __syncthreads();
    float d2 = v - mu2; red[t] = d2 * d2; __syncthreads();
    for (int s = 128; s > 0; s >>= 1) { if (t < s) red[t] += red[t + s]; __syncthreads(); }
    float var2 = red[0] * (1.f / CIN); __syncthreads();
    float z = apg[t] * ((v - mu2) * rsqrtf(var2 + 1e-6f)) + apb[t];
    g_bp[b * CIN + t] = gelu_f(z);
}

// ---------------- xcT split: x[b][c][hw]*(1+s) -> bf16 hi/lo [b][hw][c] ----------------
__global__ void k_xcsplit(const float* __restrict__ x) {
    __shared__ float tile[32][33];
    int b = blockIdx.z, c0 = blockIdx.y * 32, h0 = blockIdx.x * 32;
    int t = threadIdx.x;
    const float* xb = x + ((size_t)b * CIN + c0) * HW + h0;
#pragma unroll
    for (int i = 0; i < 4; i++) {
        int r = (t >> 5) + 8 * i;
        tile[r][t & 31] = xb[(size_t)r * HW + (t & 31)];
    }
    __syncthreads();
#pragma unroll
    for (int i = 0; i < 4; i++) {
        int hr = (t >> 5) + 8 * i, cc = t & 31;
        float v = tile[cc][hr] * (1.f + g_s[b * CIN + c0 + cc]);
        __nv_bfloat16 h, l; splitf(v, h, l);
        size_t idx = ((size_t)b * HW + h0 + hr) * CIN + c0 + cc;
        g_xth[idx] = h; g_xtl[idx] = l;
    }
}

// ---------------- split/transpose for 128-channel fp32 maps ----------------
template <bool STRAIGHT>
__global__ void k_splitT(const float* __restrict__ in,
                         __nv_bfloat16* __restrict__ th, __nv_bfloat16* __restrict__ tl,
                         __nv_bfloat16* __restrict__ sh, __nv_bfloat16* __restrict__ sl) {
    __shared__ float tile[32][33];
    int b = blockIdx.z, c0 = blockIdx.y * 32, h0 = blockIdx.x * 32;
    int t = threadIdx.x;
    const float* ib = in + ((size_t)b * COUT + c0) * HW + h0;
#pragma unroll
    for (int i = 0; i < 4; i++) {
        int r = (t >> 5) + 8 * i, col = t & 31;
        float v = ib[(size_t)r * HW + col];
        tile[r][col] = v;
        if (STRAIGHT) {
            __nv_bfloat16 h, l; splitf(v, h, l);
            size_t idx = ((size_t)b * COUT + c0 + r) * HW + h0 + col;
            sh[idx] = h; sl[idx] = l;
        }
    }
    __syncthreads();
#pragma unroll
    for (int i = 0; i < 4; i++) {
        int hr = (t >> 5) + 8 * i, cc = t & 31;
        float v = tile[cc][hr];
        __nv_bfloat16 h, l; splitf(v, h, l);
        size_t idx = ((size_t)b * HW + h0 + hr) * COUT + c0 + cc;
        th[idx] = h; tl[idx] = l;
    }
}

// ---------------- bp broadcast into catT channels [1024,1280) ----------------
__global__ void k_bp_cat() {
    int b = blockIdx.y, h0 = blockIdx.x * 32;
    int c = threadIdx.x;
    __nv_bfloat16 h, l; splitf(g_bp[b * CIN + c], h, l);
    for (int r = 0; r < 32; r++) {
        size_t idx = ((size_t)b * HW + h0 + r) * 1280 + 1024 + c;
        g_cth[idx] = h; g_ctl[idx] = l;
    }
}

// ---------------- HMMA bf16x2-split GEMM, 256x128 tile, 512 thr ----------
// EPI 0: LN+GELU -> catT bf16 split;  EPI 1: LN+GELU -> f32 [m][hw];
// EPI 2: +bias(gam) -> f32 [m][hw].
// Per buf (61440B): Ah 0, Al 20480, Bh 40960, Bl 51200. Epilogue Ds 256x129 f32.
template <bool CONV3, int EPI>
__global__ void __launch_bounds__(512, 1) k_hgemm(
    const __nv_bfloat16* __restrict__ Whi, const __nv_bfloat16* __restrict__ Wlo,
    const __nv_bfloat16* __restrict__ Ihi, const __nv_bfloat16* __restrict__ Ilo,
    const float* __restrict__ gam, const float* __restrict__ bet,
    float* __restrict__ outF, __nv_bfloat16* __restrict__ cth, __nv_bfloat16* __restrict__ ctl,
    int coff, int Kc, int dil) {
    extern __shared__ __align__(16) char dsm[];
    __shared__ int s_tapn, s_tp[9], s_dy[9], s_dx[9];
    __shared__ float sgam[256], sbet[256], smean[128], srstd[128];
    __shared__ float red4[4][128];

    const int b = blockIdx.y, y = blockIdx.x;       // y: 128-wide spatial tile (2 rows)
    const int t = threadIdx.x, wid = t >> 5, lane = t & 31;
    const int mw = wid >> 2, nw = wid & 3;
    const uint32_t sbase = (uint32_t)__cvta_generic_to_shared(dsm);

    if (CONV3 && t == 0) {
        int n = 0;
        for (int tap = 0; tap < 9; tap++) {
            int dy = (tap / 3 - 1) * dil;
            int y0 = y * 2 + dy, y1 = y * 2 + 1 + dy;
            if ((unsigned)y0 < 64u || (unsigned)y1 < 64u) {
                s_tp[n] = tap; s_dy[n] = dy; s_dx[n] = (tap % 3 - 1) * dil; n++;
            }
        }
        s_tapn = n;
    }
    if (t < 256) { sgam[t] = gam[t]; sbet[t] = bet[t]; }
    __syncthreads();

    const int nkc = Kc / 32;
    const int T = CONV3 ? s_tapn * nkc : nkc;
    const __nv_bfloat16* Ib_hi = Ihi + (size_t)b * HW * Kc;
    const __nv_bfloat16* Ib_lo = Ilo + (size_t)b * HW * Kc;

    float acc[4][4][4];
#pragma unroll
    for (int i = 0; i < 4; i++)
#pragma unroll
        for (int j = 0; j < 4; j++)
#pragma unroll
            for (int r = 0; r < 4; r++) acc[i][j][r] = 0.f;

    // ---- async G->S tile load (6 x cp16 per thread) ----
    auto loadG = [&](int it, int buf) {
        int tap_i = CONV3 ? (it / nkc) : 0;
        int kc = (CONV3 ? (it - tap_i * nkc) : it) * 32;
        uint32_t base = sbase + buf * 61440;
        int arow = t >> 1, ak = (t & 1) * 16;
        int grow = CONV3 ? (s_tp[tap_i] * 256 + arow) : arow;
        const __nv_bfloat16* ah = Whi + (size_t)grow * Kc + kc + ak;
        const __nv_bfloat16* al = Wlo + (size_t)grow * Kc + kc + ak;
        uint32_t da = base + arow * 80 + ak * 2;
        cp16(da, ah, 16);
        cp16(da + 16, ah + 8, 16);
        cp16(da + 20480, al, 16);
        cp16(da + 20480 + 16, al + 8, 16);
        int n = t >> 2, q = t & 3;
        int hw; int ok = 16;
        if (CONV3) {
            int yy = y * 2 + (n >> 6) + s_dy[tap_i];
            int xx = (n & 63) + s_dx[tap_i];
            if ((unsigned)yy < 64u && (unsigned)xx < 64u) hw = yy * 64 + xx;
            else { hw = 0; ok = 0; }
        } else hw = y * 128 + n;
        uint32_t db = base + 40960 + n * 80 + q * 16;
        cp16(db, Ib_hi + (size_t)hw * Kc + kc + q * 8, ok);
        cp16(db + 10240, Ib_lo + (size_t)hw * Kc + kc + q * 8, ok);
        CP_COMMIT();
    };

    loadG(0, 0);
    if (T > 1) loadG(1, 1);

    const int lr = lane >> 2, lc = 2 * (lane & 3);
    // ldmatrix per-lane address offsets
    const uint32_t a_loff = (uint32_t)(((lane & 7) + ((lane >> 3) & 1) * 8) * 80
                                       + (lane >> 4) * 16);
    const uint32_t b_loff = (uint32_t)((lane & 7) * 80 + ((lane >> 3) & 1) * 16);
    const uint32_t a_wbase = (uint32_t)(mw * 64 * 80) + a_loff;
    const uint32_t b_wbase = 40960u + (uint32_t)(nw * 32 * 80) + b_loff;

    for (int it = 0; it < T; ++it) {
        int cur = it & 1;
        if (it + 1 < T) CP_WAIT1(); else CP_WAIT0();
        __syncthreads();
        uint32_t sb = sbase + cur * 61440;
#pragma unroll
        for (int ks = 0; ks < 2; ks++) {
            uint32_t kboff = ks * 32;
            uint32_t bh[4][2], bl[4][2];
#pragma unroll
            for (int j = 0; j < 4; j++) {
                uint32_t ba = sb + b_wbase + j * (8 * 80) + kboff;
                ldsm_x2(bh[j], ba);
                ldsm_x2(bl[j], ba + 10240);
            }
#pragma unroll
            for (int i = 0; i < 4; i++) {
                uint32_t aa = sb + a_wbase + i * (16 * 80) + kboff;
                uint32_t ah[4], al[4];
                ldsm_x4(ah, aa);
                ldsm_x4(al, aa + 20480);
#pragma unroll
                for (int j = 0; j < 4; j++) {
                    mma16816(acc[i][j], ah, bh[j]);
                    mma16816(acc[i][j], ah, bl[j]);
                    mma16816(acc[i][j], al, bh[j]);
                }
            }
        }
        __syncthreads();
        if (it + 2 < T) loadG(it + 2, cur);
    }

    // ---- stage D (256x128 fp32) into smem, pitch 129
    float* Ds = reinterpret_cast<float*>(dsm);
#pragma unroll
    for (int i = 0; i < 4; i++) {
        int r0 = mw * 64 + i * 16 + lr;
#pragma unroll
        for (int j = 0; j < 4; j++) {
            int c = nw * 32 + j * 8 + lc;
            Ds[r0 * 129 + c] = acc[i][j][0];
            Ds[r0 * 129 + c + 1] = acc[i][j][1];
            Ds[(r0 + 8) * 129 + c] = acc[i][j][2];
            Ds[(r0 + 8) * 129 + c + 1] = acc[i][j][3];
        }
    }
    __syncthreads();
    if (EPI != 2) {
        int n = t & 127, p = t >> 7;
        float s = 0.f;
        for (int mm = p * 64; mm < p * 64 + 64; mm++) s += Ds[mm * 129 + n];
        red4[p][n] = s;
        __syncthreads();
        if (t < 128)
            smean[t] = (red4[0][t] + red4[1][t] + red4[2][t] + red4[3][t]) * (1.f / 256.f);
        __syncthreads();
        float mu = smean[n];
        s = 0.f;
        for (int mm = p * 64; mm < p * 64 + 64; mm++) {
            float d = Ds[mm * 129 + n] - mu; s += d * d;
        }
        red4[p][n] = s;
        __syncthreads();
        if (t < 128)
            srstd[t] = rsqrtf((red4[0][t] + red4[1][t] + red4[2][t] + red4[3][t]) * (1.f / 256.f) + 1e-6f);
        __syncthreads();
    }
    if (EPI == 0) {
        int n2 = t >> 2, m0q = (t & 3) * 64;
        float mu = smean[n2], rs = srstd[n2];
        size_t rowb = ((size_t)b * HW + y * 128 + n2) * 1280 + coff + m0q;
#pragma unroll
        for (int blk = 0; blk < 64; blk += 8) {
            __align__(16) unsigned short h8[8], l8[8];
#pragma unroll
            for (int j = 0; j < 8; j++) {
                int m = m0q + blk + j;
                float vv = gelu_f((Ds[m * 129 + n2] - mu) * rs * sgam[m] + sbet[m]);
                __nv_bfloat16 h, l; splitf(vv, h, l);
                h8[j] = *reinterpret_cast<unsigned short*>(&h);
                l8[j] = *reinterpret_cast<unsigned short*>(&l);
            }
            *reinterpret_cast<uint4*>(cth + rowb + blk) = *reinterpret_cast<uint4*>(h8);
            *reinterpret_cast<uint4*>(ctl + rowb + blk) = *reinterpret_cast<uint4*>(l8);
        }
    } else if (EPI == 1) {
        int m = t >> 1, nh = (t & 1) * 64;
        float gmm = sgam[m], bt2 = sbet[m];
        size_t ob = ((size_t)b * CIN + m) * HW + y * 128 + nh;
#pragma unroll
        for (int blk = 0; blk < 64; blk += 4) {
            float4 v4;
            float* vp = &v4.x;
#pragma unroll
            for (int j = 0; j < 4; j++) {
                int n3 = nh + blk + j;
                vp[j] = gelu_f((Ds[m * 129 + n3] - smean[n3]) * srstd[n3] * gmm + bt2);
            }
            *reinterpret_cast<float4*>(outF + ob + blk) = v4;
        }
    } else {
        int m = t >> 1, nh = (t & 1) * 64;
        float bias = sgam[m];
        size_t ob = ((size_t)b * CIN + m) * HW + y * 128 + nh;
#pragma unroll
        for (int blk = 0; blk < 64; blk += 4) {
            float4 v4;
            float* vp = &v4.x;
#pragma unroll
            for (int j = 0; j < 4; j++) vp[j] = Ds[m * 129 + nh + blk + j] + bias;
            *reinterpret_cast<float4*>(outF + ob + blk) = v4;
        }
    }
}

// ---------------- HMMA S-GEMM: S[b,q,p] = (1/64) sum_c xaT[q,c] * x1T[p,c] ----------
__global__ void __launch_bounds__(256, 1) k_sgemm_h() {
    extern __shared__ __align__(16) char dsm[];
    const int b = blockIdx.z, q0 = blockIdx.y * 128, p0 = blockIdx.x * 64;
    const int t = threadIdx.x, wid = t >> 5, lane = t & 31;
    const int mw = wid >> 1, nw = wid & 1;
    const int lr = lane >> 2, lc = 2 * (lane & 3);
    const __nv_bfloat16* Qh = g_xath + (size_t)b * HW * COUT;
    const __nv_bfloat16* Ql = g_xatl + (size_t)b * HW * COUT;
    const __nv_bfloat16* Ph = g_x1th + (size_t)b * HW * COUT;
    const __nv_bfloat16* Pl = g_x1tl + (size_t)b * HW * COUT;

    float acc[2][4][4];
#pragma unroll
    for (int i = 0; i < 2; i++)
#pragma unroll
        for (int j = 0; j < 4; j++)
#pragma unroll
            for (int r = 0; r < 4; r++) acc[i][j][r] = 0.f;

    uint4 rah[2], ral[2], rbh, rbl;
    auto loadG = [&](int it) {
        int kc = it * 32;
        int ar = t >> 1, ak = (t & 1) * 16;
        const __nv_bfloat16* sh = Qh + (size_t)(q0 + ar) * COUT + kc + ak;
        const __nv_bfloat16* sl = Ql + (size_t)(q0 + ar) * COUT + kc + ak;
        rah[0] = *reinterpret_cast<const uint4*>(sh);
        rah[1] = *reinterpret_cast<const uint4*>(sh + 8);
        ral[0] = *reinterpret_cast<const uint4*>(sl);
        ral[1] = *reinterpret_cast<const uint4*>(sl + 8);
        int br = t >> 2, bk = (t & 3) * 8;
        rbh = *reinterpret_cast<const uint4*>(Ph + (size_t)(p0 + br) * COUT + kc + bk);
        rbl = *reinterpret_cast<const uint4*>(Pl + (size_t)(p0 + br) * COUT + kc + bk);
    };
    auto storeS = [&](int buf) {
        char* base = dsm + buf * 30720;
        int ar = t >> 1, ak = (t & 1) * 16;
        *reinterpret_cast<uint4*>(base + ar * 80 + ak * 2) = rah[0];
        *reinterpret_cast<uint4*>(base + ar * 80 + ak * 2 + 16) = rah[1];
        *reinterpret_cast<uint4*>(base + 10240 + ar * 80 + ak * 2) = ral[0];
        *reinterpret_cast<uint4*>(base + 10240 + ar * 80 + ak * 2 + 16) = ral[1];
        int br = t >> 2, bk = (t & 3) * 8;
        *reinterpret_cast<uint4*>(base + 20480 + br * 80 + bk * 2) = rbh;
        *reinterpret_cast<uint4*>(base + 25600 + br * 80 + bk * 2) = rbl;
    };

    loadG(0); storeS(0); __syncthreads();

    for (int it = 0; it < 4; ++it) {
        int cur = it & 1;
        bool more = (it + 1 < 4);
        if (more) loadG(it + 1);
        const char* base = dsm + cur * 30720;
        const char* Asm = base;
        const char* Alm = base + 10240;
        const char* Bhm = base + 20480;
        const char* Blm = base + 25600;
#pragma unroll
        for (int ks = 0; ks < 2; ks++) {
            int kb = ks * 16;
            uint32_t bh[4][2], bl[4][2];
#pragma unroll
            for (int j = 0; j < 4; j++) {
                int n = nw * 32 + j * 8 + lr;
                int off = n * 80 + (kb + lc) * 2;
                bh[j][0] = *reinterpret_cast<const uint32_t*>(Bhm + off);
                bh[j][1] = *reinterpret_cast<const uint32_t*>(Bhm + off + 16);
                bl[j][0] = *reinterpret_cast<const uint32_t*>(Blm + off);
                bl[j][1] = *reinterpret_cast<const uint32_t*>(Blm + off + 16);
            }
#pragma unroll
            for (int i = 0; i < 2; i++) {
                int r = mw * 32 + i * 16 + lr;
                int off = r * 80 + (kb + lc) * 2;
                uint32_t ah[4], al[4];
                ah[0] = *reinterpret_cast<const uint32_t*>(Asm + off);
                ah[1] = *reinterpret_cast<const uint32_t*>(Asm + off + 640);
                ah[2] = *reinterpret_cast<const uint32_t*>(Asm + off + 16);
                ah[3] = *reinterpret_cast<const uint32_t*>(Asm + off + 656);
                al[0] = *reinterpret_cast<const uint32_t*>(Alm + off);
                al[1] = *reinterpret_cast<const uint32_t*>(Alm + off + 640);
                al[2] = *reinterpret_cast<const uint32_t*>(Alm + off + 16);
                al[3] = *reinterpret_cast<const uint32_t*>(Alm + off + 656);
#pragma unroll
                for (int j = 0; j < 4; j++) {
                    mma16816(acc[i][j], ah, bh[j]);
                    mma16816(acc[i][j], ah, bl[j]);
                    mma16816(acc[i][j], al, bh[j]);
                }
            }
        }
        if (more) storeS(cur ^ 1);
        __syncthreads();
    }

    float* S = g_S + (size_t)b * HW * HW;
    const float sc = 1.f / 64.f;
#pragma unroll
    for (int i = 0; i < 2; i++) {
#pragma unroll
        for (int j = 0; j < 4; j++) {
            int q = q0 + mw * 32 + i * 16 + lr;
            int p = p0 + nw * 32 + j * 8 + lc;
            float2 v0 = make_float2(acc[i][j][0] * sc, acc[i][j][1] * sc);
            float2 v1 = make_float2(acc[i][j][2] * sc, acc[i][j][3] * sc);
            *reinterpret_cast<float2*>(S + (size_t)q * HW + p) = v0;
            *reinterpret_cast<float2*>(S + (size_t)(q + 8) * HW + p) = v1;
        }
    }
}

// ---------------- row softmax; emits bf16 hi/lo probs ----------------
__global__ void __launch_bounds__(256) k_softmax() {
    const size_t row = blockIdx.x;
    const float* r = g_S + row * (size_t)HW;
    __nv_bfloat16* oh = g_Ah + row * (size_t)HW;
    __nv_bfloat16* ol = g_Al + row * (size_t)HW;
    __shared__ float buf[HW];
    __shared__ float red[256];
    int t = threadIdx.x;
    float m = -1e30f;
    for (int i = t; i < HW; i += 256) { float v = r[i]; buf[i] = v; m = fmaxf(m, v); }
    red[t] = m; __syncthreads();
    for (int s = 128; s > 0; s >>= 1) { if (t < s) red[t] = fmaxf(red[t], red[t + s]); __syncthreads(); }
    float mx = red[0]; __syncthreads();
    float s = 0.f;
    for (int i = t; i < HW; i += 256) { float e = expf(buf[i] - mx); buf[i] = e; s += e; }
    red[t] = s; __syncthreads();
    for (int o = 128; o > 0; o >>= 1) { if (t < o) red[t] += red[t + o]; __syncthreads(); }
    float inv = 1.f / red[0];
    for (int i = t; i < HW; i += 256) {
        float p = buf[i] * inv;
        __nv_bfloat16 h, l; splitf(p, h, l);
        oh[i] = h; ol[i] = l;
    }
}

// ---------------- HMMA L-GEMM: OT[b,j,c] = split(sum_q x1[c,q]*A[q,j] + xa[c,j]) ------
__global__ void __launch_bounds__(256, 1) k_lgemm_h() {
    extern __shared__ __align__(16) char dsm[];
    const int b = blockIdx.y, j0g = blockIdx.x * 64;
    const int t = threadIdx.x, wid = t >> 5, lane = t & 31;
    const int mw = wid >> 1, nw = wid & 1;
    const int lr = lane >> 2, lc = 2 * (lane & 3);
    const __nv_bfloat16* Xh = g_x1h + (size_t)b * COUT * HW;
    const __nv_bfloat16* Xl = g_x1l + (size_t)b * COUT * HW;
    const __nv_bfloat16* Aph = g_Ah + (size_t)b * HW * HW;
    const __nv_bfloat16* Apl = g_Al + (size_t)b * HW * HW;

    float acc[2][4][4];
#pragma unroll
    for (int i = 0; i < 2; i++)
#pragma unroll
        for (int j = 0; j < 4; j++)
#pragma unroll
            for (int r = 0; r < 4; r++) acc[i][j][r] = 0.f;

    uint4 rah[2], ral[2];
    ushort4 rb[4];
    auto loadG = [&](int it) {
        int kc = it * 32;
        int ar = t >> 1, ak = (t & 1) * 16;
        const __nv_bfloat16* sh = Xh + (size_t)ar * HW + kc + ak;
        const __nv_bfloat16* sl = Xl + (size_t)ar * HW + kc + ak;
        rah[0] = *reinterpret_cast<const uint4*>(sh);
        rah[1] = *reinterpret_cast<const uint4*>(sh + 8);
        ral[0] = *reinterpret_cast<const uint4*>(sl);
        ral[1] = *reinterpret_cast<const uint4*>(sl + 8);
        int qp = t >> 4, jt = t & 15;
        size_t a0 = (size_t)(kc + 2 * qp) * HW + j0g + jt * 4;
        rb[0] = *reinterpret_cast<const ushort4*>(Aph + a0);
        rb[1] = *reinterpret_cast<const ushort4*>(Aph + a0 + HW);
        rb[2] = *reinterpret_cast<const ushort4*>(Apl + a0);
        rb[3] = *reinterpret_cast<const ushort4*>(Apl + a0 + HW);
    };
    auto storeS = [&](int buf) {
        char* base = dsm + buf * 29184;
        int ar = t >> 1, ak = (t & 1) * 16;
        *reinterpret_cast<uint4*>(base + ar * 80 + ak * 2) = rah[0];
        *reinterpret_cast<uint4*>(base + ar * 80 + ak * 2 + 16) = rah[1];
        *reinterpret_cast<uint4*>(base + 10240 + ar * 80 + ak * 2) = ral[0];
        *reinterpret_cast<uint4*>(base + 10240 + ar * 80 + ak * 2 + 16) = ral[1];
        int qp = t >> 4, jt = t & 15;
        char* bh = base + 20480;
        char* bl = base + 24832;
        int j4 = jt * 4;
        *reinterpret_cast<uint32_t*>(bh + (j4 + 0) * 68 + qp * 4) =
            (uint32_t)rb[0].x | ((uint32_t)rb[1].x << 16);
        *reinterpret_cast<uint32_t*>(bh + (j4 + 1) * 68 + qp * 4) =
            (uint32_t)rb[0].y | ((uint32_t)rb[1].y << 16);
        *reinterpret_cast<uint32_t*>(bh + (j4 + 2) * 68 + qp * 4) =
            (uint32_t)rb[0].z | ((uint32_t)rb[1].z << 16);
        *reinterpret_cast<uint32_t*>(bh + (j4 + 3) * 68 + qp * 4) =
            (uint32_t)rb[0].w | ((uint32_t)rb[1].w << 16);
        *reinterpret_cast<uint32_t*>(bl + (j4 + 0) * 68 + qp * 4) =
            (uint32_t)rb[2].x | ((uint32_t)rb[3].x << 16);
        *reinterpret_cast<uint32_t*>(bl + (j4 + 1) * 68 + qp * 4) =
            (uint32_t)rb[2].y | ((uint32_t)rb[3].y << 16);
        *reinterpret_cast<uint32_t*>(bl + (j4 + 2) * 68 + qp * 4) =
            (uint32_t)rb[2].z | ((uint32_t)rb[3].z << 16);
        *reinterpret_cast<uint32_t*>(bl + (j4 + 3) * 68 + qp * 4) =
            (uint32_t)rb[2].w | ((uint32_t)rb[3].w << 16);
    };

    loadG(0); storeS(0); __syncthreads();

    const int T = HW / 32;
    for (int it = 0; it < T; ++it) {
        int cur = it & 1;
        bool more = (it + 1 < T);
        if (more) loadG(it + 1);
        const char* base = dsm + cur * 29184;
        const char* Asm = base;
        const char* Alm = base + 10240;
        const char* Bhm = base + 20480;
        const char* Blm = base + 24832;
#pragma unroll
        for (int ks = 0; ks < 2; ks++) {
            int kb = ks * 16;
            uint32_t bh[4][2], bl[4][2];
#pragma unroll
            for (int j = 0; j < 4; j++) {
                int n = nw * 32 + j * 8 + lr;
                int off = n * 68 + (kb + lc) * 2;
                bh[j][0] = *reinterpret_cast<const uint32_t*>(Bhm + off);
                bh[j][1] = *reinterpret_cast<const uint32_t*>(Bhm + off + 16);
                bl[j][0] = *reinterpret_cast<const uint32_t*>(Blm + off);
                bl[j][1] = *reinterpret_cast<const uint32_t*>(Blm + off + 16);
            }
#pragma unroll
            for (int i = 0; i < 2; i++) {
                int r = mw * 32 + i * 16 + lr;
                int off = r * 80 + (kb + lc) * 2;
                uint32_t ah[4], al[4];
                ah[0] = *reinterpret_cast<const uint32_t*>(Asm + off);
                ah[1] = *reinterpret_cast<const uint32_t*>(Asm + off + 640);
                ah[2] = *reinterpret_cast<const uint32_t*>(Asm + off + 16);
                ah[3] = *reinterpret_cast<const uint32_t*>(Asm + off + 656);
                al[0] = *reinterpret_cast<const uint32_t*>(Alm + off);
                al[1] = *reinterpret_cast<const uint32_t*>(Alm + off + 640);
                al[2] = *reinterpret_cast<const uint32_t*>(Alm + off + 16);
                al[3] = *reinterpret_cast<const uint32_t*>(Alm + off + 656);
#pragma unroll
                for (int j = 0; j < 4; j++) {
                    mma16816(acc[i][j], ah, bh[j]);
                    mma16816(acc[i][j], ah, bl[j]);
                    mma16816(acc[i][j], al, bh[j]);
                }
            }
        }
        if (more) storeS(cur ^ 1);
        __syncthreads();
    }

    // ---- stage (acc + xa) as Ds[j][c], then coalesced bf16-split OT write
    const float* xab = g_xa + (size_t)b * COUT * HW;
    float* Ds = reinterpret_cast<float*>(dsm);
#pragma unroll
    for (int i = 0; i < 2; i++) {
#pragma unroll
        for (int j = 0; j < 4; j++) {
            int c = mw * 32 + i * 16 + lr;
            int col = nw * 32 + j * 8 + lc;
            size_t i0 = (size_t)c * HW + j0g + col;
            size_t i8 = (size_t)(c + 8) * HW + j0g + col;
            float2 x0 = *reinterpret_cast<const float2*>(xab + i0);
            float2 x8 = *reinterpret_cast<const float2*>(xab + i8);
            Ds[col * 129 + c] = acc[i][j][0] + x0.x;
            Ds[(col + 1) * 129 + c] = acc[i][j][1] + x0.y;
            Ds[col * 129 + c + 8] = acc[i][j][2] + x8.x;
            Ds[(col + 1) * 129 + c + 8] = acc[i][j][3] + x8.y;
        }
    }
    __syncthreads();
    {
        int jj = t >> 2, c0q = (t & 3) * 32;
        size_t rowb = ((size_t)b * HW + j0g + jj) * COUT + c0q;
#pragma unroll
        for (int blk = 0; blk < 32; blk += 8) {
            __align__(16) unsigned short h8[8], l8[8];
#pragma unroll
            for (int j = 0; j < 8; j++) {
                float vv = Ds[jj * 129 + c0q + blk + j];
                __nv_bfloat16 h, l; splitf(vv, h, l);
                h8[j] = *reinterpret_cast<unsigned short*>(&h);
                l8[j] = *reinterpret_cast<unsigned short*>(&l);
            }
            *reinterpret_cast<uint4*>(g_oth + rowb + blk) = *reinterpret_cast<uint4*>(h8);
            *reinterpret_cast<uint4*>(g_otl + rowb + blk) = *reinterpret_cast<uint4*>(l8);
        }
    }
}

// ---------------- FFMA pipelined GEMM (conv1 x2) ----------------
template <int BM, int MODE>
__global__ void __launch_bounds__(256, 2) k_gemm(
    const float* __restrict__ Wg, size_t wb_stride,
    const float* __restrict__ In, size_t in_bstride,
    const float* __restrict__ P1,
    const float* __restrict__ Addp, size_t add_bstride,
    float* __restrict__ Out, size_t out_bstride,
    int Kc) {
    constexpr int TM = BM / 32;
    constexpr int NAREG = (BM == 256) ? 4 : 2;
    const int b = blockIdx.y;
    const int y = blockIdx.x;
    const int n0 = y * BN;
    const int t = threadIdx.x;
    const int ty = t >> 3, tx = t & 7;

    __shared__ __align__(16) float As[2][KT][BM];
    __shared__ __align__(16) float Bs[2][KT][BN];

    const int total = Kc / KT;
    const float* Wb = Wg + (size_t)b * wb_stride;
    const float* Inb = In + (size_t)b * in_bstride;

    ull acc2[TM][4];
#pragma unroll
    for (int i = 0; i < TM; i++)
#pragma unroll
        for (int j = 0; j < 4; j++) acc2[i][j] = 0ULL;

    float4 ra[NAREG];
    float rb[4];

    auto loadG = [&](int it) {
        int k0 = it * KT;
        if (BM == 256) {
            const float* wrow = Wb + (size_t)t * Kc + k0;
#pragma unroll
            for (int q = 0; q < 4; q++)
                ra[q] = *reinterpret_cast<const float4*>(wrow + q * 4);
        } else {
            int m = t >> 1, ko = (t & 1) * 8;
            const float* wrow = Wb + (size_t)m * Kc + k0 + ko;
#pragma unroll
            for (int q = 0; q < 2; q++)
                ra[q] = *reinterpret_cast<const float4*>(wrow + q * 4);
        }
        int k = t >> 4, nb = (t & 15) * 4;
        float4 v = *reinterpret_cast<const float4*>(Inb + (size_t)(k0 + k) * HW + n0 + nb);
        rb[0] = v.x; rb[1] = v.y; rb[2] = v.z; rb[3] = v.w;
    };
    auto storeS = [&](int buf) {
        if (BM == 256) {
#pragma unroll
            for (int q = 0; q < 4; q++) {
                As[buf][q * 4 + 0][t] = ra[q].x; As[buf][q * 4 + 1][t] = ra[q].y;
                As[buf][q * 4 + 2][t] = ra[q].z; As[buf][q * 4 + 3][t] = ra[q].w;
            }
        } else {
            int m = t >> 1, ko = (t & 1) * 8;
#pragma unroll
            for (int q = 0; q < 2; q++) {
                As[buf][ko + q * 4 + 0][m] = ra[q].x; As[buf][ko + q * 4 + 1][m] = ra[q].y;
                As[buf][ko + q * 4 + 2][m] = ra[q].z; As[buf][ko + q * 4 + 3][m] = ra[q].w;
            }
        }
        int k = t >> 4, nb = (t & 15) * 4;
        Bs[buf][k][nb] = rb[0]; Bs[buf][k][nb + 1] = rb[1];
        Bs[buf][k][nb + 2] = rb[2]; Bs[buf][k][nb + 3] = rb[3];
    };

    loadG(0);
    storeS(0);
    __syncthreads();

    for (int it = 0; it < total; ++it) {
        int cur = it & 1;
        bool more = (it + 1 < total);
        if (more) loadG(it + 1);
#pragma unroll
        for (int k = 0; k < KT; k++) {
            ull a2[TM], b2[4];
#pragma unroll
            for (int i = 0; i < TM; i += 4) {
                float4 v = *reinterpret_cast<const float4*>(&As[cur][k][ty * TM + i]);
                a2[i] = pack2f(v.x); a2[i + 1] = pack2f(v.y);
                a2[i + 2] = pack2f(v.z); a2[i + 3] = pack2f(v.w);
            }
            {
                float4 v0 = *reinterpret_cast<const float4*>(&Bs[cur][k][tx * 8]);
                float4 v1 = *reinterpret_cast<const float4*>(&Bs[cur][k][tx * 8 + 4]);
                b2[0] = pack2(v0.x, v0.y); b2[1] = pack2(v0.z, v0.w);
                b2[2] = pack2(v1.x, v1.y); b2[3] = pack2(v1.z, v1.w);
            }
#pragma unroll
            for (int i = 0; i < TM; i++)
#pragma unroll
                for (int j = 0; j < 4; j++) fma2(acc2[i][j], a2[i], b2[j]);
        }
        if (more) storeS(cur ^ 1);
        __syncthreads();
    }

    float* Ob = Out + (size_t)b * out_bstride;
#pragma unroll
    for (int i = 0; i < TM; i++) {
        int m = ty * TM + i;
        float bias = (MODE == 0) ? P1[m] : 0.f;
        const float* addrow = (MODE == 2)
            ? (Addp + (size_t)b * add_bstride + (size_t)m * HW + n0 + tx * 8)
            : nullptr;
        float o8[8];
#pragma unroll
        for (int j = 0; j < 4; j++) {
            float2 f = unpk2(acc2[i][j]);
            o8[2 * j] = f.x + bias; o8[2 * j + 1] = f.y + bias;
            if (MODE == 2) { o8[2 * j] += addrow[2 * j]; o8[2 * j + 1] += addrow[2 * j + 1]; }
        }
        float* dst = Ob + (size_t)m * HW + n0 + tx * 8;
        *reinterpret_cast<float4*>(dst) = make_float4(o8[0], o8[1], o8[2], o8[3]);
        *reinterpret_cast<float4*>(dst + 4) = make_float4(o8[4], o8[5], o8[6], o8[7]);
    }
}

// ---------------- host launch ----------------
extern "C" void kernel_launch(void* const* d_in, const int* in_sizes, int n_in,
                              void* d_out, int out_size) {
    (void)in_sizes; (void)n_in; (void)out_size;
    const float* x       = (const float*)d_in[0];
    const float* conv1_w = (const float*)d_in[1];
    const float* conv1_b = (const float*)d_in[2];
    const float* conv2_w = (const float*)d_in[3];
    const float* conv2_b = (const float*)d_in[4];
    const float* cw_w1   = (const float*)d_in[5];
    const float* cw_b1   = (const float*)d_in[6];
    const float* cw_ln_g = (const float*)d_in[7];
    const float* cw_ln_b = (const float*)d_in[8];
    const float* cw_w2   = (const float*)d_in[9];
    const float* cw_b2   = (const float*)d_in[10];
    const float* aspp0_w = (const float*)d_in[11];
    const float* aspp0_g = (const float*)d_in[12];
    const float* aspp0_b = (const float*)d_in[13];
    const float* aspp1_w = (const float*)d_in[14];
    const float* aspp1_g = (const float*)d_in[15];
    const float* aspp1_b = (const float*)d_in[16];
    const float* aspp2_w = (const float*)d_in[17];
    const float* aspp2_g = (const float*)d_in[18];
    const float* aspp2_b = (const float*)d_in[19];
    const float* aspp3_w = (const float*)d_in[20];
    const float* aspp3_g = (const float*)d_in[21];
    const float* aspp3_b = (const float*)d_in[22];
    const float* asppp_w = (const float*)d_in[23];
    const float* asppp_g = (const float*)d_in[24];
    const float* asppp_b = (const float*)d_in[25];
    const float* proj_w  = (const float*)d_in[26];
    const float* proj_g  = (const float*)d_in[27];
    const float* proj_b  = (const float*)d_in[28];

    void* pv;
    float *p_x1, *p_proj, *p_xa;
    __nv_bfloat16 *p_xth, *p_xtl, *p_cth, *p_ctl, *p_w3h, *p_w3l, *p_a0h, *p_a0l, *p_pjh, *p_pjl;
    __nv_bfloat16 *p_x1th, *p_x1tl, *p_xath, *p_xatl, *p_x1h, *p_x1l, *p_c2h, *p_c2l;
    __nv_bfloat16 *p_oth, *p_otl;
    cudaGetSymbolAddress(&pv, g_x1);   p_x1   = (float*)pv;
    cudaGetSymbolAddress(&pv, g_proj); p_proj = (float*)pv;
    cudaGetSymbolAddress(&pv, g_xa);   p_xa   = (float*)pv;
    cudaGetSymbolAddress(&pv, g_xth);  p_xth  = (__nv_bfloat16*)pv;
    cudaGetSymbolAddress(&pv, g_xtl);  p_xtl  = (__nv_bfloat16*)pv;
    cudaGetSymbolAddress(&pv, g_cth);  p_cth  = (__nv_bfloat16*)pv;
    cudaGetSymbolAddress(&pv, g_ctl);  p_ctl  = (__nv_bfloat16*)pv;
    cudaGetSymbolAddress(&pv, g_w3h);  p_w3h  = (__nv_bfloat16*)pv;
    cudaGetSymbolAddress(&pv, g_w3l);  p_w3l  = (__nv_bfloat16*)pv;
    cudaGetSymbolAddress(&pv, g_a0h);  p_a0h  = (__nv_bfloat16*)pv;
    cudaGetSymbolAddress(&pv, g_a0l);  p_a0l  = (__nv_bfloat16*)pv;
    cudaGetSymbolAddress(&pv, g_pjh);  p_pjh  = (__nv_bfloat16*)pv;
    cudaGetSymbolAddress(&pv, g_pjl);  p_pjl  = (__nv_bfloat16*)pv;
    cudaGetSymbolAddress(&pv, g_c2h);  p_c2h  = (__nv_bfloat16*)pv;
    cudaGetSymbolAddress(&pv, g_c2l);  p_c2l  = (__nv_bfloat16*)pv;
    cudaGetSymbolAddress(&pv, g_x1th); p_x1th = (__nv_bfloat16*)pv;
    cudaGetSymbolAddress(&pv, g_x1tl); p_x1tl = (__nv_bfloat16*)pv;
    cudaGetSymbolAddress(&pv, g_xath); p_xath = (__nv_bfloat16*)pv;
    cudaGetSymbolAddress(&pv, g_xatl); p_xatl = (__nv_bfloat16*)pv;
    cudaGetSymbolAddress(&pv, g_x1h);  p_x1h  = (__nv_bfloat16*)pv;
    cudaGetSymbolAddress(&pv, g_x1l);  p_x1l  = (__nv_bfloat16*)pv;
    cudaGetSymbolAddress(&pv, g_oth);  p_oth  = (__nv_bfloat16*)pv;
    cudaGetSymbolAddress(&pv, g_otl);  p_otl  = (__nv_bfloat16*)pv;

    const int TG_SMEM = 135168;   // max(2x61440 mainloop, 256x129x4 = 132096 epilogue)
    cudaFuncSetAttribute(k_hgemm<false, 0>, cudaFuncAttributeMaxDynamicSharedMemorySize, TG_SMEM);
    cudaFuncSetAttribute(k_hgemm<true, 0>, cudaFuncAttributeMaxDynamicSharedMemorySize, TG_SMEM);
    cudaFuncSetAttribute(k_hgemm<false, 1>, cudaFuncAttributeMaxDynamicSharedMemorySize, TG_SMEM);
    cudaFuncSetAttribute(k_hgemm<false, 2>, cudaFuncAttributeMaxDynamicSharedMemorySize, TG_SMEM);
    cudaFuncSetAttribute(k_sgemm_h, cudaFuncAttributeMaxDynamicSharedMemorySize, 61440);
    cudaFuncSetAttribute(k_lgemm_h, cudaFuncAttributeMaxDynamicSharedMemorySize, 58368);

    dim3 g64(HW / BN, BATCH);
    dim3 gh(HW / 128, BATCH);

    // 1-3: prep (launch #4 = aspp0 HMMA gets profiled)
    k_prep<<<3456, 256>>>(aspp1_w, aspp2_w, aspp3_w, aspp0_w, proj_w, conv2_w, x);
    k_cw<<<BATCH, 256>>>(cw_w1, cw_b1, cw_ln_g, cw_ln_b, cw_w2, cw_b2,
                         asppp_w, asppp_g, asppp_b);
    k_xcsplit<<<dim3(128, 8, BATCH), 256>>>(x);
    // 4-7: ASPP branches (HMMA, ldmatrix + cp.async)
    k_hgemm<false, 0><<<gh, 512, TG_SMEM>>>(p_a0h, p_a0l, p_xth, p_xtl,
        aspp0_g, aspp0_b, nullptr, p_cth, p_ctl, 0, CIN, 0);
    k_hgemm<true, 0><<<gh, 512, TG_SMEM>>>(p_w3h + 0 * 9 * 65536, p_w3l + 0 * 9 * 65536,
        p_xth, p_xtl, aspp1_g, aspp1_b, nullptr, p_cth, p_ctl, 256, CIN, 3);
    k_hgemm<true, 0><<<gh, 512, TG_SMEM>>>(p_w3h + 1 * 9 * 65536, p_w3l + 1 * 9 * 65536,
        p_xth, p_xtl, aspp2_g, aspp2_b, nullptr, p_cth, p_ctl, 512, CIN, 6);
    k_hgemm<true, 0><<<gh, 512, TG_SMEM>>>(p_w3h + 2 * 9 * 65536, p_w3l + 2 * 9 * 65536,
        p_xth, p_xtl, aspp3_g, aspp3_b, nullptr, p_cth, p_ctl, 768, CIN, 9);
    // 8: global-pool branch into catT
    k_bp_cat<<<dim3(128, BATCH), 256>>>();
    // 9: proj (HMMA, K=1280) -> f32
    k_hgemm<false, 1><<<gh, 512, TG_SMEM>>>(p_pjh, p_pjl, p_cth, p_ctl,
        proj_g, proj_b, p_proj, nullptr, nullptr, 0, 5 * CIN, 0);
    // 10-11: conv1 twice (FFMA)
    k_gemm<128, 0><<<g64, 256>>>(conv1_w, 0, x, (size_t)CIN * HW, conv1_b,
                                 nullptr, 0, p_x1, (size_t)COUT * HW, CIN);
    k_gemm<128, 0><<<g64, 256>>>(conv1_w, 0, p_proj, (size_t)CIN * HW, conv1_b,
                                 nullptr, 0, p_xa, (size_t)COUT * HW, CIN);
    // 12-13: split x1 (straight + T), xa (T)
    k_splitT<true><<<dim3(128, 4, BATCH), 256>>>(p_x1, p_x1th, p_x1tl, p_x1h, p_x1l);
    k_splitT<false><<<dim3(128, 4, BATCH), 256>>>(p_xa, p_xath, p_xatl, nullptr, nullptr);
    // 14-16: attention (HMMA S, softmax->bf16, HMMA L -> OT split)
    k_sgemm_h<<<dim3(64, 32, BATCH), 256, 61440>>>();
    k_softmax<<<BATCH * HW, 256>>>();
    k_lgemm_h<<<dim3(64, BATCH), 256, 58368>>>();
    // 17: out = conv2(O) + b (HMMA bias epilogue, K=128)
    k_hgemm<false, 2><<<gh, 512, TG_SMEM>>>(p_c2h, p_c2l, p_oth, p_otl,
        conv2_b, conv2_b, (float*)d_out, nullptr, nullptr, 0, COUT, 0);
}

// round 10
// speedup vs baseline: 2.5219x; 1.0546x over previous
#include <cuda_runtime.h>
#include <cuda_bf16.h>
#include <math.h>
#include <stdint.h>

#define BATCH 4
#define CIN 256
#define COUT 128
#define HH 64
#define WW 64
#define HW 4096
#define BN 64
#define KT 16

typedef unsigned long long ull;

// ---------------- scratch (static device globals; no allocs) ----------------
__device__ float g_x1[BATCH * COUT * HW];
__device__ float g_proj[BATCH * CIN * HW];
__device__ float g_xa[BATCH * COUT * HW];
__device__ float g_S[(size_t)BATCH * HW * HW];
__device__ float g_avg[BATCH * CIN];
__device__ float g_mx[BATCH * CIN];
__device__ float g_s[BATCH * CIN];
__device__ float g_bp[BATCH * CIN];
// bf16 split operands
__device__ __nv_bfloat16 g_xth[BATCH * HW * CIN];
__device__ __nv_bfloat16 g_xtl[BATCH * HW * CIN];
__device__ __nv_bfloat16 g_cth[(size_t)BATCH * HW * 5 * CIN];
__device__ __nv_bfloat16 g_ctl[(size_t)BATCH * HW * 5 * CIN];
__device__ __nv_bfloat16 g_w3h[3 * 9 * CIN * CIN];
__device__ __nv_bfloat16 g_w3l[3 * 9 * CIN * CIN];
__device__ __nv_bfloat16 g_a0h[CIN * CIN];
__device__ __nv_bfloat16 g_a0l[CIN * CIN];
__device__ __nv_bfloat16 g_pjh[CIN * 5 * CIN];
__device__ __nv_bfloat16 g_pjl[CIN * 5 * CIN];
__device__ __nv_bfloat16 g_c2h[CIN * COUT];
__device__ __nv_bfloat16 g_c2l[CIN * COUT];
// attention operands
__device__ __nv_bfloat16 g_x1th[BATCH * HW * COUT];
__device__ __nv_bfloat16 g_x1tl[BATCH * HW * COUT];
__device__ __nv_bfloat16 g_xath[BATCH * HW * COUT];
__device__ __nv_bfloat16 g_xatl[BATCH * HW * COUT];
__device__ __nv_bfloat16 g_x1h[BATCH * COUT * HW];
__device__ __nv_bfloat16 g_x1l[BATCH * COUT * HW];
__device__ __nv_bfloat16 g_Ah[(size_t)BATCH * HW * HW];
__device__ __nv_bfloat16 g_Al[(size_t)BATCH * HW * HW];
__device__ __nv_bfloat16 g_oth[BATCH * HW * COUT];
__device__ __nv_bfloat16 g_otl[BATCH * HW * COUT];

__device__ __forceinline__ float gelu_f(float x) {
    return 0.5f * x * (1.0f + erff(x * 0.70710678118654752440f));
}
__device__ __forceinline__ void splitf(float v, __nv_bfloat16& h, __nv_bfloat16& l) {
    h = __float2bfloat16(v);
    l = __float2bfloat16(v - __bfloat162float(h));
}

// ---------------- HMMA m16n8k16 bf16 ----------------
__device__ __forceinline__ void mma16816(float* d, const uint32_t* a, const uint32_t* b) {
    asm volatile(
        "mma.sync.aligned.m16n8k16.row.col.f32.bf16.bf16.f32 "
        "{%0,%1,%2,%3}, {%4,%5,%6,%7}, {%8,%9}, {%0,%1,%2,%3};"
        : "+f"(d[0]), "+f"(d[1]), "+f"(d[2]), "+f"(d[3])
        : "r"(a[0]), "r"(a[1]), "r"(a[2]), "r"(a[3]), "r"(b[0]), "r"(b[1]));
}
__device__ __forceinline__ void ldsm_x4(uint32_t* r, uint32_t addr) {
    asm volatile("ldmatrix.sync.aligned.m8n8.x4.shared.b16 {%0,%1,%2,%3}, [%4];"
                 : "=r"(r[0]), "=r"(r[1]), "=r"(r[2]), "=r"(r[3]) : "r"(addr));
}
__device__ __forceinline__ void ldsm_x2(uint32_t* r, uint32_t addr) {
    asm volatile("ldmatrix.sync.aligned.m8n8.x2.shared.b16 {%0,%1}, [%2];"
                 : "=r"(r[0]), "=r"(r[1]) : "r"(addr));
}
__device__ __forceinline__ void ldsm_x2t(uint32_t* r, uint32_t addr) {
    asm volatile("ldmatrix.sync.aligned.m8n8.x2.trans.shared.b16 {%0,%1}, [%2];"
                 : "=r"(r[0]), "=r"(r[1]) : "r"(addr));
}

// ---------------- cp.async helpers ----------------
__device__ __forceinline__ void cp16(uint32_t d, const void* s, int ssz) {
    asm volatile("cp.async.ca.shared.global [%0], [%1], 16, %2;"
                 :: "r"(d), "l"(s), "r"(ssz) : "memory");
}
#define CP_COMMIT() asm volatile("cp.async.commit_group;" ::: "memory")
#define CP_WAIT1()  asm volatile("cp.async.wait_group 1;" ::: "memory")
#define CP_WAIT0()  asm volatile("cp.async.wait_group 0;" ::: "memory")

// ---------------- packed helpers for FFMA path ----------------
__device__ __forceinline__ ull pack2f(float x) {
    ull r; asm("mov.b64 %0, {%1, %1};" : "=l"(r) : "f"(x)); return r;
}
__device__ __forceinline__ ull pack2(float x, float y) {
    ull r; asm("mov.b64 %0, {%1, %2};" : "=l"(r) : "f"(x), "f"(y)); return r;
}
__device__ __forceinline__ void fma2(ull& d, ull a, ull b) {
    asm("fma.rn.f32x2 %0, %1, %2, %0;" : "+l"(d) : "l"(a), "l"(b));
}
__device__ __forceinline__ float2 unpk2(ull v) {
    float2 f; asm("mov.b64 {%0, %1}, %2;" : "=f"(f.x), "=f"(f.y) : "l"(v)); return f;
}

// ---------------- prep: weight split/transpose + per-(b,c) stats ----------------
__global__ void k_prep(const float* __restrict__ w1, const float* __restrict__ w2,
                       const float* __restrict__ w3, const float* __restrict__ a0,
                       const float* __restrict__ pj, const float* __restrict__ c2,
                       const float* __restrict__ x) {
    if (blockIdx.x < 2432) {
        int e = blockIdx.x * 256 + threadIdx.x;
        if (e < 196608) {
            const float* srcs[3] = { w1, w2, w3 };
            int conv = e >> 16, mc = e & 65535, m = mc >> 8, c = mc & 255;
            const float* src = srcs[conv] + (size_t)m * 2304 + (size_t)c * 9;
            size_t dbase = (size_t)conv * 9 * 65536 + (size_t)m * 256 + c;
#pragma unroll
            for (int tap = 0; tap < 9; tap++) {
                __nv_bfloat16 h, l; splitf(src[tap], h, l);
                g_w3h[dbase + (size_t)tap * 65536] = h;
                g_w3l[dbase + (size_t)tap * 65536] = l;
            }
        } else if (e < 262144) {
            int i = e - 196608;
            __nv_bfloat16 h, l; splitf(a0[i], h, l);
            g_a0h[i] = h; g_a0l[i] = l;
        } else if (e < 589824) {
            int i = e - 262144;
            __nv_bfloat16 h, l; splitf(pj[i], h, l);
            g_pjh[i] = h; g_pjl[i] = l;
        } else if (e < 622592) {
            int i = e - 589824;
            __nv_bfloat16 h, l; splitf(c2[i], h, l);
            g_c2h[i] = h; g_c2l[i] = l;
        }
    } else {
        int bc = blockIdx.x - 2432;
        const float* p = x + (size_t)bc * HW;
        int t = threadIdx.x;
        float s = 0.f, m = -1e30f;
        for (int i = t; i < HW; i += 256) { float v = p[i]; s += v; m = fmaxf(m, v); }
        __shared__ float ss[256], sm[256];
        ss[t] = s; sm[t] = m; __syncthreads();
        for (int o = 128; o > 0; o >>= 1) {
            if (t < o) { ss[t] += ss[t + o]; sm[t] = fmaxf(sm[t], sm[t + o]); }
            __syncthreads();
        }
        if (t == 0) { g_avg[bc] = ss[0] * (1.f / HW); g_mx[bc] = sm[0]; }
    }
}

// ---------------- channel weighting MLP + global-pool ASPP branch ----------------
__global__ void k_cw(const float* __restrict__ w1, const float* __restrict__ bb1,
                     const float* __restrict__ lg, const float* __restrict__ lb,
                     const float* __restrict__ w2, const float* __restrict__ bb2,
                     const float* __restrict__ apw, const float* __restrict__ apg,
                     const float* __restrict__ apb) {
    int b = blockIdx.x, t = threadIdx.x;
    __shared__ float o[CIN];
    __shared__ float h[COUT];
    __shared__ float red[256];
    __shared__ float gp[CIN];
    float avg = g_avg[b * CIN + t], mx = g_mx[b * CIN + t];
    o[t] = fabsf(avg - mx) * avg;
    __syncthreads();
    float hv = 0.f;
    if (t < COUT) {
        hv = bb1[t];
        const float* wr = w1 + t * CIN;
        for (int i = 0; i < CIN; i++) hv = fmaf(o[i], wr[i], hv);
    }
    red[t] = (t < COUT) ? hv : 0.f; __syncthreads();
    for (int s = 128; s > 0; s >>= 1) { if (t < s) red[t] += red[t + s]; __syncthreads(); }
    float mu = red[0] * (1.f / COUT); __syncthreads();
    float dv = (t < COUT) ? (hv - mu) : 0.f;
    red[t] = dv * dv; __syncthreads();
    for (int s = 128; s > 0; s >>= 1) { if (t < s) red[t] += red[t + s]; __syncthreads(); }
    float var = red[0] * (1.f / COUT); __syncthreads();
    if (t < COUT) h[t] = lg[t] * ((hv - mu) * rsqrtf(var + 1e-5f)) + lb[t];
    __syncthreads();
    float sv = bb2[t];
    const float* wr2 = w2 + t * COUT;
    for (int j = 0; j < COUT; j++) sv = fmaf(h[j], wr2[j], sv);
    float sig = 1.f / (1.f + expf(-sv));
    g_s[b * CIN + t] = sig;
    gp[t] = (1.f + sig) * avg;
    __syncthreads();
    float v = 0.f;
    const float* ar = apw + t * CIN;
    for (int i = 0; i < CIN; i++) v = fmaf(ar[i], gp[i], v);
    red[t] = v; __syncthreads();
    for (int s = 128; s > 0; s >>= 1) { if (t < s) red[t] += red[t + s]; __syncthreads(); }
    float mu2 = red[0] * (1.f / CIN); __syncthreads();
    float d2 = v - mu2; red[t] = d2 * d2; __syncthreads();
    for (int s = 128; s > 0; s >>= 1) { if (t < s) red[t] += red[t + s]; __syncthreads(); }
    float var2 = red[0] * (1.f / CIN); __syncthreads();
    float z = apg[t] * ((v - mu2) * rsqrtf(var2 + 1e-6f)) + apb[t];
    g_bp[b * CIN + t] = gelu_f(z);
}

// ---------------- xcT split: x[b][c][hw]*(1+s) -> bf16 hi/lo [b][hw][c] ----------------
__global__ void k_xcsplit(const float* __restrict__ x) {
    __shared__ float tile[32][33];
    int b = blockIdx.z, c0 = blockIdx.y * 32, h0 = blockIdx.x * 32;
    int t = threadIdx.x;
    const float* xb = x + ((size_t)b * CIN + c0) * HW + h0;
#pragma unroll
    for (int i = 0; i < 4; i++) {
        int r = (t >> 5) + 8 * i;
        tile[r][t & 31] = xb[(size_t)r * HW + (t & 31)];
    }
    __syncthreads();
#pragma unroll
    for (int i = 0; i < 4; i++) {
        int hr = (t >> 5) + 8 * i, cc = t & 31;
        float v = tile[cc][hr] * (1.f + g_s[b * CIN + c0 + cc]);
        __nv_bfloat16 h, l; splitf(v, h, l);
        size_t idx = ((size_t)b * HW + h0 + hr) * CIN + c0 + cc;
        g_xth[idx] = h; g_xtl[idx] = l;
    }
}

// ---------------- split/transpose for 128-channel fp32 maps ----------------
template <bool STRAIGHT>
__global__ void k_splitT(const float* __restrict__ in,
                         __nv_bfloat16* __restrict__ th, __nv_bfloat16* __restrict__ tl,
                         __nv_bfloat16* __restrict__ sh, __nv_bfloat16* __restrict__ sl) {
    __shared__ float tile[32][33];
    int b = blockIdx.z, c0 = blockIdx.y * 32, h0 = blockIdx.x * 32;
    int t = threadIdx.x;
    const float* ib = in + ((size_t)b * COUT + c0) * HW + h0;
#pragma unroll
    for (int i = 0; i < 4; i++) {
        int r = (t >> 5) + 8 * i, col = t & 31;
        float v = ib[(size_t)r * HW + col];
        tile[r][col] = v;
        if (STRAIGHT) {
            __nv_bfloat16 h, l; splitf(v, h, l);
            size_t idx = ((size_t)b * COUT + c0 + r) * HW + h0 + col;
            sh[idx] = h; sl[idx] = l;
        }
    }
    __syncthreads();
#pragma unroll
    for (int i = 0; i < 4; i++) {
        int hr = (t >> 5) + 8 * i, cc = t & 31;
        float v = tile[cc][hr];
        __nv_bfloat16 h, l; splitf(v, h, l);
        size_t idx = ((size_t)b * HW + h0 + hr) * COUT + c0 + cc;
        th[idx] = h; tl[idx] = l;
    }
}

// ---------------- bp broadcast into catT channels [1024,1280) ----------------
__global__ void k_bp_cat() {
    int b = blockIdx.y, h0 = blockIdx.x * 32;
    int c = threadIdx.x;
    __nv_bfloat16 h, l; splitf(g_bp[b * CIN + c], h, l);
    for (int r = 0; r < 32; r++) {
        size_t idx = ((size_t)b * HW + h0 + r) * 1280 + 1024 + c;
        g_cth[idx] = h; g_ctl[idx] = l;
    }
}

// ---------------- HMMA bf16x2-split GEMM, 256x128 tile, 512 thr ----------
// EPI 0: LN+GELU -> catT bf16 split;  EPI 1: LN+GELU -> f32 [m][hw];
// EPI 2: +bias(gam) -> f32 [m][hw].
template <bool CONV3, int EPI>
__global__ void __launch_bounds__(512, 1) k_hgemm(
    const __nv_bfloat16* __restrict__ Whi, const __nv_bfloat16* __restrict__ Wlo,
    const __nv_bfloat16* __restrict__ Ihi, const __nv_bfloat16* __restrict__ Ilo,
    const float* __restrict__ gam, const float* __restrict__ bet,
    float* __restrict__ outF, __nv_bfloat16* __restrict__ cth, __nv_bfloat16* __restrict__ ctl,
    int coff, int Kc, int dil) {
    extern __shared__ __align__(16) char dsm[];
    __shared__ int s_tapn, s_tp[9], s_dy[9], s_dx[9];
    __shared__ float sgam[256], sbet[256], smean[128], srstd[128];
    __shared__ float red4[4][128];

    const int b = blockIdx.y, y = blockIdx.x;
    const int t = threadIdx.x, wid = t >> 5, lane = t & 31;
    const int mw = wid >> 2, nw = wid & 3;
    const uint32_t sbase = (uint32_t)__cvta_generic_to_shared(dsm);

    if (CONV3 && t == 0) {
        int n = 0;
        for (int tap = 0; tap < 9; tap++) {
            int dy = (tap / 3 - 1) * dil;
            int y0 = y * 2 + dy, y1 = y * 2 + 1 + dy;
            if ((unsigned)y0 < 64u || (unsigned)y1 < 64u) {
                s_tp[n] = tap; s_dy[n] = dy; s_dx[n] = (tap % 3 - 1) * dil; n++;
            }
        }
        s_tapn = n;
    }
    if (t < 256) { sgam[t] = gam[t]; sbet[t] = bet[t]; }
    __syncthreads();

    const int nkc = Kc / 32;
    const int T = CONV3 ? s_tapn * nkc : nkc;
    const __nv_bfloat16* Ib_hi = Ihi + (size_t)b * HW * Kc;
    const __nv_bfloat16* Ib_lo = Ilo + (size_t)b * HW * Kc;

    float acc[4][4][4];
#pragma unroll
    for (int i = 0; i < 4; i++)
#pragma unroll
        for (int j = 0; j < 4; j++)
#pragma unroll
            for (int r = 0; r < 4; r++) acc[i][j][r] = 0.f;

    auto loadG = [&](int it, int buf) {
        int tap_i = CONV3 ? (it / nkc) : 0;
        int kc = (CONV3 ? (it - tap_i * nkc) : it) * 32;
        uint32_t base = sbase + buf * 61440;
        int arow = t >> 1, ak = (t & 1) * 16;
        int grow = CONV3 ? (s_tp[tap_i] * 256 + arow) : arow;
        const __nv_bfloat16* ah = Whi + (size_t)grow * Kc + kc + ak;
        const __nv_bfloat16* al = Wlo + (size_t)grow * Kc + kc + ak;
        uint32_t da = base + arow * 80 + ak * 2;
        cp16(da, ah, 16);
        cp16(da + 16, ah + 8, 16);
        cp16(da + 20480, al, 16);
        cp16(da + 20480 + 16, al + 8, 16);
        int n = t >> 2, q = t & 3;
        int hw; int ok = 16;
        if (CONV3) {
            int yy = y * 2 + (n >> 6) + s_dy[tap_i];
            int xx = (n & 63) + s_dx[tap_i];
            if ((unsigned)yy < 64u && (unsigned)xx < 64u) hw = yy * 64 + xx;
            else { hw = 0; ok = 0; }
        } else hw = y * 128 + n;
        uint32_t db = base + 40960 + n * 80 + q * 16;
        cp16(db, Ib_hi + (size_t)hw * Kc + kc + q * 8, ok);
        cp16(db + 10240, Ib_lo + (size_t)hw * Kc + kc + q * 8, ok);
        CP_COMMIT();
    };

    loadG(0, 0);
    if (T > 1) loadG(1, 1);

    const int lr = lane >> 2, lc = 2 * (lane & 3);
    const uint32_t a_loff = (uint32_t)(((lane & 7) + ((lane >> 3) & 1) * 8) * 80
                                       + (lane >> 4) * 16);
    const uint32_t b_loff = (uint32_t)((lane & 7) * 80 + ((lane >> 3) & 1) * 16);
    const uint32_t a_wbase = (uint32_t)(mw * 64 * 80) + a_loff;
    const uint32_t b_wbase = 40960u + (uint32_t)(nw * 32 * 80) + b_loff;

    for (int it = 0; it < T; ++it) {
        int cur = it & 1;
        if (it + 1 < T) CP_WAIT1(); else CP_WAIT0();
        __syncthreads();
        uint32_t sb = sbase + cur * 61440;
#pragma unroll
        for (int ks = 0; ks < 2; ks++) {
            uint32_t kboff = ks * 32;
            uint32_t bh[4][2], bl[4][2];
#pragma unroll
            for (int j = 0; j < 4; j++) {
                uint32_t ba = sb + b_wbase + j * (8 * 80) + kboff;
                ldsm_x2(bh[j], ba);
                ldsm_x2(bl[j], ba + 10240);
            }
#pragma unroll
            for (int i = 0; i < 4; i++) {
                uint32_t aa = sb + a_wbase + i * (16 * 80) + kboff;
                uint32_t ah[4], al[4];
                ldsm_x4(ah, aa);
                ldsm_x4(al, aa + 20480);
#pragma unroll
                for (int j = 0; j < 4; j++) {
                    mma16816(acc[i][j], ah, bh[j]);
                    mma16816(acc[i][j], ah, bl[j]);
                    mma16816(acc[i][j], al, bh[j]);
                }
            }
        }
        __syncthreads();
        if (it + 2 < T) loadG(it + 2, cur);
    }

    float* Ds = reinterpret_cast<float*>(dsm);
#pragma unroll
    for (int i = 0; i < 4; i++) {
        int r0 = mw * 64 + i * 16 + lr;
#pragma unroll
        for (int j = 0; j < 4; j++) {
            int c = nw * 32 + j * 8 + lc;
            Ds[r0 * 129 + c] = acc[i][j][0];
            Ds[r0 * 129 + c + 1] = acc[i][j][1];
            Ds[(r0 + 8) * 129 + c] = acc[i][j][2];
            Ds[(r0 + 8) * 129 + c + 1] = acc[i][j][3];
        }
    }
    __syncthreads();
    if (EPI != 2) {
        int n = t & 127, p = t >> 7;
        float s = 0.f;
        for (int mm = p * 64; mm < p * 64 + 64; mm++) s += Ds[mm * 129 + n];
        red4[p][n] = s;
        __syncthreads();
        if (t < 128)
            smean[t] = (red4[0][t] + red4[1][t] + red4[2][t] + red4[3][t]) * (1.f / 256.f);
        __syncthreads();
        float mu = smean[n];
        s = 0.f;
        for (int mm = p * 64; mm < p * 64 + 64; mm++) {
            float d = Ds[mm * 129 + n] - mu; s += d * d;
        }
        red4[p][n] = s;
        __syncthreads();
        if (t < 128)
            srstd[t] = rsqrtf((red4[0][t] + red4[1][t] + red4[2][t] + red4[3][t]) * (1.f / 256.f) + 1e-6f);
        __syncthreads();
    }
    if (EPI == 0) {
        int n2 = t >> 2, m0q = (t & 3) * 64;
        float mu = smean[n2], rs = srstd[n2];
        size_t rowb = ((size_t)b * HW + y * 128 + n2) * 1280 + coff + m0q;
#pragma unroll
        for (int blk = 0; blk < 64; blk += 8) {
            __align__(16) unsigned short h8[8], l8[8];
#pragma unroll
            for (int j = 0; j < 8; j++) {
                int m = m0q + blk + j;
                float vv = gelu_f((Ds[m * 129 + n2] - mu) * rs * sgam[m] + sbet[m]);
                __nv_bfloat16 h, l; splitf(vv, h, l);
                h8[j] = *reinterpret_cast<unsigned short*>(&h);
                l8[j] = *reinterpret_cast<unsigned short*>(&l);
            }
            *reinterpret_cast<uint4*>(cth + rowb + blk) = *reinterpret_cast<uint4*>(h8);
            *reinterpret_cast<uint4*>(ctl + rowb + blk) = *reinterpret_cast<uint4*>(l8);
        }
    } else if (EPI == 1) {
        int m = t >> 1, nh = (t & 1) * 64;
        float gmm = sgam[m], bt2 = sbet[m];
        size_t ob = ((size_t)b * CIN + m) * HW + y * 128 + nh;
#pragma unroll
        for (int blk = 0; blk < 64; blk += 4) {
            float4 v4;
            float* vp = &v4.x;
#pragma unroll
            for (int j = 0; j < 4; j++) {
                int n3 = nh + blk + j;
                vp[j] = gelu_f((Ds[m * 129 + n3] - smean[n3]) * srstd[n3] * gmm + bt2);
            }
            *reinterpret_cast<float4*>(outF + ob + blk) = v4;
        }
    } else {
        int m = t >> 1, nh = (t & 1) * 64;
        float bias = sgam[m];
        size_t ob = ((size_t)b * CIN + m) * HW + y * 128 + nh;
#pragma unroll
        for (int blk = 0; blk < 64; blk += 4) {
            float4 v4;
            float* vp = &v4.x;
#pragma unroll
            for (int j = 0; j < 4; j++) vp[j] = Ds[m * 129 + nh + blk + j] + bias;
            *reinterpret_cast<float4*>(outF + ob + blk) = v4;
        }
    }
}

// ---------------- HMMA S-GEMM v2: 256(q)x128(p) tile, 512 thr, cp.async+ldmatrix ----
__global__ void __launch_bounds__(512, 1) k_sgemm2() {
    extern __shared__ __align__(16) char dsm[];
    const int b = blockIdx.z, q0 = blockIdx.y * 256, p0 = blockIdx.x * 128;
    const int t = threadIdx.x, wid = t >> 5, lane = t & 31;
    const int mw = wid >> 2, nw = wid & 3;
    const uint32_t sbase = (uint32_t)__cvta_generic_to_shared(dsm);
    const __nv_bfloat16* Qh = g_xath + (size_t)b * HW * COUT;
    const __nv_bfloat16* Ql = g_xatl + (size_t)b * HW * COUT;
    const __nv_bfloat16* Ph = g_x1th + (size_t)b * HW * COUT;
    const __nv_bfloat16* Pl = g_x1tl + (size_t)b * HW * COUT;

    float acc[4][4][4];
#pragma unroll
    for (int i = 0; i < 4; i++)
#pragma unroll
        for (int j = 0; j < 4; j++)
#pragma unroll
            for (int r = 0; r < 4; r++) acc[i][j][r] = 0.f;

    auto loadG = [&](int it, int buf) {
        int kc = it * 32;
        uint32_t base = sbase + buf * 61440;
        int arow = t >> 1, ak = (t & 1) * 16;
        const __nv_bfloat16* ah = Qh + (size_t)(q0 + arow) * COUT + kc + ak;
        const __nv_bfloat16* al = Ql + (size_t)(q0 + arow) * COUT + kc + ak;
        uint32_t da = base + arow * 80 + ak * 2;
        cp16(da, ah, 16);
        cp16(da + 16, ah + 8, 16);
        cp16(da + 20480, al, 16);
        cp16(da + 20480 + 16, al + 8, 16);
        int n = t >> 2, q = t & 3;
        uint32_t db = base + 40960 + n * 80 + q * 16;
        cp16(db, Ph + (size_t)(p0 + n) * COUT + kc + q * 8, 16);
        cp16(db + 10240, Pl + (size_t)(p0 + n) * COUT + kc + q * 8, 16);
        CP_COMMIT();
    };

    loadG(0, 0);
    loadG(1, 1);

    const int lr = lane >> 2, lc = 2 * (lane & 3);
    const uint32_t a_loff = (uint32_t)(((lane & 7) + ((lane >> 3) & 1) * 8) * 80
                                       + (lane >> 4) * 16);
    const uint32_t b_loff = (uint32_t)((lane & 7) * 80 + ((lane >> 3) & 1) * 16);
    const uint32_t a_wbase = (uint32_t)(mw * 64 * 80) + a_loff;
    const uint32_t b_wbase = 40960u + (uint32_t)(nw * 32 * 80) + b_loff;

    const int T = COUT / 32;  // 4
    for (int it = 0; it < T; ++it) {
        int cur = it & 1;
        if (it + 1 < T) CP_WAIT1(); else CP_WAIT0();
        __syncthreads();
        uint32_t sb = sbase + cur * 61440;
#pragma unroll
        for (int ks = 0; ks < 2; ks++) {
            uint32_t kboff = ks * 32;
            uint32_t bh[4][2], bl[4][2];
#pragma unroll
            for (int j = 0; j < 4; j++) {
                uint32_t ba = sb + b_wbase + j * (8 * 80) + kboff;
                ldsm_x2(bh[j], ba);
                ldsm_x2(bl[j], ba + 10240);
            }
#pragma unroll
            for (int i = 0; i < 4; i++) {
                uint32_t aa = sb + a_wbase + i * (16 * 80) + kboff;
                uint32_t ah[4], al[4];
                ldsm_x4(ah, aa);
                ldsm_x4(al, aa + 20480);
#pragma unroll
                for (int j = 0; j < 4; j++) {
                    mma16816(acc[i][j], ah, bh[j]);
                    mma16816(acc[i][j], ah, bl[j]);
                    mma16816(acc[i][j], al, bh[j]);
                }
            }
        }
        __syncthreads();
        if (it + 2 < T) loadG(it + 2, cur);
    }

    // stage + scaled f32 write
    float* Ds = reinterpret_cast<float*>(dsm);
#pragma unroll
    for (int i = 0; i < 4; i++) {
        int r0 = mw * 64 + i * 16 + lr;
#pragma unroll
        for (int j = 0; j < 4; j++) {
            int c = nw * 32 + j * 8 + lc;
            Ds[r0 * 129 + c] = acc[i][j][0];
            Ds[r0 * 129 + c + 1] = acc[i][j][1];
            Ds[(r0 + 8) * 129 + c] = acc[i][j][2];
            Ds[(r0 + 8) * 129 + c + 1] = acc[i][j][3];
        }
    }
    __syncthreads();
    {
        const float sc = 1.f / 64.f;
        int m = t >> 1, nh = (t & 1) * 64;
        float* So = g_S + (size_t)b * HW * HW + (size_t)(q0 + m) * HW + p0 + nh;
#pragma unroll
        for (int blk = 0; blk < 64; blk += 4) {
            float4 v4;
            float* vp = &v4.x;
#pragma unroll
            for (int j = 0; j < 4; j++) vp[j] = Ds[m * 129 + nh + blk + j] * sc;
            *reinterpret_cast<float4*>(So + blk) = v4;
        }
    }
}

// ---------------- row softmax; emits bf16 hi/lo probs ----------------
__global__ void __launch_bounds__(256) k_softmax() {
    const size_t row = blockIdx.x;
    const float* r = g_S + row * (size_t)HW;
    __nv_bfloat16* oh = g_Ah + row * (size_t)HW;
    __nv_bfloat16* ol = g_Al + row * (size_t)HW;
    __shared__ float buf[HW];
    __shared__ float red[256];
    int t = threadIdx.x;
    float m = -1e30f;
    for (int i = t; i < HW; i += 256) { float v = r[i]; buf[i] = v; m = fmaxf(m, v); }
    red[t] = m; __syncthreads();
    for (int s = 128; s > 0; s >>= 1) { if (t < s) red[t] = fmaxf(red[t], red[t + s]); __syncthreads(); }
    float mx = red[0]; __syncthreads();
    float s = 0.f;
    for (int i = t; i < HW; i += 256) { float e = expf(buf[i] - mx); buf[i] = e; s += e; }
    red[t] = s; __syncthreads();
    for (int o = 128; o > 0; o >>= 1) { if (t < o) red[t] += red[t + o]; __syncthreads(); }
    float inv = 1.f / red[0];
    for (int i = t; i < HW; i += 256) {
        float p = buf[i] * inv;
        __nv_bfloat16 h, l; splitf(p, h, l);
        oh[i] = h; ol[i] = l;
    }
}

// ---------------- HMMA L-GEMM v2: 128(c)x128(j) tile, 512 thr, trans-B ldmatrix ----
// OT[b,j,c] = split(sum_q x1[c,q]*A[q,j] + xa[c,j])
// Per buf (37888B): Ah 0 (128x80), Al 10240, Bh 20480 (32x272), Bl 29184.
__global__ void __launch_bounds__(512, 1) k_lgemm2() {
    extern __shared__ __align__(16) char dsm[];
    const int b = blockIdx.y, j0g = blockIdx.x * 128;
    const int t = threadIdx.x, wid = t >> 5, lane = t & 31;
    const int mw = wid >> 2, nw = wid & 3;
    const uint32_t sbase = (uint32_t)__cvta_generic_to_shared(dsm);
    const __nv_bfloat16* Xh = g_x1h + (size_t)b * COUT * HW;
    const __nv_bfloat16* Xl = g_x1l + (size_t)b * COUT * HW;
    const __nv_bfloat16* Aph = g_Ah + (size_t)b * HW * HW;
    const __nv_bfloat16* Apl = g_Al + (size_t)b * HW * HW;

    float acc[2][4][4];
#pragma unroll
    for (int i = 0; i < 2; i++)
#pragma unroll
        for (int j = 0; j < 4; j++)
#pragma unroll
            for (int r = 0; r < 4; r++) acc[i][j][r] = 0.f;

    auto loadG = [&](int it, int buf) {
        int kc = it * 32;
        uint32_t base = sbase + buf * 37888;
        int c = t >> 2, cq = t & 3;
        const __nv_bfloat16* ah = Xh + (size_t)c * HW + kc + cq * 8;
        const __nv_bfloat16* al = Xl + (size_t)c * HW + kc + cq * 8;
        uint32_t da = base + c * 80 + cq * 16;
        cp16(da, ah, 16);
        cp16(da + 10240, al, 16);
        int k = t >> 4, jt = t & 15;
        const __nv_bfloat16* bh = Aph + (size_t)(kc + k) * HW + j0g + jt * 8;
        const __nv_bfloat16* bl = Apl + (size_t)(kc + k) * HW + j0g + jt * 8;
        uint32_t db = base + 20480 + k * 272 + jt * 16;
        cp16(db, bh, 16);
        cp16(db + 8704, bl, 16);
        CP_COMMIT();
    };

    loadG(0, 0);
    loadG(1, 1);

    const int lr = lane >> 2, lc = 2 * (lane & 3);
    const uint32_t a_loff = (uint32_t)(((lane & 7) + ((lane >> 3) & 1) * 8) * 80
                                       + (lane >> 4) * 16);
    const uint32_t a_wbase = (uint32_t)(mw * 32 * 80) + a_loff;
    const uint32_t bt_loff = (uint32_t)((lane & 15) * 272);

    const int T = HW / 32;
    for (int it = 0; it < T; ++it) {
        int cur = it & 1;
        if (it + 1 < T) CP_WAIT1(); else CP_WAIT0();
        __syncthreads();
        uint32_t sb = sbase + cur * 37888;
#pragma unroll
        for (int ks = 0; ks < 2; ks++) {
            uint32_t bh[4][2], bl[4][2];
#pragma unroll
            for (int j = 0; j < 4; j++) {
                uint32_t ba = sb + 20480 + bt_loff + ks * (16 * 272)
                              + (nw * 32 + j * 8) * 2;
                ldsm_x2t(bh[j], ba);
                ldsm_x2t(bl[j], ba + 8704);
            }
#pragma unroll
            for (int i = 0; i < 2; i++) {
                uint32_t aa = sb + a_wbase + i * (16 * 80) + ks * 32;
                uint32_t ah[4], al[4];
                ldsm_x4(ah, aa);
                ldsm_x4(al, aa + 10240);
#pragma unroll
                for (int j = 0; j < 4; j++) {
                    mma16816(acc[i][j], ah, bh[j]);
                    mma16816(acc[i][j], ah, bl[j]);
                    mma16816(acc[i][j], al, bh[j]);
                }
            }
        }
        __syncthreads();
        if (it + 2 < T) loadG(it + 2, cur);
    }

    // stage (acc + xa) as Ds[j][c] (128x129), coalesced OT split write
    const float* xab = g_xa + (size_t)b * COUT * HW;
    float* Ds = reinterpret_cast<float*>(dsm);
#pragma unroll
    for (int i = 0; i < 2; i++) {
#pragma unroll
        for (int j = 0; j < 4; j++) {
            int c = mw * 32 + i * 16 + lr;
            int col = nw * 32 + j * 8 + lc;
            size_t i0 = (size_t)c * HW + j0g + col;
            size_t i8 = (size_t)(c + 8) * HW + j0g + col;
            float2 x0 = *reinterpret_cast<const float2*>(xab + i0);
            float2 x8 = *reinterpret_cast<const float2*>(xab + i8);
            Ds[col * 129 + c] = acc[i][j][0] + x0.x;
            Ds[(col + 1) * 129 + c] = acc[i][j][1] + x0.y;
            Ds[col * 129 + c + 8] = acc[i][j][2] + x8.x;
            Ds[(col + 1) * 129 + c + 8] = acc[i][j][3] + x8.y;
        }
    }
    __syncthreads();
    {
        int jj = t >> 2, c0q = (t & 3) * 32;
        size_t rowb = ((size_t)b * HW + j0g + jj) * COUT + c0q;
#pragma unroll
        for (int blk = 0; blk < 32; blk += 8) {
            __align__(16) unsigned short h8[8], l8[8];
#pragma unroll
            for (int j = 0; j < 8; j++) {
                float vv = Ds[jj * 129 + c0q + blk + j];
                __nv_bfloat16 h, l; splitf(vv, h, l);
                h8[j] = *reinterpret_cast<unsigned short*>(&h);
                l8[j] = *reinterpret_cast<unsigned short*>(&l);
            }
            *reinterpret_cast<uint4*>(g_oth + rowb + blk) = *reinterpret_cast<uint4*>(h8);
            *reinterpret_cast<uint4*>(g_otl + rowb + blk) = *reinterpret_cast<uint4*>(l8);
        }
    }
}

// ---------------- FFMA pipelined GEMM (conv1 x2) ----------------
template <int BM, int MODE>
__global__ void __launch_bounds__(256, 2) k_gemm(
    const float* __restrict__ Wg, size_t wb_stride,
    const float* __restrict__ In, size_t in_bstride,
    const float* __restrict__ P1,
    const float* __restrict__ Addp, size_t add_bstride,
    float* __restrict__ Out, size_t out_bstride,
    int Kc) {
    constexpr int TM = BM / 32;
    constexpr int NAREG = (BM == 256) ? 4 : 2;
    const int b = blockIdx.y;
    const int y = blockIdx.x;
    const int n0 = y * BN;
    const int t = threadIdx.x;
    const int ty = t >> 3, tx = t & 7;

    __shared__ __align__(16) float As[2][KT][BM];
    __shared__ __align__(16) float Bs[2][KT][BN];

    const int total = Kc / KT;
    const float* Wb = Wg + (size_t)b * wb_stride;
    const float* Inb = In + (size_t)b * in_bstride;

    ull acc2[TM][4];
#pragma unroll
    for (int i = 0; i < TM; i++)
#pragma unroll
        for (int j = 0; j < 4; j++) acc2[i][j] = 0ULL;

    float4 ra[NAREG];
    float rb[4];

    auto loadG = [&](int it) {
        int k0 = it * KT;
        if (BM == 256) {
            const float* wrow = Wb + (size_t)t * Kc + k0;
#pragma unroll
            for (int q = 0; q < 4; q++)
                ra[q] = *reinterpret_cast<const float4*>(wrow + q * 4);
        } else {
            int m = t >> 1, ko = (t & 1) * 8;
            const float* wrow = Wb + (size_t)m * Kc + k0 + ko;
#pragma unroll
            for (int q = 0; q < 2; q++)
                ra[q] = *reinterpret_cast<const float4*>(wrow + q * 4);
        }
        int k = t >> 4, nb = (t & 15) * 4;
        float4 v = *reinterpret_cast<const float4*>(Inb + (size_t)(k0 + k) * HW + n0 + nb);
        rb[0] = v.x; rb[1] = v.y; rb[2] = v.z; rb[3] = v.w;
    };
    auto storeS = [&](int buf) {
        if (BM == 256) {
#pragma unroll
            for (int q = 0; q < 4; q++) {
                As[buf][q * 4 + 0][t] = ra[q].x; As[buf][q * 4 + 1][t] = ra[q].y;
                As[buf][q * 4 + 2][t] = ra[q].z; As[buf][q * 4 + 3][t] = ra[q].w;
            }
        } else {
            int m = t >> 1, ko = (t & 1) * 8;
#pragma unroll
            for (int q = 0; q < 2; q++) {
                As[buf][ko + q * 4 + 0][m] = ra[q].x; As[buf][ko + q * 4 + 1][m] = ra[q].y;
                As[buf][ko + q * 4 + 2][m] = ra[q].z; As[buf][ko + q * 4 + 3][m] = ra[q].w;
            }
        }
        int k = t >> 4, nb = (t & 15) * 4;
        Bs[buf][k][nb] = rb[0]; Bs[buf][k][nb + 1] = rb[1];
        Bs[buf][k][nb + 2] = rb[2]; Bs[buf][k][nb + 3] = rb[3];
    };

    loadG(0);
    storeS(0);
    __syncthreads();

    for (int it = 0; it < total; ++it) {
        int cur = it & 1;
        bool more = (it + 1 < total);
        if (more) loadG(it + 1);
#pragma unroll
        for (int k = 0; k < KT; k++) {
            ull a2[TM], b2[4];
#pragma unroll
            for (int i = 0; i < TM; i += 4) {
                float4 v = *reinterpret_cast<const float4*>(&As[cur][k][ty * TM + i]);
                a2[i] = pack2f(v.x); a2[i + 1] = pack2f(v.y);
                a2[i + 2] = pack2f(v.z); a2[i + 3] = pack2f(v.w);
            }
            {
                float4 v0 = *reinterpret_cast<const float4*>(&Bs[cur][k][tx * 8]);
                float4 v1 = *reinterpret_cast<const float4*>(&Bs[cur][k][tx * 8 + 4]);
                b2[0] = pack2(v0.x, v0.y); b2[1] = pack2(v0.z, v0.w);
                b2[2] = pack2(v1.x, v1.y); b2[3] = pack2(v1.z, v1.w);
            }
#pragma unroll
            for (int i = 0; i < TM; i++)
#pragma unroll
                for (int j = 0; j < 4; j++) fma2(acc2[i][j], a2[i], b2[j]);
        }
        if (more) storeS(cur ^ 1);
        __syncthreads();
    }

    float* Ob = Out + (size_t)b * out_bstride;
#pragma unroll
    for (int i = 0; i < TM; i++) {
        int m = ty * TM + i;
        float bias = (MODE == 0) ? P1[m] : 0.f;
        const float* addrow = (MODE == 2)
            ? (Addp + (size_t)b * add_bstride + (size_t)m * HW + n0 + tx * 8)
            : nullptr;
        float o8[8];
#pragma unroll
        for (int j = 0; j < 4; j++) {
            float2 f = unpk2(acc2[i][j]);
            o8[2 * j] = f.x + bias; o8[2 * j + 1] = f.y + bias;
            if (MODE == 2) { o8[2 * j] += addrow[2 * j]; o8[2 * j + 1] += addrow[2 * j + 1]; }
        }
        float* dst = Ob + (size_t)m * HW + n0 + tx * 8;
        *reinterpret_cast<float4*>(dst) = make_float4(o8[0], o8[1], o8[2], o8[3]);
        *reinterpret_cast<float4*>(dst + 4) = make_float4(o8[4], o8[5], o8[6], o8[7]);
    }
}

// ---------------- host launch ----------------
extern "C" void kernel_launch(void* const* d_in, const int* in_sizes, int n_in,
                              void* d_out, int out_size) {
    (void)in_sizes; (void)n_in; (void)out_size;
    const float* x       = (const float*)d_in[0];
    const float* conv1_w = (const float*)d_in[1];
    const float* conv1_b = (const float*)d_in[2];
    const float* conv2_w = (const float*)d_in[3];
    const float* conv2_b = (const float*)d_in[4];
    const float* cw_w1   = (const float*)d_in[5];
    const float* cw_b1   = (const float*)d_in[6];
    const float* cw_ln_g = (const float*)d_in[7];
    const float* cw_ln_b = (const float*)d_in[8];
    const float* cw_w2   = (const float*)d_in[9];
    const float* cw_b2   = (const float*)d_in[10];
    const float* aspp0_w = (const float*)d_in[11];
    const float* aspp0_g = (const float*)d_in[12];
    const float* aspp0_b = (const float*)d_in[13];
    const float* aspp1_w = (const float*)d_in[14];
    const float* aspp1_g = (const float*)d_in[15];
    const float* aspp1_b = (const float*)d_in[16];
    const float* aspp2_w = (const float*)d_in[17];
    const float* aspp2_g = (const float*)d_in[18];
    const float* aspp2_b = (const float*)d_in[19];
    const float* aspp3_w = (const float*)d_in[20];
    const float* aspp3_g = (const float*)d_in[21];
    const float* aspp3_b = (const float*)d_in[22];
    const float* asppp_w = (const float*)d_in[23];
    const float* asppp_g = (const float*)d_in[24];
    const float* asppp_b = (const float*)d_in[25];
    const float* proj_w  = (const float*)d_in[26];
    const float* proj_g  = (const float*)d_in[27];
    const float* proj_b  = (const float*)d_in[28];

    void* pv;
    float *p_x1, *p_proj, *p_xa;
    __nv_bfloat16 *p_xth, *p_xtl, *p_cth, *p_ctl, *p_w3h, *p_w3l, *p_a0h, *p_a0l, *p_pjh, *p_pjl;
    __nv_bfloat16 *p_x1th, *p_x1tl, *p_xath, *p_xatl, *p_x1h, *p_x1l, *p_c2h, *p_c2l;
    __nv_bfloat16 *p_oth, *p_otl;
    cudaGetSymbolAddress(&pv, g_x1);   p_x1   = (float*)pv;
    cudaGetSymbolAddress(&pv, g_proj); p_proj = (float*)pv;
    cudaGetSymbolAddress(&pv, g_xa);   p_xa   = (float*)pv;
    cudaGetSymbolAddress(&pv, g_xth);  p_xth  = (__nv_bfloat16*)pv;
    cudaGetSymbolAddress(&pv, g_xtl);  p_xtl  = (__nv_bfloat16*)pv;
    cudaGetSymbolAddress(&pv, g_cth);  p_cth  = (__nv_bfloat16*)pv;
    cudaGetSymbolAddress(&pv, g_ctl);  p_ctl  = (__nv_bfloat16*)pv;
    cudaGetSymbolAddress(&pv, g_w3h);  p_w3h  = (__nv_bfloat16*)pv;
    cudaGetSymbolAddress(&pv, g_w3l);  p_w3l  = (__nv_bfloat16*)pv;
    cudaGetSymbolAddress(&pv, g_a0h);  p_a0h  = (__nv_bfloat16*)pv;
    cudaGetSymbolAddress(&pv, g_a0l);  p_a0l  = (__nv_bfloat16*)pv;
    cudaGetSymbolAddress(&pv, g_pjh);  p_pjh  = (__nv_bfloat16*)pv;
    cudaGetSymbolAddress(&pv, g_pjl);  p_pjl  = (__nv_bfloat16*)pv;
    cudaGetSymbolAddress(&pv, g_c2h);  p_c2h  = (__nv_bfloat16*)pv;
    cudaGetSymbolAddress(&pv, g_c2l);  p_c2l  = (__nv_bfloat16*)pv;
    cudaGetSymbolAddress(&pv, g_x1th); p_x1th = (__nv_bfloat16*)pv;
    cudaGetSymbolAddress(&pv, g_x1tl); p_x1tl = (__nv_bfloat16*)pv;
    cudaGetSymbolAddress(&pv, g_xath); p_xath = (__nv_bfloat16*)pv;
    cudaGetSymbolAddress(&pv, g_xatl); p_xatl = (__nv_bfloat16*)pv;
    cudaGetSymbolAddress(&pv, g_x1h);  p_x1h  = (__nv_bfloat16*)pv;
    cudaGetSymbolAddress(&pv, g_x1l);  p_x1l  = (__nv_bfloat16*)pv;
    cudaGetSymbolAddress(&pv, g_oth);  p_oth  = (__nv_bfloat16*)pv;
    cudaGetSymbolAddress(&pv, g_otl);  p_otl  = (__nv_bfloat16*)pv;

    const int TG_SMEM = 135168;
    cudaFuncSetAttribute(k_hgemm<false, 0>, cudaFuncAttributeMaxDynamicSharedMemorySize, TG_SMEM);
    cudaFuncSetAttribute(k_hgemm<true, 0>, cudaFuncAttributeMaxDynamicSharedMemorySize, TG_SMEM);
    cudaFuncSetAttribute(k_hgemm<false, 1>, cudaFuncAttributeMaxDynamicSharedMemorySize, TG_SMEM);
    cudaFuncSetAttribute(k_hgemm<false, 2>, cudaFuncAttributeMaxDynamicSharedMemorySize, TG_SMEM);
    cudaFuncSetAttribute(k_sgemm2, cudaFuncAttributeMaxDynamicSharedMemorySize, TG_SMEM);
    cudaFuncSetAttribute(k_lgemm2, cudaFuncAttributeMaxDynamicSharedMemorySize, 75776);

    dim3 g64(HW / BN, BATCH);
    dim3 gh(HW / 128, BATCH);

    // 1-3: prep (launch #4 = aspp0 HMMA gets profiled)
    k_prep<<<3456, 256>>>(aspp1_w, aspp2_w, aspp3_w, aspp0_w, proj_w, conv2_w, x);
    k_cw<<<BATCH, 256>>>(cw_w1, cw_b1, cw_ln_g, cw_ln_b, cw_w2, cw_b2,
                         asppp_w, asppp_g, asppp_b);
    k_xcsplit<<<dim3(128, 8, BATCH), 256>>>(x);
    // 4-7: ASPP branches (HMMA)
    k_hgemm<false, 0><<<gh, 512, TG_SMEM>>>(p_a0h, p_a0l, p_xth, p_xtl,
        aspp0_g, aspp0_b, nullptr, p_cth, p_ctl, 0, CIN, 0);
    k_hgemm<true, 0><<<gh, 512, TG_SMEM>>>(p_w3h + 0 * 9 * 65536, p_w3l + 0 * 9 * 65536,
        p_xth, p_xtl, aspp1_g, aspp1_b, nullptr, p_cth, p_ctl, 256, CIN, 3);
    k_hgemm<true, 0><<<gh, 512, TG_SMEM>>>(p_w3h + 1 * 9 * 65536, p_w3l + 1 * 9 * 65536,
        p_xth, p_xtl, aspp2_g, aspp2_b, nullptr, p_cth, p_ctl, 512, CIN, 6);
    k_hgemm<true, 0><<<gh, 512, TG_SMEM>>>(p_w3h + 2 * 9 * 65536, p_w3l + 2 * 9 * 65536,
        p_xth, p_xtl, aspp3_g, aspp3_b, nullptr, p_cth, p_ctl, 768, CIN, 9);
    // 8: global-pool branch into catT
    k_bp_cat<<<dim3(128, BATCH), 256>>>();
    // 9: proj (HMMA, K=1280) -> f32
    k_hgemm<false, 1><<<gh, 512, TG_SMEM>>>(p_pjh, p_pjl, p_cth, p_ctl,
        proj_g, proj_b, p_proj, nullptr, nullptr, 0, 5 * CIN, 0);
    // 10-11: conv1 twice (FFMA)
    k_gemm<128, 0><<<g64, 256>>>(conv1_w, 0, x, (size_t)CIN * HW, conv1_b,
                                 nullptr, 0, p_x1, (size_t)COUT * HW, CIN);
    k_gemm<128, 0><<<g64, 256>>>(conv1_w, 0, p_proj, (size_t)CIN * HW, conv1_b,
                                 nullptr, 0, p_xa, (size_t)COUT * HW, CIN);
    // 12-13: split x1 (straight + T), xa (T)
    k_splitT<true><<<dim3(128, 4, BATCH), 256>>>(p_x1, p_x1th, p_x1tl, p_x1h, p_x1l);
    k_splitT<false><<<dim3(128, 4, BATCH), 256>>>(p_xa, p_xath, p_xatl, nullptr, nullptr);
    // 14-16: attention (HMMA v2 S, softmax->bf16, HMMA v2 L -> OT split)
    k_sgemm2<<<dim3(HW / 128, HW / 256, BATCH), 512, TG_SMEM>>>();
    k_softmax<<<BATCH * HW, 256>>>();
    k_lgemm2<<<dim3(HW / 128, BATCH), 512, 75776>>>();
    // 17: out = conv2(O) + b (HMMA bias epilogue, K=128)
    k_hgemm<false, 2><<<gh, 512, TG_SMEM>>>(p_c2h, p_c2l, p_oth, p_otl,
        conv2_b, conv2_b, (float*)d_out, nullptr, nullptr, 0, COUT, 0);
}

// round 11
// speedup vs baseline: 2.7635x; 1.0958x over previous
#include <cuda_runtime.h>
#include <cuda_bf16.h>
#include <math.h>
#include <stdint.h>

#define BATCH 4
#define CIN 256
#define COUT 128
#define HH 64
#define WW 64
#define HW 4096
#define BN 64
#define KT 16

typedef unsigned long long ull;

// ---------------- scratch (static device globals; no allocs) ----------------
__device__ float g_x1[BATCH * COUT * HW];
__device__ float g_proj[BATCH * CIN * HW];
__device__ float g_xa[BATCH * COUT * HW];
__device__ float g_S[(size_t)BATCH * HW * HW];
__device__ float g_avg[BATCH * CIN];
__device__ float g_mx[BATCH * CIN];
__device__ float g_s[BATCH * CIN];
__device__ float g_bp[BATCH * CIN];
// bf16 split operands
__device__ __nv_bfloat16 g_xth[BATCH * HW * CIN];
__device__ __nv_bfloat16 g_xtl[BATCH * HW * CIN];
__device__ __nv_bfloat16 g_cth[(size_t)BATCH * HW * 5 * CIN];
__device__ __nv_bfloat16 g_ctl[(size_t)BATCH * HW * 5 * CIN];
__device__ __nv_bfloat16 g_w3h[3 * 9 * CIN * CIN];
__device__ __nv_bfloat16 g_w3l[3 * 9 * CIN * CIN];
__device__ __nv_bfloat16 g_a0h[CIN * CIN];
__device__ __nv_bfloat16 g_a0l[CIN * CIN];
__device__ __nv_bfloat16 g_pjh[CIN * 5 * CIN];
__device__ __nv_bfloat16 g_pjl[CIN * 5 * CIN];
__device__ __nv_bfloat16 g_c2h[CIN * COUT];
__device__ __nv_bfloat16 g_c2l[CIN * COUT];
// attention operands
__device__ __nv_bfloat16 g_x1th[BATCH * HW * COUT];
__device__ __nv_bfloat16 g_x1tl[BATCH * HW * COUT];
__device__ __nv_bfloat16 g_xath[BATCH * HW * COUT];
__device__ __nv_bfloat16 g_xatl[BATCH * HW * COUT];
__device__ __nv_bfloat16 g_x1h[BATCH * COUT * HW];
__device__ __nv_bfloat16 g_x1l[BATCH * COUT * HW];
__device__ __nv_bfloat16 g_Ah[(size_t)BATCH * HW * HW];
__device__ __nv_bfloat16 g_Al[(size_t)BATCH * HW * HW];
__device__ __nv_bfloat16 g_oth[BATCH * HW * COUT];
__device__ __nv_bfloat16 g_otl[BATCH * HW * COUT];

__device__ __forceinline__ float gelu_f(float x) {
    return 0.5f * x * (1.0f + erff(x * 0.70710678118654752440f));
}
__device__ __forceinline__ void splitf(float v, __nv_bfloat16& h, __nv_bfloat16& l) {
    h = __float2bfloat16(v);
    l = __float2bfloat16(v - __bfloat162float(h));
}

// ---------------- HMMA m16n8k16 bf16 ----------------
__device__ __forceinline__ void mma16816(float* d, const uint32_t* a, const uint32_t* b) {
    asm volatile(
        "mma.sync.aligned.m16n8k16.row.col.f32.bf16.bf16.f32 "
        "{%0,%1,%2,%3}, {%4,%5,%6,%7}, {%8,%9}, {%0,%1,%2,%3};"
        : "+f"(d[0]), "+f"(d[1]), "+f"(d[2]), "+f"(d[3])
        : "r"(a[0]), "r"(a[1]), "r"(a[2]), "r"(a[3]), "r"(b[0]), "r"(b[1]));
}
__device__ __forceinline__ void ldsm_x4(uint32_t* r, uint32_t addr) {
    asm volatile("ldmatrix.sync.aligned.m8n8.x4.shared.b16 {%0,%1,%2,%3}, [%4];"
                 : "=r"(r[0]), "=r"(r[1]), "=r"(r[2]), "=r"(r[3]) : "r"(addr));
}
__device__ __forceinline__ void ldsm_x4t(uint32_t* r, uint32_t addr) {
    asm volatile("ldmatrix.sync.aligned.m8n8.x4.trans.shared.b16 {%0,%1,%2,%3}, [%4];"
                 : "=r"(r[0]), "=r"(r[1]), "=r"(r[2]), "=r"(r[3]) : "r"(addr));
}

// ---------------- cp.async helpers ----------------
__device__ __forceinline__ void cp16(uint32_t d, const void* s, int ssz) {
    asm volatile("cp.async.ca.shared.global [%0], [%1], 16, %2;"
                 :: "r"(d), "l"(s), "r"(ssz) : "memory");
}
#define CP_COMMIT() asm volatile("cp.async.commit_group;" ::: "memory")
#define CP_WAIT1()  asm volatile("cp.async.wait_group 1;" ::: "memory")
#define CP_WAIT0()  asm volatile("cp.async.wait_group 0;" ::: "memory")

// ---------------- packed helpers for FFMA path ----------------
__device__ __forceinline__ ull pack2f(float x) {
    ull r; asm("mov.b64 %0, {%1, %1};" : "=l"(r) : "f"(x)); return r;
}
__device__ __forceinline__ ull pack2(float x, float y) {
    ull r; asm("mov.b64 %0, {%1, %2};" : "=l"(r) : "f"(x), "f"(y)); return r;
}
__device__ __forceinline__ void fma2(ull& d, ull a, ull b) {
    asm("fma.rn.f32x2 %0, %1, %2, %0;" : "+l"(d) : "l"(a), "l"(b));
}
__device__ __forceinline__ float2 unpk2(ull v) {
    float2 f; asm("mov.b64 {%0, %1}, %2;" : "=f"(f.x), "=f"(f.y) : "l"(v)); return f;
}

// ---------------- prep: weight split/transpose + per-(b,c) stats ----------------
__global__ void k_prep(const float* __restrict__ w1, const float* __restrict__ w2,
                       const float* __restrict__ w3, const float* __restrict__ a0,
                       const float* __restrict__ pj, const float* __restrict__ c2,
                       const float* __restrict__ x) {
    if (blockIdx.x < 2432) {
        int e = blockIdx.x * 256 + threadIdx.x;
        if (e < 196608) {
            const float* srcs[3] = { w1, w2, w3 };
            int conv = e >> 16, mc = e & 65535, m = mc >> 8, c = mc & 255;
            const float* src = srcs[conv] + (size_t)m * 2304 + (size_t)c * 9;
            size_t dbase = (size_t)conv * 9 * 65536 + (size_t)m * 256 + c;
#pragma unroll
            for (int tap = 0; tap < 9; tap++) {
                __nv_bfloat16 h, l; splitf(src[tap], h, l);
                g_w3h[dbase + (size_t)tap * 65536] = h;
                g_w3l[dbase + (size_t)tap * 65536] = l;
            }
        } else if (e < 262144) {
            int i = e - 196608;
            __nv_bfloat16 h, l; splitf(a0[i], h, l);
            g_a0h[i] = h; g_a0l[i] = l;
        } else if (e < 589824) {
            int i = e - 262144;
            __nv_bfloat16 h, l; splitf(pj[i], h, l);
            g_pjh[i] = h; g_pjl[i] = l;
        } else if (e < 622592) {
            int i = e - 589824;
            __nv_bfloat16 h, l; splitf(c2[i], h, l);
            g_c2h[i] = h; g_c2l[i] = l;
        }
    } else {
        int bc = blockIdx.x - 2432;
        const float* p = x + (size_t)bc * HW;
        int t = threadIdx.x;
        float s = 0.f, m = -1e30f;
        for (int i = t; i < HW; i += 256) { float v = p[i]; s += v; m = fmaxf(m, v); }
        __shared__ float ss[256], sm[256];
        ss[t] = s; sm[t] = m; __syncthreads();
        for (int o = 128; o > 0; o >>= 1) {
            if (t < o) { ss[t] += ss[t + o]; sm[t] = fmaxf(sm[t], sm[t + o]); }
            __syncthreads();
        }
        if (t == 0) { g_avg[bc] = ss[0] * (1.f / HW); g_mx[bc] = sm[0]; }
    }
}

// ---------------- channel weighting MLP + global-pool ASPP branch ----------------
__global__ void k_cw(const float* __restrict__ w1, const float* __restrict__ bb1,
                     const float* __restrict__ lg, const float* __restrict__ lb,
                     const float* __restrict__ w2, const float* __restrict__ bb2,
                     const float* __restrict__ apw, const float* __restrict__ apg,
                     const float* __restrict__ apb) {
    int b = blockIdx.x, t = threadIdx.x;
    __shared__ float o[CIN];
    __shared__ float h[COUT];
    __shared__ float red[256];
    __shared__ float gp[CIN];
    float avg = g_avg[b * CIN + t], mx = g_mx[b * CIN + t];
    o[t] = fabsf(avg - mx) * avg;
    __syncthreads();
    float hv = 0.f;
    if (t < COUT) {
        hv = bb1[t];
        const float* wr = w1 + t * CIN;
        for (int i = 0; i < CIN; i++) hv = fmaf(o[i], wr[i], hv);
    }
    red[t] = (t < COUT) ? hv : 0.f; __syncthreads();
    for (int s = 128; s > 0; s >>= 1) { if (t < s) red[t] += red[t + s]; __syncthreads(); }
    float mu = red[0] * (1.f / COUT); __syncthreads();
    float dv = (t < COUT) ? (hv - mu) : 0.f;
    red[t] = dv * dv; __syncthreads();
    for (int s = 128; s > 0; s >>= 1) { if (t < s) red[t] += red[t + s]; __syncthreads(); }
    float var = red[0] * (1.f / COUT); __syncthreads();
    if (t < COUT) h[t] = lg[t] * ((hv - mu) * rsqrtf(var + 1e-5f)) + lb[t];
    __syncthreads();
    float sv = bb2[t];
    const float* wr2 = w2 + t * COUT;
    for (int j = 0; j < COUT; j++) sv = fmaf(h[j], wr2[j], sv);
    float sig = 1.f / (1.f + expf(-sv));
    g_s[b * CIN + t] = sig;
    gp[t] = (1.f + sig) * avg;
    __syncthreads();
    float v = 0.f;
    const float* ar = apw + t * CIN;
    for (int i = 0; i < CIN; i++) v = fmaf(ar[i], gp[i], v);
    red[t] = v; __syncthreads();
    for (int s = 128; s > 0; s >>= 1) { if (t < s) red[t] += red[t + s]; __syncthreads(); }
    float mu2 = red[0] * (1.f / CIN); __syncthreads();
    float d2 = v - mu2; red[t] = d2 * d2; __syncthreads();
    for (int s = 128; s > 0; s >>= 1) { if (t < s) red[t] += red[t + s]; __syncthreads(); }
    float var2 = red[0] * (1.f / CIN); __syncthreads();
    float z = apg[t] * ((v - mu2) * rsqrtf(var2 + 1e-6f)) + apb[t];
    g_bp[b * CIN + t] = gelu_f(z);
}

// ---------------- xcT split ----------------
__global__ void k_xcsplit(const float* __restrict__ x) {
    __shared__ float tile[32][33];
    int b = blockIdx.z, c0 = blockIdx.y * 32, h0 = blockIdx.x * 32;
    int t = threadIdx.x;
    const float* xb = x + ((size_t)b * CIN + c0) * HW + h0;
#pragma unroll
    for (int i = 0; i < 4; i++) {
        int r = (t >> 5) + 8 * i;
        tile[r][t & 31] = xb[(size_t)r * HW + (t & 31)];
    }
    __syncthreads();
#pragma unroll
    for (int i = 0; i < 4; i++) {
        int hr = (t >> 5) + 8 * i, cc = t & 31;
        float v = tile[cc][hr] * (1.f + g_s[b * CIN + c0 + cc]);
        __nv_bfloat16 h, l; splitf(v, h, l);
        size_t idx = ((size_t)b * HW + h0 + hr) * CIN + c0 + cc;
        g_xth[idx] = h; g_xtl[idx] = l;
    }
}

// ---------------- split/transpose for 128-channel fp32 maps ----------------
template <bool STRAIGHT>
__global__ void k_splitT(const float* __restrict__ in,
                         __nv_bfloat16* __restrict__ th, __nv_bfloat16* __restrict__ tl,
                         __nv_bfloat16* __restrict__ sh, __nv_bfloat16* __restrict__ sl) {
    __shared__ float tile[32][33];
    int b = blockIdx.z, c0 = blockIdx.y * 32, h0 = blockIdx.x * 32;
    int t = threadIdx.x;
    const float* ib = in + ((size_t)b * COUT + c0) * HW + h0;
#pragma unroll
    for (int i = 0; i < 4; i++) {
        int r = (t >> 5) + 8 * i, col = t & 31;
        float v = ib[(size_t)r * HW + col];
        tile[r][col] = v;
        if (STRAIGHT) {
            __nv_bfloat16 h, l; splitf(v, h, l);
            size_t idx = ((size_t)b * COUT + c0 + r) * HW + h0 + col;
            sh[idx] = h; sl[idx] = l;
        }
    }
    __syncthreads();
#pragma unroll
    for (int i = 0; i < 4; i++) {
        int hr = (t >> 5) + 8 * i, cc = t & 31;
        float v = tile[cc][hr];
        __nv_bfloat16 h, l; splitf(v, h, l);
        size_t idx = ((size_t)b * HW + h0 + hr) * COUT + c0 + cc;
        th[idx] = h; tl[idx] = l;
    }
}

// ---------------- bp broadcast into catT channels [1024,1280) ----------------
__global__ void k_bp_cat() {
    int b = blockIdx.y, h0 = blockIdx.x * 32;
    int c = threadIdx.x;
    __nv_bfloat16 h, l; splitf(g_bp[b * CIN + c], h, l);
    for (int r = 0; r < 32; r++) {
        size_t idx = ((size_t)b * HW + h0 + r) * 1280 + 1024 + c;
        g_cth[idx] = h; g_ctl[idx] = l;
    }
}

struct AsppArgs {
    const __nv_bfloat16* wh[4];
    const __nv_bfloat16* wl[4];
    const float* g[4];
    const float* bt[4];
    int dil[4];
    int coff[4];
};

// ---------------- merged ASPP HMMA kernel: 256x128 tile, tri-buffer, Bx4 -----------
// branch = blockIdx.z (0: 1x1, 1-3: dilated 3x3). LN+GELU -> catT bf16 split.
__global__ void __launch_bounds__(512, 1) k_aspp(
    AsppArgs A_, const __nv_bfloat16* __restrict__ Ihi, const __nv_bfloat16* __restrict__ Ilo,
    __nv_bfloat16* __restrict__ cth, __nv_bfloat16* __restrict__ ctl) {
    extern __shared__ __align__(16) char dsm[];
    __shared__ int s_tapn, s_tp[9], s_dy[9], s_dx[9];
    __shared__ float sgam[256], sbet[256], smean[128], srstd[128];
    __shared__ float red4[4][128];

    const int br = blockIdx.z, b = blockIdx.y, y = blockIdx.x;
    const int t = threadIdx.x, wid = t >> 5, lane = t & 31;
    const int mw = wid >> 2, nw = wid & 3;
    const uint32_t sbase = (uint32_t)__cvta_generic_to_shared(dsm);
    const __nv_bfloat16* Whi = A_.wh[br];
    const __nv_bfloat16* Wlo = A_.wl[br];
    const int dil = A_.dil[br], coff = A_.coff[br];

    if (t == 0) {
        if (dil == 0) {
            s_tapn = 1; s_tp[0] = 0; s_dy[0] = 0; s_dx[0] = 0;
        } else {
            int n = 0;
            for (int tap = 0; tap < 9; tap++) {
                int dy = (tap / 3 - 1) * dil;
                int y0 = y * 2 + dy, y1 = y * 2 + 1 + dy;
                if ((unsigned)y0 < 64u || (unsigned)y1 < 64u) {
                    s_tp[n] = tap; s_dy[n] = dy; s_dx[n] = (tap % 3 - 1) * dil; n++;
                }
            }
            s_tapn = n;
        }
    }
    if (t < 256) { sgam[t] = A_.g[br][t]; sbet[t] = A_.bt[br][t]; }
    __syncthreads();

    const int T = s_tapn * 8;
    const __nv_bfloat16* Ib_hi = Ihi + (size_t)b * HW * CIN;
    const __nv_bfloat16* Ib_lo = Ilo + (size_t)b * HW * CIN;

    float acc[4][4][4];
#pragma unroll
    for (int i = 0; i < 4; i++)
#pragma unroll
        for (int j = 0; j < 4; j++)
#pragma unroll
            for (int r = 0; r < 4; r++) acc[i][j][r] = 0.f;

    auto loadG = [&](int it, int buf) {
        int tap_i = it >> 3;
        int kc = (it & 7) * 32;
        uint32_t base = sbase + buf * 61440;
        int arow = t >> 1, ak = (t & 1) * 16;
        int grow = s_tp[tap_i] * 256 + arow;
        const __nv_bfloat16* ah = Whi + (size_t)grow * CIN + kc + ak;
        const __nv_bfloat16* al = Wlo + (size_t)grow * CIN + kc + ak;
        uint32_t da = base + arow * 80 + ak * 2;
        cp16(da, ah, 16);
        cp16(da + 16, ah + 8, 16);
        cp16(da + 20480, al, 16);
        cp16(da + 20480 + 16, al + 8, 16);
        int n = t >> 2, q = t & 3;
        int hw; int ok = 16;
        int yy = y * 2 + (n >> 6) + s_dy[tap_i];
        int xx = (n & 63) + s_dx[tap_i];
        if ((unsigned)yy < 64u && (unsigned)xx < 64u) hw = yy * 64 + xx;
        else { hw = 0; ok = (dil == 0) ? 16 : 0; }
        if (dil == 0) hw = y * 128 + n;
        uint32_t db = base + 40960 + n * 80 + q * 16;
        cp16(db, Ib_hi + (size_t)hw * CIN + kc + q * 8, ok);
        cp16(db + 10240, Ib_lo + (size_t)hw * CIN + kc + q * 8, ok);
        CP_COMMIT();
    };

    loadG(0, 0);
    if (T > 1) loadG(1, 1);

    const int lr = lane >> 2, lc = 2 * (lane & 3);
    const uint32_t a_loff = (uint32_t)(((lane & 7) + ((lane >> 3) & 1) * 8) * 80
                                       + (lane >> 4) * 16);
    const uint32_t b_loff4 = (uint32_t)(((lane & 7) + ((lane >> 4) & 1) * 8) * 80
                                        + ((lane >> 3) & 1) * 16);
    const uint32_t a_wbase = (uint32_t)(mw * 64 * 80) + a_loff;
    const uint32_t b_wbase = 40960u + (uint32_t)(nw * 32 * 80) + b_loff4;

    int cur = 0;
    for (int it = 0; it < T; ++it) {
        if (it + 1 < T) CP_WAIT1(); else CP_WAIT0();
        __syncthreads();
        uint32_t sb = sbase + cur * 61440;
#pragma unroll
        for (int ks = 0; ks < 2; ks++) {
            uint32_t kboff = ks * 32;
            uint32_t bh[4][2], bl[4][2];
#pragma unroll
            for (int jp = 0; jp < 2; jp++) {
                uint32_t ba = sb + b_wbase + jp * (16 * 80) + kboff;
                uint32_t r[4];
                ldsm_x4(r, ba);
                bh[2 * jp][0] = r[0]; bh[2 * jp][1] = r[1];
                bh[2 * jp + 1][0] = r[2]; bh[2 * jp + 1][1] = r[3];
                ldsm_x4(r, ba + 10240);
                bl[2 * jp][0] = r[0]; bl[2 * jp][1] = r[1];
                bl[2 * jp + 1][0] = r[2]; bl[2 * jp + 1][1] = r[3];
            }
#pragma unroll
            for (int i = 0; i < 4; i++) {
                uint32_t aa = sb + a_wbase + i * (16 * 80) + kboff;
                uint32_t ah[4], al[4];
                ldsm_x4(ah, aa);
                ldsm_x4(al, aa + 20480);
#pragma unroll
                for (int j = 0; j < 4; j++) {
                    mma16816(acc[i][j], ah, bh[j]);
                    mma16816(acc[i][j], ah, bl[j]);
                    mma16816(acc[i][j], al, bh[j]);
                }
            }
        }
        if (it + 2 < T) loadG(it + 2, (cur + 2 >= 3) ? cur - 1 : cur + 2);
        cur = (cur + 1 == 3) ? 0 : cur + 1;
    }
    __syncthreads();

    float* Ds = reinterpret_cast<float*>(dsm);
#pragma unroll
    for (int i = 0; i < 4; i++) {
        int r0 = mw * 64 + i * 16 + lr;
#pragma unroll
        for (int j = 0; j < 4; j++) {
            int c = nw * 32 + j * 8 + lc;
            Ds[r0 * 129 + c] = acc[i][j][0];
            Ds[r0 * 129 + c + 1] = acc[i][j][1];
            Ds[(r0 + 8) * 129 + c] = acc[i][j][2];
            Ds[(r0 + 8) * 129 + c + 1] = acc[i][j][3];
        }
    }
    __syncthreads();
    {
        int n = t & 127, p = t >> 7;
        float s = 0.f;
        for (int mm = p * 64; mm < p * 64 + 64; mm++) s += Ds[mm * 129 + n];
        red4[p][n] = s;
        __syncthreads();
        if (t < 128)
            smean[t] = (red4[0][t] + red4[1][t] + red4[2][t] + red4[3][t]) * (1.f / 256.f);
        __syncthreads();
        float mu = smean[n];
        s = 0.f;
        for (int mm = p * 64; mm < p * 64 + 64; mm++) {
            float d = Ds[mm * 129 + n] - mu; s += d * d;
        }
        red4[p][n] = s;
        __syncthreads();
        if (t < 128)
            srstd[t] = rsqrtf((red4[0][t] + red4[1][t] + red4[2][t] + red4[3][t]) * (1.f / 256.f) + 1e-6f);
        __syncthreads();
    }
    {
        int n2 = t >> 2, m0q = (t & 3) * 64;
        float mu = smean[n2], rs = srstd[n2];
        size_t rowb = ((size_t)b * HW + y * 128 + n2) * 1280 + coff + m0q;
#pragma unroll
        for (int blk = 0; blk < 64; blk += 8) {
            __align__(16) unsigned short h8[8], l8[8];
#pragma unroll
            for (int j = 0; j < 8; j++) {
                int m = m0q + blk + j;
                float vv = gelu_f((Ds[m * 129 + n2] - mu) * rs * sgam[m] + sbet[m]);
                __nv_bfloat16 h, l; splitf(vv, h, l);
                h8[j] = *reinterpret_cast<unsigned short*>(&h);
                l8[j] = *reinterpret_cast<unsigned short*>(&l);
            }
            *reinterpret_cast<uint4*>(cth + rowb + blk) = *reinterpret_cast<uint4*>(h8);
            *reinterpret_cast<uint4*>(ctl + rowb + blk) = *reinterpret_cast<uint4*>(l8);
        }
    }
}

// ---------------- HMMA GEMM (proj EPI1 / conv2 EPI2), tri-buffer, Bx4 ----------
template <int EPI>
__global__ void __launch_bounds__(512, 1) k_hgemm(
    const __nv_bfloat16* __restrict__ Whi, const __nv_bfloat16* __restrict__ Wlo,
    const __nv_bfloat16* __restrict__ Ihi, const __nv_bfloat16* __restrict__ Ilo,
    const float* __restrict__ gam, const float* __restrict__ bet,
    float* __restrict__ outF, int Kc) {
    extern __shared__ __align__(16) char dsm[];
    __shared__ float sgam[256], sbet[256], smean[128], srstd[128];
    __shared__ float red4[4][128];

    const int b = blockIdx.y, y = blockIdx.x;
    const int t = threadIdx.x, wid = t >> 5, lane = t & 31;
    const int mw = wid >> 2, nw = wid & 3;
    const uint32_t sbase = (uint32_t)__cvta_generic_to_shared(dsm);

    if (t < 256) { sgam[t] = gam[t]; sbet[t] = bet[t]; }
    __syncthreads();

    const int T = Kc / 32;
    const __nv_bfloat16* Ib_hi = Ihi + (size_t)b * HW * Kc;
    const __nv_bfloat16* Ib_lo = Ilo + (size_t)b * HW * Kc;

    float acc[4][4][4];
#pragma unroll
    for (int i = 0; i < 4; i++)
#pragma unroll
        for (int j = 0; j < 4; j++)
#pragma unroll
            for (int r = 0; r < 4; r++) acc[i][j][r] = 0.f;

    auto loadG = [&](int it, int buf) {
        int kc = it * 32;
        uint32_t base = sbase + buf * 61440;
        int arow = t >> 1, ak = (t & 1) * 16;
        const __nv_bfloat16* ah = Whi + (size_t)arow * Kc + kc + ak;
        const __nv_bfloat16* al = Wlo + (size_t)arow * Kc + kc + ak;
        uint32_t da = base + arow * 80 + ak * 2;
        cp16(da, ah, 16);
        cp16(da + 16, ah + 8, 16);
        cp16(da + 20480, al, 16);
        cp16(da + 20480 + 16, al + 8, 16);
        int n = t >> 2, q = t & 3;
        int hw = y * 128 + n;
        uint32_t db = base + 40960 + n * 80 + q * 16;
        cp16(db, Ib_hi + (size_t)hw * Kc + kc + q * 8, 16);
        cp16(db + 10240, Ib_lo + (size_t)hw * Kc + kc + q * 8, 16);
        CP_COMMIT();
    };

    loadG(0, 0);
    if (T > 1) loadG(1, 1);

    const int lr = lane >> 2, lc = 2 * (lane & 3);
    const uint32_t a_loff = (uint32_t)(((lane & 7) + ((lane >> 3) & 1) * 8) * 80
                                       + (lane >> 4) * 16);
    const uint32_t b_loff4 = (uint32_t)(((lane & 7) + ((lane >> 4) & 1) * 8) * 80
                                        + ((lane >> 3) & 1) * 16);
    const uint32_t a_wbase = (uint32_t)(mw * 64 * 80) + a_loff;
    const uint32_t b_wbase = 40960u + (uint32_t)(nw * 32 * 80) + b_loff4;

    int cur = 0;
    for (int it = 0; it < T; ++it) {
        if (it + 1 < T) CP_WAIT1(); else CP_WAIT0();
        __syncthreads();
        uint32_t sb = sbase + cur * 61440;
#pragma unroll
        for (int ks = 0; ks < 2; ks++) {
            uint32_t kboff = ks * 32;
            uint32_t bh[4][2], bl[4][2];
#pragma unroll
            for (int jp = 0; jp < 2; jp++) {
                uint32_t ba = sb + b_wbase + jp * (16 * 80) + kboff;
                uint32_t r[4];
                ldsm_x4(r, ba);
                bh[2 * jp][0] = r[0]; bh[2 * jp][1] = r[1];
                bh[2 * jp + 1][0] = r[2]; bh[2 * jp + 1][1] = r[3];
                ldsm_x4(r, ba + 10240);
                bl[2 * jp][0] = r[0]; bl[2 * jp][1] = r[1];
                bl[2 * jp + 1][0] = r[2]; bl[2 * jp + 1][1] = r[3];
            }
#pragma unroll
            for (int i = 0; i < 4; i++) {
                uint32_t aa = sb + a_wbase + i * (16 * 80) + kboff;
                uint32_t ah[4], al[4];
                ldsm_x4(ah, aa);
                ldsm_x4(al, aa + 20480);
#pragma unroll
                for (int j = 0; j < 4; j++) {
                    mma16816(acc[i][j], ah, bh[j]);
                    mma16816(acc[i][j], ah, bl[j]);
                    mma16816(acc[i][j], al, bh[j]);
                }
            }
        }
        if (it + 2 < T) loadG(it + 2, (cur + 2 >= 3) ? cur - 1 : cur + 2);
        cur = (cur + 1 == 3) ? 0 : cur + 1;
    }
    __syncthreads();

    float* Ds = reinterpret_cast<float*>(dsm);
#pragma unroll
    for (int i = 0; i < 4; i++) {
        int r0 = mw * 64 + i * 16 + lr;
#pragma unroll
        for (int j = 0; j < 4; j++) {
            int c = nw * 32 + j * 8 + lc;
            Ds[r0 * 129 + c] = acc[i][j][0];
            Ds[r0 * 129 + c + 1] = acc[i][j][1];
            Ds[(r0 + 8) * 129 + c] = acc[i][j][2];
            Ds[(r0 + 8) * 129 + c + 1] = acc[i][j][3];
        }
    }
    __syncthreads();
    if (EPI == 1) {
        int n = t & 127, p = t >> 7;
        float s = 0.f;
        for (int mm = p * 64; mm < p * 64 + 64; mm++) s += Ds[mm * 129 + n];
        red4[p][n] = s;
        __syncthreads();
        if (t < 128)
            smean[t] = (red4[0][t] + red4[1][t] + red4[2][t] + red4[3][t]) * (1.f / 256.f);
        __syncthreads();
        float mu = smean[n];
        s = 0.f;
        for (int mm = p * 64; mm < p * 64 + 64; mm++) {
            float d = Ds[mm * 129 + n] - mu; s += d * d;
        }
        red4[p][n] = s;
        __syncthreads();
        if (t < 128)
            srstd[t] = rsqrtf((red4[0][t] + red4[1][t] + red4[2][t] + red4[3][t]) * (1.f / 256.f) + 1e-6f);
        __syncthreads();
        int m = t >> 1, nh = (t & 1) * 64;
        float gmm = sgam[m], bt2 = sbet[m];
        size_t ob = ((size_t)b * CIN + m) * HW + y * 128 + nh;
#pragma unroll
        for (int blk = 0; blk < 64; blk += 4) {
            float4 v4;
            float* vp = &v4.x;
#pragma unroll
            for (int j = 0; j < 4; j++) {
                int n3 = nh + blk + j;
                vp[j] = gelu_f((Ds[m * 129 + n3] - smean[n3]) * srstd[n3] * gmm + bt2);
            }
            *reinterpret_cast<float4*>(outF + ob + blk) = v4;
        }
    } else {
        int m = t >> 1, nh = (t & 1) * 64;
        float bias = sgam[m];
        size_t ob = ((size_t)b * CIN + m) * HW + y * 128 + nh;
#pragma unroll
        for (int blk = 0; blk < 64; blk += 4) {
            float4 v4;
            float* vp = &v4.x;
#pragma unroll
            for (int j = 0; j < 4; j++) vp[j] = Ds[m * 129 + nh + blk + j] + bias;
            *reinterpret_cast<float4*>(outF + ob + blk) = v4;
        }
    }
}

// ---------------- HMMA S-GEMM: 256(q)x128(p), tri-buffer, Bx4 ----------
__global__ void __launch_bounds__(512, 1) k_sgemm2() {
    extern __shared__ __align__(16) char dsm[];
    const int b = blockIdx.z, q0 = blockIdx.y * 256, p0 = blockIdx.x * 128;
    const int t = threadIdx.x, wid = t >> 5, lane = t & 31;
    const int mw = wid >> 2, nw = wid & 3;
    const uint32_t sbase = (uint32_t)__cvta_generic_to_shared(dsm);
    const __nv_bfloat16* Qh = g_xath + (size_t)b * HW * COUT;
    const __nv_bfloat16* Ql = g_xatl + (size_t)b * HW * COUT;
    const __nv_bfloat16* Ph = g_x1th + (size_t)b * HW * COUT;
    const __nv_bfloat16* Pl = g_x1tl + (size_t)b * HW * COUT;

    float acc[4][4][4];
#pragma unroll
    for (int i = 0; i < 4; i++)
#pragma unroll
        for (int j = 0; j < 4; j++)
#pragma unroll
            for (int r = 0; r < 4; r++) acc[i][j][r] = 0.f;

    auto loadG = [&](int it, int buf) {
        int kc = it * 32;
        uint32_t base = sbase + buf * 61440;
        int arow = t >> 1, ak = (t & 1) * 16;
        const __nv_bfloat16* ah = Qh + (size_t)(q0 + arow) * COUT + kc + ak;
        const __nv_bfloat16* al = Ql + (size_t)(q0 + arow) * COUT + kc + ak;
        uint32_t da = base + arow * 80 + ak * 2;
        cp16(da, ah, 16);
        cp16(da + 16, ah + 8, 16);
        cp16(da + 20480, al, 16);
        cp16(da + 20480 + 16, al + 8, 16);
        int n = t >> 2, q = t & 3;
        uint32_t db = base + 40960 + n * 80 + q * 16;
        cp16(db, Ph + (size_t)(p0 + n) * COUT + kc + q * 8, 16);
        cp16(db + 10240, Pl + (size_t)(p0 + n) * COUT + kc + q * 8, 16);
        CP_COMMIT();
    };

    loadG(0, 0);
    loadG(1, 1);

    const int lr = lane >> 2, lc = 2 * (lane & 3);
    const uint32_t a_loff = (uint32_t)(((lane & 7) + ((lane >> 3) & 1) * 8) * 80
                                       + (lane >> 4) * 16);
    const uint32_t b_loff4 = (uint32_t)(((lane & 7) + ((lane >> 4) & 1) * 8) * 80
                                        + ((lane >> 3) & 1) * 16);
    const uint32_t a_wbase = (uint32_t)(mw * 64 * 80) + a_loff;
    const uint32_t b_wbase = 40960u + (uint32_t)(nw * 32 * 80) + b_loff4;

    const int T = COUT / 32;
    int cur = 0;
    for (int it = 0; it < T; ++it) {
        if (it + 1 < T) CP_WAIT1(); else CP_WAIT0();
        __syncthreads();
        uint32_t sb = sbase + cur * 61440;
#pragma unroll
        for (int ks = 0; ks < 2; ks++) {
            uint32_t kboff = ks * 32;
            uint32_t bh[4][2], bl[4][2];
#pragma unroll
            for (int jp = 0; jp < 2; jp++) {
                uint32_t ba = sb + b_wbase + jp * (16 * 80) + kboff;
                uint32_t r[4];
                ldsm_x4(r, ba);
                bh[2 * jp][0] = r[0]; bh[2 * jp][1] = r[1];
                bh[2 * jp + 1][0] = r[2]; bh[2 * jp + 1][1] = r[3];
                ldsm_x4(r, ba + 10240);
                bl[2 * jp][0] = r[0]; bl[2 * jp][1] = r[1];
                bl[2 * jp + 1][0] = r[2]; bl[2 * jp + 1][1] = r[3];
            }
#pragma unroll
            for (int i = 0; i < 4; i++) {
                uint32_t aa = sb + a_wbase + i * (16 * 80) + kboff;
                uint32_t ah[4], al[4];
                ldsm_x4(ah, aa);
                ldsm_x4(al, aa + 20480);
#pragma unroll
                for (int j = 0; j < 4; j++) {
                    mma16816(acc[i][j], ah, bh[j]);
                    mma16816(acc[i][j], ah, bl[j]);
                    mma16816(acc[i][j], al, bh[j]);
                }
            }
        }
        if (it + 2 < T) loadG(it + 2, (cur + 2 >= 3) ? cur - 1 : cur + 2);
        cur = (cur + 1 == 3) ? 0 : cur + 1;
    }
    __syncthreads();

    float* Ds = reinterpret_cast<float*>(dsm);
#pragma unroll
    for (int i = 0; i < 4; i++) {
        int r0 = mw * 64 + i * 16 + lr;
#pragma unroll
        for (int j = 0; j < 4; j++) {
            int c = nw * 32 + j * 8 + lc;
            Ds[r0 * 129 + c] = acc[i][j][0];
            Ds[r0 * 129 + c + 1] = acc[i][j][1];
            Ds[(r0 + 8) * 129 + c] = acc[i][j][2];
            Ds[(r0 + 8) * 129 + c + 1] = acc[i][j][3];
        }
    }
    __syncthreads();
    {
        const float sc = 1.f / 64.f;
        int m = t >> 1, nh = (t & 1) * 64;
        float* So = g_S + (size_t)b * HW * HW + (size_t)(q0 + m) * HW + p0 + nh;
#pragma unroll
        for (int blk = 0; blk < 64; blk += 4) {
            float4 v4;
            float* vp = &v4.x;
#pragma unroll
            for (int j = 0; j < 4; j++) vp[j] = Ds[m * 129 + nh + blk + j] * sc;
            *reinterpret_cast<float4*>(So + blk) = v4;
        }
    }
}

// ---------------- row softmax; emits bf16 hi/lo probs ----------------
__global__ void __launch_bounds__(256) k_softmax() {
    const size_t row = blockIdx.x;
    const float* r = g_S + row * (size_t)HW;
    __nv_bfloat16* oh = g_Ah + row * (size_t)HW;
    __nv_bfloat16* ol = g_Al + row * (size_t)HW;
    __shared__ float buf[HW];
    __shared__ float red[256];
    int t = threadIdx.x;
    float m = -1e30f;
    for (int i = t; i < HW; i += 256) { float v = r[i]; buf[i] = v; m = fmaxf(m, v); }
    red[t] = m; __syncthreads();
    for (int s = 128; s > 0; s >>= 1) { if (t < s) red[t] = fmaxf(red[t], red[t + s]); __syncthreads(); }
    float mx = red[0]; __syncthreads();
    float s = 0.f;
    for (int i = t; i < HW; i += 256) { float e = expf(buf[i] - mx); buf[i] = e; s += e; }
    red[t] = s; __syncthreads();
    for (int o = 128; o > 0; o >>= 1) { if (t < o) red[t] += red[t + o]; __syncthreads(); }
    float inv = 1.f / red[0];
    for (int i = t; i < HW; i += 256) {
        float p = buf[i] * inv;
        __nv_bfloat16 h, l; splitf(p, h, l);
        oh[i] = h; ol[i] = l;
    }
}

// ---------------- HMMA L-GEMM: 128(c)x128(j), tri-buffer, trans-B x4 ----------
__global__ void __launch_bounds__(512, 1) k_lgemm2() {
    extern __shared__ __align__(16) char dsm[];
    const int b = blockIdx.y, j0g = blockIdx.x * 128;
    const int t = threadIdx.x, wid = t >> 5, lane = t & 31;
    const int mw = wid >> 2, nw = wid & 3;
    const uint32_t sbase = (uint32_t)__cvta_generic_to_shared(dsm);
    const __nv_bfloat16* Xh = g_x1h + (size_t)b * COUT * HW;
    const __nv_bfloat16* Xl = g_x1l + (size_t)b * COUT * HW;
    const __nv_bfloat16* Aph = g_Ah + (size_t)b * HW * HW;
    const __nv_bfloat16* Apl = g_Al + (size_t)b * HW * HW;

    float acc[2][4][4];
#pragma unroll
    for (int i = 0; i < 2; i++)
#pragma unroll
        for (int j = 0; j < 4; j++)
#pragma unroll
            for (int r = 0; r < 4; r++) acc[i][j][r] = 0.f;

    auto loadG = [&](int it, int buf) {
        int kc = it * 32;
        uint32_t base = sbase + buf * 37888;
        int c = t >> 2, cq = t & 3;
        const __nv_bfloat16* ah = Xh + (size_t)c * HW + kc + cq * 8;
        const __nv_bfloat16* al = Xl + (size_t)c * HW + kc + cq * 8;
        uint32_t da = base + c * 80 + cq * 16;
        cp16(da, ah, 16);
        cp16(da + 10240, al, 16);
        int k = t >> 4, jt = t & 15;
        const __nv_bfloat16* bh = Aph + (size_t)(kc + k) * HW + j0g + jt * 8;
        const __nv_bfloat16* bl = Apl + (size_t)(kc + k) * HW + j0g + jt * 8;
        uint32_t db = base + 20480 + k * 272 + jt * 16;
        cp16(db, bh, 16);
        cp16(db + 8704, bl, 16);
        CP_COMMIT();
    };

    loadG(0, 0);
    loadG(1, 1);

    const int lr = lane >> 2, lc = 2 * (lane & 3);
    const uint32_t a_loff = (uint32_t)(((lane & 7) + ((lane >> 3) & 1) * 8) * 80
                                       + (lane >> 4) * 16);
    const uint32_t a_wbase = (uint32_t)(mw * 32 * 80) + a_loff;
    const uint32_t bt_loff4 = (uint32_t)((lane & 15) * 272 + ((lane >> 4) & 1) * 16);

    const int T = HW / 32;
    int cur = 0;
    for (int it = 0; it < T; ++it) {
        if (it + 1 < T) CP_WAIT1(); else CP_WAIT0();
        __syncthreads();
        uint32_t sb = sbase + cur * 37888;
#pragma unroll
        for (int ks = 0; ks < 2; ks++) {
            uint32_t bh[4][2], bl[4][2];
#pragma unroll
            for (int jp = 0; jp < 2; jp++) {
                uint32_t ba = sb + 20480 + bt_loff4 + ks * (16 * 272)
                              + (nw * 32 + jp * 16) * 2;
                uint32_t r[4];
                ldsm_x4t(r, ba);
                bh[2 * jp][0] = r[0]; bh[2 * jp][1] = r[1];
                bh[2 * jp + 1][0] = r[2]; bh[2 * jp + 1][1] = r[3];
                ldsm_x4t(r, ba + 8704);
                bl[2 * jp][0] = r[0]; bl[2 * jp][1] = r[1];
                bl[2 * jp + 1][0] = r[2]; bl[2 * jp + 1][1] = r[3];
            }
#pragma unroll
            for (int i = 0; i < 2; i++) {
                uint32_t aa = sb + a_wbase + i * (16 * 80) + ks * 32;
                uint32_t ah[4], al[4];
                ldsm_x4(ah, aa);
                ldsm_x4(al, aa + 10240);
#pragma unroll
                for (int j = 0; j < 4; j++) {
                    mma16816(acc[i][j], ah, bh[j]);
                    mma16816(acc[i][j], ah, bl[j]);
                    mma16816(acc[i][j], al, bh[j]);
                }
            }
        }
        if (it + 2 < T) loadG(it + 2, (cur + 2 >= 3) ? cur - 1 : cur + 2);
        cur = (cur + 1 == 3) ? 0 : cur + 1;
    }
    __syncthreads();

    const float* xab = g_xa + (size_t)b * COUT * HW;
    float* Ds = reinterpret_cast<float*>(dsm);
#pragma unroll
    for (int i = 0; i < 2; i++) {
#pragma unroll
        for (int j = 0; j < 4; j++) {
            int c = mw * 32 + i * 16 + lr;
            int col = nw * 32 + j * 8 + lc;
            size_t i0 = (size_t)c * HW + j0g + col;
            size_t i8 = (size_t)(c + 8) * HW + j0g + col;
            float2 x0 = *reinterpret_cast<const float2*>(xab + i0);
            float2 x8 = *reinterpret_cast<const float2*>(xab + i8);
            Ds[col * 129 + c] = acc[i][j][0] + x0.x;
            Ds[(col + 1) * 129 + c] = acc[i][j][1] + x0.y;
            Ds[col * 129 + c + 8] = acc[i][j][2] + x8.x;
            Ds[(col + 1) * 129 + c + 8] = acc[i][j][3] + x8.y;
        }
    }
    __syncthreads();
    {
        int jj = t >> 2, c0q = (t & 3) * 32;
        size_t rowb = ((size_t)b * HW + j0g + jj) * COUT + c0q;
#pragma unroll
        for (int blk = 0; blk < 32; blk += 8) {
            __align__(16) unsigned short h8[8], l8[8];
#pragma unroll
            for (int j = 0; j < 8; j++) {
                float vv = Ds[jj * 129 + c0q + blk + j];
                __nv_bfloat16 h, l; splitf(vv, h, l);
                h8[j] = *reinterpret_cast<unsigned short*>(&h);
                l8[j] = *reinterpret_cast<unsigned short*>(&l);
            }
            *reinterpret_cast<uint4*>(g_oth + rowb + blk) = *reinterpret_cast<uint4*>(h8);
            *reinterpret_cast<uint4*>(g_otl + rowb + blk) = *reinterpret_cast<uint4*>(l8);
        }
    }
}

// ---------------- FFMA pipelined GEMM (conv1 x2) ----------------
template <int BM, int MODE>
__global__ void __launch_bounds__(256, 2) k_gemm(
    const float* __restrict__ Wg, size_t wb_stride,
    const float* __restrict__ In, size_t in_bstride,
    const float* __restrict__ P1,
    const float* __restrict__ Addp, size_t add_bstride,
    float* __restrict__ Out, size_t out_bstride,
    int Kc) {
    constexpr int TM = BM / 32;
    constexpr int NAREG = (BM == 256) ? 4 : 2;
    const int b = blockIdx.y;
    const int y = blockIdx.x;
    const int n0 = y * BN;
    const int t = threadIdx.x;
    const int ty = t >> 3, tx = t & 7;

    __shared__ __align__(16) float As[2][KT][BM];
    __shared__ __align__(16) float Bs[2][KT][BN];

    const int total = Kc / KT;
    const float* Wb = Wg + (size_t)b * wb_stride;
    const float* Inb = In + (size_t)b * in_bstride;

    ull acc2[TM][4];
#pragma unroll
    for (int i = 0; i < TM; i++)
#pragma unroll
        for (int j = 0; j < 4; j++) acc2[i][j] = 0ULL;

    float4 ra[NAREG];
    float rb[4];

    auto loadG = [&](int it) {
        int k0 = it * KT;
        if (BM == 256) {
            const float* wrow = Wb + (size_t)t * Kc + k0;
#pragma unroll
            for (int q = 0; q < 4; q++)
                ra[q] = *reinterpret_cast<const float4*>(wrow + q * 4);
        } else {
            int m = t >> 1, ko = (t & 1) * 8;
            const float* wrow = Wb + (size_t)m * Kc + k0 + ko;
#pragma unroll
            for (int q = 0; q < 2; q++)
                ra[q] = *reinterpret_cast<const float4*>(wrow + q * 4);
        }
        int k = t >> 4, nb = (t & 15) * 4;
        float4 v = *reinterpret_cast<const float4*>(Inb + (size_t)(k0 + k) * HW + n0 + nb);
        rb[0] = v.x; rb[1] = v.y; rb[2] = v.z; rb[3] = v.w;
    };
    auto storeS = [&](int buf) {
        if (BM == 256) {
#pragma unroll
            for (int q = 0; q < 4; q++) {
                As[buf][q * 4 + 0][t] = ra[q].x; As[buf][q * 4 + 1][t] = ra[q].y;
                As[buf][q * 4 + 2][t] = ra[q].z; As[buf][q * 4 + 3][t] = ra[q].w;
            }
        } else {
            int m = t >> 1, ko = (t & 1) * 8;
#pragma unroll
            for (int q = 0; q < 2; q++) {
                As[buf][ko + q * 4 + 0][m] = ra[q].x; As[buf][ko + q * 4 + 1][m] = ra[q].y;
                As[buf][ko + q * 4 + 2][m] = ra[q].z; As[buf][ko + q * 4 + 3][m] = ra[q].w;
            }
        }
        int k = t >> 4, nb = (t & 15) * 4;
        Bs[buf][k][nb] = rb[0]; Bs[buf][k][nb + 1] = rb[1];
        Bs[buf][k][nb + 2] = rb[2]; Bs[buf][k][nb + 3] = rb[3];
    };

    loadG(0);
    storeS(0);
    __syncthreads();

    for (int it = 0; it < total; ++it) {
        int cur = it & 1;
        bool more = (it + 1 < total);
        if (more) loadG(it + 1);
#pragma unroll
        for (int k = 0; k < KT; k++) {
            ull a2[TM], b2[4];
#pragma unroll
            for (int i = 0; i < TM; i += 4) {
                float4 v = *reinterpret_cast<const float4*>(&As[cur][k][ty * TM + i]);
                a2[i] = pack2f(v.x); a2[i + 1] = pack2f(v.y);
                a2[i + 2] = pack2f(v.z); a2[i + 3] = pack2f(v.w);
            }
            {
                float4 v0 = *reinterpret_cast<const float4*>(&Bs[cur][k][tx * 8]);
                float4 v1 = *reinterpret_cast<const float4*>(&Bs[cur][k][tx * 8 + 4]);
                b2[0] = pack2(v0.x, v0.y); b2[1] = pack2(v0.z, v0.w);
                b2[2] = pack2(v1.x, v1.y); b2[3] = pack2(v1.z, v1.w);
            }
#pragma unroll
            for (int i = 0; i < TM; i++)
#pragma unroll
                for (int j = 0; j < 4; j++) fma2(acc2[i][j], a2[i], b2[j]);
        }
        if (more) storeS(cur ^ 1);
        __syncthreads();
    }

    float* Ob = Out + (size_t)b * out_bstride;
#pragma unroll
    for (int i = 0; i < TM; i++) {
        int m = ty * TM + i;
        float bias = (MODE == 0) ? P1[m] : 0.f;
        const float* addrow = (MODE == 2)
            ? (Addp + (size_t)b * add_bstride + (size_t)m * HW + n0 + tx * 8)
            : nullptr;
        float o8[8];
#pragma unroll
        for (int j = 0; j < 4; j++) {
            float2 f = unpk2(acc2[i][j]);
            o8[2 * j] = f.x + bias; o8[2 * j + 1] = f.y + bias;
            if (MODE == 2) { o8[2 * j] += addrow[2 * j]; o8[2 * j + 1] += addrow[2 * j + 1]; }
        }
        float* dst = Ob + (size_t)m * HW + n0 + tx * 8;
        *reinterpret_cast<float4*>(dst) = make_float4(o8[0], o8[1], o8[2], o8[3]);
        *reinterpret_cast<float4*>(dst + 4) = make_float4(o8[4], o8[5], o8[6], o8[7]);
    }
}

// ---------------- host launch ----------------
extern "C" void kernel_launch(void* const* d_in, const int* in_sizes, int n_in,
                              void* d_out, int out_size) {
    (void)in_sizes; (void)n_in; (void)out_size;
    const float* x       = (const float*)d_in[0];
    const float* conv1_w = (const float*)d_in[1];
    const float* conv1_b = (const float*)d_in[2];
    const float* conv2_w = (const float*)d_in[3];
    const float* conv2_b = (const float*)d_in[4];
    const float* cw_w1   = (const float*)d_in[5];
    const float* cw_b1   = (const float*)d_in[6];
    const float* cw_ln_g = (const float*)d_in[7];
    const float* cw_ln_b = (const float*)d_in[8];
    const float* cw_w2   = (const float*)d_in[9];
    const float* cw_b2   = (const float*)d_in[10];
    const float* aspp0_w = (const float*)d_in[11];
    const float* aspp0_g = (const float*)d_in[12];
    const float* aspp0_b = (const float*)d_in[13];
    const float* aspp1_w = (const float*)d_in[14];
    const float* aspp1_g = (const float*)d_in[15];
    const float* aspp1_b = (const float*)d_in[16];
    const float* aspp2_w = (const float*)d_in[17];
    const float* aspp2_g = (const float*)d_in[18];
    const float* aspp2_b = (const float*)d_in[19];
    const float* aspp3_w = (const float*)d_in[20];
    const float* aspp3_g = (const float*)d_in[21];
    const float* aspp3_b = (const float*)d_in[22];
    const float* asppp_w = (const float*)d_in[23];
    const float* asppp_g = (const float*)d_in[24];
    const float* asppp_b = (const float*)d_in[25];
    const float* proj_w  = (const float*)d_in[26];
    const float* proj_g  = (const float*)d_in[27];
    const float* proj_b  = (const float*)d_in[28];

    void* pv;
    float *p_x1, *p_proj, *p_xa;
    __nv_bfloat16 *p_xth, *p_xtl, *p_cth, *p_ctl, *p_w3h, *p_w3l, *p_a0h, *p_a0l, *p_pjh, *p_pjl;
    __nv_bfloat16 *p_x1th, *p_x1tl, *p_xath, *p_xatl, *p_x1h, *p_x1l, *p_c2h, *p_c2l;
    __nv_bfloat16 *p_oth, *p_otl;
    cudaGetSymbolAddress(&pv, g_x1);   p_x1   = (float*)pv;
    cudaGetSymbolAddress(&pv, g_proj); p_proj = (float*)pv;
    cudaGetSymbolAddress(&pv, g_xa);   p_xa   = (float*)pv;
    cudaGetSymbolAddress(&pv, g_xth);  p_xth  = (__nv_bfloat16*)pv;
    cudaGetSymbolAddress(&pv, g_xtl);  p_xtl  = (__nv_bfloat16*)pv;
    cudaGetSymbolAddress(&pv, g_cth);  p_cth  = (__nv_bfloat16*)pv;
    cudaGetSymbolAddress(&pv, g_ctl);  p_ctl  = (__nv_bfloat16*)pv;
    cudaGetSymbolAddress(&pv, g_w3h);  p_w3h  = (__nv_bfloat16*)pv;
    cudaGetSymbolAddress(&pv, g_w3l);  p_w3l  = (__nv_bfloat16*)pv;
    cudaGetSymbolAddress(&pv, g_a0h);  p_a0h  = (__nv_bfloat16*)pv;
    cudaGetSymbolAddress(&pv, g_a0l);  p_a0l  = (__nv_bfloat16*)pv;
    cudaGetSymbolAddress(&pv, g_pjh);  p_pjh  = (__nv_bfloat16*)pv;
    cudaGetSymbolAddress(&pv, g_pjl);  p_pjl  = (__nv_bfloat16*)pv;
    cudaGetSymbolAddress(&pv, g_c2h);  p_c2h  = (__nv_bfloat16*)pv;
    cudaGetSymbolAddress(&pv, g_c2l);  p_c2l  = (__nv_bfloat16*)pv;
    cudaGetSymbolAddress(&pv, g_x1th); p_x1th = (__nv_bfloat16*)pv;
    cudaGetSymbolAddress(&pv, g_x1tl); p_x1tl = (__nv_bfloat16*)pv;
    cudaGetSymbolAddress(&pv, g_xath); p_xath = (__nv_bfloat16*)pv;
    cudaGetSymbolAddress(&pv, g_xatl); p_xatl = (__nv_bfloat16*)pv;
    cudaGetSymbolAddress(&pv, g_x1h);  p_x1h  = (__nv_bfloat16*)pv;
    cudaGetSymbolAddress(&pv, g_x1l);  p_x1l  = (__nv_bfloat16*)pv;
    cudaGetSymbolAddress(&pv, g_oth);  p_oth  = (__nv_bfloat16*)pv;
    cudaGetSymbolAddress(&pv, g_otl);  p_otl  = (__nv_bfloat16*)pv;

    const int TRI_SMEM = 184320;   // 3 x 61440; epilogue (132096) aliases
    cudaFuncSetAttribute(k_aspp, cudaFuncAttributeMaxDynamicSharedMemorySize, TRI_SMEM);
    cudaFuncSetAttribute(k_hgemm<1>, cudaFuncAttributeMaxDynamicSharedMemorySize, TRI_SMEM);
    cudaFuncSetAttribute(k_hgemm<2>, cudaFuncAttributeMaxDynamicSharedMemorySize, TRI_SMEM);
    cudaFuncSetAttribute(k_sgemm2, cudaFuncAttributeMaxDynamicSharedMemorySize, TRI_SMEM);
    cudaFuncSetAttribute(k_lgemm2, cudaFuncAttributeMaxDynamicSharedMemorySize, 113664);

    dim3 g64(HW / BN, BATCH);
    dim3 gh(HW / 128, BATCH);

    AsppArgs aa;
    aa.wh[0] = p_a0h; aa.wl[0] = p_a0l; aa.g[0] = aspp0_g; aa.bt[0] = aspp0_b;
    aa.dil[0] = 0; aa.coff[0] = 0;
    aa.wh[1] = p_w3h; aa.wl[1] = p_w3l; aa.g[1] = aspp1_g; aa.bt[1] = aspp1_b;
    aa.dil[1] = 3; aa.coff[1] = 256;
    aa.wh[2] = p_w3h + 9 * 65536; aa.wl[2] = p_w3l + 9 * 65536;
    aa.g[2] = aspp2_g; aa.bt[2] = aspp2_b; aa.dil[2] = 6; aa.coff[2] = 512;
    aa.wh[3] = p_w3h + 18 * 65536; aa.wl[3] = p_w3l + 18 * 65536;
    aa.g[3] = aspp3_g; aa.bt[3] = aspp3_b; aa.dil[3] = 9; aa.coff[3] = 768;

    // 1-3: prep (launch #4 = merged ASPP gets profiled)
    k_prep<<<3456, 256>>>(aspp1_w, aspp2_w, aspp3_w, aspp0_w, proj_w, conv2_w, x);
    k_cw<<<BATCH, 256>>>(cw_w1, cw_b1, cw_ln_g, cw_ln_b, cw_w2, cw_b2,
                         asppp_w, asppp_g, asppp_b);
    k_xcsplit<<<dim3(128, 8, BATCH), 256>>>(x);
    // 4: merged ASPP branches (HMMA, tri-buffer, Bx4)
    k_aspp<<<dim3(HW / 128, BATCH, 4), 512, TRI_SMEM>>>(aa, p_xth, p_xtl, p_cth, p_ctl);
    // 5: global-pool branch into catT
    k_bp_cat<<<dim3(128, BATCH), 256>>>();
    // 6: proj (HMMA, K=1280) -> f32
    k_hgemm<1><<<gh, 512, TRI_SMEM>>>(p_pjh, p_pjl, p_cth, p_ctl,
                                      proj_g, proj_b, p_proj, 5 * CIN);
    // 7-8: conv1 twice (FFMA)
    k_gemm<128, 0><<<g64, 256>>>(conv1_w, 0, x, (size_t)CIN * HW, conv1_b,
                                 nullptr, 0, p_x1, (size_t)COUT * HW, CIN);
    k_gemm<128, 0><<<g64, 256>>>(conv1_w, 0, p_proj, (size_t)CIN * HW, conv1_b,
                                 nullptr, 0, p_xa, (size_t)COUT * HW, CIN);
    // 9-10: split x1 (straight + T), xa (T)
    k_splitT<true><<<dim3(128, 4, BATCH), 256>>>(p_x1, p_x1th, p_x1tl, p_x1h, p_x1l);
    k_splitT<false><<<dim3(128, 4, BATCH), 256>>>(p_xa, p_xath, p_xatl, nullptr, nullptr);
    // 11-13: attention
    k_sgemm2<<<dim3(HW / 128, HW / 256, BATCH), 512, TRI_SMEM>>>();
    k_softmax<<<BATCH * HW, 256>>>();
    k_lgemm2<<<dim3(HW / 128, BATCH), 512, 113664>>>();
    // 14: out = conv2(O) + b (HMMA bias epilogue, K=128)
    k_hgemm<2><<<gh, 512, TRI_SMEM>>>(p_c2h, p_c2l, p_oth, p_otl,
                                      conv2_b, conv2_b, (float*)d_out, COUT);
}

// round 12
// speedup vs baseline: 2.8797x; 1.0421x over previous
#include <cuda_runtime.h>
#include <cuda_bf16.h>
#include <math.h>
#include <stdint.h>

#define BATCH 4
#define CIN 256
#define COUT 128
#define HH 64
#define WW 64
#define HW 4096

typedef unsigned long long ull;

// ---------------- scratch (static device globals; no allocs) ----------------
__device__ float g_xa[BATCH * COUT * HW];
__device__ float g_S[(size_t)BATCH * HW * HW];
__device__ float g_avg[BATCH * CIN];
__device__ float g_mx[BATCH * CIN];
__device__ float g_s[BATCH * CIN];
__device__ float g_bp[BATCH * CIN];
// bf16 split operands
__device__ __nv_bfloat16 g_xth[BATCH * HW * CIN];   // xcT hi [b][hw][c]
__device__ __nv_bfloat16 g_xtl[BATCH * HW * CIN];
__device__ __nv_bfloat16 g_xTh[BATCH * HW * CIN];   // raw xT hi [b][hw][c]
__device__ __nv_bfloat16 g_xTl[BATCH * HW * CIN];
__device__ __nv_bfloat16 g_cth[(size_t)BATCH * HW * 5 * CIN];
__device__ __nv_bfloat16 g_ctl[(size_t)BATCH * HW * 5 * CIN];
__device__ __nv_bfloat16 g_pth[BATCH * HW * CIN];   // projT hi [b][hw][c]
__device__ __nv_bfloat16 g_ptl[BATCH * HW * CIN];
__device__ __nv_bfloat16 g_w3h[3 * 9 * CIN * CIN];
__device__ __nv_bfloat16 g_w3l[3 * 9 * CIN * CIN];
__device__ __nv_bfloat16 g_a0h[CIN * CIN];
__device__ __nv_bfloat16 g_a0l[CIN * CIN];
__device__ __nv_bfloat16 g_pjh[CIN * 5 * CIN];
__device__ __nv_bfloat16 g_pjl[CIN * 5 * CIN];
__device__ __nv_bfloat16 g_c2h[CIN * COUT];
__device__ __nv_bfloat16 g_c2l[CIN * COUT];
__device__ __nv_bfloat16 g_c1h[COUT * CIN];
__device__ __nv_bfloat16 g_c1l[COUT * CIN];
// attention operands
__device__ __nv_bfloat16 g_x1th[BATCH * HW * COUT];
__device__ __nv_bfloat16 g_x1tl[BATCH * HW * COUT];
__device__ __nv_bfloat16 g_xath[BATCH * HW * COUT];
__device__ __nv_bfloat16 g_xatl[BATCH * HW * COUT];
__device__ __nv_bfloat16 g_x1h[BATCH * COUT * HW];
__device__ __nv_bfloat16 g_x1l[BATCH * COUT * HW];
__device__ __nv_bfloat16 g_Ah[(size_t)BATCH * HW * HW];
__device__ __nv_bfloat16 g_Al[(size_t)BATCH * HW * HW];
__device__ __nv_bfloat16 g_oth[BATCH * HW * COUT];
__device__ __nv_bfloat16 g_otl[BATCH * HW * COUT];

__device__ __forceinline__ float gelu_f(float x) {
    return 0.5f * x * (1.0f + erff(x * 0.70710678118654752440f));
}
__device__ __forceinline__ void splitf(float v, __nv_bfloat16& h, __nv_bfloat16& l) {
    h = __float2bfloat16(v);
    l = __float2bfloat16(v - __bfloat162float(h));
}

// ---------------- HMMA m16n8k16 bf16 ----------------
__device__ __forceinline__ void mma16816(float* d, const uint32_t* a, const uint32_t* b) {
    asm volatile(
        "mma.sync.aligned.m16n8k16.row.col.f32.bf16.bf16.f32 "
        "{%0,%1,%2,%3}, {%4,%5,%6,%7}, {%8,%9}, {%0,%1,%2,%3};"
        : "+f"(d[0]), "+f"(d[1]), "+f"(d[2]), "+f"(d[3])
        : "r"(a[0]), "r"(a[1]), "r"(a[2]), "r"(a[3]), "r"(b[0]), "r"(b[1]));
}
__device__ __forceinline__ void ldsm_x4(uint32_t* r, uint32_t addr) {
    asm volatile("ldmatrix.sync.aligned.m8n8.x4.shared.b16 {%0,%1,%2,%3}, [%4];"
                 : "=r"(r[0]), "=r"(r[1]), "=r"(r[2]), "=r"(r[3]) : "r"(addr));
}
__device__ __forceinline__ void ldsm_x4t(uint32_t* r, uint32_t addr) {
    asm volatile("ldmatrix.sync.aligned.m8n8.x4.trans.shared.b16 {%0,%1,%2,%3}, [%4];"
                 : "=r"(r[0]), "=r"(r[1]), "=r"(r[2]), "=r"(r[3]) : "r"(addr));
}

// ---------------- cp.async helpers ----------------
__device__ __forceinline__ void cp16(uint32_t d, const void* s, int ssz) {
    asm volatile("cp.async.ca.shared.global [%0], [%1], 16, %2;"
                 :: "r"(d), "l"(s), "r"(ssz) : "memory");
}
#define CP_COMMIT() asm volatile("cp.async.commit_group;" ::: "memory")
#define CP_WAIT1()  asm volatile("cp.async.wait_group 1;" ::: "memory")
#define CP_WAIT0()  asm volatile("cp.async.wait_group 0;" ::: "memory")

// ---------------- prep: weight splits + per-(b,c) stats ----------------
__global__ void k_prep(const float* __restrict__ w1, const float* __restrict__ w2,
                       const float* __restrict__ w3, const float* __restrict__ a0,
                       const float* __restrict__ pj, const float* __restrict__ c2,
                       const float* __restrict__ c1, const float* __restrict__ x) {
    if (blockIdx.x < 2560) {
        int e = blockIdx.x * 256 + threadIdx.x;
        if (e < 196608) {
            const float* srcs[3] = { w1, w2, w3 };
            int conv = e >> 16, mc = e & 65535, m = mc >> 8, c = mc & 255;
            const float* src = srcs[conv] + (size_t)m * 2304 + (size_t)c * 9;
            size_t dbase = (size_t)conv * 9 * 65536 + (size_t)m * 256 + c;
#pragma unroll
            for (int tap = 0; tap < 9; tap++) {
                __nv_bfloat16 h, l; splitf(src[tap], h, l);
                g_w3h[dbase + (size_t)tap * 65536] = h;
                g_w3l[dbase + (size_t)tap * 65536] = l;
            }
        } else if (e < 262144) {
            int i = e - 196608;
            __nv_bfloat16 h, l; splitf(a0[i], h, l);
            g_a0h[i] = h; g_a0l[i] = l;
        } else if (e < 589824) {
            int i = e - 262144;
            __nv_bfloat16 h, l; splitf(pj[i], h, l);
            g_pjh[i] = h; g_pjl[i] = l;
        } else if (e < 622592) {
            int i = e - 589824;
            __nv_bfloat16 h, l; splitf(c2[i], h, l);
            g_c2h[i] = h; g_c2l[i] = l;
        } else if (e < 655360) {
            int i = e - 622592;
            __nv_bfloat16 h, l; splitf(c1[i], h, l);
            g_c1h[i] = h; g_c1l[i] = l;
        }
    } else {
        int bc = blockIdx.x - 2560;
        const float* p = x + (size_t)bc * HW;
        int t = threadIdx.x;
        float s = 0.f, m = -1e30f;
        for (int i = t; i < HW; i += 256) { float v = p[i]; s += v; m = fmaxf(m, v); }
        __shared__ float ss[256], sm[256];
        ss[t] = s; sm[t] = m; __syncthreads();
        for (int o = 128; o > 0; o >>= 1) {
            if (t < o) { ss[t] += ss[t + o]; sm[t] = fmaxf(sm[t], sm[t + o]); }
            __syncthreads();
        }
        if (t == 0) { g_avg[bc] = ss[0] * (1.f / HW); g_mx[bc] = sm[0]; }
    }
}

// ---------------- channel weighting MLP + global-pool ASPP branch ----------------
__global__ void k_cw(const float* __restrict__ w1, const float* __restrict__ bb1,
                     const float* __restrict__ lg, const float* __restrict__ lb,
                     const float* __restrict__ w2, const float* __restrict__ bb2,
                     const float* __restrict__ apw, const float* __restrict__ apg,
                     const float* __restrict__ apb) {
    int b = blockIdx.x, t = threadIdx.x;
    __shared__ float o[CIN];
    __shared__ float h[COUT];
    __shared__ float red[256];
    __shared__ float gp[CIN];
    float avg = g_avg[b * CIN + t], mx = g_mx[b * CIN + t];
    o[t] = fabsf(avg - mx) * avg;
    __syncthreads();
    float hv = 0.f;
    if (t < COUT) {
        hv = bb1[t];
        const float* wr = w1 + t * CIN;
        for (int i = 0; i < CIN; i++) hv = fmaf(o[i], wr[i], hv);
    }
    red[t] = (t < COUT) ? hv : 0.f; __syncthreads();
    for (int s = 128; s > 0; s >>= 1) { if (t < s) red[t] += red[t + s]; __syncthreads(); }
    float mu = red[0] * (1.f / COUT); __syncthreads();
    float dv = (t < COUT) ? (hv - mu) : 0.f;
    red[t] = dv * dv; __syncthreads();
    for (int s = 128; s > 0; s >>= 1) { if (t < s) red[t] += red[t + s]; __syncthreads(); }
    float var = red[0] * (1.f / COUT); __syncthreads();
    if (t < COUT) h[t] = lg[t] * ((hv - mu) * rsqrtf(var + 1e-5f)) + lb[t];
    __syncthreads();
    float sv = bb2[t];
    const float* wr2 = w2 + t * COUT;
    for (int j = 0; j < COUT; j++) sv = fmaf(h[j], wr2[j], sv);
    float sig = 1.f / (1.f + expf(-sv));
    g_s[b * CIN + t] = sig;
    gp[t] = (1.f + sig) * avg;
    __syncthreads();
    float v = 0.f;
    const float* ar = apw + t * CIN;
    for (int i = 0; i < CIN; i++) v = fmaf(ar[i], gp[i], v);
    red[t] = v; __syncthreads();
    for (int s = 128; s > 0; s >>= 1) { if (t < s) red[t] += red[t + s]; __syncthreads(); }
    float mu2 = red[0] * (1.f / CIN); __syncthreads();
    float d2 = v - mu2; red[t] = d2 * d2; __syncthreads();
    for (int s = 128; s > 0; s >>= 1) { if (t < s) red[t] += red[t + s]; __syncthreads(); }
    float var2 = red[0] * (1.f / CIN); __syncthreads();
    float z = apg[t] * ((v - mu2) * rsqrtf(var2 + 1e-6f)) + apb[t];
    g_bp[b * CIN + t] = gelu_f(z);
}

// ---------------- xT / xcT split: x -> raw and scaled bf16 hi/lo [b][hw][c] --------
__global__ void k_xcsplit(const float* __restrict__ x) {
    __shared__ float tile[32][33];
    int b = blockIdx.z, c0 = blockIdx.y * 32, h0 = blockIdx.x * 32;
    int t = threadIdx.x;
    const float* xb = x + ((size_t)b * CIN + c0) * HW + h0;
#pragma unroll
    for (int i = 0; i < 4; i++) {
        int r = (t >> 5) + 8 * i;
        tile[r][t & 31] = xb[(size_t)r * HW + (t & 31)];
    }
    __syncthreads();
#pragma unroll
    for (int i = 0; i < 4; i++) {
        int hr = (t >> 5) + 8 * i, cc = t & 31;
        float vr = tile[cc][hr];
        size_t idx = ((size_t)b * HW + h0 + hr) * CIN + c0 + cc;
        __nv_bfloat16 h, l;
        splitf(vr, h, l);
        g_xTh[idx] = h; g_xTl[idx] = l;
        float v = vr * (1.f + g_s[b * CIN + c0 + cc]);
        splitf(v, h, l);
        g_xth[idx] = h; g_xtl[idx] = l;
    }
}

// ---------------- bp broadcast into catT channels [1024,1280) ----------------
__global__ void k_bp_cat() {
    int b = blockIdx.y, h0 = blockIdx.x * 32;
    int c = threadIdx.x;
    __nv_bfloat16 h, l; splitf(g_bp[b * CIN + c], h, l);
    for (int r = 0; r < 32; r++) {
        size_t idx = ((size_t)b * HW + h0 + r) * 1280 + 1024 + c;
        g_cth[idx] = h; g_ctl[idx] = l;
    }
}

struct AsppArgs {
    const __nv_bfloat16* wh[4];
    const __nv_bfloat16* wl[4];
    const float* g[4];
    const float* bt[4];
    int dil[4];
    int coff[4];
};

// ---------------- merged ASPP HMMA kernel: 256x128 tile, tri-buffer, Bx4 -----------
__global__ void __launch_bounds__(512, 1) k_aspp(
    AsppArgs A_, const __nv_bfloat16* __restrict__ Ihi, const __nv_bfloat16* __restrict__ Ilo,
    __nv_bfloat16* __restrict__ cth, __nv_bfloat16* __restrict__ ctl) {
    extern __shared__ __align__(16) char dsm[];
    __shared__ int s_tapn, s_tp[9], s_dy[9], s_dx[9];
    __shared__ float sgam[256], sbet[256], smean[128], srstd[128];
    __shared__ float red4[4][128];

    const int br = blockIdx.z, b = blockIdx.y, y = blockIdx.x;
    const int t = threadIdx.x, wid = t >> 5, lane = t & 31;
    const int mw = wid >> 2, nw = wid & 3;
    const uint32_t sbase = (uint32_t)__cvta_generic_to_shared(dsm);
    const __nv_bfloat16* Whi = A_.wh[br];
    const __nv_bfloat16* Wlo = A_.wl[br];
    const int dil = A_.dil[br], coff = A_.coff[br];

    if (t == 0) {
        if (dil == 0) {
            s_tapn = 1; s_tp[0] = 0; s_dy[0] = 0; s_dx[0] = 0;
        } else {
            int n = 0;
            for (int tap = 0; tap < 9; tap++) {
                int dy = (tap / 3 - 1) * dil;
                int y0 = y * 2 + dy, y1 = y * 2 + 1 + dy;
                if ((unsigned)y0 < 64u || (unsigned)y1 < 64u) {
                    s_tp[n] = tap; s_dy[n] = dy; s_dx[n] = (tap % 3 - 1) * dil; n++;
                }
            }
            s_tapn = n;
        }
    }
    if (t < 256) { sgam[t] = A_.g[br][t]; sbet[t] = A_.bt[br][t]; }
    __syncthreads();

    const int T = s_tapn * 8;
    const __nv_bfloat16* Ib_hi = Ihi + (size_t)b * HW * CIN;
    const __nv_bfloat16* Ib_lo = Ilo + (size_t)b * HW * CIN;

    float acc[4][4][4];
#pragma unroll
    for (int i = 0; i < 4; i++)
#pragma unroll
        for (int j = 0; j < 4; j++)
#pragma unroll
            for (int r = 0; r < 4; r++) acc[i][j][r] = 0.f;

    auto loadG = [&](int it, int buf) {
        int tap_i = it >> 3;
        int kc = (it & 7) * 32;
        uint32_t base = sbase + buf * 61440;
        int arow = t >> 1, ak = (t & 1) * 16;
        int grow = s_tp[tap_i] * 256 + arow;
        const __nv_bfloat16* ah = Whi + (size_t)grow * CIN + kc + ak;
        const __nv_bfloat16* al = Wlo + (size_t)grow * CIN + kc + ak;
        uint32_t da = base + arow * 80 + ak * 2;
        cp16(da, ah, 16);
        cp16(da + 16, ah + 8, 16);
        cp16(da + 20480, al, 16);
        cp16(da + 20480 + 16, al + 8, 16);
        int n = t >> 2, q = t & 3;
        int hw; int ok = 16;
        int yy = y * 2 + (n >> 6) + s_dy[tap_i];
        int xx = (n & 63) + s_dx[tap_i];
        if ((unsigned)yy < 64u && (unsigned)xx < 64u) hw = yy * 64 + xx;
        else { hw = 0; ok = (dil == 0) ? 16 : 0; }
        if (dil == 0) hw = y * 128 + n;
        uint32_t db = base + 40960 + n * 80 + q * 16;
        cp16(db, Ib_hi + (size_t)hw * CIN + kc + q * 8, ok);
        cp16(db + 10240, Ib_lo + (size_t)hw * CIN + kc + q * 8, ok);
        CP_COMMIT();
    };

    loadG(0, 0);
    if (T > 1) loadG(1, 1);

    const int lr = lane >> 2, lc = 2 * (lane & 3);
    const uint32_t a_loff = (uint32_t)(((lane & 7) + ((lane >> 3) & 1) * 8) * 80
                                       + (lane >> 4) * 16);
    const uint32_t b_loff4 = (uint32_t)(((lane & 7) + ((lane >> 4) & 1) * 8) * 80
                                        + ((lane >> 3) & 1) * 16);
    const uint32_t a_wbase = (uint32_t)(mw * 64 * 80) + a_loff;
    const uint32_t b_wbase = 40960u + (uint32_t)(nw * 32 * 80) + b_loff4;

    int cur = 0;
    for (int it = 0; it < T; ++it) {
        if (it + 1 < T) CP_WAIT1(); else CP_WAIT0();
        __syncthreads();
        uint32_t sb = sbase + cur * 61440;
#pragma unroll
        for (int ks = 0; ks < 2; ks++) {
            uint32_t kboff = ks * 32;
            uint32_t bh[4][2], bl[4][2];
#pragma unroll
            for (int jp = 0; jp < 2; jp++) {
                uint32_t ba = sb + b_wbase + jp * (16 * 80) + kboff;
                uint32_t r[4];
                ldsm_x4(r, ba);
                bh[2 * jp][0] = r[0]; bh[2 * jp][1] = r[1];
                bh[2 * jp + 1][0] = r[2]; bh[2 * jp + 1][1] = r[3];
                ldsm_x4(r, ba + 10240);
                bl[2 * jp][0] = r[0]; bl[2 * jp][1] = r[1];
                bl[2 * jp + 1][0] = r[2]; bl[2 * jp + 1][1] = r[3];
            }
#pragma unroll
            for (int i = 0; i < 4; i++) {
                uint32_t aa = sb + a_wbase + i * (16 * 80) + kboff;
                uint32_t ah[4], al[4];
                ldsm_x4(ah, aa);
                ldsm_x4(al, aa + 20480);
#pragma unroll
                for (int j = 0; j < 4; j++) {
                    mma16816(acc[i][j], ah, bh[j]);
                    mma16816(acc[i][j], ah, bl[j]);
                    mma16816(acc[i][j], al, bh[j]);
                }
            }
        }
        if (it + 2 < T) loadG(it + 2, (cur + 2 >= 3) ? cur - 1 : cur + 2);
        cur = (cur + 1 == 3) ? 0 : cur + 1;
    }
    __syncthreads();

    float* Ds = reinterpret_cast<float*>(dsm);
#pragma unroll
    for (int i = 0; i < 4; i++) {
        int r0 = mw * 64 + i * 16 + lr;
#pragma unroll
        for (int j = 0; j < 4; j++) {
            int c = nw * 32 + j * 8 + lc;
            Ds[r0 * 129 + c] = acc[i][j][0];
            Ds[r0 * 129 + c + 1] = acc[i][j][1];
            Ds[(r0 + 8) * 129 + c] = acc[i][j][2];
            Ds[(r0 + 8) * 129 + c + 1] = acc[i][j][3];
        }
    }
    __syncthreads();
    {
        int n = t & 127, p = t >> 7;
        float s = 0.f;
        for (int mm = p * 64; mm < p * 64 + 64; mm++) s += Ds[mm * 129 + n];
        red4[p][n] = s;
        __syncthreads();
        if (t < 128)
            smean[t] = (red4[0][t] + red4[1][t] + red4[2][t] + red4[3][t]) * (1.f / 256.f);
        __syncthreads();
        float mu = smean[n];
        s = 0.f;
        for (int mm = p * 64; mm < p * 64 + 64; mm++) {
            float d = Ds[mm * 129 + n] - mu; s += d * d;
        }
        red4[p][n] = s;
        __syncthreads();
        if (t < 128)
            srstd[t] = rsqrtf((red4[0][t] + red4[1][t] + red4[2][t] + red4[3][t]) * (1.f / 256.f) + 1e-6f);
        __syncthreads();
    }
    {
        int n2 = t >> 2, m0q = (t & 3) * 64;
        float mu = smean[n2], rs = srstd[n2];
        size_t rowb = ((size_t)b * HW + y * 128 + n2) * 1280 + coff + m0q;
#pragma unroll
        for (int blk = 0; blk < 64; blk += 8) {
            __align__(16) unsigned short h8[8], l8[8];
#pragma unroll
            for (int j = 0; j < 8; j++) {
                int m = m0q + blk + j;
                float vv = gelu_f((Ds[m * 129 + n2] - mu) * rs * sgam[m] + sbet[m]);
                __nv_bfloat16 h, l; splitf(vv, h, l);
                h8[j] = *reinterpret_cast<unsigned short*>(&h);
                l8[j] = *reinterpret_cast<unsigned short*>(&l);
            }
            *reinterpret_cast<uint4*>(cth + rowb + blk) = *reinterpret_cast<uint4*>(h8);
            *reinterpret_cast<uint4*>(ctl + rowb + blk) = *reinterpret_cast<uint4*>(l8);
        }
    }
}

// ---------------- HMMA GEMM M=256 (proj EPI1 -> bf16T split / conv2 EPI2 -> f32) ----
template <int EPI>
__global__ void __launch_bounds__(512, 1) k_hgemm(
    const __nv_bfloat16* __restrict__ Whi, const __nv_bfloat16* __restrict__ Wlo,
    const __nv_bfloat16* __restrict__ Ihi, const __nv_bfloat16* __restrict__ Ilo,
    const float* __restrict__ gam, const float* __restrict__ bet,
    float* __restrict__ outF, __nv_bfloat16* __restrict__ bth, __nv_bfloat16* __restrict__ btl,
    int ostride, int Kc) {
    extern __shared__ __align__(16) char dsm[];
    __shared__ float sgam[256], sbet[256], smean[128], srstd[128];
    __shared__ float red4[4][128];

    const int b = blockIdx.y, y = blockIdx.x;
    const int t = threadIdx.x, wid = t >> 5, lane = t & 31;
    const int mw = wid >> 2, nw = wid & 3;
    const uint32_t sbase = (uint32_t)__cvta_generic_to_shared(dsm);

    if (t < 256) { sgam[t] = gam[t]; sbet[t] = bet[t]; }
    __syncthreads();

    const int T = Kc / 32;
    const __nv_bfloat16* Ib_hi = Ihi + (size_t)b * HW * Kc;
    const __nv_bfloat16* Ib_lo = Ilo + (size_t)b * HW * Kc;

    float acc[4][4][4];
#pragma unroll
    for (int i = 0; i < 4; i++)
#pragma unroll
        for (int j = 0; j < 4; j++)
#pragma unroll
            for (int r = 0; r < 4; r++) acc[i][j][r] = 0.f;

    auto loadG = [&](int it, int buf) {
        int kc = it * 32;
        uint32_t base = sbase + buf * 61440;
        int arow = t >> 1, ak = (t & 1) * 16;
        const __nv_bfloat16* ah = Whi + (size_t)arow * Kc + kc + ak;
        const __nv_bfloat16* al = Wlo + (size_t)arow * Kc + kc + ak;
        uint32_t da = base + arow * 80 + ak * 2;
        cp16(da, ah, 16);
        cp16(da + 16, ah + 8, 16);
        cp16(da + 20480, al, 16);
        cp16(da + 20480 + 16, al + 8, 16);
        int n = t >> 2, q = t & 3;
        int hw = y * 128 + n;
        uint32_t db = base + 40960 + n * 80 + q * 16;
        cp16(db, Ib_hi + (size_t)hw * Kc + kc + q * 8, 16);
        cp16(db + 10240, Ib_lo + (size_t)hw * Kc + kc + q * 8, 16);
        CP_COMMIT();
    };

    loadG(0, 0);
    if (T > 1) loadG(1, 1);

    const int lr = lane >> 2, lc = 2 * (lane & 3);
    const uint32_t a_loff = (uint32_t)(((lane & 7) + ((lane >> 3) & 1) * 8) * 80
                                       + (lane >> 4) * 16);
    const uint32_t b_loff4 = (uint32_t)(((lane & 7) + ((lane >> 4) & 1) * 8) * 80
                                        + ((lane >> 3) & 1) * 16);
    const uint32_t a_wbase = (uint32_t)(mw * 64 * 80) + a_loff;
    const uint32_t b_wbase = 40960u + (uint32_t)(nw * 32 * 80) + b_loff4;

    int cur = 0;
    for (int it = 0; it < T; ++it) {
        if (it + 1 < T) CP_WAIT1(); else CP_WAIT0();
        __syncthreads();
        uint32_t sb = sbase + cur * 61440;
#pragma unroll
        for (int ks = 0; ks < 2; ks++) {
            uint32_t kboff = ks * 32;
            uint32_t bh[4][2], bl[4][2];
#pragma unroll
            for (int jp = 0; jp < 2; jp++) {
                uint32_t ba = sb + b_wbase + jp * (16 * 80) + kboff;
                uint32_t r[4];
                ldsm_x4(r, ba);
                bh[2 * jp][0] = r[0]; bh[2 * jp][1] = r[1];
                bh[2 * jp + 1][0] = r[2]; bh[2 * jp + 1][1] = r[3];
                ldsm_x4(r, ba + 10240);
                bl[2 * jp][0] = r[0]; bl[2 * jp][1] = r[1];
                bl[2 * jp + 1][0] = r[2]; bl[2 * jp + 1][1] = r[3];
            }
#pragma unroll
            for (int i = 0; i < 4; i++) {
                uint32_t aa = sb + a_wbase + i * (16 * 80) + kboff;
                uint32_t ah[4], al[4];
                ldsm_x4(ah, aa);
                ldsm_x4(al, aa + 20480);
#pragma unroll
                for (int j = 0; j < 4; j++) {
                    mma16816(acc[i][j], ah, bh[j]);
                    mma16816(acc[i][j], ah, bl[j]);
                    mma16816(acc[i][j], al, bh[j]);
                }
            }
        }
        if (it + 2 < T) loadG(it + 2, (cur + 2 >= 3) ? cur - 1 : cur + 2);
        cur = (cur + 1 == 3) ? 0 : cur + 1;
    }
    __syncthreads();

    float* Ds = reinterpret_cast<float*>(dsm);
#pragma unroll
    for (int i = 0; i < 4; i++) {
        int r0 = mw * 64 + i * 16 + lr;
#pragma unroll
        for (int j = 0; j < 4; j++) {
            int c = nw * 32 + j * 8 + lc;
            Ds[r0 * 129 + c] = acc[i][j][0];
            Ds[r0 * 129 + c + 1] = acc[i][j][1];
            Ds[(r0 + 8) * 129 + c] = acc[i][j][2];
            Ds[(r0 + 8) * 129 + c + 1] = acc[i][j][3];
        }
    }
    __syncthreads();
    if (EPI == 1) {
        int n = t & 127, p = t >> 7;
        float s = 0.f;
        for (int mm = p * 64; mm < p * 64 + 64; mm++) s += Ds[mm * 129 + n];
        red4[p][n] = s;
        __syncthreads();
        if (t < 128)
            smean[t] = (red4[0][t] + red4[1][t] + red4[2][t] + red4[3][t]) * (1.f / 256.f);
        __syncthreads();
        float mu = smean[n];
        s = 0.f;
        for (int mm = p * 64; mm < p * 64 + 64; mm++) {
            float d = Ds[mm * 129 + n] - mu; s += d * d;
        }
        red4[p][n] = s;
        __syncthreads();
        if (t < 128)
            srstd[t] = rsqrtf((red4[0][t] + red4[1][t] + red4[2][t] + red4[3][t]) * (1.f / 256.f) + 1e-6f);
        __syncthreads();
        // transposed bf16 split: row n2, 64-channel chunk
        int n2 = t >> 2, m0q = (t & 3) * 64;
        float mu2 = smean[n2], rs = srstd[n2];
        size_t rowb = ((size_t)b * HW + y * 128 + n2) * ostride + m0q;
#pragma unroll
        for (int blk = 0; blk < 64; blk += 8) {
            __align__(16) unsigned short h8[8], l8[8];
#pragma unroll
            for (int j = 0; j < 8; j++) {
                int m = m0q + blk + j;
                float vv = gelu_f((Ds[m * 129 + n2] - mu2) * rs * sgam[m] + sbet[m]);
                __nv_bfloat16 h, l; splitf(vv, h, l);
                h8[j] = *reinterpret_cast<unsigned short*>(&h);
                l8[j] = *reinterpret_cast<unsigned short*>(&l);
            }
            *reinterpret_cast<uint4*>(bth + rowb + blk) = *reinterpret_cast<uint4*>(h8);
            *reinterpret_cast<uint4*>(btl + rowb + blk) = *reinterpret_cast<uint4*>(l8);
        }
    } else {
        int m = t >> 1, nh = (t & 1) * 64;
        float bias = sgam[m];
        size_t ob = ((size_t)b * CIN + m) * HW + y * 128 + nh;
#pragma unroll
        for (int blk = 0; blk < 64; blk += 4) {
            float4 v4;
            float* vp = &v4.x;
#pragma unroll
            for (int j = 0; j < 4; j++) vp[j] = Ds[m * 129 + nh + blk + j] + bias;
            *reinterpret_cast<float4*>(outF + ob + blk) = v4;
        }
    }
}

// ---------------- HMMA conv1: 128x128 tile, K=256; fused dual-layout epilogue -------
// XA=false: x1  -> x1T split + x1 straight split
// XA=true : xa  -> xaT split + xa straight fp32
template <bool XA>
__global__ void __launch_bounds__(512, 1) k_conv1(
    const __nv_bfloat16* __restrict__ Whi, const __nv_bfloat16* __restrict__ Wlo,
    const __nv_bfloat16* __restrict__ Ihi, const __nv_bfloat16* __restrict__ Ilo,
    const float* __restrict__ bias,
    __nv_bfloat16* __restrict__ th, __nv_bfloat16* __restrict__ tl,
    __nv_bfloat16* __restrict__ sh, __nv_bfloat16* __restrict__ sl,
    float* __restrict__ sf) {
    extern __shared__ __align__(16) char dsm[];
    __shared__ float sb2[128];
    const int b = blockIdx.y, y = blockIdx.x;
    const int t = threadIdx.x, wid = t >> 5, lane = t & 31;
    const int mw = wid >> 2, nw = wid & 3;
    const uint32_t sbase = (uint32_t)__cvta_generic_to_shared(dsm);

    if (t < 128) sb2[t] = bias[t];
    __syncthreads();

    const __nv_bfloat16* Ib_hi = Ihi + (size_t)b * HW * CIN;
    const __nv_bfloat16* Ib_lo = Ilo + (size_t)b * HW * CIN;

    float acc[2][4][4];
#pragma unroll
    for (int i = 0; i < 2; i++)
#pragma unroll
        for (int j = 0; j < 4; j++)
#pragma unroll
            for (int r = 0; r < 4; r++) acc[i][j][r] = 0.f;

    auto loadG = [&](int it, int buf) {
        int kc = it * 32;
        uint32_t base = sbase + buf * 40960;
        int r = t >> 2, q = t & 3;
        cp16(base + r * 80 + q * 16, Whi + (size_t)r * CIN + kc + q * 8, 16);
        cp16(base + 10240 + r * 80 + q * 16, Wlo + (size_t)r * CIN + kc + q * 8, 16);
        int hw = y * 128 + r;
        cp16(base + 20480 + r * 80 + q * 16, Ib_hi + (size_t)hw * CIN + kc + q * 8, 16);
        cp16(base + 30720 + r * 80 + q * 16, Ib_lo + (size_t)hw * CIN + kc + q * 8, 16);
        CP_COMMIT();
    };

    loadG(0, 0);
    loadG(1, 1);

    const int lr = lane >> 2, lc = 2 * (lane & 3);
    const uint32_t a_loff = (uint32_t)(((lane & 7) + ((lane >> 3) & 1) * 8) * 80
                                       + (lane >> 4) * 16);
    const uint32_t b_loff4 = (uint32_t)(((lane & 7) + ((lane >> 4) & 1) * 8) * 80
                                        + ((lane >> 3) & 1) * 16);
    const uint32_t a_wbase = (uint32_t)(mw * 32 * 80) + a_loff;
    const uint32_t b_wbase = 20480u + (uint32_t)(nw * 32 * 80) + b_loff4;

    const int T = CIN / 32;  // 8
    int cur = 0;
    for (int it = 0; it < T; ++it) {
        if (it + 1 < T) CP_WAIT1(); else CP_WAIT0();
        __syncthreads();
        uint32_t sb = sbase + cur * 40960;
#pragma unroll
        for (int ks = 0; ks < 2; ks++) {
            uint32_t kboff = ks * 32;
            uint32_t bh[4][2], bl[4][2];
#pragma unroll
            for (int jp = 0; jp < 2; jp++) {
                uint32_t ba = sb + b_wbase + jp * (16 * 80) + kboff;
                uint32_t r[4];
                ldsm_x4(r, ba);
                bh[2 * jp][0] = r[0]; bh[2 * jp][1] = r[1];
                bh[2 * jp + 1][0] = r[2]; bh[2 * jp + 1][1] = r[3];
                ldsm_x4(r, ba + 10240);
                bl[2 * jp][0] = r[0]; bl[2 * jp][1] = r[1];
                bl[2 * jp + 1][0] = r[2]; bl[2 * jp + 1][1] = r[3];
            }
#pragma unroll
            for (int i = 0; i < 2; i++) {
                uint32_t aa = sb + a_wbase + i * (16 * 80) + kboff;
                uint32_t ah[4], al[4];
                ldsm_x4(ah, aa);
                ldsm_x4(al, aa + 10240);
#pragma unroll
                for (int j = 0; j < 4; j++) {
                    mma16816(acc[i][j], ah, bh[j]);
                    mma16816(acc[i][j], ah, bl[j]);
                    mma16816(acc[i][j], al, bh[j]);
                }
            }
        }
        if (it + 2 < T) loadG(it + 2, (cur + 2 >= 3) ? cur - 1 : cur + 2);
        cur = (cur + 1 == 3) ? 0 : cur + 1;
    }
    __syncthreads();

    // stage Ds[m][n] (128x128, pitch 129) with bias
    float* Ds = reinterpret_cast<float*>(dsm);
#pragma unroll
    for (int i = 0; i < 2; i++) {
        int r0 = mw * 32 + i * 16 + lr;
#pragma unroll
        for (int j = 0; j < 4; j++) {
            int c = nw * 32 + j * 8 + lc;
            Ds[r0 * 129 + c] = acc[i][j][0] + sb2[r0];
            Ds[r0 * 129 + c + 1] = acc[i][j][1] + sb2[r0];
            Ds[(r0 + 8) * 129 + c] = acc[i][j][2] + sb2[r0 + 8];
            Ds[(r0 + 8) * 129 + c + 1] = acc[i][j][3] + sb2[r0 + 8];
        }
    }
    __syncthreads();
    // transposed split: thread owns row n2 (hw), 32-channel chunk
    {
        int n2 = t >> 2, m0 = (t & 3) * 32;
        size_t rowb = ((size_t)b * HW + y * 128 + n2) * COUT + m0;
#pragma unroll
        for (int blk = 0; blk < 32; blk += 8) {
            __align__(16) unsigned short h8[8], l8[8];
#pragma unroll
            for (int j = 0; j < 8; j++) {
                float vv = Ds[(m0 + blk + j) * 129 + n2];
                __nv_bfloat16 h, l; splitf(vv, h, l);
                h8[j] = *reinterpret_cast<unsigned short*>(&h);
                l8[j] = *reinterpret_cast<unsigned short*>(&l);
            }
            *reinterpret_cast<uint4*>(th + rowb + blk) = *reinterpret_cast<uint4*>(h8);
            *reinterpret_cast<uint4*>(tl + rowb + blk) = *reinterpret_cast<uint4*>(l8);
        }
    }
    // straight: thread owns channel m, 32-hw chunk
    {
        int m = t >> 2, nh = (t & 3) * 32;
        size_t ob = ((size_t)b * COUT + m) * HW + y * 128 + nh;
        if (XA) {
#pragma unroll
            for (int blk = 0; blk < 32; blk += 4) {
                float4 v4;
                float* vp = &v4.x;
#pragma unroll
                for (int j = 0; j < 4; j++) vp[j] = Ds[m * 129 + nh + blk + j];
                *reinterpret_cast<float4*>(sf + ob + blk) = v4;
            }
        } else {
#pragma unroll
            for (int blk = 0; blk < 32; blk += 8) {
                __align__(16) unsigned short h8[8], l8[8];
#pragma unroll
                for (int j = 0; j < 8; j++) {
                    float vv = Ds[m * 129 + nh + blk + j];
                    __nv_bfloat16 h, l; splitf(vv, h, l);
                    h8[j] = *reinterpret_cast<unsigned short*>(&h);
                    l8[j] = *reinterpret_cast<unsigned short*>(&l);
                }
                *reinterpret_cast<uint4*>(sh + ob + blk) = *reinterpret_cast<uint4*>(h8);
                *reinterpret_cast<uint4*>(sl + ob + blk) = *reinterpret_cast<uint4*>(l8);
            }
        }
    }
}

// ---------------- HMMA S-GEMM: 256(q)x128(p), tri-buffer, Bx4 ----------
__global__ void __launch_bounds__(512, 1) k_sgemm2() {
    extern __shared__ __align__(16) char dsm[];
    const int b = blockIdx.z, q0 = blockIdx.y * 256, p0 = blockIdx.x * 128;
    const int t = threadIdx.x, wid = t >> 5, lane = t & 31;
    const int mw = wid >> 2, nw = wid & 3;
    const uint32_t sbase = (uint32_t)__cvta_generic_to_shared(dsm);
    const __nv_bfloat16* Qh = g_xath + (size_t)b * HW * COUT;
    const __nv_bfloat16* Ql = g_xatl + (size_t)b * HW * COUT;
    const __nv_bfloat16* Ph = g_x1th + (size_t)b * HW * COUT;
    const __nv_bfloat16* Pl = g_x1tl + (size_t)b * HW * COUT;

    float acc[4][4][4];
#pragma unroll
    for (int i = 0; i < 4; i++)
#pragma unroll
        for (int j = 0; j < 4; j++)
#pragma unroll
            for (int r = 0; r < 4; r++) acc[i][j][r] = 0.f;

    auto loadG = [&](int it, int buf) {
        int kc = it * 32;
        uint32_t base = sbase + buf * 61440;
        int arow = t >> 1, ak = (t & 1) * 16;
        const __nv_bfloat16* ah = Qh + (size_t)(q0 + arow) * COUT + kc + ak;
        const __nv_bfloat16* al = Ql + (size_t)(q0 + arow) * COUT + kc + ak;
        uint32_t da = base + arow * 80 + ak * 2;
        cp16(da, ah, 16);
        cp16(da + 16, ah + 8, 16);
        cp16(da + 20480, al, 16);
        cp16(da + 20480 + 16, al + 8, 16);
        int n = t >> 2, q = t & 3;
        uint32_t db = base + 40960 + n * 80 + q * 16;
        cp16(db, Ph + (size_t)(p0 + n) * COUT + kc + q * 8, 16);
        cp16(db + 10240, Pl + (size_t)(p0 + n) * COUT + kc + q * 8, 16);
        CP_COMMIT();
    };

    loadG(0, 0);
    loadG(1, 1);

    const int lr = lane >> 2, lc = 2 * (lane & 3);
    const uint32_t a_loff = (uint32_t)(((lane & 7) + ((lane >> 3) & 1) * 8) * 80
                                       + (lane >> 4) * 16);
    const uint32_t b_loff4 = (uint32_t)(((lane & 7) + ((lane >> 4) & 1) * 8) * 80
                                        + ((lane >> 3) & 1) * 16);
    const uint32_t a_wbase = (uint32_t)(mw * 64 * 80) + a_loff;
    const uint32_t b_wbase = 40960u + (uint32_t)(nw * 32 * 80) + b_loff4;

    const int T = COUT / 32;
    int cur = 0;
    for (int it = 0; it < T; ++it) {
        if (it + 1 < T) CP_WAIT1(); else CP_WAIT0();
        __syncthreads();
        uint32_t sb = sbase + cur * 61440;
#pragma unroll
        for (int ks = 0; ks < 2; ks++) {
            uint32_t kboff = ks * 32;
            uint32_t bh[4][2], bl[4][2];
#pragma unroll
            for (int jp = 0; jp < 2; jp++) {
                uint32_t ba = sb + b_wbase + jp * (16 * 80) + kboff;
                uint32_t r[4];
                ldsm_x4(r, ba);
                bh[2 * jp][0] = r[0]; bh[2 * jp][1] = r[1];
                bh[2 * jp + 1][0] = r[2]; bh[2 * jp + 1][1] = r[3];
                ldsm_x4(r, ba + 10240);
                bl[2 * jp][0] = r[0]; bl[2 * jp][1] = r[1];
                bl[2 * jp + 1][0] = r[2]; bl[2 * jp + 1][1] = r[3];
            }
#pragma unroll
            for (int i = 0; i < 4; i++) {
                uint32_t aa = sb + a_wbase + i * (16 * 80) + kboff;
                uint32_t ah[4], al[4];
                ldsm_x4(ah, aa);
                ldsm_x4(al, aa + 20480);
#pragma unroll
                for (int j = 0; j < 4; j++) {
                    mma16816(acc[i][j], ah, bh[j]);
                    mma16816(acc[i][j], ah, bl[j]);
                    mma16816(acc[i][j], al, bh[j]);
                }
            }
        }
        if (it + 2 < T) loadG(it + 2, (cur + 2 >= 3) ? cur - 1 : cur + 2);
        cur = (cur + 1 == 3) ? 0 : cur + 1;
    }
    __syncthreads();

    float* Ds = reinterpret_cast<float*>(dsm);
#pragma unroll
    for (int i = 0; i < 4; i++) {
        int r0 = mw * 64 + i * 16 + lr;
#pragma unroll
        for (int j = 0; j < 4; j++) {
            int c = nw * 32 + j * 8 + lc;
            Ds[r0 * 129 + c] = acc[i][j][0];
            Ds[r0 * 129 + c + 1] = acc[i][j][1];
            Ds[(r0 + 8) * 129 + c] = acc[i][j][2];
            Ds[(r0 + 8) * 129 + c + 1] = acc[i][j][3];
        }
    }
    __syncthreads();
    {
        const float sc = 1.f / 64.f;
        int m = t >> 1, nh = (t & 1) * 64;
        float* So = g_S + (size_t)b * HW * HW + (size_t)(q0 + m) * HW + p0 + nh;
#pragma unroll
        for (int blk = 0; blk < 64; blk += 4) {
            float4 v4;
            float* vp = &v4.x;
#pragma unroll
            for (int j = 0; j < 4; j++) vp[j] = Ds[m * 129 + nh + blk + j] * sc;
            *reinterpret_cast<float4*>(So + blk) = v4;
        }
    }
}

// ---------------- row softmax; emits bf16 hi/lo probs ----------------
__global__ void __launch_bounds__(256) k_softmax() {
    const size_t row = blockIdx.x;
    const float* r = g_S + row * (size_t)HW;
    __nv_bfloat16* oh = g_Ah + row * (size_t)HW;
    __nv_bfloat16* ol = g_Al + row * (size_t)HW;
    __shared__ float buf[HW];
    __shared__ float red[256];
    int t = threadIdx.x;
    float m = -1e30f;
    for (int i = t; i < HW; i += 256) { float v = r[i]; buf[i] = v; m = fmaxf(m, v); }
    red[t] = m; __syncthreads();
    for (int s = 128; s > 0; s >>= 1) { if (t < s) red[t] = fmaxf(red[t], red[t + s]); __syncthreads(); }
    float mx = red[0]; __syncthreads();
    float s = 0.f;
    for (int i = t; i < HW; i += 256) { float e = expf(buf[i] - mx); buf[i] = e; s += e; }
    red[t] = s; __syncthreads();
    for (int o = 128; o > 0; o >>= 1) { if (t < o) red[t] += red[t + o]; __syncthreads(); }
    float inv = 1.f / red[0];
    for (int i = t; i < HW; i += 256) {
        float p = buf[i] * inv;
        __nv_bfloat16 h, l; splitf(p, h, l);
        oh[i] = h; ol[i] = l;
    }
}

// ---------------- HMMA L-GEMM: 128(c)x128(j), tri-buffer, trans-B x4 ----------
__global__ void __launch_bounds__(512, 1) k_lgemm2() {
    extern __shared__ __align__(16) char dsm[];
    const int b = blockIdx.y, j0g = blockIdx.x * 128;
    const int t = threadIdx.x, wid = t >> 5, lane = t & 31;
    const int mw = wid >> 2, nw = wid & 3;
    const uint32_t sbase = (uint32_t)__cvta_generic_to_shared(dsm);
    const __nv_bfloat16* Xh = g_x1h + (size_t)b * COUT * HW;
    const __nv_bfloat16* Xl = g_x1l + (size_t)b * COUT * HW;
    const __nv_bfloat16* Aph = g_Ah + (size_t)b * HW * HW;
    const __nv_bfloat16* Apl = g_Al + (size_t)b * HW * HW;

    float acc[2][4][4];
#pragma unroll
    for (int i = 0; i < 2; i++)
#pragma unroll
        for (int j = 0; j < 4; j++)
#pragma unroll
            for (int r = 0; r < 4; r++) acc[i][j][r] = 0.f;

    auto loadG = [&](int it, int buf) {
        int kc = it * 32;
        uint32_t base = sbase + buf * 37888;
        int c = t >> 2, cq = t & 3;
        const __nv_bfloat16* ah = Xh + (size_t)c * HW + kc + cq * 8;
        const __nv_bfloat16* al = Xl + (size_t)c * HW + kc + cq * 8;
        uint32_t da = base + c * 80 + cq * 16;
        cp16(da, ah, 16);
        cp16(da + 10240, al, 16);
        int k = t >> 4, jt = t & 15;
        const __nv_bfloat16* bh = Aph + (size_t)(kc + k) * HW + j0g + jt * 8;
        const __nv_bfloat16* bl = Apl + (size_t)(kc + k) * HW + j0g + jt * 8;
        uint32_t db = base + 20480 + k * 272 + jt * 16;
        cp16(db, bh, 16);
        cp16(db + 8704, bl, 16);
        CP_COMMIT();
    };

    loadG(0, 0);
    loadG(1, 1);

    const int lr = lane >> 2, lc = 2 * (lane & 3);
    const uint32_t a_loff = (uint32_t)(((lane & 7) + ((lane >> 3) & 1) * 8) * 80
                                       + (lane >> 4) * 16);
    const uint32_t a_wbase = (uint32_t)(mw * 32 * 80) + a_loff;
    const uint32_t bt_loff4 = (uint32_t)((lane & 15) * 272 + ((lane >> 4) & 1) * 16);

    const int T = HW / 32;
    int cur = 0;
    for (int it = 0; it < T; ++it) {
        if (it + 1 < T) CP_WAIT1(); else CP_WAIT0();
        __syncthreads();
        uint32_t sb = sbase + cur * 37888;
#pragma unroll
        for (int ks = 0; ks < 2; ks++) {
            uint32_t bh[4][2], bl[4][2];
#pragma unroll
            for (int jp = 0; jp < 2; jp++) {
                uint32_t ba = sb + 20480 + bt_loff4 + ks * (16 * 272)
                              + (nw * 32 + jp * 16) * 2;
                uint32_t r[4];
                ldsm_x4t(r, ba);
                bh[2 * jp][0] = r[0]; bh[2 * jp][1] = r[1];
                bh[2 * jp + 1][0] = r[2]; bh[2 * jp + 1][1] = r[3];
                ldsm_x4t(r, ba + 8704);
                bl[2 * jp][0] = r[0]; bl[2 * jp][1] = r[1];
                bl[2 * jp + 1][0] = r[2]; bl[2 * jp + 1][1] = r[3];
            }
#pragma unroll
            for (int i = 0; i < 2; i++) {
                uint32_t aa = sb + a_wbase + i * (16 * 80) + ks * 32;
                uint32_t ah[4], al[4];
                ldsm_x4(ah, aa);
                ldsm_x4(al, aa + 10240);
#pragma unroll
                for (int j = 0; j < 4; j++) {
                    mma16816(acc[i][j], ah, bh[j]);
                    mma16816(acc[i][j], ah, bl[j]);
                    mma16816(acc[i][j], al, bh[j]);
                }
            }
        }
        if (it + 2 < T) loadG(it + 2, (cur + 2 >= 3) ? cur - 1 : cur + 2);
        cur = (cur + 1 == 3) ? 0 : cur + 1;
    }
    __syncthreads();

    const float* xab = g_xa + (size_t)b * COUT * HW;
    float* Ds = reinterpret_cast<float*>(dsm);
#pragma unroll
    for (int i = 0; i < 2; i++) {
#pragma unroll
        for (int j = 0; j < 4; j++) {
            int c = mw * 32 + i * 16 + lr;
            int col = nw * 32 + j * 8 + lc;
            size_t i0 = (size_t)c * HW + j0g + col;
            size_t i8 = (size_t)(c + 8) * HW + j0g + col;
            float2 x0 = *reinterpret_cast<const float2*>(xab + i0);
            float2 x8 = *reinterpret_cast<const float2*>(xab + i8);
            Ds[col * 129 + c] = acc[i][j][0] + x0.x;
            Ds[(col + 1) * 129 + c] = acc[i][j][1] + x0.y;
            Ds[col * 129 + c + 8] = acc[i][j][2] + x8.x;
            Ds[(col + 1) * 129 + c + 8] = acc[i][j][3] + x8.y;
        }
    }
    __syncthreads();
    {
        int jj = t >> 2, c0q = (t & 3) * 32;
        size_t rowb = ((size_t)b * HW + j0g + jj) * COUT + c0q;
#pragma unroll
        for (int blk = 0; blk < 32; blk += 8) {
            __align__(16) unsigned short h8[8], l8[8];
#pragma unroll
            for (int j = 0; j < 8; j++) {
                float vv = Ds[jj * 129 + c0q + blk + j];
                __nv_bfloat16 h, l; splitf(vv, h, l);
                h8[j] = *reinterpret_cast<unsigned short*>(&h);
                l8[j] = *reinterpret_cast<unsigned short*>(&l);
            }
            *reinterpret_cast<uint4*>(g_oth + rowb + blk) = *reinterpret_cast<uint4*>(h8);
            *reinterpret_cast<uint4*>(g_otl + rowb + blk) = *reinterpret_cast<uint4*>(l8);
        }
    }
}

// ---------------- host launch ----------------
extern "C" void kernel_launch(void* const* d_in, const int* in_sizes, int n_in,
                              void* d_out, int out_size) {
    (void)in_sizes; (void)n_in; (void)out_size;
    const float* x       = (const float*)d_in[0];
    const float* conv1_w = (const float*)d_in[1];
    const float* conv1_b = (const float*)d_in[2];
    const float* conv2_w = (const float*)d_in[3];
    const float* conv2_b = (const float*)d_in[4];
    const float* cw_w1   = (const float*)d_in[5];
    const float* cw_b1   = (const float*)d_in[6];
    const float* cw_ln_g = (const float*)d_in[7];
    const float* cw_ln_b = (const float*)d_in[8];
    const float* cw_w2   = (const float*)d_in[9];
    const float* cw_b2   = (const float*)d_in[10];
    const float* aspp0_w = (const float*)d_in[11];
    const float* aspp0_g = (const float*)d_in[12];
    const float* aspp0_b = (const float*)d_in[13];
    const float* aspp1_w = (const float*)d_in[14];
    const float* aspp1_g = (const float*)d_in[15];
    const float* aspp1_b = (const float*)d_in[16];
    const float* aspp2_w = (const float*)d_in[17];
    const float* aspp2_g = (const float*)d_in[18];
    const float* aspp2_b = (const float*)d_in[19];
    const float* aspp3_w = (const float*)d_in[20];
    const float* aspp3_g = (const float*)d_in[21];
    const float* aspp3_b = (const float*)d_in[22];
    const float* asppp_w = (const float*)d_in[23];
    const float* asppp_g = (const float*)d_in[24];
    const float* asppp_b = (const float*)d_in[25];
    const float* proj_w  = (const float*)d_in[26];
    const float* proj_g  = (const float*)d_in[27];
    const float* proj_b  = (const float*)d_in[28];

    void* pv;
    float *p_xa;
    __nv_bfloat16 *p_xth, *p_xtl, *p_xTh, *p_xTl, *p_cth, *p_ctl, *p_pth, *p_ptl;
    __nv_bfloat16 *p_w3h, *p_w3l, *p_a0h, *p_a0l, *p_pjh, *p_pjl, *p_c2h, *p_c2l, *p_c1h, *p_c1l;
    __nv_bfloat16 *p_x1th, *p_x1tl, *p_xath, *p_xatl, *p_x1h, *p_x1l, *p_oth, *p_otl;
    cudaGetSymbolAddress(&pv, g_xa);   p_xa   = (float*)pv;
    cudaGetSymbolAddress(&pv, g_xth);  p_xth  = (__nv_bfloat16*)pv;
    cudaGetSymbolAddress(&pv, g_xtl);  p_xtl  = (__nv_bfloat16*)pv;
    cudaGetSymbolAddress(&pv, g_xTh);  p_xTh  = (__nv_bfloat16*)pv;
    cudaGetSymbolAddress(&pv, g_xTl);  p_xTl  = (__nv_bfloat16*)pv;
    cudaGetSymbolAddress(&pv, g_cth);  p_cth  = (__nv_bfloat16*)pv;
    cudaGetSymbolAddress(&pv, g_ctl);  p_ctl  = (__nv_bfloat16*)pv;
    cudaGetSymbolAddress(&pv, g_pth);  p_pth  = (__nv_bfloat16*)pv;
    cudaGetSymbolAddress(&pv, g_ptl);  p_ptl  = (__nv_bfloat16*)pv;
    cudaGetSymbolAddress(&pv, g_w3h);  p_w3h  = (__nv_bfloat16*)pv;
    cudaGetSymbolAddress(&pv, g_w3l);  p_w3l  = (__nv_bfloat16*)pv;
    cudaGetSymbolAddress(&pv, g_a0h);  p_a0h  = (__nv_bfloat16*)pv;
    cudaGetSymbolAddress(&pv, g_a0l);  p_a0l  = (__nv_bfloat16*)pv;
    cudaGetSymbolAddress(&pv, g_pjh);  p_pjh  = (__nv_bfloat16*)pv;
    cudaGetSymbolAddress(&pv, g_pjl);  p_pjl  = (__nv_bfloat16*)pv;
    cudaGetSymbolAddress(&pv, g_c2h);  p_c2h  = (__nv_bfloat16*)pv;
    cudaGetSymbolAddress(&pv, g_c2l);  p_c2l  = (__nv_bfloat16*)pv;
    cudaGetSymbolAddress(&pv, g_c1h);  p_c1h  = (__nv_bfloat16*)pv;
    cudaGetSymbolAddress(&pv, g_c1l);  p_c1l  = (__nv_bfloat16*)pv;
    cudaGetSymbolAddress(&pv, g_x1th); p_x1th = (__nv_bfloat16*)pv;
    cudaGetSymbolAddress(&pv, g_x1tl); p_x1tl = (__nv_bfloat16*)pv;
    cudaGetSymbolAddress(&pv, g_xath); p_xath = (__nv_bfloat16*)pv;
    cudaGetSymbolAddress(&pv, g_xatl); p_xatl = (__nv_bfloat16*)pv;
    cudaGetSymbolAddress(&pv, g_x1h);  p_x1h  = (__nv_bfloat16*)pv;
    cudaGetSymbolAddress(&pv, g_x1l);  p_x1l  = (__nv_bfloat16*)pv;
    cudaGetSymbolAddress(&pv, g_oth);  p_oth  = (__nv_bfloat16*)pv;
    cudaGetSymbolAddress(&pv, g_otl);  p_otl  = (__nv_bfloat16*)pv;

    const int TRI_SMEM = 184320;
    const int C1_SMEM = 122880;
    cudaFuncSetAttribute(k_aspp, cudaFuncAttributeMaxDynamicSharedMemorySize, TRI_SMEM);
    cudaFuncSetAttribute(k_hgemm<1>, cudaFuncAttributeMaxDynamicSharedMemorySize, TRI_SMEM);
    cudaFuncSetAttribute(k_hgemm<2>, cudaFuncAttributeMaxDynamicSharedMemorySize, TRI_SMEM);
    cudaFuncSetAttribute(k_conv1<false>, cudaFuncAttributeMaxDynamicSharedMemorySize, C1_SMEM);
    cudaFuncSetAttribute(k_conv1<true>, cudaFuncAttributeMaxDynamicSharedMemorySize, C1_SMEM);
    cudaFuncSetAttribute(k_sgemm2, cudaFuncAttributeMaxDynamicSharedMemorySize, TRI_SMEM);
    cudaFuncSetAttribute(k_lgemm2, cudaFuncAttributeMaxDynamicSharedMemorySize, 113664);

    dim3 gh(HW / 128, BATCH);

    AsppArgs aa;
    aa.wh[0] = p_a0h; aa.wl[0] = p_a0l; aa.g[0] = aspp0_g; aa.bt[0] = aspp0_b;
    aa.dil[0] = 0; aa.coff[0] = 0;
    aa.wh[1] = p_w3h; aa.wl[1] = p_w3l; aa.g[1] = aspp1_g; aa.bt[1] = aspp1_b;
    aa.dil[1] = 3; aa.coff[1] = 256;
    aa.wh[2] = p_w3h + 9 * 65536; aa.wl[2] = p_w3l + 9 * 65536;
    aa.g[2] = aspp2_g; aa.bt[2] = aspp2_b; aa.dil[2] = 6; aa.coff[2] = 512;
    aa.wh[3] = p_w3h + 18 * 65536; aa.wl[3] = p_w3l + 18 * 65536;
    aa.g[3] = aspp3_g; aa.bt[3] = aspp3_b; aa.dil[3] = 9; aa.coff[3] = 768;

    k_prep<<<3584, 256>>>(aspp1_w, aspp2_w, aspp3_w, aspp0_w, proj_w, conv2_w, conv1_w, x);
    k_cw<<<BATCH, 256>>>(cw_w1, cw_b1, cw_ln_g, cw_ln_b, cw_w2, cw_b2,
                         asppp_w, asppp_g, asppp_b);
    k_xcsplit<<<dim3(128, 8, BATCH), 256>>>(x);
    // merged ASPP branches
    k_aspp<<<dim3(HW / 128, BATCH, 4), 512, TRI_SMEM>>>(aa, p_xth, p_xtl, p_cth, p_ctl);
    k_bp_cat<<<dim3(128, BATCH), 256>>>();
    // proj (K=1280) -> projT bf16 split
    k_hgemm<1><<<gh, 512, TRI_SMEM>>>(p_pjh, p_pjl, p_cth, p_ctl,
                                      proj_g, proj_b, nullptr, p_pth, p_ptl, CIN, 5 * CIN);
    // conv1 x2 (HMMA, fused layout epilogues)
    k_conv1<false><<<gh, 512, C1_SMEM>>>(p_c1h, p_c1l, p_xTh, p_xTl, conv1_b,
                                         p_x1th, p_x1tl, p_x1h, p_x1l, nullptr);
    k_conv1<true><<<gh, 512, C1_SMEM>>>(p_c1h, p_c1l, p_pth, p_ptl, conv1_b,
                                        p_xath, p_xatl, nullptr, nullptr, p_xa);
    // attention
    k_sgemm2<<<dim3(HW / 128, HW / 256, BATCH), 512, TRI_SMEM>>>();
    k_softmax<<<BATCH * HW, 256>>>();
    k_lgemm2<<<dim3(HW / 128, BATCH), 512, 113664>>>();
    // conv2 (HMMA bias epilogue, K=128)
    k_hgemm<2><<<gh, 512, TRI_SMEM>>>(p_c2h, p_c2l, p_oth, p_otl,
                                      conv2_b, conv2_b, (float*)d_out, nullptr, nullptr,
                                      0, COUT);
}